// round 3
// baseline (speedup 1.0000x reference)
#include <cuda_runtime.h>
#include <math.h>

#define BB 2
#define LL 2048
#define DD 1024
#define HH 4
#define DV 256
#define CKN 32
#define NC 64              // LL / CKN
#define NROW (BB*LL)       // 4096
#define GIN 1056
#define HID 2048
#define NG 8               // Dv groups of 32 in the scan

// ------------------------- scratch (device globals) -------------------------
__device__ float g_qlin[NROW*DD];
__device__ float g_klin[NROW*DD];
__device__ float g_vlin[NROW*DD];
__device__ float g_qc[NROW*DD];
__device__ float g_kc[NROW*DD];
__device__ float g_vc[NROW*DD];
__device__ float g_beta[NROW*HH];
__device__ float g_qn[NROW*DD];
__device__ float g_kn[NROW*DD];
__device__ float g_u[NROW*DD];
__device__ float g_w[NROW*DD];
__device__ float g_attn[BB*HH*NC*CKN*CKN];
__device__ float g_delta[NROW*DD];
__device__ float g_short[NROW*DD];
__device__ float g_long[NROW*DD];
__device__ float g_gatein[NROW*GIN];
__device__ float g_hmid[NROW*HID];
__device__ float g_probs[NROW*16];
__device__ float g_mix[NROW*DD];

// ------------------------- generic SGEMM: C = A(MxK) @ B(NxK)^T --------------
// mode 0: plain.  mode 1: +bias[col], exact GELU.
__global__ __launch_bounds__(256) void sgemm_nt(
    const float* __restrict__ A, const float* __restrict__ B,
    float* __restrict__ C, const float* __restrict__ bias,
    int M, int N, int K, int mode)
{
    __shared__ float As[8][128];
    __shared__ float Bs[8][128];
    int tid = threadIdx.x;
    int bm = blockIdx.y * 128, bn = blockIdx.x * 128;
    int lr = tid >> 1;
    int lc = (tid & 1) * 4;
    const float* Ap = A + (size_t)(bm + lr) * K + lc;
    const float* Bp = B + (size_t)(bn + lr) * K + lc;
    int ty = tid >> 4, tx = tid & 15;
    float acc[8][8];
#pragma unroll
    for (int i = 0; i < 8; i++)
#pragma unroll
        for (int j = 0; j < 8; j++) acc[i][j] = 0.f;

    for (int kt = 0; kt < K; kt += 8) {
        float4 av = *(const float4*)(Ap + kt);
        float4 bv = *(const float4*)(Bp + kt);
        As[lc+0][lr] = av.x; As[lc+1][lr] = av.y; As[lc+2][lr] = av.z; As[lc+3][lr] = av.w;
        Bs[lc+0][lr] = bv.x; Bs[lc+1][lr] = bv.y; Bs[lc+2][lr] = bv.z; Bs[lc+3][lr] = bv.w;
        __syncthreads();
#pragma unroll
        for (int kk = 0; kk < 8; kk++) {
            float a[8], b[8];
            *(float4*)(a)   = *(const float4*)&As[kk][ty*8];
            *(float4*)(a+4) = *(const float4*)&As[kk][ty*8+4];
            *(float4*)(b)   = *(const float4*)&Bs[kk][tx*8];
            *(float4*)(b+4) = *(const float4*)&Bs[kk][tx*8+4];
#pragma unroll
            for (int i = 0; i < 8; i++)
#pragma unroll
                for (int j = 0; j < 8; j++) acc[i][j] = fmaf(a[i], b[j], acc[i][j]);
        }
        __syncthreads();
    }
#pragma unroll
    for (int i = 0; i < 8; i++) {
        int row = bm + ty*8 + i;
        float v[8];
#pragma unroll
        for (int j = 0; j < 8; j++) {
            float x = acc[i][j];
            if (mode == 1) {
                x += bias[bn + tx*8 + j];
                x = 0.5f * x * (1.f + erff(x * 0.70710678118654752f));
            }
            v[j] = x;
        }
        *(float4*)&C[(size_t)row*N + bn + tx*8]     = *(float4*)(v);
        *(float4*)&C[(size_t)row*N + bn + tx*8 + 4] = *(float4*)(v+4);
    }
}

// ------------------------- depthwise causal conv4 + SiLU --------------------
__global__ __launch_bounds__(256) void conv4_silu(
    const float* __restrict__ x, const float* __restrict__ w, float* __restrict__ y)
{
    int idx = blockIdx.x * 256 + threadIdx.x;       // over NROW*DD
    int d = idx & (DD-1);
    int l = (idx >> 10) & (LL-1);
    float4 wv = *(const float4*)(w + d*4);
    const float* xp = x + (size_t)idx;
    float acc = wv.w * xp[0];
    if (l >= 1) acc += wv.z * xp[-DD];
    if (l >= 2) acc += wv.y * xp[-2*DD];
    if (l >= 3) acc += wv.x * xp[-3*DD];
    y[idx] = acc / (1.f + expf(-acc));
}

// ------------------------- beta = sigmoid(hs @ Wb^T) ------------------------
__global__ __launch_bounds__(128) void beta_kernel(
    const float* __restrict__ hs, const float* __restrict__ Wb)
{
    __shared__ float red[4][128];
    int n = blockIdx.x, tid = threadIdx.x;
    const float* hr = hs + (size_t)n * DD;
    float s0=0,s1=0,s2=0,s3=0;
    for (int i = tid; i < DD; i += 128) {
        float x = hr[i];
        s0 += x * Wb[i];
        s1 += x * Wb[DD + i];
        s2 += x * Wb[2*DD + i];
        s3 += x * Wb[3*DD + i];
    }
    red[0][tid]=s0; red[1][tid]=s1; red[2][tid]=s2; red[3][tid]=s3;
    __syncthreads();
    for (int st = 64; st > 0; st >>= 1) {
        if (tid < st)
#pragma unroll
            for (int h = 0; h < 4; h++) red[h][tid] += red[h][tid + st];
        __syncthreads();
    }
    if (tid < 4) g_beta[(size_t)n*HH + tid] = 1.f / (1.f + expf(-red[tid][0]));
}

// ------------------------- per-chunk delta-rule precompute ------------------
__global__ __launch_bounds__(256) void precompute_kernel()
{
    __shared__ float ks[32][261];
    __shared__ float Am[32][33];
    __shared__ float rnk[32], rnq[32], bet[32];
    int blk = blockIdx.x;           // (b*HH + h)*NC + c
    int c  = blk % NC;
    int bh = blk / NC;
    int h  = bh % HH;
    int b  = bh / HH;
    int tid = threadIdx.x;
    int l0 = c * 32;

    for (int e = tid; e < 32*256; e += 256) {
        int r = e >> 8, d = e & 255;
        ks[r][d] = g_kc[((size_t)(b*LL + l0 + r))*DD + h*DV + d];
    }
    if (tid < 32) bet[tid] = g_beta[((size_t)(b*LL + l0 + tid))*HH + h];
    __syncthreads();

    {   // k row norms
        int r = tid >> 3, part = tid & 7;
        float s = 0.f;
        for (int j = 0; j < 32; j++) { float x = ks[r][part*32 + j]; s += x*x; }
        s += __shfl_down_sync(0xffffffffu, s, 4, 8);
        s += __shfl_down_sync(0xffffffffu, s, 2, 8);
        s += __shfl_down_sync(0xffffffffu, s, 1, 8);
        if (part == 0) rnk[r] = rsqrtf(s + 1e-6f);
    }
    {   // q row norms (from global)
        int r = tid >> 3, part = tid & 7;
        const float* qrow = g_qc + ((size_t)(b*LL + l0 + r))*DD + h*DV;
        float s = 0.f;
        for (int j = 0; j < 32; j++) { float x = qrow[part*32 + j]; s += x*x; }
        s += __shfl_down_sync(0xffffffffu, s, 4, 8);
        s += __shfl_down_sync(0xffffffffu, s, 2, 8);
        s += __shfl_down_sync(0xffffffffu, s, 1, 8);
        if (part == 0) rnq[r] = rsqrtf(s + 1e-6f);
    }
    __syncthreads();

    size_t obase = (size_t)blk * (32*256);
    for (int e = tid; e < 32*256; e += 256) {
        int r = e >> 8, d = e & 255;
        float kv = ks[r][d] * rnk[r];
        ks[r][d] = kv;
        g_kn[obase + e] = kv;
        float qv = g_qc[((size_t)(b*LL + l0 + r))*DD + h*DV + d] * rnq[r];
        g_qn[obase + e] = qv;
    }
    __syncthreads();

    // A = -beta_i * (kn_i . kn_j), strictly lower
    for (int e = tid; e < 1024; e += 256) {
        int i = e >> 5, j = e & 31;
        float a = 0.f;
        if (j < i) {
            float s = 0.f;
            for (int d = 0; d < 256; d++) s += ks[i][d] * ks[j][d];
            a = -bet[i] * s;
        }
        Am[i][j] = a;
    }
    __syncthreads();

    // iterative inversion: row i gets A[i,:i] += A[i,:] @ A[:, :i]
    if (tid < 32) {
        int lane = tid;
        for (int i = 1; i < 32; i++) {
            float t = 0.f;
            if (lane < i) for (int p = 0; p < i; p++) t += Am[i][p] * Am[p][lane];
            __syncwarp();
            if (lane < i) Am[i][lane] += t;
            __syncwarp();
        }
    }
    __syncthreads();
    if (tid < 32) Am[tid][tid] += 1.f;     // T = A + I
    __syncthreads();

    // u = T @ (beta*v),  w = T @ (beta*kn)
    {
        int d = tid;
        float vr[32], kr[32];
#pragma unroll
        for (int j = 0; j < 32; j++) {
            vr[j] = g_vc[((size_t)(b*LL + l0 + j))*DD + h*DV + d] * bet[j];
            kr[j] = ks[j][d] * bet[j];
        }
        for (int i = 0; i < 32; i++) {
            float su = 0.f, sw = 0.f;
#pragma unroll
            for (int j = 0; j < 32; j++) {
                float a = Am[i][j];
                su = fmaf(a, vr[j], su);
                sw = fmaf(a, kr[j], sw);
            }
            g_u[obase + i*256 + d] = su;
            g_w[obase + i*256 + d] = sw;
        }
    }

    // attn = tril(qn @ kn^T) incl. diagonal
    {
        size_t abase = (size_t)blk * 1024;
        for (int e = tid*4; e < tid*4 + 4; e++) {
            int i = e >> 5, j = e & 31;
            float a = 0.f;
            if (j <= i) {
                const float* qrow = g_qn + obase + i*256;
                float s = 0.f;
                for (int d = 0; d < 256; d++) s += qrow[d] * ks[j][d];
                a = s;
            }
            g_attn[abase + e] = a;
        }
    }
}

// ------------------------- sequential inter-chunk scan ----------------------
#define SCAN_SMEM ((256*33 + 32*257 + 2*32*33) * 4)
__global__ __launch_bounds__(256) void scan_kernel()
{
    extern __shared__ float sm[];
    float* S    = sm;                   // 256 x 33
    float* tile = S + 256*33;           // 32 x 257
    float* Ui   = tile + 32*257;        // 32 x 33
    float* At   = Ui + 32*33;           // 32 x 33

    int blk = blockIdx.x;               // (b*HH+h)*NG + g
    int g  = blk & (NG-1);
    int bh = blk >> 3;
    int b  = bh >> 2;
    int h  = bh & 3;
    int tid = threadIdx.x;
    int cc = tid & 31;
    int rq = tid >> 5;                  // 0..7
    int r0 = rq * 4;
    int p0 = rq * 32;

    for (int e = tid; e < 256*33; e += 256) S[e] = 0.f;
    __syncthreads();

    for (int c = 0; c < NC; c++) {
        size_t base = ((size_t)bh*NC + c) * (32*256);
        for (int e = tid; e < 1024; e += 256) {
            int r = e >> 5, j = e & 31;
            Ui[r*33 + j] = g_u[base + r*256 + g*32 + j];
            At[r*33 + j] = g_attn[((size_t)bh*NC + c)*1024 + e];
        }
        for (int e = tid; e < 8192; e += 256)
            tile[(e>>8)*257 + (e&255)] = g_w[base + e];
        __syncthreads();

        // u_i = u - w @ S
        float a0 = Ui[(r0+0)*33+cc], a1 = Ui[(r0+1)*33+cc];
        float a2 = Ui[(r0+2)*33+cc], a3 = Ui[(r0+3)*33+cc];
        for (int p = 0; p < 256; p++) {
            float s = S[p*33 + cc];
            a0 -= tile[(r0+0)*257+p] * s;
            a1 -= tile[(r0+1)*257+p] * s;
            a2 -= tile[(r0+2)*257+p] * s;
            a3 -= tile[(r0+3)*257+p] * s;
        }
        Ui[(r0+0)*33+cc] = a0; Ui[(r0+1)*33+cc] = a1;
        Ui[(r0+2)*33+cc] = a2; Ui[(r0+3)*33+cc] = a3;
        __syncthreads();

        // load q tile; hoist u_i column
        for (int e = tid; e < 8192; e += 256)
            tile[(e>>8)*257 + (e&255)] = g_qn[base + e];
        float ur[32];
#pragma unroll
        for (int j = 0; j < 32; j++) ur[j] = Ui[j*33 + cc];
        __syncthreads();

        // o = q @ S + attn @ u_i
        float o0=0.f,o1=0.f,o2=0.f,o3=0.f;
        for (int p = 0; p < 256; p++) {
            float s = S[p*33 + cc];
            o0 = fmaf(tile[(r0+0)*257+p], s, o0);
            o1 = fmaf(tile[(r0+1)*257+p], s, o1);
            o2 = fmaf(tile[(r0+2)*257+p], s, o2);
            o3 = fmaf(tile[(r0+3)*257+p], s, o3);
        }
#pragma unroll
        for (int j = 0; j < 32; j++) {
            float u = ur[j];
            o0 = fmaf(At[(r0+0)*33+j], u, o0);
            o1 = fmaf(At[(r0+1)*33+j], u, o1);
            o2 = fmaf(At[(r0+2)*33+j], u, o2);
            o3 = fmaf(At[(r0+3)*33+j], u, o3);
        }
        {
            size_t ob = ((size_t)(b*LL + c*32 + r0))*DD + h*DV + g*32 + cc;
            g_delta[ob]        = o0;
            g_delta[ob + DD]   = o1;
            g_delta[ob + 2*DD] = o2;
            g_delta[ob + 3*DD] = o3;
        }
        __syncthreads();

        // load k tile
        for (int e = tid; e < 8192; e += 256)
            tile[(e>>8)*257 + (e&255)] = g_kn[base + e];
        __syncthreads();

        // S += k^T @ u_i
        for (int p = p0; p < p0 + 32; p++) {
            float a = 0.f;
#pragma unroll
            for (int r = 0; r < 32; r++) a = fmaf(tile[r*257 + p], ur[r], a);
            S[p*33 + cc] += a;
        }
        __syncthreads();
    }
}

// ------------------------- per-(head,channel) FIR conv ----------------------
template<int K>
__global__ __launch_bounds__(256) void fir_kernel(
    const float* __restrict__ fw, float* __restrict__ y)
{
    __shared__ float vbuf[(128 + K - 1) * 32];
    __shared__ float wbuf[32 * K];
    int bh = blockIdx.x;
    int b = bh / HH, h = bh % HH;
    int l0 = blockIdx.y * 128;
    int d0 = blockIdx.z * 32;
    int tid = threadIdx.x;

    for (int idx = tid; idx < 32*K; idx += 256)
        wbuf[idx] = fw[(size_t)(h*DV + d0)*K + idx];
    for (int idx = tid; idx < (128 + K - 1)*32; idx += 256) {
        int lr = idx >> 5, d = idx & 31;
        int l = l0 - (K - 1) + lr;
        vbuf[idx] = (l >= 0) ? g_vc[((size_t)(b*LL + l))*DD + h*DV + d0 + d] : 0.f;
    }
    __syncthreads();

    int d = tid & 31;
    int lr0 = (tid >> 5) * 16;
    for (int m = 0; m < 16; m++) {
        int lr = lr0 + m;
        float acc = 0.f;
#pragma unroll
        for (int t = 0; t < K; t++)
            acc = fmaf(vbuf[(lr + t)*32 + d], wbuf[d*K + t], acc);
        y[((size_t)(b*LL + l0 + lr))*DD + h*DV + d0 + d] = acc;
    }
}

// ------------------------- gate input assembly (hs + stats) -----------------
__global__ __launch_bounds__(256) void stats_kernel(const float* __restrict__ hs)
{
    int n = blockIdx.x, tid = threadIdx.x;
    for (int i = tid; i < DD; i += 256)
        g_gatein[(size_t)n*GIN + i] = hs[(size_t)n*DD + i];
    int warp = tid >> 5, lane = tid & 31;
    for (int rep = 0; rep < 2; rep++) {
        int combo = warp*2 + rep;
        int path = combo >> 2, h = combo & 3;
        const float* p;
        if      (path == 0) p = g_short;
        else if (path == 1) p = g_long;
        else if (path == 2) p = g_delta;
        else                p = g_vc;
        p += (size_t)n*DD + h*DV;
        float s1 = 0.f, s2 = 0.f;
        for (int j = lane; j < 256; j += 32) { float x = p[j]; s1 += x; s2 += x*x; }
#pragma unroll
        for (int st = 16; st > 0; st >>= 1) {
            s1 += __shfl_down_sync(0xffffffffu, s1, st);
            s2 += __shfl_down_sync(0xffffffffu, s2, st);
        }
        if (lane == 0) {
            float m  = s1 * (1.f/256.f);
            float va = s2 * (1.f/256.f) - m*m;
            g_gatein[(size_t)n*GIN + DD + path*8 + h*2]     = m;
            g_gatein[(size_t)n*GIN + DD + path*8 + h*2 + 1] = va;
        }
    }
}

// ------------------------- gate2 + softmax + floor --------------------------
__global__ __launch_bounds__(256) void gate2_kernel(
    const float* __restrict__ w2, const float* __restrict__ log_temp,
    const float* __restrict__ base_bias, const float* __restrict__ floor_raw)
{
    __shared__ float hrow[HID];
    __shared__ float lg[16];
    int n = blockIdx.x, tid = threadIdx.x;
    for (int i = tid; i < HID; i += 256) hrow[i] = g_hmid[(size_t)n*HID + i];
    __syncthreads();
    int warp = tid >> 5, lane = tid & 31;
    for (int rep = 0; rep < 2; rep++) {
        int o = warp*2 + rep;
        const float* wr = w2 + (size_t)o*HID;
        float s = 0.f;
        for (int i = lane; i < HID; i += 32) s = fmaf(hrow[i], wr[i], s);
#pragma unroll
        for (int st = 16; st > 0; st >>= 1) s += __shfl_down_sync(0xffffffffu, s, st);
        if (lane == 0) lg[o] = s;
    }
    __syncthreads();
    if (tid < 4) {
        int h = tid;
        float temp = log1pf(expf(log_temp[h])) + 1e-4f;
        float z[4], m = -1e30f;
#pragma unroll
        for (int i = 0; i < 4; i++) {
            z[i] = (lg[h*4+i] + base_bias[h*4+i]) / temp;
            m = fmaxf(m, z[i]);
        }
        float e[4], s = 0.f;
#pragma unroll
        for (int i = 0; i < 4; i++) { e[i] = expf(z[i] - m); s += e[i]; }
        float p[4], s2 = 0.f;
#pragma unroll
        for (int i = 0; i < 4; i++) {
            p[i] = e[i] / s;
            float f = 0.05f / (1.f + expf(-floor_raw[h*4+i]));
            p[i] = fmaxf(p[i], f);
            s2 += p[i];
        }
#pragma unroll
        for (int i = 0; i < 4; i++) g_probs[(size_t)n*16 + h*4 + i] = p[i] / s2;
    }
}

// ------------------------- path mix + RMS norm ------------------------------
__global__ __launch_bounds__(256) void mix_kernel(const float* __restrict__ onorm)
{
    __shared__ float pr[16];
    __shared__ float wsum[8];
    int n = blockIdx.x, tid = threadIdx.x;
    if (tid < 16) pr[tid] = g_probs[(size_t)n*16 + tid];
    __syncthreads();
    int h = tid >> 6;
    int dd = (tid & 63) * 4;
    size_t pb = (size_t)n*DD + h*DV + dd;
    float4 sh = *(const float4*)&g_short[pb];
    float4 lo = *(const float4*)&g_long[pb];
    float4 de = *(const float4*)&g_delta[pb];
    float4 vv = *(const float4*)&g_vc[pb];
    float p0 = pr[h*4+0], p1 = pr[h*4+1], p2 = pr[h*4+2], p3 = pr[h*4+3];
    float o[4];
    o[0] = p0*sh.x + p1*lo.x + p2*de.x + p3*vv.x;
    o[1] = p0*sh.y + p1*lo.y + p2*de.y + p3*vv.y;
    o[2] = p0*sh.z + p1*lo.z + p2*de.z + p3*vv.z;
    o[3] = p0*sh.w + p1*lo.w + p2*de.w + p3*vv.w;
    float ss = o[0]*o[0] + o[1]*o[1] + o[2]*o[2] + o[3]*o[3];
#pragma unroll
    for (int st = 16; st > 0; st >>= 1) ss += __shfl_down_sync(0xffffffffu, ss, st);
    int warp = tid >> 5, lane = tid & 31;
    if (lane == 0) wsum[warp] = ss;
    __syncthreads();
    float tot = wsum[h*2] + wsum[h*2+1];
    float scale = rsqrtf(tot * (1.f/256.f) + 1e-5f);
    float r[4];
#pragma unroll
    for (int j = 0; j < 4; j++) r[j] = o[j] * scale * onorm[dd + j];
    *(float4*)&g_mix[pb] = *(float4*)r;
}

// ------------------------- launch ------------------------------------------
extern "C" void kernel_launch(void* const* d_in, const int* in_sizes, int n_in,
                              void* d_out, int out_size)
{
    const float* hs        = (const float*)d_in[0];
    const float* Wq        = (const float*)d_in[1];
    const float* Wk        = (const float*)d_in[2];
    const float* Wv        = (const float*)d_in[3];
    const float* Wb        = (const float*)d_in[4];
    const float* qconv_w   = (const float*)d_in[5];
    const float* kconv_w   = (const float*)d_in[6];
    const float* vconv_w   = (const float*)d_in[7];
    const float* fir_s     = (const float*)d_in[8];
    const float* fir_l     = (const float*)d_in[9];
    const float* gate_w1   = (const float*)d_in[10];
    const float* gate_b1   = (const float*)d_in[11];
    const float* gate_w2   = (const float*)d_in[12];
    const float* log_temp  = (const float*)d_in[13];
    const float* base_bias = (const float*)d_in[14];
    const float* floor_raw = (const float*)d_in[15];
    const float* onorm_w   = (const float*)d_in[16];
    const float* Wo        = (const float*)d_in[17];
    float* out = (float*)d_out;

    void *p_qlin, *p_klin, *p_vlin, *p_qc, *p_kc, *p_vc, *p_gatein, *p_hmid,
         *p_mix, *p_short, *p_long;
    cudaGetSymbolAddress(&p_qlin, g_qlin);
    cudaGetSymbolAddress(&p_klin, g_klin);
    cudaGetSymbolAddress(&p_vlin, g_vlin);
    cudaGetSymbolAddress(&p_qc, g_qc);
    cudaGetSymbolAddress(&p_kc, g_kc);
    cudaGetSymbolAddress(&p_vc, g_vc);
    cudaGetSymbolAddress(&p_gatein, g_gatein);
    cudaGetSymbolAddress(&p_hmid, g_hmid);
    cudaGetSymbolAddress(&p_mix, g_mix);
    cudaGetSymbolAddress(&p_short, g_short);
    cudaGetSymbolAddress(&p_long, g_long);

    cudaFuncSetAttribute(scan_kernel,
        cudaFuncAttributeMaxDynamicSharedMemorySize, SCAN_SMEM);

    dim3 blk(256);
    dim3 gD(DD/128, NROW/128);          // N=1024 GEMMs

    // q/k/v projections
    sgemm_nt<<<gD, blk>>>(hs, Wq, (float*)p_qlin, nullptr, NROW, DD, DD, 0);
    sgemm_nt<<<gD, blk>>>(hs, Wk, (float*)p_klin, nullptr, NROW, DD, DD, 0);
    sgemm_nt<<<gD, blk>>>(hs, Wv, (float*)p_vlin, nullptr, NROW, DD, DD, 0);

    // causal conv4 + SiLU
    int nconv = NROW*DD/256;
    conv4_silu<<<nconv, blk>>>((const float*)p_qlin, qconv_w, (float*)p_qc);
    conv4_silu<<<nconv, blk>>>((const float*)p_klin, kconv_w, (float*)p_kc);
    conv4_silu<<<nconv, blk>>>((const float*)p_vlin, vconv_w, (float*)p_vc);

    // beta
    beta_kernel<<<NROW, 128>>>(hs, Wb);

    // delta-rule
    precompute_kernel<<<BB*HH*NC, blk>>>();
    scan_kernel<<<BB*HH*NG, blk, SCAN_SMEM>>>();

    // FIR paths
    fir_kernel<3><<<dim3(BB*HH, LL/128, DV/32), blk>>>(fir_s, (float*)p_short);
    fir_kernel<63><<<dim3(BB*HH, LL/128, DV/32), blk>>>(fir_l, (float*)p_long);

    // gate
    stats_kernel<<<NROW, blk>>>(hs);
    sgemm_nt<<<dim3(HID/128, NROW/128), blk>>>((const float*)p_gatein, gate_w1,
                                               (float*)p_hmid, gate_b1,
                                               NROW, HID, GIN, 1);
    gate2_kernel<<<NROW, blk>>>(gate_w2, log_temp, base_bias, floor_raw);

    // mix + RMS norm
    mix_kernel<<<NROW, blk>>>(onorm_w);

    // output projection
    sgemm_nt<<<gD, blk>>>((const float*)p_mix, Wo, out, nullptr, NROW, DD, DD, 0);
}

// round 4
// speedup vs baseline: 1.3775x; 1.3775x over previous
#include <cuda_runtime.h>
#include <math.h>

#define BB 2
#define LL 2048
#define DD 1024
#define HH 4
#define DV 256
#define CKN 32
#define NC 64              // LL / CKN
#define NROW (BB*LL)       // 4096
#define GIN 1056
#define HID 2048
#define NG 8               // Dv groups of 32 in the scan

// ------------------------- scratch (device globals) -------------------------
__device__ float g_qlin[NROW*DD];
__device__ float g_klin[NROW*DD];
__device__ float g_vlin[NROW*DD];
__device__ float g_qc[NROW*DD];
__device__ float g_kc[NROW*DD];
__device__ float g_vc[NROW*DD];
__device__ float g_beta[NROW*HH];
__device__ float g_qn[NROW*DD];
__device__ float g_kn[NROW*DD];
__device__ float g_u[NROW*DD];
__device__ float g_w[NROW*DD];
__device__ float g_attn[BB*HH*NC*CKN*CKN];
__device__ float g_delta[NROW*DD];
__device__ float g_short[NROW*DD];
__device__ float g_long[NROW*DD];
__device__ float g_gatein[NROW*GIN];
__device__ float g_hmid[NROW*HID];
__device__ float g_probs[NROW*16];
__device__ float g_mix[NROW*DD];

// ------------------------- tf32 helpers -------------------------------------
__device__ __forceinline__ unsigned f2tf(float x) {
    unsigned r;
    asm("cvt.rna.tf32.f32 %0, %1;" : "=r"(r) : "f"(x));
    return r;
}

__device__ __forceinline__ void mma_tf32(float* c, const unsigned* a, const unsigned* b) {
    asm volatile(
        "mma.sync.aligned.m16n8k8.row.col.f32.tf32.tf32.f32 "
        "{%0,%1,%2,%3}, {%4,%5,%6,%7}, {%8,%9}, {%0,%1,%2,%3};"
        : "+f"(c[0]), "+f"(c[1]), "+f"(c[2]), "+f"(c[3])
        : "r"(a[0]), "r"(a[1]), "r"(a[2]), "r"(a[3]), "r"(b[0]), "r"(b[1]));
}

// ------------------- tf32 tensor-core GEMM: C = A(MxK) @ B(NxK)^T ------------
// Block tile 128x128, 256 threads (8 warps, 2x4), warp tile 64x32.
// blockIdx.z selects among up to 3 (B, C) pairs for batching q/k/v.
// mode 0: plain.  mode 1: +bias[col], exact GELU.
#define LDB 20
__global__ __launch_bounds__(256, 2) void tf32_gemm(
    const float* __restrict__ A,
    const float* __restrict__ Bm0, const float* __restrict__ Bm1, const float* __restrict__ Bm2,
    float* __restrict__ Cm0, float* __restrict__ Cm1, float* __restrict__ Cm2,
    const float* __restrict__ bias, int M, int N, int K, int mode)
{
    __shared__ unsigned As[2][128*LDB];
    __shared__ unsigned Bs[2][128*LDB];

    const float* B = (blockIdx.z == 0) ? Bm0 : (blockIdx.z == 1) ? Bm1 : Bm2;
    float*       C = (blockIdx.z == 0) ? Cm0 : (blockIdx.z == 1) ? Cm1 : Cm2;

    int tid  = threadIdx.x;
    int bm   = blockIdx.y * 128, bn = blockIdx.x * 128;
    int lrow = tid >> 1;
    int lcol = (tid & 1) * 8;
    const float* Ap = A + (size_t)(bm + lrow) * K + lcol;
    const float* Bp = B + (size_t)(bn + lrow) * K + lcol;

    int wid = tid >> 5, lane = tid & 31;
    int wm = (wid >> 2) * 64, wn = (wid & 3) * 32;
    int lr = lane >> 2, lk = lane & 3;

    float acc[4][4][4];
#pragma unroll
    for (int mi = 0; mi < 4; mi++)
#pragma unroll
        for (int ni = 0; ni < 4; ni++)
#pragma unroll
            for (int j = 0; j < 4; j++) acc[mi][ni][j] = 0.f;

    // preload tile 0
    {
        float4 a0 = *(const float4*)(Ap);
        float4 a1 = *(const float4*)(Ap + 4);
        float4 b0 = *(const float4*)(Bp);
        float4 b1 = *(const float4*)(Bp + 4);
        unsigned* as = &As[0][lrow*LDB + lcol];
        unsigned* bs = &Bs[0][lrow*LDB + lcol];
        as[0]=f2tf(a0.x); as[1]=f2tf(a0.y); as[2]=f2tf(a0.z); as[3]=f2tf(a0.w);
        as[4]=f2tf(a1.x); as[5]=f2tf(a1.y); as[6]=f2tf(a1.z); as[7]=f2tf(a1.w);
        bs[0]=f2tf(b0.x); bs[1]=f2tf(b0.y); bs[2]=f2tf(b0.z); bs[3]=f2tf(b0.w);
        bs[4]=f2tf(b1.x); bs[5]=f2tf(b1.y); bs[6]=f2tf(b1.z); bs[7]=f2tf(b1.w);
    }

    int niter = K >> 4;
    int cur = 0;
    for (int it = 0; it < niter; it++) {
        __syncthreads();
        float4 na0, na1, nb0, nb1;
        bool more = (it + 1 < niter);
        if (more) {
            const float* Ap2 = Ap + (it + 1) * 16;
            const float* Bp2 = Bp + (it + 1) * 16;
            na0 = *(const float4*)(Ap2);
            na1 = *(const float4*)(Ap2 + 4);
            nb0 = *(const float4*)(Bp2);
            nb1 = *(const float4*)(Bp2 + 4);
        }

        const unsigned* Ac = As[cur];
        const unsigned* Bc = Bs[cur];
#pragma unroll
        for (int ks = 0; ks < 2; ks++) {
            int kb = ks * 8;
            unsigned af[4][4], bf[4][2];
#pragma unroll
            for (int mi = 0; mi < 4; mi++) {
                int r = wm + mi*16 + lr;
                af[mi][0] = Ac[r*LDB + kb + lk];
                af[mi][1] = Ac[(r+8)*LDB + kb + lk];
                af[mi][2] = Ac[r*LDB + kb + lk + 4];
                af[mi][3] = Ac[(r+8)*LDB + kb + lk + 4];
            }
#pragma unroll
            for (int ni = 0; ni < 4; ni++) {
                int n = wn + ni*8 + lr;
                bf[ni][0] = Bc[n*LDB + kb + lk];
                bf[ni][1] = Bc[n*LDB + kb + lk + 4];
            }
#pragma unroll
            for (int mi = 0; mi < 4; mi++)
#pragma unroll
                for (int ni = 0; ni < 4; ni++)
                    mma_tf32(acc[mi][ni], af[mi], bf[ni]);
        }

        if (more) {
            int nxt = cur ^ 1;
            unsigned* as = &As[nxt][lrow*LDB + lcol];
            unsigned* bs = &Bs[nxt][lrow*LDB + lcol];
            as[0]=f2tf(na0.x); as[1]=f2tf(na0.y); as[2]=f2tf(na0.z); as[3]=f2tf(na0.w);
            as[4]=f2tf(na1.x); as[5]=f2tf(na1.y); as[6]=f2tf(na1.z); as[7]=f2tf(na1.w);
            bs[0]=f2tf(nb0.x); bs[1]=f2tf(nb0.y); bs[2]=f2tf(nb0.z); bs[3]=f2tf(nb0.w);
            bs[4]=f2tf(nb1.x); bs[5]=f2tf(nb1.y); bs[6]=f2tf(nb1.z); bs[7]=f2tf(nb1.w);
        }
        cur ^= 1;
    }

#pragma unroll
    for (int mi = 0; mi < 4; mi++) {
        int r0 = bm + wm + mi*16 + lr;
#pragma unroll
        for (int ni = 0; ni < 4; ni++) {
            int c = bn + wn + ni*8 + 2*lk;
            float v[4] = {acc[mi][ni][0], acc[mi][ni][1], acc[mi][ni][2], acc[mi][ni][3]};
            if (mode == 1) {
                float b0 = bias[c], b1 = bias[c+1];
                v[0] += b0; v[1] += b1; v[2] += b0; v[3] += b1;
#pragma unroll
                for (int j = 0; j < 4; j++)
                    v[j] = 0.5f * v[j] * (1.f + erff(v[j] * 0.70710678118654752f));
            }
            float2 lo = {v[0], v[1]};
            float2 hi = {v[2], v[3]};
            *(float2*)&C[(size_t)r0*N + c]       = lo;
            *(float2*)&C[(size_t)(r0+8)*N + c]   = hi;
        }
    }
}

// ------------------------- depthwise causal conv4 + SiLU --------------------
__global__ __launch_bounds__(256) void conv4_silu(
    const float* __restrict__ x, const float* __restrict__ w, float* __restrict__ y)
{
    int idx = blockIdx.x * 256 + threadIdx.x;       // over NROW*DD
    int d = idx & (DD-1);
    int l = (idx >> 10) & (LL-1);
    float4 wv = *(const float4*)(w + d*4);
    const float* xp = x + (size_t)idx;
    float acc = wv.w * xp[0];
    if (l >= 1) acc += wv.z * xp[-DD];
    if (l >= 2) acc += wv.y * xp[-2*DD];
    if (l >= 3) acc += wv.x * xp[-3*DD];
    y[idx] = acc / (1.f + expf(-acc));
}

// ------------------------- beta = sigmoid(hs @ Wb^T) ------------------------
__global__ __launch_bounds__(128) void beta_kernel(
    const float* __restrict__ hs, const float* __restrict__ Wb)
{
    __shared__ float red[4][128];
    int n = blockIdx.x, tid = threadIdx.x;
    const float* hr = hs + (size_t)n * DD;
    float s0=0,s1=0,s2=0,s3=0;
    for (int i = tid; i < DD; i += 128) {
        float x = hr[i];
        s0 += x * Wb[i];
        s1 += x * Wb[DD + i];
        s2 += x * Wb[2*DD + i];
        s3 += x * Wb[3*DD + i];
    }
    red[0][tid]=s0; red[1][tid]=s1; red[2][tid]=s2; red[3][tid]=s3;
    __syncthreads();
    for (int st = 64; st > 0; st >>= 1) {
        if (tid < st)
#pragma unroll
            for (int h = 0; h < 4; h++) red[h][tid] += red[h][tid + st];
        __syncthreads();
    }
    if (tid < 4) g_beta[(size_t)n*HH + tid] = 1.f / (1.f + expf(-red[tid][0]));
}

// ------------------------- per-chunk delta-rule precompute ------------------
__global__ __launch_bounds__(256) void precompute_kernel()
{
    __shared__ float ks[32][261];
    __shared__ float Am[32][33];
    __shared__ float rnk[32], rnq[32], bet[32];
    int blk = blockIdx.x;           // (b*HH + h)*NC + c
    int c  = blk % NC;
    int bh = blk / NC;
    int h  = bh % HH;
    int b  = bh / HH;
    int tid = threadIdx.x;
    int l0 = c * 32;

    for (int e = tid; e < 32*256; e += 256) {
        int r = e >> 8, d = e & 255;
        ks[r][d] = g_kc[((size_t)(b*LL + l0 + r))*DD + h*DV + d];
    }
    if (tid < 32) bet[tid] = g_beta[((size_t)(b*LL + l0 + tid))*HH + h];
    __syncthreads();

    {   // k row norms
        int r = tid >> 3, part = tid & 7;
        float s = 0.f;
        for (int j = 0; j < 32; j++) { float x = ks[r][part*32 + j]; s += x*x; }
        s += __shfl_down_sync(0xffffffffu, s, 4, 8);
        s += __shfl_down_sync(0xffffffffu, s, 2, 8);
        s += __shfl_down_sync(0xffffffffu, s, 1, 8);
        if (part == 0) rnk[r] = rsqrtf(s + 1e-6f);
    }
    {   // q row norms (from global)
        int r = tid >> 3, part = tid & 7;
        const float* qrow = g_qc + ((size_t)(b*LL + l0 + r))*DD + h*DV;
        float s = 0.f;
        for (int j = 0; j < 32; j++) { float x = qrow[part*32 + j]; s += x*x; }
        s += __shfl_down_sync(0xffffffffu, s, 4, 8);
        s += __shfl_down_sync(0xffffffffu, s, 2, 8);
        s += __shfl_down_sync(0xffffffffu, s, 1, 8);
        if (part == 0) rnq[r] = rsqrtf(s + 1e-6f);
    }
    __syncthreads();

    size_t obase = (size_t)blk * (32*256);
    for (int e = tid; e < 32*256; e += 256) {
        int r = e >> 8, d = e & 255;
        float kv = ks[r][d] * rnk[r];
        ks[r][d] = kv;
        g_kn[obase + e] = kv;
        float qv = g_qc[((size_t)(b*LL + l0 + r))*DD + h*DV + d] * rnq[r];
        g_qn[obase + e] = qv;
    }
    __syncthreads();

    // A = -beta_i * (kn_i . kn_j), strictly lower
    for (int e = tid; e < 1024; e += 256) {
        int i = e >> 5, j = e & 31;
        float a = 0.f;
        if (j < i) {
            float s = 0.f;
            for (int d = 0; d < 256; d++) s += ks[i][d] * ks[j][d];
            a = -bet[i] * s;
        }
        Am[i][j] = a;
    }
    __syncthreads();

    // iterative inversion: row i gets A[i,:i] += A[i,:] @ A[:, :i]
    if (tid < 32) {
        int lane = tid;
        for (int i = 1; i < 32; i++) {
            float t = 0.f;
            if (lane < i) for (int p = 0; p < i; p++) t += Am[i][p] * Am[p][lane];
            __syncwarp();
            if (lane < i) Am[i][lane] += t;
            __syncwarp();
        }
    }
    __syncthreads();
    if (tid < 32) Am[tid][tid] += 1.f;     // T = A + I
    __syncthreads();

    // u = T @ (beta*v),  w = T @ (beta*kn)
    {
        int d = tid;
        float vr[32], kr[32];
#pragma unroll
        for (int j = 0; j < 32; j++) {
            vr[j] = g_vc[((size_t)(b*LL + l0 + j))*DD + h*DV + d] * bet[j];
            kr[j] = ks[j][d] * bet[j];
        }
        for (int i = 0; i < 32; i++) {
            float su = 0.f, sw = 0.f;
#pragma unroll
            for (int j = 0; j < 32; j++) {
                float a = Am[i][j];
                su = fmaf(a, vr[j], su);
                sw = fmaf(a, kr[j], sw);
            }
            g_u[obase + i*256 + d] = su;
            g_w[obase + i*256 + d] = sw;
        }
    }

    // attn = tril(qn @ kn^T) incl. diagonal
    {
        size_t abase = (size_t)blk * 1024;
        for (int e = tid*4; e < tid*4 + 4; e++) {
            int i = e >> 5, j = e & 31;
            float a = 0.f;
            if (j <= i) {
                const float* qrow = g_qn + obase + i*256;
                float s = 0.f;
                for (int d = 0; d < 256; d++) s += qrow[d] * ks[j][d];
                a = s;
            }
            g_attn[abase + e] = a;
        }
    }
}

// ------------------------- sequential inter-chunk scan ----------------------
#define SCAN_SMEM ((256*33 + 32*257 + 2*32*33) * 4)
__global__ __launch_bounds__(256) void scan_kernel()
{
    extern __shared__ float sm[];
    float* S    = sm;                   // 256 x 33
    float* tile = S + 256*33;           // 32 x 257
    float* Ui   = tile + 32*257;        // 32 x 33
    float* At   = Ui + 32*33;           // 32 x 33

    int blk = blockIdx.x;               // (b*HH+h)*NG + g
    int g  = blk & (NG-1);
    int bh = blk >> 3;
    int b  = bh >> 2;
    int h  = bh & 3;
    int tid = threadIdx.x;
    int cc = tid & 31;
    int rq = tid >> 5;                  // 0..7
    int r0 = rq * 4;
    int p0 = rq * 32;

    for (int e = tid; e < 256*33; e += 256) S[e] = 0.f;
    __syncthreads();

    for (int c = 0; c < NC; c++) {
        size_t base = ((size_t)bh*NC + c) * (32*256);
        for (int e = tid; e < 1024; e += 256) {
            int r = e >> 5, j = e & 31;
            Ui[r*33 + j] = g_u[base + r*256 + g*32 + j];
            At[r*33 + j] = g_attn[((size_t)bh*NC + c)*1024 + e];
        }
        for (int e = tid; e < 8192; e += 256)
            tile[(e>>8)*257 + (e&255)] = g_w[base + e];
        __syncthreads();

        // u_i = u - w @ S
        float a0 = Ui[(r0+0)*33+cc], a1 = Ui[(r0+1)*33+cc];
        float a2 = Ui[(r0+2)*33+cc], a3 = Ui[(r0+3)*33+cc];
        for (int p = 0; p < 256; p++) {
            float s = S[p*33 + cc];
            a0 -= tile[(r0+0)*257+p] * s;
            a1 -= tile[(r0+1)*257+p] * s;
            a2 -= tile[(r0+2)*257+p] * s;
            a3 -= tile[(r0+3)*257+p] * s;
        }
        Ui[(r0+0)*33+cc] = a0; Ui[(r0+1)*33+cc] = a1;
        Ui[(r0+2)*33+cc] = a2; Ui[(r0+3)*33+cc] = a3;
        __syncthreads();

        // load q tile; hoist u_i column
        for (int e = tid; e < 8192; e += 256)
            tile[(e>>8)*257 + (e&255)] = g_qn[base + e];
        float ur[32];
#pragma unroll
        for (int j = 0; j < 32; j++) ur[j] = Ui[j*33 + cc];
        __syncthreads();

        // o = q @ S + attn @ u_i
        float o0=0.f,o1=0.f,o2=0.f,o3=0.f;
        for (int p = 0; p < 256; p++) {
            float s = S[p*33 + cc];
            o0 = fmaf(tile[(r0+0)*257+p], s, o0);
            o1 = fmaf(tile[(r0+1)*257+p], s, o1);
            o2 = fmaf(tile[(r0+2)*257+p], s, o2);
            o3 = fmaf(tile[(r0+3)*257+p], s, o3);
        }
#pragma unroll
        for (int j = 0; j < 32; j++) {
            float u = ur[j];
            o0 = fmaf(At[(r0+0)*33+j], u, o0);
            o1 = fmaf(At[(r0+1)*33+j], u, o1);
            o2 = fmaf(At[(r0+2)*33+j], u, o2);
            o3 = fmaf(At[(r0+3)*33+j], u, o3);
        }
        {
            size_t ob = ((size_t)(b*LL + c*32 + r0))*DD + h*DV + g*32 + cc;
            g_delta[ob]        = o0;
            g_delta[ob + DD]   = o1;
            g_delta[ob + 2*DD] = o2;
            g_delta[ob + 3*DD] = o3;
        }
        __syncthreads();

        // load k tile
        for (int e = tid; e < 8192; e += 256)
            tile[(e>>8)*257 + (e&255)] = g_kn[base + e];
        __syncthreads();

        // S += k^T @ u_i
        for (int p = p0; p < p0 + 32; p++) {
            float a = 0.f;
#pragma unroll
            for (int r = 0; r < 32; r++) a = fmaf(tile[r*257 + p], ur[r], a);
            S[p*33 + cc] += a;
        }
        __syncthreads();
    }
}

// ------------------------- per-(head,channel) FIR conv ----------------------
template<int K>
__global__ __launch_bounds__(256) void fir_kernel(
    const float* __restrict__ fw, float* __restrict__ y)
{
    __shared__ float vbuf[(128 + K - 1) * 32];
    __shared__ float wbuf[32 * K];
    int bh = blockIdx.x;
    int b = bh / HH, h = bh % HH;
    int l0 = blockIdx.y * 128;
    int d0 = blockIdx.z * 32;
    int tid = threadIdx.x;

    for (int idx = tid; idx < 32*K; idx += 256)
        wbuf[idx] = fw[(size_t)(h*DV + d0)*K + idx];
    for (int idx = tid; idx < (128 + K - 1)*32; idx += 256) {
        int lr = idx >> 5, d = idx & 31;
        int l = l0 - (K - 1) + lr;
        vbuf[idx] = (l >= 0) ? g_vc[((size_t)(b*LL + l))*DD + h*DV + d0 + d] : 0.f;
    }
    __syncthreads();

    int d = tid & 31;
    int lr0 = (tid >> 5) * 16;
    for (int m = 0; m < 16; m++) {
        int lr = lr0 + m;
        float acc = 0.f;
#pragma unroll
        for (int t = 0; t < K; t++)
            acc = fmaf(vbuf[(lr + t)*32 + d], wbuf[d*K + t], acc);
        y[((size_t)(b*LL + l0 + lr))*DD + h*DV + d0 + d] = acc;
    }
}

// ------------------------- gate input assembly (hs + stats) -----------------
__global__ __launch_bounds__(256) void stats_kernel(const float* __restrict__ hs)
{
    int n = blockIdx.x, tid = threadIdx.x;
    for (int i = tid; i < DD; i += 256)
        g_gatein[(size_t)n*GIN + i] = hs[(size_t)n*DD + i];
    int warp = tid >> 5, lane = tid & 31;
    for (int rep = 0; rep < 2; rep++) {
        int combo = warp*2 + rep;
        int path = combo >> 2, h = combo & 3;
        const float* p;
        if      (path == 0) p = g_short;
        else if (path == 1) p = g_long;
        else if (path == 2) p = g_delta;
        else                p = g_vc;
        p += (size_t)n*DD + h*DV;
        float s1 = 0.f, s2 = 0.f;
        for (int j = lane; j < 256; j += 32) { float x = p[j]; s1 += x; s2 += x*x; }
#pragma unroll
        for (int st = 16; st > 0; st >>= 1) {
            s1 += __shfl_down_sync(0xffffffffu, s1, st);
            s2 += __shfl_down_sync(0xffffffffu, s2, st);
        }
        if (lane == 0) {
            float m  = s1 * (1.f/256.f);
            float va = s2 * (1.f/256.f) - m*m;
            g_gatein[(size_t)n*GIN + DD + path*8 + h*2]     = m;
            g_gatein[(size_t)n*GIN + DD + path*8 + h*2 + 1] = va;
        }
    }
}

// ------------------------- gate2 + softmax + floor --------------------------
__global__ __launch_bounds__(256) void gate2_kernel(
    const float* __restrict__ w2, const float* __restrict__ log_temp,
    const float* __restrict__ base_bias, const float* __restrict__ floor_raw)
{
    __shared__ float hrow[HID];
    __shared__ float lg[16];
    int n = blockIdx.x, tid = threadIdx.x;
    for (int i = tid; i < HID; i += 256) hrow[i] = g_hmid[(size_t)n*HID + i];
    __syncthreads();
    int warp = tid >> 5, lane = tid & 31;
    for (int rep = 0; rep < 2; rep++) {
        int o = warp*2 + rep;
        const float* wr = w2 + (size_t)o*HID;
        float s = 0.f;
        for (int i = lane; i < HID; i += 32) s = fmaf(hrow[i], wr[i], s);
#pragma unroll
        for (int st = 16; st > 0; st >>= 1) s += __shfl_down_sync(0xffffffffu, s, st);
        if (lane == 0) lg[o] = s;
    }
    __syncthreads();
    if (tid < 4) {
        int h = tid;
        float temp = log1pf(expf(log_temp[h])) + 1e-4f;
        float z[4], m = -1e30f;
#pragma unroll
        for (int i = 0; i < 4; i++) {
            z[i] = (lg[h*4+i] + base_bias[h*4+i]) / temp;
            m = fmaxf(m, z[i]);
        }
        float e[4], s = 0.f;
#pragma unroll
        for (int i = 0; i < 4; i++) { e[i] = expf(z[i] - m); s += e[i]; }
        float p[4], s2 = 0.f;
#pragma unroll
        for (int i = 0; i < 4; i++) {
            p[i] = e[i] / s;
            float f = 0.05f / (1.f + expf(-floor_raw[h*4+i]));
            p[i] = fmaxf(p[i], f);
            s2 += p[i];
        }
#pragma unroll
        for (int i = 0; i < 4; i++) g_probs[(size_t)n*16 + h*4 + i] = p[i] / s2;
    }
}

// ------------------------- path mix + RMS norm ------------------------------
__global__ __launch_bounds__(256) void mix_kernel(const float* __restrict__ onorm)
{
    __shared__ float pr[16];
    __shared__ float wsum[8];
    int n = blockIdx.x, tid = threadIdx.x;
    if (tid < 16) pr[tid] = g_probs[(size_t)n*16 + tid];
    __syncthreads();
    int h = tid >> 6;
    int dd = (tid & 63) * 4;
    size_t pb = (size_t)n*DD + h*DV + dd;
    float4 sh = *(const float4*)&g_short[pb];
    float4 lo = *(const float4*)&g_long[pb];
    float4 de = *(const float4*)&g_delta[pb];
    float4 vv = *(const float4*)&g_vc[pb];
    float p0 = pr[h*4+0], p1 = pr[h*4+1], p2 = pr[h*4+2], p3 = pr[h*4+3];
    float o[4];
    o[0] = p0*sh.x + p1*lo.x + p2*de.x + p3*vv.x;
    o[1] = p0*sh.y + p1*lo.y + p2*de.y + p3*vv.y;
    o[2] = p0*sh.z + p1*lo.z + p2*de.z + p3*vv.z;
    o[3] = p0*sh.w + p1*lo.w + p2*de.w + p3*vv.w;
    float ss = o[0]*o[0] + o[1]*o[1] + o[2]*o[2] + o[3]*o[3];
#pragma unroll
    for (int st = 16; st > 0; st >>= 1) ss += __shfl_down_sync(0xffffffffu, ss, st);
    int warp = tid >> 5, lane = tid & 31;
    if (lane == 0) wsum[warp] = ss;
    __syncthreads();
    float tot = wsum[h*2] + wsum[h*2+1];
    float scale = rsqrtf(tot * (1.f/256.f) + 1e-5f);
    float r[4];
#pragma unroll
    for (int j = 0; j < 4; j++) r[j] = o[j] * scale * onorm[dd + j];
    *(float4*)&g_mix[pb] = *(float4*)r;
}

// ------------------------- launch ------------------------------------------
extern "C" void kernel_launch(void* const* d_in, const int* in_sizes, int n_in,
                              void* d_out, int out_size)
{
    const float* hs        = (const float*)d_in[0];
    const float* Wq        = (const float*)d_in[1];
    const float* Wk        = (const float*)d_in[2];
    const float* Wv        = (const float*)d_in[3];
    const float* Wb        = (const float*)d_in[4];
    const float* qconv_w   = (const float*)d_in[5];
    const float* kconv_w   = (const float*)d_in[6];
    const float* vconv_w   = (const float*)d_in[7];
    const float* fir_s     = (const float*)d_in[8];
    const float* fir_l     = (const float*)d_in[9];
    const float* gate_w1   = (const float*)d_in[10];
    const float* gate_b1   = (const float*)d_in[11];
    const float* gate_w2   = (const float*)d_in[12];
    const float* log_temp  = (const float*)d_in[13];
    const float* base_bias = (const float*)d_in[14];
    const float* floor_raw = (const float*)d_in[15];
    const float* onorm_w   = (const float*)d_in[16];
    const float* Wo        = (const float*)d_in[17];
    float* out = (float*)d_out;

    void *p_qlin, *p_klin, *p_vlin, *p_qc, *p_kc, *p_vc, *p_gatein, *p_hmid,
         *p_mix, *p_short, *p_long;
    cudaGetSymbolAddress(&p_qlin, g_qlin);
    cudaGetSymbolAddress(&p_klin, g_klin);
    cudaGetSymbolAddress(&p_vlin, g_vlin);
    cudaGetSymbolAddress(&p_qc, g_qc);
    cudaGetSymbolAddress(&p_kc, g_kc);
    cudaGetSymbolAddress(&p_vc, g_vc);
    cudaGetSymbolAddress(&p_gatein, g_gatein);
    cudaGetSymbolAddress(&p_hmid, g_hmid);
    cudaGetSymbolAddress(&p_mix, g_mix);
    cudaGetSymbolAddress(&p_short, g_short);
    cudaGetSymbolAddress(&p_long, g_long);

    cudaFuncSetAttribute(scan_kernel,
        cudaFuncAttributeMaxDynamicSharedMemorySize, SCAN_SMEM);

    dim3 blk(256);

    // q/k/v projections — one batched tensor-core launch
    tf32_gemm<<<dim3(DD/128, NROW/128, 3), blk>>>(
        hs, Wq, Wk, Wv,
        (float*)p_qlin, (float*)p_klin, (float*)p_vlin,
        nullptr, NROW, DD, DD, 0);

    // causal conv4 + SiLU
    int nconv = NROW*DD/256;
    conv4_silu<<<nconv, blk>>>((const float*)p_qlin, qconv_w, (float*)p_qc);
    conv4_silu<<<nconv, blk>>>((const float*)p_klin, kconv_w, (float*)p_kc);
    conv4_silu<<<nconv, blk>>>((const float*)p_vlin, vconv_w, (float*)p_vc);

    // beta
    beta_kernel<<<NROW, 128>>>(hs, Wb);

    // delta-rule
    precompute_kernel<<<BB*HH*NC, blk>>>();
    scan_kernel<<<BB*HH*NG, blk, SCAN_SMEM>>>();

    // FIR paths
    fir_kernel<3><<<dim3(BB*HH, LL/128, DV/32), blk>>>(fir_s, (float*)p_short);
    fir_kernel<63><<<dim3(BB*HH, LL/128, DV/32), blk>>>(fir_l, (float*)p_long);

    // gate
    stats_kernel<<<NROW, blk>>>(hs);
    tf32_gemm<<<dim3(HID/128, NROW/128, 1), blk>>>(
        (const float*)p_gatein, gate_w1, nullptr, nullptr,
        (float*)p_hmid, nullptr, nullptr,
        gate_b1, NROW, HID, GIN, 1);
    gate2_kernel<<<NROW, blk>>>(gate_w2, log_temp, base_bias, floor_raw);

    // mix + RMS norm
    mix_kernel<<<NROW, blk>>>(onorm_w);

    // output projection
    tf32_gemm<<<dim3(DD/128, NROW/128, 1), blk>>>(
        (const float*)p_mix, Wo, nullptr, nullptr,
        out, nullptr, nullptr,
        nullptr, NROW, DD, DD, 0);
}

// round 5
// speedup vs baseline: 1.9777x; 1.4357x over previous
#include <cuda_runtime.h>
#include <math.h>

#define BB 2
#define LL 2048
#define DD 1024
#define HH 4
#define DV 256
#define CKN 32
#define NC 64              // LL / CKN
#define NROW (BB*LL)       // 4096
#define GIN 1056
#define HID 2048
#define NG 8               // Dv groups of 32 in the scan

// ------------------------- scratch (device globals) -------------------------
__device__ float g_qlin[NROW*DD];
__device__ float g_klin[NROW*DD];
__device__ float g_vlin[NROW*DD];
__device__ float g_qc[NROW*DD];
__device__ float g_kc[NROW*DD];
__device__ float g_vc[NROW*DD];
__device__ float g_beta[NROW*HH];
__device__ float g_qn[NROW*DD];
__device__ float g_kn[NROW*DD];
__device__ float g_u[NROW*DD];
__device__ float g_w[NROW*DD];
__device__ float g_attn[BB*HH*NC*CKN*CKN];
__device__ float g_delta[NROW*DD];
__device__ float g_short[NROW*DD];
__device__ float g_long[NROW*DD];
__device__ float g_gatein[NROW*GIN];
__device__ float g_hmid[NROW*HID];
__device__ float g_probs[NROW*16];
__device__ float g_mix[NROW*DD];

// ------------------------- tf32 helpers -------------------------------------
__device__ __forceinline__ unsigned f2tf(float x) {
    unsigned r;
    asm("cvt.rna.tf32.f32 %0, %1;" : "=r"(r) : "f"(x));
    return r;
}

__device__ __forceinline__ void mma_tf32(float* c, const unsigned* a, const unsigned* b) {
    asm volatile(
        "mma.sync.aligned.m16n8k8.row.col.f32.tf32.tf32.f32 "
        "{%0,%1,%2,%3}, {%4,%5,%6,%7}, {%8,%9}, {%0,%1,%2,%3};"
        : "+f"(c[0]), "+f"(c[1]), "+f"(c[2]), "+f"(c[3])
        : "r"(a[0]), "r"(a[1]), "r"(a[2]), "r"(a[3]), "r"(b[0]), "r"(b[1]));
}

// ------------------- tf32 tensor-core GEMM: C = A(MxK) @ B(NxK)^T ------------
// Block tile 128x128, 256 threads (8 warps, 2x4), warp tile 64x32.
// blockIdx.z selects among up to 3 (B, C) pairs for batching q/k/v.
// mode 0: plain.  mode 1: +bias[col], exact GELU.
#define LDB 20
__global__ __launch_bounds__(256, 2) void tf32_gemm(
    const float* __restrict__ A,
    const float* __restrict__ Bm0, const float* __restrict__ Bm1, const float* __restrict__ Bm2,
    float* __restrict__ Cm0, float* __restrict__ Cm1, float* __restrict__ Cm2,
    const float* __restrict__ bias, int M, int N, int K, int mode)
{
    __shared__ unsigned As[2][128*LDB];
    __shared__ unsigned Bs[2][128*LDB];

    const float* B = (blockIdx.z == 0) ? Bm0 : (blockIdx.z == 1) ? Bm1 : Bm2;
    float*       C = (blockIdx.z == 0) ? Cm0 : (blockIdx.z == 1) ? Cm1 : Cm2;

    int tid  = threadIdx.x;
    int bm   = blockIdx.y * 128, bn = blockIdx.x * 128;
    int lrow = tid >> 1;
    int lcol = (tid & 1) * 8;
    const float* Ap = A + (size_t)(bm + lrow) * K + lcol;
    const float* Bp = B + (size_t)(bn + lrow) * K + lcol;

    int wid = tid >> 5, lane = tid & 31;
    int wm = (wid >> 2) * 64, wn = (wid & 3) * 32;
    int lr = lane >> 2, lk = lane & 3;

    float acc[4][4][4];
#pragma unroll
    for (int mi = 0; mi < 4; mi++)
#pragma unroll
        for (int ni = 0; ni < 4; ni++)
#pragma unroll
            for (int j = 0; j < 4; j++) acc[mi][ni][j] = 0.f;

    // preload tile 0
    {
        float4 a0 = *(const float4*)(Ap);
        float4 a1 = *(const float4*)(Ap + 4);
        float4 b0 = *(const float4*)(Bp);
        float4 b1 = *(const float4*)(Bp + 4);
        unsigned* as = &As[0][lrow*LDB + lcol];
        unsigned* bs = &Bs[0][lrow*LDB + lcol];
        as[0]=f2tf(a0.x); as[1]=f2tf(a0.y); as[2]=f2tf(a0.z); as[3]=f2tf(a0.w);
        as[4]=f2tf(a1.x); as[5]=f2tf(a1.y); as[6]=f2tf(a1.z); as[7]=f2tf(a1.w);
        bs[0]=f2tf(b0.x); bs[1]=f2tf(b0.y); bs[2]=f2tf(b0.z); bs[3]=f2tf(b0.w);
        bs[4]=f2tf(b1.x); bs[5]=f2tf(b1.y); bs[6]=f2tf(b1.z); bs[7]=f2tf(b1.w);
    }

    int niter = K >> 4;
    int cur = 0;
    for (int it = 0; it < niter; it++) {
        __syncthreads();
        float4 na0, na1, nb0, nb1;
        bool more = (it + 1 < niter);
        if (more) {
            const float* Ap2 = Ap + (it + 1) * 16;
            const float* Bp2 = Bp + (it + 1) * 16;
            na0 = *(const float4*)(Ap2);
            na1 = *(const float4*)(Ap2 + 4);
            nb0 = *(const float4*)(Bp2);
            nb1 = *(const float4*)(Bp2 + 4);
        }

        const unsigned* Ac = As[cur];
        const unsigned* Bc = Bs[cur];
#pragma unroll
        for (int ks = 0; ks < 2; ks++) {
            int kb = ks * 8;
            unsigned af[4][4], bf[4][2];
#pragma unroll
            for (int mi = 0; mi < 4; mi++) {
                int r = wm + mi*16 + lr;
                af[mi][0] = Ac[r*LDB + kb + lk];
                af[mi][1] = Ac[(r+8)*LDB + kb + lk];
                af[mi][2] = Ac[r*LDB + kb + lk + 4];
                af[mi][3] = Ac[(r+8)*LDB + kb + lk + 4];
            }
#pragma unroll
            for (int ni = 0; ni < 4; ni++) {
                int n = wn + ni*8 + lr;
                bf[ni][0] = Bc[n*LDB + kb + lk];
                bf[ni][1] = Bc[n*LDB + kb + lk + 4];
            }
#pragma unroll
            for (int mi = 0; mi < 4; mi++)
#pragma unroll
                for (int ni = 0; ni < 4; ni++)
                    mma_tf32(acc[mi][ni], af[mi], bf[ni]);
        }

        if (more) {
            int nxt = cur ^ 1;
            unsigned* as = &As[nxt][lrow*LDB + lcol];
            unsigned* bs = &Bs[nxt][lrow*LDB + lcol];
            as[0]=f2tf(na0.x); as[1]=f2tf(na0.y); as[2]=f2tf(na0.z); as[3]=f2tf(na0.w);
            as[4]=f2tf(na1.x); as[5]=f2tf(na1.y); as[6]=f2tf(na1.z); as[7]=f2tf(na1.w);
            bs[0]=f2tf(nb0.x); bs[1]=f2tf(nb0.y); bs[2]=f2tf(nb0.z); bs[3]=f2tf(nb0.w);
            bs[4]=f2tf(nb1.x); bs[5]=f2tf(nb1.y); bs[6]=f2tf(nb1.z); bs[7]=f2tf(nb1.w);
        }
        cur ^= 1;
    }

#pragma unroll
    for (int mi = 0; mi < 4; mi++) {
        int r0 = bm + wm + mi*16 + lr;
#pragma unroll
        for (int ni = 0; ni < 4; ni++) {
            int c = bn + wn + ni*8 + 2*lk;
            float v[4] = {acc[mi][ni][0], acc[mi][ni][1], acc[mi][ni][2], acc[mi][ni][3]};
            if (mode == 1) {
                float b0 = bias[c], b1 = bias[c+1];
                v[0] += b0; v[1] += b1; v[2] += b0; v[3] += b1;
#pragma unroll
                for (int j = 0; j < 4; j++)
                    v[j] = 0.5f * v[j] * (1.f + erff(v[j] * 0.70710678118654752f));
            }
            float2 lo = {v[0], v[1]};
            float2 hi = {v[2], v[3]};
            *(float2*)&C[(size_t)r0*N + c]       = lo;
            *(float2*)&C[(size_t)(r0+8)*N + c]   = hi;
        }
    }
}

// ------------------- depthwise causal conv4 + SiLU (3 streams batched) ------
__global__ __launch_bounds__(256) void conv4_silu3(
    const float* __restrict__ x0, const float* __restrict__ x1, const float* __restrict__ x2,
    const float* __restrict__ w0, const float* __restrict__ w1, const float* __restrict__ w2,
    float* __restrict__ y0, float* __restrict__ y1, float* __restrict__ y2)
{
    const float* x; const float* w; float* y;
    if (blockIdx.y == 0)      { x = x0; w = w0; y = y0; }
    else if (blockIdx.y == 1) { x = x1; w = w1; y = y1; }
    else                      { x = x2; w = w2; y = y2; }
    int idx = blockIdx.x * 256 + threadIdx.x;       // over NROW*DD
    int d = idx & (DD-1);
    int l = (idx >> 10) & (LL-1);
    float4 wv = *(const float4*)(w + d*4);
    const float* xp = x + (size_t)idx;
    float acc = wv.w * xp[0];
    if (l >= 1) acc += wv.z * xp[-DD];
    if (l >= 2) acc += wv.y * xp[-2*DD];
    if (l >= 3) acc += wv.x * xp[-3*DD];
    y[idx] = acc / (1.f + expf(-acc));
}

// ------------------------- beta = sigmoid(hs @ Wb^T) ------------------------
__global__ __launch_bounds__(128) void beta_kernel(
    const float* __restrict__ hs, const float* __restrict__ Wb)
{
    __shared__ float red[4][128];
    int n = blockIdx.x, tid = threadIdx.x;
    const float* hr = hs + (size_t)n * DD;
    float s0=0,s1=0,s2=0,s3=0;
    for (int i = tid; i < DD; i += 128) {
        float x = hr[i];
        s0 += x * Wb[i];
        s1 += x * Wb[DD + i];
        s2 += x * Wb[2*DD + i];
        s3 += x * Wb[3*DD + i];
    }
    red[0][tid]=s0; red[1][tid]=s1; red[2][tid]=s2; red[3][tid]=s3;
    __syncthreads();
    for (int st = 64; st > 0; st >>= 1) {
        if (tid < st)
#pragma unroll
            for (int h = 0; h < 4; h++) red[h][tid] += red[h][tid + st];
        __syncthreads();
    }
    if (tid < 4) g_beta[(size_t)n*HH + tid] = 1.f / (1.f + expf(-red[tid][0]));
}

// ------------------------- per-chunk delta-rule precompute ------------------
__global__ __launch_bounds__(256) void precompute_kernel()
{
    __shared__ float ks[32][261];
    __shared__ float Am[32][33];
    __shared__ float rnk[32], rnq[32], bet[32];
    int blk = blockIdx.x;           // (b*HH + h)*NC + c
    int c  = blk % NC;
    int bh = blk / NC;
    int h  = bh % HH;
    int b  = bh / HH;
    int tid = threadIdx.x;
    int l0 = c * 32;

    for (int e = tid; e < 32*256; e += 256) {
        int r = e >> 8, d = e & 255;
        ks[r][d] = g_kc[((size_t)(b*LL + l0 + r))*DD + h*DV + d];
    }
    if (tid < 32) bet[tid] = g_beta[((size_t)(b*LL + l0 + tid))*HH + h];
    __syncthreads();

    {   // k row norms
        int r = tid >> 3, part = tid & 7;
        float s = 0.f;
        for (int j = 0; j < 32; j++) { float x = ks[r][part*32 + j]; s += x*x; }
        s += __shfl_down_sync(0xffffffffu, s, 4, 8);
        s += __shfl_down_sync(0xffffffffu, s, 2, 8);
        s += __shfl_down_sync(0xffffffffu, s, 1, 8);
        if (part == 0) rnk[r] = rsqrtf(s + 1e-6f);
    }
    {   // q row norms (from global)
        int r = tid >> 3, part = tid & 7;
        const float* qrow = g_qc + ((size_t)(b*LL + l0 + r))*DD + h*DV;
        float s = 0.f;
        for (int j = 0; j < 32; j++) { float x = qrow[part*32 + j]; s += x*x; }
        s += __shfl_down_sync(0xffffffffu, s, 4, 8);
        s += __shfl_down_sync(0xffffffffu, s, 2, 8);
        s += __shfl_down_sync(0xffffffffu, s, 1, 8);
        if (part == 0) rnq[r] = rsqrtf(s + 1e-6f);
    }
    __syncthreads();

    size_t obase = (size_t)blk * (32*256);
    for (int e = tid; e < 32*256; e += 256) {
        int r = e >> 8, d = e & 255;
        float kv = ks[r][d] * rnk[r];
        ks[r][d] = kv;
        g_kn[obase + e] = kv;
        float qv = g_qc[((size_t)(b*LL + l0 + r))*DD + h*DV + d] * rnq[r];
        g_qn[obase + e] = qv;
    }
    __syncthreads();

    // A = -beta_i * (kn_i . kn_j), strictly lower
    for (int e = tid; e < 1024; e += 256) {
        int i = e >> 5, j = e & 31;
        float a = 0.f;
        if (j < i) {
            float s = 0.f;
            for (int d = 0; d < 256; d++) s += ks[i][d] * ks[j][d];
            a = -bet[i] * s;
        }
        Am[i][j] = a;
    }
    __syncthreads();

    // iterative inversion: row i gets A[i,:i] += A[i,:] @ A[:, :i]
    if (tid < 32) {
        int lane = tid;
        for (int i = 1; i < 32; i++) {
            float t = 0.f;
            if (lane < i) for (int p = 0; p < i; p++) t += Am[i][p] * Am[p][lane];
            __syncwarp();
            if (lane < i) Am[i][lane] += t;
            __syncwarp();
        }
    }
    __syncthreads();
    if (tid < 32) Am[tid][tid] += 1.f;     // T = A + I
    __syncthreads();

    // u = T @ (beta*v),  w = T @ (beta*kn)
    {
        int d = tid;
        float vr[32], kr[32];
#pragma unroll
        for (int j = 0; j < 32; j++) {
            vr[j] = g_vc[((size_t)(b*LL + l0 + j))*DD + h*DV + d] * bet[j];
            kr[j] = ks[j][d] * bet[j];
        }
        for (int i = 0; i < 32; i++) {
            float su = 0.f, sw = 0.f;
#pragma unroll
            for (int j = 0; j < 32; j++) {
                float a = Am[i][j];
                su = fmaf(a, vr[j], su);
                sw = fmaf(a, kr[j], sw);
            }
            g_u[obase + i*256 + d] = su;
            g_w[obase + i*256 + d] = sw;
        }
    }

    // attn = tril(qn @ kn^T) incl. diagonal
    {
        size_t abase = (size_t)blk * 1024;
        for (int e = tid*4; e < tid*4 + 4; e++) {
            int i = e >> 5, j = e & 31;
            float a = 0.f;
            if (j <= i) {
                const float* qrow = g_qn + obase + i*256;
                float s = 0.f;
                for (int d = 0; d < 256; d++) s += qrow[d] * ks[j][d];
                a = s;
            }
            g_attn[abase + e] = a;
        }
    }
}

// --------------- sequential inter-chunk scan (tensor-core mma) --------------
// Per block: one (b,h) pair and one 32-wide Dv slice g.
// S (256x32) kept fp32 in smem (exact accumulation) + tf32 shadow.
// Per chunk:  u_i = u - w@S ; o = q@S + attn@u_i ; S += k^T@u_i  — all on mma.
#define SSTR 40     // stride for [.. x 32] arrays (bank-conflict-free frags)
#define TSTR 264    // stride for [32 x 256] tiles
#define SCAN_SMEM ((256*SSTR*2 + 32*TSTR + 3*32*SSTR) * 4)
__global__ __launch_bounds__(256) void scan_kernel()
{
    extern __shared__ float sm[];
    float*    Sf  = sm;                           // [256][SSTR] fp32 master
    unsigned* Stf = (unsigned*)(sm + 256*SSTR);   // [256][SSTR] tf32 shadow
    unsigned* Ttf = Stf + 256*SSTR;               // [32][TSTR]  w/q/k tile tf32
    float*    Ui  = (float*)(Ttf + 32*TSTR);      // [32][SSTR]  u then u_i fp32
    unsigned* Utf = (unsigned*)(Ui + 32*SSTR);    // [32][SSTR]  u_i tf32
    unsigned* Atf = Utf + 32*SSTR;                // [32][SSTR]  attn tf32

    int blk = blockIdx.x;               // (b*HH+h)*NG + g
    int g  = blk & (NG-1);
    int bh = blk >> 3;
    int b  = bh >> 2;
    int h  = bh & 3;
    int tid = threadIdx.x;
    int wid = tid >> 5, lane = tid & 31;
    int lr = lane >> 2, lk = lane & 3;
    int m0 = (wid >> 2) * 16;           // (1)/(2) warp tile: 2 x 4
    int n0 = (wid & 3) * 8;

    for (int e = tid; e < 256*SSTR; e += 256) { Sf[e] = 0.f; Stf[e] = 0u; }
    __syncthreads();

    for (int c = 0; c < NC; c++) {
        size_t base = ((size_t)bh*NC + c) * (32*256);
        size_t abase = ((size_t)bh*NC + c) * 1024;

        // load u slice (32x32) + attn (32x32) ; w tile (32x256) as tf32
        for (int e = tid; e < 1024; e += 256) {
            int r = e >> 5, j = e & 31;
            Ui[r*SSTR + j]  = g_u[base + r*256 + g*32 + j];
            Atf[r*SSTR + j] = f2tf(g_attn[abase + e]);
        }
        for (int e = tid*4; e < 8192; e += 1024) {
            float4 v = *(const float4*)&g_w[base + e];
            unsigned* dst = &Ttf[(e >> 8)*TSTR + (e & 255)];
            dst[0]=f2tf(v.x); dst[1]=f2tf(v.y); dst[2]=f2tf(v.z); dst[3]=f2tf(v.w);
        }
        __syncthreads();

        // (1) u_i = u - w@S    (32x32, K=256)
        {
            float acc[4] = {0.f, 0.f, 0.f, 0.f};
#pragma unroll 4
            for (int kb = 0; kb < 256; kb += 8) {
                unsigned a[4], bf[2];
                a[0] = Ttf[(m0+lr)*TSTR + kb+lk];
                a[1] = Ttf[(m0+lr+8)*TSTR + kb+lk];
                a[2] = Ttf[(m0+lr)*TSTR + kb+lk+4];
                a[3] = Ttf[(m0+lr+8)*TSTR + kb+lk+4];
                bf[0] = Stf[(kb+lk)*SSTR + n0+lr];
                bf[1] = Stf[(kb+lk+4)*SSTR + n0+lr];
                mma_tf32(acc, a, bf);
            }
            int r0 = m0 + lr, r1 = r0 + 8, cb = n0 + 2*lk;
            float u0 = Ui[r0*SSTR+cb]   - acc[0];
            float u1 = Ui[r0*SSTR+cb+1] - acc[1];
            float u2 = Ui[r1*SSTR+cb]   - acc[2];
            float u3 = Ui[r1*SSTR+cb+1] - acc[3];
            Ui[r0*SSTR+cb] = u0; Ui[r0*SSTR+cb+1] = u1;
            Ui[r1*SSTR+cb] = u2; Ui[r1*SSTR+cb+1] = u3;
            Utf[r0*SSTR+cb] = f2tf(u0); Utf[r0*SSTR+cb+1] = f2tf(u1);
            Utf[r1*SSTR+cb] = f2tf(u2); Utf[r1*SSTR+cb+1] = f2tf(u3);
        }
        __syncthreads();

        // load q tile
        for (int e = tid*4; e < 8192; e += 1024) {
            float4 v = *(const float4*)&g_qn[base + e];
            unsigned* dst = &Ttf[(e >> 8)*TSTR + (e & 255)];
            dst[0]=f2tf(v.x); dst[1]=f2tf(v.y); dst[2]=f2tf(v.z); dst[3]=f2tf(v.w);
        }
        __syncthreads();

        // (2) o = q@S + attn@u_i  -> g_delta
        {
            float acc[4] = {0.f, 0.f, 0.f, 0.f};
#pragma unroll 4
            for (int kb = 0; kb < 256; kb += 8) {
                unsigned a[4], bf[2];
                a[0] = Ttf[(m0+lr)*TSTR + kb+lk];
                a[1] = Ttf[(m0+lr+8)*TSTR + kb+lk];
                a[2] = Ttf[(m0+lr)*TSTR + kb+lk+4];
                a[3] = Ttf[(m0+lr+8)*TSTR + kb+lk+4];
                bf[0] = Stf[(kb+lk)*SSTR + n0+lr];
                bf[1] = Stf[(kb+lk+4)*SSTR + n0+lr];
                mma_tf32(acc, a, bf);
            }
#pragma unroll
            for (int kb = 0; kb < 32; kb += 8) {
                unsigned a[4], bf[2];
                a[0] = Atf[(m0+lr)*SSTR + kb+lk];
                a[1] = Atf[(m0+lr+8)*SSTR + kb+lk];
                a[2] = Atf[(m0+lr)*SSTR + kb+lk+4];
                a[3] = Atf[(m0+lr+8)*SSTR + kb+lk+4];
                bf[0] = Utf[(kb+lk)*SSTR + n0+lr];
                bf[1] = Utf[(kb+lk+4)*SSTR + n0+lr];
                mma_tf32(acc, a, bf);
            }
            size_t ob = ((size_t)(b*LL + c*32 + m0 + lr))*DD + h*DV + g*32 + n0 + 2*lk;
            float2 lo = {acc[0], acc[1]};
            float2 hi = {acc[2], acc[3]};
            *(float2*)&g_delta[ob]        = lo;
            *(float2*)&g_delta[ob + 8*DD] = hi;
        }
        __syncthreads();

        // load k tile
        for (int e = tid*4; e < 8192; e += 1024) {
            float4 v = *(const float4*)&g_kn[base + e];
            unsigned* dst = &Ttf[(e >> 8)*TSTR + (e & 255)];
            dst[0]=f2tf(v.x); dst[1]=f2tf(v.y); dst[2]=f2tf(v.z); dst[3]=f2tf(v.w);
        }
        __syncthreads();

        // (3) S += k^T @ u_i   (M=256, N=32, K=32); k^T read transposed
#pragma unroll
        for (int t = 0; t < 2; t++) {
            int tm = (wid*2 + t) * 16;
#pragma unroll
            for (int tn = 0; tn < 4; tn++) {
                int nn = tn*8;
                int r0 = tm + lr, r1 = r0 + 8, cb = nn + 2*lk;
                float acc[4];
                acc[0] = Sf[r0*SSTR+cb]; acc[1] = Sf[r0*SSTR+cb+1];
                acc[2] = Sf[r1*SSTR+cb]; acc[3] = Sf[r1*SSTR+cb+1];
#pragma unroll
                for (int kb = 0; kb < 32; kb += 8) {
                    unsigned a[4], bf[2];
                    a[0] = Ttf[(kb+lk)*TSTR + tm+lr];
                    a[1] = Ttf[(kb+lk)*TSTR + tm+lr+8];
                    a[2] = Ttf[(kb+lk+4)*TSTR + tm+lr];
                    a[3] = Ttf[(kb+lk+4)*TSTR + tm+lr+8];
                    bf[0] = Utf[(kb+lk)*SSTR + nn+lr];
                    bf[1] = Utf[(kb+lk+4)*SSTR + nn+lr];
                    mma_tf32(acc, a, bf);
                }
                Sf[r0*SSTR+cb] = acc[0]; Sf[r0*SSTR+cb+1] = acc[1];
                Sf[r1*SSTR+cb] = acc[2]; Sf[r1*SSTR+cb+1] = acc[3];
                Stf[r0*SSTR+cb] = f2tf(acc[0]); Stf[r0*SSTR+cb+1] = f2tf(acc[1]);
                Stf[r1*SSTR+cb] = f2tf(acc[2]); Stf[r1*SSTR+cb+1] = f2tf(acc[3]);
            }
        }
        __syncthreads();
    }
}

// ------------------------- per-(head,channel) FIR conv ----------------------
template<int K>
__global__ __launch_bounds__(256) void fir_kernel(
    const float* __restrict__ fw, float* __restrict__ y)
{
    __shared__ float vbuf[(128 + K - 1) * 32];
    __shared__ float wbuf[32 * K];
    int bh = blockIdx.x;
    int b = bh / HH, h = bh % HH;
    int l0 = blockIdx.y * 128;
    int d0 = blockIdx.z * 32;
    int tid = threadIdx.x;

    for (int idx = tid; idx < 32*K; idx += 256)
        wbuf[idx] = fw[(size_t)(h*DV + d0)*K + idx];
    for (int idx = tid; idx < (128 + K - 1)*32; idx += 256) {
        int lr = idx >> 5, d = idx & 31;
        int l = l0 - (K - 1) + lr;
        vbuf[idx] = (l >= 0) ? g_vc[((size_t)(b*LL + l))*DD + h*DV + d0 + d] : 0.f;
    }
    __syncthreads();

    int d = tid & 31;
    int lr0 = (tid >> 5) * 16;
    for (int m = 0; m < 16; m++) {
        int lr = lr0 + m;
        float acc = 0.f;
#pragma unroll
        for (int t = 0; t < K; t++)
            acc = fmaf(vbuf[(lr + t)*32 + d], wbuf[d*K + t], acc);
        y[((size_t)(b*LL + l0 + lr))*DD + h*DV + d0 + d] = acc;
    }
}

// ------------------------- gate input assembly (hs + stats) -----------------
__global__ __launch_bounds__(256) void stats_kernel(const float* __restrict__ hs)
{
    int n = blockIdx.x, tid = threadIdx.x;
    for (int i = tid; i < DD; i += 256)
        g_gatein[(size_t)n*GIN + i] = hs[(size_t)n*DD + i];
    int warp = tid >> 5, lane = tid & 31;
    for (int rep = 0; rep < 2; rep++) {
        int combo = warp*2 + rep;
        int path = combo >> 2, h = combo & 3;
        const float* p;
        if      (path == 0) p = g_short;
        else if (path == 1) p = g_long;
        else if (path == 2) p = g_delta;
        else                p = g_vc;
        p += (size_t)n*DD + h*DV;
        float s1 = 0.f, s2 = 0.f;
        for (int j = lane; j < 256; j += 32) { float x = p[j]; s1 += x; s2 += x*x; }
#pragma unroll
        for (int st = 16; st > 0; st >>= 1) {
            s1 += __shfl_down_sync(0xffffffffu, s1, st);
            s2 += __shfl_down_sync(0xffffffffu, s2, st);
        }
        if (lane == 0) {
            float m  = s1 * (1.f/256.f);
            float va = s2 * (1.f/256.f) - m*m;
            g_gatein[(size_t)n*GIN + DD + path*8 + h*2]     = m;
            g_gatein[(size_t)n*GIN + DD + path*8 + h*2 + 1] = va;
        }
    }
}

// ------------------------- gate2 + softmax + floor --------------------------
__global__ __launch_bounds__(256) void gate2_kernel(
    const float* __restrict__ w2, const float* __restrict__ log_temp,
    const float* __restrict__ base_bias, const float* __restrict__ floor_raw)
{
    __shared__ float hrow[HID];
    __shared__ float lg[16];
    int n = blockIdx.x, tid = threadIdx.x;
    for (int i = tid; i < HID; i += 256) hrow[i] = g_hmid[(size_t)n*HID + i];
    __syncthreads();
    int warp = tid >> 5, lane = tid & 31;
    for (int rep = 0; rep < 2; rep++) {
        int o = warp*2 + rep;
        const float* wr = w2 + (size_t)o*HID;
        float s = 0.f;
        for (int i = lane; i < HID; i += 32) s = fmaf(hrow[i], wr[i], s);
#pragma unroll
        for (int st = 16; st > 0; st >>= 1) s += __shfl_down_sync(0xffffffffu, s, st);
        if (lane == 0) lg[o] = s;
    }
    __syncthreads();
    if (tid < 4) {
        int h = tid;
        float temp = log1pf(expf(log_temp[h])) + 1e-4f;
        float z[4], m = -1e30f;
#pragma unroll
        for (int i = 0; i < 4; i++) {
            z[i] = (lg[h*4+i] + base_bias[h*4+i]) / temp;
            m = fmaxf(m, z[i]);
        }
        float e[4], s = 0.f;
#pragma unroll
        for (int i = 0; i < 4; i++) { e[i] = expf(z[i] - m); s += e[i]; }
        float p[4], s2 = 0.f;
#pragma unroll
        for (int i = 0; i < 4; i++) {
            p[i] = e[i] / s;
            float f = 0.05f / (1.f + expf(-floor_raw[h*4+i]));
            p[i] = fmaxf(p[i], f);
            s2 += p[i];
        }
#pragma unroll
        for (int i = 0; i < 4; i++) g_probs[(size_t)n*16 + h*4 + i] = p[i] / s2;
    }
}

// ------------------------- path mix + RMS norm ------------------------------
__global__ __launch_bounds__(256) void mix_kernel(const float* __restrict__ onorm)
{
    __shared__ float pr[16];
    __shared__ float wsum[8];
    int n = blockIdx.x, tid = threadIdx.x;
    if (tid < 16) pr[tid] = g_probs[(size_t)n*16 + tid];
    __syncthreads();
    int h = tid >> 6;
    int dd = (tid & 63) * 4;
    size_t pb = (size_t)n*DD + h*DV + dd;
    float4 sh = *(const float4*)&g_short[pb];
    float4 lo = *(const float4*)&g_long[pb];
    float4 de = *(const float4*)&g_delta[pb];
    float4 vv = *(const float4*)&g_vc[pb];
    float p0 = pr[h*4+0], p1 = pr[h*4+1], p2 = pr[h*4+2], p3 = pr[h*4+3];
    float o[4];
    o[0] = p0*sh.x + p1*lo.x + p2*de.x + p3*vv.x;
    o[1] = p0*sh.y + p1*lo.y + p2*de.y + p3*vv.y;
    o[2] = p0*sh.z + p1*lo.z + p2*de.z + p3*vv.z;
    o[3] = p0*sh.w + p1*lo.w + p2*de.w + p3*vv.w;
    float ss = o[0]*o[0] + o[1]*o[1] + o[2]*o[2] + o[3]*o[3];
#pragma unroll
    for (int st = 16; st > 0; st >>= 1) ss += __shfl_down_sync(0xffffffffu, ss, st);
    int warp = tid >> 5, lane = tid & 31;
    if (lane == 0) wsum[warp] = ss;
    __syncthreads();
    float tot = wsum[h*2] + wsum[h*2+1];
    float scale = rsqrtf(tot * (1.f/256.f) + 1e-5f);
    float r[4];
#pragma unroll
    for (int j = 0; j < 4; j++) r[j] = o[j] * scale * onorm[dd + j];
    *(float4*)&g_mix[pb] = *(float4*)r;
}

// ------------------------- launch ------------------------------------------
extern "C" void kernel_launch(void* const* d_in, const int* in_sizes, int n_in,
                              void* d_out, int out_size)
{
    const float* hs        = (const float*)d_in[0];
    const float* Wq        = (const float*)d_in[1];
    const float* Wk        = (const float*)d_in[2];
    const float* Wv        = (const float*)d_in[3];
    const float* Wb        = (const float*)d_in[4];
    const float* qconv_w   = (const float*)d_in[5];
    const float* kconv_w   = (const float*)d_in[6];
    const float* vconv_w   = (const float*)d_in[7];
    const float* fir_s     = (const float*)d_in[8];
    const float* fir_l     = (const float*)d_in[9];
    const float* gate_w1   = (const float*)d_in[10];
    const float* gate_b1   = (const float*)d_in[11];
    const float* gate_w2   = (const float*)d_in[12];
    const float* log_temp  = (const float*)d_in[13];
    const float* base_bias = (const float*)d_in[14];
    const float* floor_raw = (const float*)d_in[15];
    const float* onorm_w   = (const float*)d_in[16];
    const float* Wo        = (const float*)d_in[17];
    float* out = (float*)d_out;

    void *p_qlin, *p_klin, *p_vlin, *p_qc, *p_kc, *p_vc, *p_gatein, *p_hmid,
         *p_mix, *p_short, *p_long;
    cudaGetSymbolAddress(&p_qlin, g_qlin);
    cudaGetSymbolAddress(&p_klin, g_klin);
    cudaGetSymbolAddress(&p_vlin, g_vlin);
    cudaGetSymbolAddress(&p_qc, g_qc);
    cudaGetSymbolAddress(&p_kc, g_kc);
    cudaGetSymbolAddress(&p_vc, g_vc);
    cudaGetSymbolAddress(&p_gatein, g_gatein);
    cudaGetSymbolAddress(&p_hmid, g_hmid);
    cudaGetSymbolAddress(&p_mix, g_mix);
    cudaGetSymbolAddress(&p_short, g_short);
    cudaGetSymbolAddress(&p_long, g_long);

    cudaFuncSetAttribute(scan_kernel,
        cudaFuncAttributeMaxDynamicSharedMemorySize, SCAN_SMEM);

    dim3 blk(256);

    // q/k/v projections — one batched tensor-core launch
    tf32_gemm<<<dim3(DD/128, NROW/128, 3), blk>>>(
        hs, Wq, Wk, Wv,
        (float*)p_qlin, (float*)p_klin, (float*)p_vlin,
        nullptr, NROW, DD, DD, 0);

    // causal conv4 + SiLU (all three streams in one launch)
    conv4_silu3<<<dim3(NROW*DD/256, 3), blk>>>(
        (const float*)p_qlin, (const float*)p_klin, (const float*)p_vlin,
        qconv_w, kconv_w, vconv_w,
        (float*)p_qc, (float*)p_kc, (float*)p_vc);

    // beta
    beta_kernel<<<NROW, 128>>>(hs, Wb);

    // delta-rule
    precompute_kernel<<<BB*HH*NC, blk>>>();
    scan_kernel<<<BB*HH*NG, blk, SCAN_SMEM>>>();

    // FIR paths
    fir_kernel<3><<<dim3(BB*HH, LL/128, DV/32), blk>>>(fir_s, (float*)p_short);
    fir_kernel<63><<<dim3(BB*HH, LL/128, DV/32), blk>>>(fir_l, (float*)p_long);

    // gate
    stats_kernel<<<NROW, blk>>>(hs);
    tf32_gemm<<<dim3(HID/128, NROW/128, 1), blk>>>(
        (const float*)p_gatein, gate_w1, nullptr, nullptr,
        (float*)p_hmid, nullptr, nullptr,
        gate_b1, NROW, HID, GIN, 1);
    gate2_kernel<<<NROW, blk>>>(gate_w2, log_temp, base_bias, floor_raw);

    // mix + RMS norm
    mix_kernel<<<NROW, blk>>>(onorm_w);

    // output projection
    tf32_gemm<<<dim3(DD/128, NROW/128, 1), blk>>>(
        (const float*)p_mix, Wo, nullptr, nullptr,
        out, nullptr, nullptr,
        nullptr, NROW, DD, DD, 0);
}

// round 6
// speedup vs baseline: 2.0639x; 1.0436x over previous
#include <cuda_runtime.h>
#include <math.h>

#define BB 2
#define LL 2048
#define DD 1024
#define HH 4
#define DV 256
#define CKN 32
#define NC 64              // LL / CKN
#define NROW (BB*LL)       // 4096
#define GIN 1056
#define HID 2048
#define NG 8               // Dv groups of 32 in the scan

// ------------------------- scratch (device globals) -------------------------
__device__ float g_qlin[NROW*DD];
__device__ float g_klin[NROW*DD];
__device__ float g_vlin[NROW*DD];
__device__ float g_qc[NROW*DD];
__device__ float g_kc[NROW*DD];
__device__ float g_vc[NROW*DD];
__device__ float g_beta[NROW*HH];
__device__ float g_qn[NROW*DD];
__device__ float g_kn[NROW*DD];
__device__ float g_u[NROW*DD];
__device__ float g_w[NROW*DD];
__device__ float g_attn[BB*HH*NC*CKN*CKN];
__device__ float g_delta[NROW*DD];
__device__ float g_short[NROW*DD];
__device__ float g_long[NROW*DD];
__device__ float g_gatein[NROW*GIN];
__device__ float g_hmid[NROW*HID];
__device__ float g_probs[NROW*16];
__device__ float g_mix[NROW*DD];

// ------------------------- tf32 helpers -------------------------------------
__device__ __forceinline__ unsigned f2tf(float x) {
    unsigned r;
    asm("cvt.rna.tf32.f32 %0, %1;" : "=r"(r) : "f"(x));
    return r;
}

__device__ __forceinline__ void mma_tf32(float* c, const unsigned* a, const unsigned* b) {
    asm volatile(
        "mma.sync.aligned.m16n8k8.row.col.f32.tf32.tf32.f32 "
        "{%0,%1,%2,%3}, {%4,%5,%6,%7}, {%8,%9}, {%0,%1,%2,%3};"
        : "+f"(c[0]), "+f"(c[1]), "+f"(c[2]), "+f"(c[3])
        : "r"(a[0]), "r"(a[1]), "r"(a[2]), "r"(a[3]), "r"(b[0]), "r"(b[1]));
}

// ------------------- tf32 tensor-core GEMM: C = A(MxK) @ B(NxK)^T ------------
// Block tile 128x128, 256 threads (8 warps, 2x4), warp tile 64x32.
// blockIdx.z selects among up to 3 (B, C) pairs for batching q/k/v.
// mode 0: plain.  mode 1: +bias[col], exact GELU.
#define LDB 20
__global__ __launch_bounds__(256, 2) void tf32_gemm(
    const float* __restrict__ A,
    const float* __restrict__ Bm0, const float* __restrict__ Bm1, const float* __restrict__ Bm2,
    float* __restrict__ Cm0, float* __restrict__ Cm1, float* __restrict__ Cm2,
    const float* __restrict__ bias, int M, int N, int K, int mode)
{
    __shared__ unsigned As[2][128*LDB];
    __shared__ unsigned Bs[2][128*LDB];

    const float* B = (blockIdx.z == 0) ? Bm0 : (blockIdx.z == 1) ? Bm1 : Bm2;
    float*       C = (blockIdx.z == 0) ? Cm0 : (blockIdx.z == 1) ? Cm1 : Cm2;

    int tid  = threadIdx.x;
    int bm   = blockIdx.y * 128, bn = blockIdx.x * 128;
    int lrow = tid >> 1;
    int lcol = (tid & 1) * 8;
    const float* Ap = A + (size_t)(bm + lrow) * K + lcol;
    const float* Bp = B + (size_t)(bn + lrow) * K + lcol;

    int wid = tid >> 5, lane = tid & 31;
    int wm = (wid >> 2) * 64, wn = (wid & 3) * 32;
    int lr = lane >> 2, lk = lane & 3;

    float acc[4][4][4];
#pragma unroll
    for (int mi = 0; mi < 4; mi++)
#pragma unroll
        for (int ni = 0; ni < 4; ni++)
#pragma unroll
            for (int j = 0; j < 4; j++) acc[mi][ni][j] = 0.f;

    // preload tile 0
    {
        float4 a0 = *(const float4*)(Ap);
        float4 a1 = *(const float4*)(Ap + 4);
        float4 b0 = *(const float4*)(Bp);
        float4 b1 = *(const float4*)(Bp + 4);
        unsigned* as = &As[0][lrow*LDB + lcol];
        unsigned* bs = &Bs[0][lrow*LDB + lcol];
        as[0]=f2tf(a0.x); as[1]=f2tf(a0.y); as[2]=f2tf(a0.z); as[3]=f2tf(a0.w);
        as[4]=f2tf(a1.x); as[5]=f2tf(a1.y); as[6]=f2tf(a1.z); as[7]=f2tf(a1.w);
        bs[0]=f2tf(b0.x); bs[1]=f2tf(b0.y); bs[2]=f2tf(b0.z); bs[3]=f2tf(b0.w);
        bs[4]=f2tf(b1.x); bs[5]=f2tf(b1.y); bs[6]=f2tf(b1.z); bs[7]=f2tf(b1.w);
    }

    int niter = K >> 4;
    int cur = 0;
    for (int it = 0; it < niter; it++) {
        __syncthreads();
        float4 na0, na1, nb0, nb1;
        bool more = (it + 1 < niter);
        if (more) {
            const float* Ap2 = Ap + (it + 1) * 16;
            const float* Bp2 = Bp + (it + 1) * 16;
            na0 = *(const float4*)(Ap2);
            na1 = *(const float4*)(Ap2 + 4);
            nb0 = *(const float4*)(Bp2);
            nb1 = *(const float4*)(Bp2 + 4);
        }

        const unsigned* Ac = As[cur];
        const unsigned* Bc = Bs[cur];
#pragma unroll
        for (int ks = 0; ks < 2; ks++) {
            int kb = ks * 8;
            unsigned af[4][4], bf[4][2];
#pragma unroll
            for (int mi = 0; mi < 4; mi++) {
                int r = wm + mi*16 + lr;
                af[mi][0] = Ac[r*LDB + kb + lk];
                af[mi][1] = Ac[(r+8)*LDB + kb + lk];
                af[mi][2] = Ac[r*LDB + kb + lk + 4];
                af[mi][3] = Ac[(r+8)*LDB + kb + lk + 4];
            }
#pragma unroll
            for (int ni = 0; ni < 4; ni++) {
                int n = wn + ni*8 + lr;
                bf[ni][0] = Bc[n*LDB + kb + lk];
                bf[ni][1] = Bc[n*LDB + kb + lk + 4];
            }
#pragma unroll
            for (int mi = 0; mi < 4; mi++)
#pragma unroll
                for (int ni = 0; ni < 4; ni++)
                    mma_tf32(acc[mi][ni], af[mi], bf[ni]);
        }

        if (more) {
            int nxt = cur ^ 1;
            unsigned* as = &As[nxt][lrow*LDB + lcol];
            unsigned* bs = &Bs[nxt][lrow*LDB + lcol];
            as[0]=f2tf(na0.x); as[1]=f2tf(na0.y); as[2]=f2tf(na0.z); as[3]=f2tf(na0.w);
            as[4]=f2tf(na1.x); as[5]=f2tf(na1.y); as[6]=f2tf(na1.z); as[7]=f2tf(na1.w);
            bs[0]=f2tf(nb0.x); bs[1]=f2tf(nb0.y); bs[2]=f2tf(nb0.z); bs[3]=f2tf(nb0.w);
            bs[4]=f2tf(nb1.x); bs[5]=f2tf(nb1.y); bs[6]=f2tf(nb1.z); bs[7]=f2tf(nb1.w);
        }
        cur ^= 1;
    }

#pragma unroll
    for (int mi = 0; mi < 4; mi++) {
        int r0 = bm + wm + mi*16 + lr;
#pragma unroll
        for (int ni = 0; ni < 4; ni++) {
            int c = bn + wn + ni*8 + 2*lk;
            float v[4] = {acc[mi][ni][0], acc[mi][ni][1], acc[mi][ni][2], acc[mi][ni][3]};
            if (mode == 1) {
                float b0 = bias[c], b1 = bias[c+1];
                v[0] += b0; v[1] += b1; v[2] += b0; v[3] += b1;
#pragma unroll
                for (int j = 0; j < 4; j++)
                    v[j] = 0.5f * v[j] * (1.f + erff(v[j] * 0.70710678118654752f));
            }
            float2 lo = {v[0], v[1]};
            float2 hi = {v[2], v[3]};
            *(float2*)&C[(size_t)r0*N + c]       = lo;
            *(float2*)&C[(size_t)(r0+8)*N + c]   = hi;
        }
    }
}

// ------------------- depthwise causal conv4 + SiLU (3 streams batched) ------
__global__ __launch_bounds__(256) void conv4_silu3(
    const float* __restrict__ x0, const float* __restrict__ x1, const float* __restrict__ x2,
    const float* __restrict__ w0, const float* __restrict__ w1, const float* __restrict__ w2,
    float* __restrict__ y0, float* __restrict__ y1, float* __restrict__ y2)
{
    const float* x; const float* w; float* y;
    if (blockIdx.y == 0)      { x = x0; w = w0; y = y0; }
    else if (blockIdx.y == 1) { x = x1; w = w1; y = y1; }
    else                      { x = x2; w = w2; y = y2; }
    int idx = blockIdx.x * 256 + threadIdx.x;       // over NROW*DD
    int d = idx & (DD-1);
    int l = (idx >> 10) & (LL-1);
    float4 wv = *(const float4*)(w + d*4);
    const float* xp = x + (size_t)idx;
    float acc = wv.w * xp[0];
    if (l >= 1) acc += wv.z * xp[-DD];
    if (l >= 2) acc += wv.y * xp[-2*DD];
    if (l >= 3) acc += wv.x * xp[-3*DD];
    y[idx] = acc / (1.f + expf(-acc));
}

// ------------------------- beta = sigmoid(hs @ Wb^T) ------------------------
__global__ __launch_bounds__(128) void beta_kernel(
    const float* __restrict__ hs, const float* __restrict__ Wb)
{
    __shared__ float red[4][128];
    int n = blockIdx.x, tid = threadIdx.x;
    const float* hr = hs + (size_t)n * DD;
    float s0=0,s1=0,s2=0,s3=0;
    for (int i = tid; i < DD; i += 128) {
        float x = hr[i];
        s0 += x * Wb[i];
        s1 += x * Wb[DD + i];
        s2 += x * Wb[2*DD + i];
        s3 += x * Wb[3*DD + i];
    }
    red[0][tid]=s0; red[1][tid]=s1; red[2][tid]=s2; red[3][tid]=s3;
    __syncthreads();
    for (int st = 64; st > 0; st >>= 1) {
        if (tid < st)
#pragma unroll
            for (int h = 0; h < 4; h++) red[h][tid] += red[h][tid + st];
        __syncthreads();
    }
    if (tid < 4) g_beta[(size_t)n*HH + tid] = 1.f / (1.f + expf(-red[tid][0]));
}

// ---------------- per-chunk delta-rule precompute (tensor-core mma) ---------
// One block per (b,h,chunk). k/q normalized in smem (fp32->tf32 in place),
// A = -beta*(kn kn^T) and attn = tril(qn kn^T) via one fused mma pass,
// serial inversion on warp 0, then u = T'@v, w = T'@kn via mma with
// T' = (A+I) * diag(beta).
#define PSTR 264
#define PSMEM ((2*32*PSTR + 32*33 + 32*36 + 96) * 4)
__global__ __launch_bounds__(256) void precompute_kernel()
{
    extern __shared__ float psm[];
    float*    Kt  = psm;                     // [32][PSTR] k fp32 -> kn tf32
    float*    Qt  = Kt + 32*PSTR;            // [32][PSTR] q fp32 -> qn tf32 -> v tf32
    float*    Am  = Qt + 32*PSTR;            // [32][33]
    unsigned* Ttf = (unsigned*)(Am + 32*33); // [32][36]
    float*    bet = (float*)(Ttf + 32*36);   // [32]
    float*    rnk = bet + 32;                // [32]
    float*    rnq = rnk + 32;                // [32]

    int blk = blockIdx.x;           // (b*HH + h)*NC + c
    int c  = blk % NC;
    int bh = blk / NC;
    int h  = bh % HH;
    int b  = bh / HH;
    int tid = threadIdx.x;
    int l0 = c * 32;
    int wid = tid >> 5, lane = tid & 31;
    int lr = lane >> 2, lk = lane & 3;

    // 1. load k, q tiles (fp32)
    for (int e = tid*4; e < 32*256; e += 1024) {
        int r = e >> 8, d = e & 255;
        size_t gb = ((size_t)(b*LL + l0 + r))*DD + h*DV + d;
        *(float4*)&Kt[r*PSTR + d] = *(const float4*)&g_kc[gb];
        *(float4*)&Qt[r*PSTR + d] = *(const float4*)&g_qc[gb];
    }
    if (tid < 32) bet[tid] = g_beta[((size_t)(b*LL + l0 + tid))*HH + h];
    __syncthreads();

    // 2. row norms (8 threads per row)
    {
        int r = tid >> 3, part = tid & 7;
        float sk = 0.f, sq = 0.f;
        for (int j = part*32; j < part*32 + 32; j++) {
            float x = Kt[r*PSTR + j]; sk += x*x;
            float y = Qt[r*PSTR + j]; sq += y*y;
        }
        sk += __shfl_down_sync(0xffffffffu, sk, 4, 8);
        sk += __shfl_down_sync(0xffffffffu, sk, 2, 8);
        sk += __shfl_down_sync(0xffffffffu, sk, 1, 8);
        sq += __shfl_down_sync(0xffffffffu, sq, 4, 8);
        sq += __shfl_down_sync(0xffffffffu, sq, 2, 8);
        sq += __shfl_down_sync(0xffffffffu, sq, 1, 8);
        if (part == 0) { rnk[r] = rsqrtf(sk + 1e-6f); rnq[r] = rsqrtf(sq + 1e-6f); }
    }
    __syncthreads();

    // 3. normalize in place (fp32 -> global, tf32 -> smem)
    size_t obase = (size_t)blk * (32*256);
    for (int e = tid*4; e < 32*256; e += 1024) {
        int r = e >> 8, d = e & 255;
        float rk = rnk[r], rq = rnq[r];
        float4 kv = *(float4*)&Kt[r*PSTR + d];
        kv.x *= rk; kv.y *= rk; kv.z *= rk; kv.w *= rk;
        *(float4*)&g_kn[obase + e] = kv;
        unsigned* kd = (unsigned*)&Kt[r*PSTR + d];
        kd[0]=f2tf(kv.x); kd[1]=f2tf(kv.y); kd[2]=f2tf(kv.z); kd[3]=f2tf(kv.w);
        float4 qv = *(float4*)&Qt[r*PSTR + d];
        qv.x *= rq; qv.y *= rq; qv.z *= rq; qv.w *= rq;
        *(float4*)&g_qn[obase + e] = qv;
        unsigned* qd = (unsigned*)&Qt[r*PSTR + d];
        qd[0]=f2tf(qv.x); qd[1]=f2tf(qv.y); qd[2]=f2tf(qv.z); qd[3]=f2tf(qv.w);
    }
    __syncthreads();

    // 4. fused mma: Afull = kn@kn^T, attnF = qn@kn^T  (32x32, K=256)
    {
        int m0 = (wid >> 2) * 16, n0 = (wid & 3) * 8;
        const unsigned* Ku = (const unsigned*)Kt;
        const unsigned* Qu = (const unsigned*)Qt;
        float accA[4] = {0,0,0,0}, accQ[4] = {0,0,0,0};
#pragma unroll 4
        for (int kb = 0; kb < 256; kb += 8) {
            unsigned ak[4], aq[4], bf[2];
            ak[0] = Ku[(m0+lr)*PSTR + kb+lk];
            ak[1] = Ku[(m0+lr+8)*PSTR + kb+lk];
            ak[2] = Ku[(m0+lr)*PSTR + kb+lk+4];
            ak[3] = Ku[(m0+lr+8)*PSTR + kb+lk+4];
            aq[0] = Qu[(m0+lr)*PSTR + kb+lk];
            aq[1] = Qu[(m0+lr+8)*PSTR + kb+lk];
            aq[2] = Qu[(m0+lr)*PSTR + kb+lk+4];
            aq[3] = Qu[(m0+lr+8)*PSTR + kb+lk+4];
            bf[0] = Ku[(n0+lr)*PSTR + kb+lk];       // B = kn^T (transposed read)
            bf[1] = Ku[(n0+lr)*PSTR + kb+lk+4];
            mma_tf32(accA, ak, bf);
            mma_tf32(accQ, aq, bf);
        }
        size_t abase = (size_t)blk * 1024;
        int r0 = m0 + lr, r1 = r0 + 8, c0 = n0 + 2*lk, c1 = c0 + 1;
        g_attn[abase + r0*32 + c0] = (c0 <= r0) ? accQ[0] : 0.f;
        g_attn[abase + r0*32 + c1] = (c1 <= r0) ? accQ[1] : 0.f;
        g_attn[abase + r1*32 + c0] = (c0 <= r1) ? accQ[2] : 0.f;
        g_attn[abase + r1*32 + c1] = (c1 <= r1) ? accQ[3] : 0.f;
        Am[r0*33 + c0] = (c0 < r0) ? -bet[r0]*accA[0] : 0.f;
        Am[r0*33 + c1] = (c1 < r0) ? -bet[r0]*accA[1] : 0.f;
        Am[r1*33 + c0] = (c0 < r1) ? -bet[r1]*accA[2] : 0.f;
        Am[r1*33 + c1] = (c1 < r1) ? -bet[r1]*accA[3] : 0.f;
    }
    __syncthreads();

    // 5. iterative inversion (warp 0), then T' = (A+I)*diag(beta) as tf32
    if (tid < 32) {
        int ln = tid;
        for (int i = 1; i < 32; i++) {
            float t = 0.f;
            if (ln < i) for (int p = 0; p < i; p++) t += Am[i*33 + p] * Am[p*33 + ln];
            __syncwarp();
            if (ln < i) Am[i*33 + ln] += t;
            __syncwarp();
        }
    }
    __syncthreads();
    for (int e = tid; e < 1024; e += 256) {
        int i = e >> 5, j = e & 31;
        float t = Am[i*33 + j] + (i == j ? 1.f : 0.f);
        Ttf[i*36 + j] = f2tf(t * bet[j]);
    }
    // 6. load raw v tile as tf32 into Qt (reuse)
    __syncthreads();
    for (int e = tid*4; e < 32*256; e += 1024) {
        int r = e >> 8, d = e & 255;
        float4 vv = *(const float4*)&g_vc[((size_t)(b*LL + l0 + r))*DD + h*DV + d];
        unsigned* qd = (unsigned*)&Qt[r*PSTR + d];
        qd[0]=f2tf(vv.x); qd[1]=f2tf(vv.y); qd[2]=f2tf(vv.z); qd[3]=f2tf(vv.w);
    }
    __syncthreads();

    // 7. u = T'@v, w = T'@kn   (32x256, K=32)
    {
        int m0 = (wid & 1) * 16;
        int nb = (wid >> 1) * 64;
        const unsigned* Ku = (const unsigned*)Kt;
        const unsigned* Vu = (const unsigned*)Qt;
        unsigned a[4][4];
#pragma unroll
        for (int kk = 0; kk < 4; kk++) {
            int kb = kk*8;
            a[kk][0] = Ttf[(m0+lr)*36 + kb+lk];
            a[kk][1] = Ttf[(m0+lr+8)*36 + kb+lk];
            a[kk][2] = Ttf[(m0+lr)*36 + kb+lk+4];
            a[kk][3] = Ttf[(m0+lr+8)*36 + kb+lk+4];
        }
#pragma unroll
        for (int nt = 0; nt < 8; nt++) {
            int n0 = nb + nt*8;
            float au[4] = {0,0,0,0}, aw[4] = {0,0,0,0};
#pragma unroll
            for (int kk = 0; kk < 4; kk++) {
                int kb = kk*8;
                unsigned bu[2], bw[2];
                bu[0] = Vu[(kb+lk)*PSTR + n0+lr];
                bu[1] = Vu[(kb+lk+4)*PSTR + n0+lr];
                bw[0] = Ku[(kb+lk)*PSTR + n0+lr];
                bw[1] = Ku[(kb+lk+4)*PSTR + n0+lr];
                mma_tf32(au, a[kk], bu);
                mma_tf32(aw, a[kk], bw);
            }
            int r0 = m0 + lr, r1 = r0 + 8, cc = n0 + 2*lk;
            float2 u01 = {au[0], au[1]}, u23 = {au[2], au[3]};
            float2 w01 = {aw[0], aw[1]}, w23 = {aw[2], aw[3]};
            *(float2*)&g_u[obase + r0*256 + cc] = u01;
            *(float2*)&g_u[obase + r1*256 + cc] = u23;
            *(float2*)&g_w[obase + r0*256 + cc] = w01;
            *(float2*)&g_w[obase + r1*256 + cc] = w23;
        }
    }
}

// --------------- sequential inter-chunk scan (tensor-core mma) --------------
#define SSTR 40     // stride for [.. x 32] arrays (bank-conflict-free frags)
#define TSTR 264    // stride for [32 x 256] tiles
#define SCAN_SMEM ((256*SSTR*2 + 32*TSTR + 3*32*SSTR) * 4)
__global__ __launch_bounds__(256) void scan_kernel()
{
    extern __shared__ float sm[];
    float*    Sf  = sm;                           // [256][SSTR] fp32 master
    unsigned* Stf = (unsigned*)(sm + 256*SSTR);   // [256][SSTR] tf32 shadow
    unsigned* Ttf = Stf + 256*SSTR;               // [32][TSTR]  w/q/k tile tf32
    float*    Ui  = (float*)(Ttf + 32*TSTR);      // [32][SSTR]  u then u_i fp32
    unsigned* Utf = (unsigned*)(Ui + 32*SSTR);    // [32][SSTR]  u_i tf32
    unsigned* Atf = Utf + 32*SSTR;                // [32][SSTR]  attn tf32

    int blk = blockIdx.x;               // (b*HH+h)*NG + g
    int g  = blk & (NG-1);
    int bh = blk >> 3;
    int b  = bh >> 2;
    int h  = bh & 3;
    int tid = threadIdx.x;
    int wid = tid >> 5, lane = tid & 31;
    int lr = lane >> 2, lk = lane & 3;
    int m0 = (wid >> 2) * 16;           // (1)/(2) warp tile: 2 x 4
    int n0 = (wid & 3) * 8;

    for (int e = tid; e < 256*SSTR; e += 256) { Sf[e] = 0.f; Stf[e] = 0u; }
    __syncthreads();

    for (int c = 0; c < NC; c++) {
        size_t base = ((size_t)bh*NC + c) * (32*256);
        size_t abase = ((size_t)bh*NC + c) * 1024;

        // load u slice (32x32) + attn (32x32) ; w tile (32x256) as tf32
        for (int e = tid; e < 1024; e += 256) {
            int r = e >> 5, j = e & 31;
            Ui[r*SSTR + j]  = g_u[base + r*256 + g*32 + j];
            Atf[r*SSTR + j] = f2tf(g_attn[abase + e]);
        }
        for (int e = tid*4; e < 8192; e += 1024) {
            float4 v = *(const float4*)&g_w[base + e];
            unsigned* dst = &Ttf[(e >> 8)*TSTR + (e & 255)];
            dst[0]=f2tf(v.x); dst[1]=f2tf(v.y); dst[2]=f2tf(v.z); dst[3]=f2tf(v.w);
        }
        __syncthreads();

        // (1) u_i = u - w@S    (32x32, K=256)
        {
            float acc[4] = {0.f, 0.f, 0.f, 0.f};
#pragma unroll 4
            for (int kb = 0; kb < 256; kb += 8) {
                unsigned a[4], bf[2];
                a[0] = Ttf[(m0+lr)*TSTR + kb+lk];
                a[1] = Ttf[(m0+lr+8)*TSTR + kb+lk];
                a[2] = Ttf[(m0+lr)*TSTR + kb+lk+4];
                a[3] = Ttf[(m0+lr+8)*TSTR + kb+lk+4];
                bf[0] = Stf[(kb+lk)*SSTR + n0+lr];
                bf[1] = Stf[(kb+lk+4)*SSTR + n0+lr];
                mma_tf32(acc, a, bf);
            }
            int r0 = m0 + lr, r1 = r0 + 8, cb = n0 + 2*lk;
            float u0 = Ui[r0*SSTR+cb]   - acc[0];
            float u1 = Ui[r0*SSTR+cb+1] - acc[1];
            float u2 = Ui[r1*SSTR+cb]   - acc[2];
            float u3 = Ui[r1*SSTR+cb+1] - acc[3];
            Ui[r0*SSTR+cb] = u0; Ui[r0*SSTR+cb+1] = u1;
            Ui[r1*SSTR+cb] = u2; Ui[r1*SSTR+cb+1] = u3;
            Utf[r0*SSTR+cb] = f2tf(u0); Utf[r0*SSTR+cb+1] = f2tf(u1);
            Utf[r1*SSTR+cb] = f2tf(u2); Utf[r1*SSTR+cb+1] = f2tf(u3);
        }
        __syncthreads();

        // load q tile
        for (int e = tid*4; e < 8192; e += 1024) {
            float4 v = *(const float4*)&g_qn[base + e];
            unsigned* dst = &Ttf[(e >> 8)*TSTR + (e & 255)];
            dst[0]=f2tf(v.x); dst[1]=f2tf(v.y); dst[2]=f2tf(v.z); dst[3]=f2tf(v.w);
        }
        __syncthreads();

        // (2) o = q@S + attn@u_i  -> g_delta
        {
            float acc[4] = {0.f, 0.f, 0.f, 0.f};
#pragma unroll 4
            for (int kb = 0; kb < 256; kb += 8) {
                unsigned a[4], bf[2];
                a[0] = Ttf[(m0+lr)*TSTR + kb+lk];
                a[1] = Ttf[(m0+lr+8)*TSTR + kb+lk];
                a[2] = Ttf[(m0+lr)*TSTR + kb+lk+4];
                a[3] = Ttf[(m0+lr+8)*TSTR + kb+lk+4];
                bf[0] = Stf[(kb+lk)*SSTR + n0+lr];
                bf[1] = Stf[(kb+lk+4)*SSTR + n0+lr];
                mma_tf32(acc, a, bf);
            }
#pragma unroll
            for (int kb = 0; kb < 32; kb += 8) {
                unsigned a[4], bf[2];
                a[0] = Atf[(m0+lr)*SSTR + kb+lk];
                a[1] = Atf[(m0+lr+8)*SSTR + kb+lk];
                a[2] = Atf[(m0+lr)*SSTR + kb+lk+4];
                a[3] = Atf[(m0+lr+8)*SSTR + kb+lk+4];
                bf[0] = Utf[(kb+lk)*SSTR + n0+lr];
                bf[1] = Utf[(kb+lk+4)*SSTR + n0+lr];
                mma_tf32(acc, a, bf);
            }
            size_t ob = ((size_t)(b*LL + c*32 + m0 + lr))*DD + h*DV + g*32 + n0 + 2*lk;
            float2 lo = {acc[0], acc[1]};
            float2 hi = {acc[2], acc[3]};
            *(float2*)&g_delta[ob]        = lo;
            *(float2*)&g_delta[ob + 8*DD] = hi;
        }
        __syncthreads();

        // load k tile
        for (int e = tid*4; e < 8192; e += 1024) {
            float4 v = *(const float4*)&g_kn[base + e];
            unsigned* dst = &Ttf[(e >> 8)*TSTR + (e & 255)];
            dst[0]=f2tf(v.x); dst[1]=f2tf(v.y); dst[2]=f2tf(v.z); dst[3]=f2tf(v.w);
        }
        __syncthreads();

        // (3) S += k^T @ u_i   (M=256, N=32, K=32); k^T read transposed
#pragma unroll
        for (int t = 0; t < 2; t++) {
            int tm = (wid*2 + t) * 16;
#pragma unroll
            for (int tn = 0; tn < 4; tn++) {
                int nn = tn*8;
                int r0 = tm + lr, r1 = r0 + 8, cb = nn + 2*lk;
                float acc[4];
                acc[0] = Sf[r0*SSTR+cb]; acc[1] = Sf[r0*SSTR+cb+1];
                acc[2] = Sf[r1*SSTR+cb]; acc[3] = Sf[r1*SSTR+cb+1];
#pragma unroll
                for (int kb = 0; kb < 32; kb += 8) {
                    unsigned a[4], bf[2];
                    a[0] = Ttf[(kb+lk)*TSTR + tm+lr];
                    a[1] = Ttf[(kb+lk)*TSTR + tm+lr+8];
                    a[2] = Ttf[(kb+lk+4)*TSTR + tm+lr];
                    a[3] = Ttf[(kb+lk+4)*TSTR + tm+lr+8];
                    bf[0] = Utf[(kb+lk)*SSTR + nn+lr];
                    bf[1] = Utf[(kb+lk+4)*SSTR + nn+lr];
                    mma_tf32(acc, a, bf);
                }
                Sf[r0*SSTR+cb] = acc[0]; Sf[r0*SSTR+cb+1] = acc[1];
                Sf[r1*SSTR+cb] = acc[2]; Sf[r1*SSTR+cb+1] = acc[3];
                Stf[r0*SSTR+cb] = f2tf(acc[0]); Stf[r0*SSTR+cb+1] = f2tf(acc[1]);
                Stf[r1*SSTR+cb] = f2tf(acc[2]); Stf[r1*SSTR+cb+1] = f2tf(acc[3]);
            }
        }
        __syncthreads();
    }
}

// ------------------- per-(head,channel) FIR conv (float2) -------------------
template<int K>
__global__ __launch_bounds__(256) void fir_kernel(
    const float* __restrict__ fw, float* __restrict__ y)
{
    __shared__ float2 vbuf[(128 + K - 1) * 16];
    __shared__ float2 wbuf[16 * K];
    int bh = blockIdx.x;
    int b = bh / HH, h = bh % HH;
    int l0 = blockIdx.y * 128;
    int d0 = blockIdx.z * 32;
    int tid = threadIdx.x;

    for (int idx = tid; idx < 16*K; idx += 256) {
        int dp = idx / K, t = idx % K;
        float2 wv;
        wv.x = fw[(size_t)(h*DV + d0 + 2*dp)*K + t];
        wv.y = fw[(size_t)(h*DV + d0 + 2*dp + 1)*K + t];
        wbuf[dp*K + t] = wv;
    }
    for (int idx = tid; idx < (128 + K - 1)*16; idx += 256) {
        int lrr = idx >> 4, dp = idx & 15;
        int l = l0 - (K - 1) + lrr;
        vbuf[idx] = (l >= 0)
            ? *(const float2*)&g_vc[((size_t)(b*LL + l))*DD + h*DV + d0 + 2*dp]
            : make_float2(0.f, 0.f);
    }
    __syncthreads();

    int dp = tid & 15;
    int lr0 = (tid >> 4) * 8;
    for (int m = 0; m < 8; m++) {
        int lrr = lr0 + m;
        float2 acc = {0.f, 0.f};
#pragma unroll
        for (int t = 0; t < K; t++) {
            float2 v = vbuf[(lrr + t)*16 + dp];
            float2 wv = wbuf[dp*K + t];
            acc.x = fmaf(v.x, wv.x, acc.x);
            acc.y = fmaf(v.y, wv.y, acc.y);
        }
        *(float2*)&y[((size_t)(b*LL + l0 + lrr))*DD + h*DV + d0 + 2*dp] = acc;
    }
}

// ------------------------- gate input assembly (hs + stats) -----------------
__global__ __launch_bounds__(256) void stats_kernel(const float* __restrict__ hs)
{
    int n = blockIdx.x, tid = threadIdx.x;
    for (int i = tid; i < DD; i += 256)
        g_gatein[(size_t)n*GIN + i] = hs[(size_t)n*DD + i];
    int warp = tid >> 5, lane = tid & 31;
    for (int rep = 0; rep < 2; rep++) {
        int combo = warp*2 + rep;
        int path = combo >> 2, h = combo & 3;
        const float* p;
        if      (path == 0) p = g_short;
        else if (path == 1) p = g_long;
        else if (path == 2) p = g_delta;
        else                p = g_vc;
        p += (size_t)n*DD + h*DV;
        float s1 = 0.f, s2 = 0.f;
        for (int j = lane; j < 256; j += 32) { float x = p[j]; s1 += x; s2 += x*x; }
#pragma unroll
        for (int st = 16; st > 0; st >>= 1) {
            s1 += __shfl_down_sync(0xffffffffu, s1, st);
            s2 += __shfl_down_sync(0xffffffffu, s2, st);
        }
        if (lane == 0) {
            float m  = s1 * (1.f/256.f);
            float va = s2 * (1.f/256.f) - m*m;
            g_gatein[(size_t)n*GIN + DD + path*8 + h*2]     = m;
            g_gatein[(size_t)n*GIN + DD + path*8 + h*2 + 1] = va;
        }
    }
}

// ------------------------- gate2 + softmax + floor --------------------------
__global__ __launch_bounds__(256) void gate2_kernel(
    const float* __restrict__ w2, const float* __restrict__ log_temp,
    const float* __restrict__ base_bias, const float* __restrict__ floor_raw)
{
    __shared__ float hrow[HID];
    __shared__ float lg[16];
    int n = blockIdx.x, tid = threadIdx.x;
    for (int i = tid; i < HID; i += 256) hrow[i] = g_hmid[(size_t)n*HID + i];
    __syncthreads();
    int warp = tid >> 5, lane = tid & 31;
    for (int rep = 0; rep < 2; rep++) {
        int o = warp*2 + rep;
        const float* wr = w2 + (size_t)o*HID;
        float s = 0.f;
        for (int i = lane; i < HID; i += 32) s = fmaf(hrow[i], wr[i], s);
#pragma unroll
        for (int st = 16; st > 0; st >>= 1) s += __shfl_down_sync(0xffffffffu, s, st);
        if (lane == 0) lg[o] = s;
    }
    __syncthreads();
    if (tid < 4) {
        int h = tid;
        float temp = log1pf(expf(log_temp[h])) + 1e-4f;
        float z[4], m = -1e30f;
#pragma unroll
        for (int i = 0; i < 4; i++) {
            z[i] = (lg[h*4+i] + base_bias[h*4+i]) / temp;
            m = fmaxf(m, z[i]);
        }
        float e[4], s = 0.f;
#pragma unroll
        for (int i = 0; i < 4; i++) { e[i] = expf(z[i] - m); s += e[i]; }
        float p[4], s2 = 0.f;
#pragma unroll
        for (int i = 0; i < 4; i++) {
            p[i] = e[i] / s;
            float f = 0.05f / (1.f + expf(-floor_raw[h*4+i]));
            p[i] = fmaxf(p[i], f);
            s2 += p[i];
        }
#pragma unroll
        for (int i = 0; i < 4; i++) g_probs[(size_t)n*16 + h*4 + i] = p[i] / s2;
    }
}

// ------------------------- path mix + RMS norm ------------------------------
__global__ __launch_bounds__(256) void mix_kernel(const float* __restrict__ onorm)
{
    __shared__ float pr[16];
    __shared__ float wsum[8];
    int n = blockIdx.x, tid = threadIdx.x;
    if (tid < 16) pr[tid] = g_probs[(size_t)n*16 + tid];
    __syncthreads();
    int h = tid >> 6;
    int dd = (tid & 63) * 4;
    size_t pb = (size_t)n*DD + h*DV + dd;
    float4 sh = *(const float4*)&g_short[pb];
    float4 lo = *(const float4*)&g_long[pb];
    float4 de = *(const float4*)&g_delta[pb];
    float4 vv = *(const float4*)&g_vc[pb];
    float p0 = pr[h*4+0], p1 = pr[h*4+1], p2 = pr[h*4+2], p3 = pr[h*4+3];
    float o[4];
    o[0] = p0*sh.x + p1*lo.x + p2*de.x + p3*vv.x;
    o[1] = p0*sh.y + p1*lo.y + p2*de.y + p3*vv.y;
    o[2] = p0*sh.z + p1*lo.z + p2*de.z + p3*vv.z;
    o[3] = p0*sh.w + p1*lo.w + p2*de.w + p3*vv.w;
    float ss = o[0]*o[0] + o[1]*o[1] + o[2]*o[2] + o[3]*o[3];
#pragma unroll
    for (int st = 16; st > 0; st >>= 1) ss += __shfl_down_sync(0xffffffffu, ss, st);
    int warp = tid >> 5, lane = tid & 31;
    if (lane == 0) wsum[warp] = ss;
    __syncthreads();
    float tot = wsum[h*2] + wsum[h*2+1];
    float scale = rsqrtf(tot * (1.f/256.f) + 1e-5f);
    float r[4];
#pragma unroll
    for (int j = 0; j < 4; j++) r[j] = o[j] * scale * onorm[dd + j];
    *(float4*)&g_mix[pb] = *(float4*)r;
}

// ------------------------- launch ------------------------------------------
extern "C" void kernel_launch(void* const* d_in, const int* in_sizes, int n_in,
                              void* d_out, int out_size)
{
    const float* hs        = (const float*)d_in[0];
    const float* Wq        = (const float*)d_in[1];
    const float* Wk        = (const float*)d_in[2];
    const float* Wv        = (const float*)d_in[3];
    const float* Wb        = (const float*)d_in[4];
    const float* qconv_w   = (const float*)d_in[5];
    const float* kconv_w   = (const float*)d_in[6];
    const float* vconv_w   = (const float*)d_in[7];
    const float* fir_s     = (const float*)d_in[8];
    const float* fir_l     = (const float*)d_in[9];
    const float* gate_w1   = (const float*)d_in[10];
    const float* gate_b1   = (const float*)d_in[11];
    const float* gate_w2   = (const float*)d_in[12];
    const float* log_temp  = (const float*)d_in[13];
    const float* base_bias = (const float*)d_in[14];
    const float* floor_raw = (const float*)d_in[15];
    const float* onorm_w   = (const float*)d_in[16];
    const float* Wo        = (const float*)d_in[17];
    float* out = (float*)d_out;

    void *p_qlin, *p_klin, *p_vlin, *p_qc, *p_kc, *p_vc, *p_gatein, *p_hmid,
         *p_mix, *p_short, *p_long;
    cudaGetSymbolAddress(&p_qlin, g_qlin);
    cudaGetSymbolAddress(&p_klin, g_klin);
    cudaGetSymbolAddress(&p_vlin, g_vlin);
    cudaGetSymbolAddress(&p_qc, g_qc);
    cudaGetSymbolAddress(&p_kc, g_kc);
    cudaGetSymbolAddress(&p_vc, g_vc);
    cudaGetSymbolAddress(&p_gatein, g_gatein);
    cudaGetSymbolAddress(&p_hmid, g_hmid);
    cudaGetSymbolAddress(&p_mix, g_mix);
    cudaGetSymbolAddress(&p_short, g_short);
    cudaGetSymbolAddress(&p_long, g_long);

    cudaFuncSetAttribute(scan_kernel,
        cudaFuncAttributeMaxDynamicSharedMemorySize, SCAN_SMEM);
    cudaFuncSetAttribute(precompute_kernel,
        cudaFuncAttributeMaxDynamicSharedMemorySize, PSMEM);

    dim3 blk(256);

    // q/k/v projections — one batched tensor-core launch
    tf32_gemm<<<dim3(DD/128, NROW/128, 3), blk>>>(
        hs, Wq, Wk, Wv,
        (float*)p_qlin, (float*)p_klin, (float*)p_vlin,
        nullptr, NROW, DD, DD, 0);

    // causal conv4 + SiLU (all three streams in one launch)
    conv4_silu3<<<dim3(NROW*DD/256, 3), blk>>>(
        (const float*)p_qlin, (const float*)p_klin, (const float*)p_vlin,
        qconv_w, kconv_w, vconv_w,
        (float*)p_qc, (float*)p_kc, (float*)p_vc);

    // beta
    beta_kernel<<<NROW, 128>>>(hs, Wb);

    // delta-rule
    precompute_kernel<<<BB*HH*NC, blk, PSMEM>>>();
    scan_kernel<<<BB*HH*NG, blk, SCAN_SMEM>>>();

    // FIR paths
    fir_kernel<3><<<dim3(BB*HH, LL/128, DV/32), blk>>>(fir_s, (float*)p_short);
    fir_kernel<63><<<dim3(BB*HH, LL/128, DV/32), blk>>>(fir_l, (float*)p_long);

    // gate
    stats_kernel<<<NROW, blk>>>(hs);
    tf32_gemm<<<dim3(HID/128, NROW/128, 1), blk>>>(
        (const float*)p_gatein, gate_w1, nullptr, nullptr,
        (float*)p_hmid, nullptr, nullptr,
        gate_b1, NROW, HID, GIN, 1);
    gate2_kernel<<<NROW, blk>>>(gate_w2, log_temp, base_bias, floor_raw);

    // mix + RMS norm
    mix_kernel<<<NROW, blk>>>(onorm_w);

    // output projection
    tf32_gemm<<<dim3(DD/128, NROW/128, 1), blk>>>(
        (const float*)p_mix, Wo, nullptr, nullptr,
        out, nullptr, nullptr,
        nullptr, NROW, DD, DD, 0);
}

// round 7
// speedup vs baseline: 2.1820x; 1.0572x over previous
#include <cuda_runtime.h>
#include <math.h>

#define BB 2
#define LL 2048
#define DD 1024
#define HH 4
#define DV 256
#define CKN 32
#define NC 64              // LL / CKN
#define NROW (BB*LL)       // 4096
#define GIN 1056
#define HID 2048
#define NG 8               // Dv groups of 32 in the scan

// ------------------------- scratch (device globals) -------------------------
__device__ float g_qlin[NROW*DD];
__device__ float g_klin[NROW*DD];
__device__ float g_vlin[NROW*DD];
__device__ float g_qc[NROW*DD];
__device__ float g_kc[NROW*DD];
__device__ float g_vc[NROW*DD];
__device__ float g_beta[NROW*HH];
__device__ float g_qn[NROW*DD];
__device__ float g_kn[NROW*DD];
__device__ float g_u[NROW*DD];
__device__ float g_w[NROW*DD];
__device__ float g_attn[BB*HH*NC*CKN*CKN];
__device__ float g_delta[NROW*DD];
__device__ float g_short[NROW*DD];
__device__ float g_long[NROW*DD];
__device__ float g_gatein[NROW*GIN];     // stored as tf32 bit patterns
__device__ float g_hmid[NROW*HID];
__device__ float g_probs[NROW*16];
__device__ float g_mix[NROW*DD];         // stored as tf32 bit patterns
// tf32 pre-converted operands
__device__ unsigned g_hs_tf[NROW*DD];
__device__ unsigned g_wq_tf[DD*DD];
__device__ unsigned g_wk_tf[DD*DD];
__device__ unsigned g_wv_tf[DD*DD];
__device__ unsigned g_wo_tf[DD*DD];
__device__ unsigned g_gw1_tf[HID*GIN];

// ------------------------- tf32 helpers -------------------------------------
__device__ __forceinline__ unsigned f2tf(float x) {
    unsigned r;
    asm("cvt.rna.tf32.f32 %0, %1;" : "=r"(r) : "f"(x));
    return r;
}

__device__ __forceinline__ void mma_tf32(float* c, const unsigned* a, const unsigned* b) {
    asm volatile(
        "mma.sync.aligned.m16n8k8.row.col.f32.tf32.tf32.f32 "
        "{%0,%1,%2,%3}, {%4,%5,%6,%7}, {%8,%9}, {%0,%1,%2,%3};"
        : "+f"(c[0]), "+f"(c[1]), "+f"(c[2]), "+f"(c[3])
        : "r"(a[0]), "r"(a[1]), "r"(a[2]), "r"(a[3]), "r"(b[0]), "r"(b[1]));
}

// ------------------------- bulk fp32 -> tf32 conversion ---------------------
__global__ __launch_bounds__(256) void cvt_tf32_6(
    const float* __restrict__ s0, unsigned* __restrict__ d0, int n0,
    const float* __restrict__ s1, unsigned* __restrict__ d1, int n1,
    const float* __restrict__ s2, unsigned* __restrict__ d2, int n2,
    const float* __restrict__ s3, unsigned* __restrict__ d3, int n3,
    const float* __restrict__ s4, unsigned* __restrict__ d4, int n4,
    const float* __restrict__ s5, unsigned* __restrict__ d5, int n5)
{
    const float* s; unsigned* d; int n;
    switch (blockIdx.y) {
        case 0: s=s0; d=d0; n=n0; break;
        case 1: s=s1; d=d1; n=n1; break;
        case 2: s=s2; d=d2; n=n2; break;
        case 3: s=s3; d=d3; n=n3; break;
        case 4: s=s4; d=d4; n=n4; break;
        default: s=s5; d=d5; n=n5; break;
    }
    int i = (blockIdx.x * 256 + threadIdx.x) * 4;
    if (i < n) {
        float4 v = *(const float4*)(s + i);
        uint4 o;
        o.x = f2tf(v.x); o.y = f2tf(v.y); o.z = f2tf(v.z); o.w = f2tf(v.w);
        *(uint4*)(d + i) = o;
    }
}

// ------------------- tf32 tensor-core GEMM: C = A(MxK) @ B(NxK)^T ------------
// A, B already tf32 bit patterns. 4-stage cp.async pipeline, 128x128 tile,
// 256 threads (8 warps, 2x4), warp tile 64x32.
// blockIdx.z selects among up to 3 (B, C) pairs for batching q/k/v.
// mode 0: plain.  mode 1: +bias[col], exact GELU.
#define LDB 20
#define STAGES 4
#define STG_WORDS (128*LDB)
#define GEMM_SMEM (2*STAGES*STG_WORDS*4)
__global__ __launch_bounds__(256, 2) void tf32_gemm(
    const unsigned* __restrict__ A,
    const unsigned* __restrict__ Bm0, const unsigned* __restrict__ Bm1, const unsigned* __restrict__ Bm2,
    float* __restrict__ Cm0, float* __restrict__ Cm1, float* __restrict__ Cm2,
    const float* __restrict__ bias, int M, int N, int K, int mode)
{
    extern __shared__ unsigned gsm[];

    const unsigned* B = (blockIdx.z == 0) ? Bm0 : (blockIdx.z == 1) ? Bm1 : Bm2;
    float*          C = (blockIdx.z == 0) ? Cm0 : (blockIdx.z == 1) ? Cm1 : Cm2;

    int tid  = threadIdx.x;
    int bm   = blockIdx.y * 128, bn = blockIdx.x * 128;
    int lrow = tid >> 1;
    int lcol = (tid & 1) * 8;
    const unsigned* Ap = A + (size_t)(bm + lrow) * K + lcol;
    const unsigned* Bp = B + (size_t)(bn + lrow) * K + lcol;

    unsigned smb;
    asm("{ .reg .u64 t; cvta.to.shared.u64 t, %1; cvt.u32.u64 %0, t; }"
        : "=r"(smb) : "l"(gsm));
    const unsigned STG_BYTES = STG_WORDS * 4;
    unsigned a_sm = smb + (lrow*LDB + lcol)*4;
    unsigned b_sm = a_sm + STAGES*STG_BYTES;

    int wid = tid >> 5, lane = tid & 31;
    int wm = (wid >> 2) * 64, wn = (wid & 3) * 32;
    int lr = lane >> 2, lk = lane & 3;

    float acc[4][4][4];
#pragma unroll
    for (int mi = 0; mi < 4; mi++)
#pragma unroll
        for (int ni = 0; ni < 4; ni++)
#pragma unroll
            for (int j = 0; j < 4; j++) acc[mi][ni][j] = 0.f;

    int niter = K >> 4;

#define GEMM_ISSUE(s, kt) do {                                                   \
        unsigned as_ = a_sm + (s)*STG_BYTES;                                     \
        unsigned bs_ = b_sm + (s)*STG_BYTES;                                     \
        asm volatile("cp.async.cg.shared.global [%0], [%1], 16;" :: "r"(as_),    "l"(Ap + (kt)));     \
        asm volatile("cp.async.cg.shared.global [%0], [%1], 16;" :: "r"(as_+16), "l"(Ap + (kt) + 4)); \
        asm volatile("cp.async.cg.shared.global [%0], [%1], 16;" :: "r"(bs_),    "l"(Bp + (kt)));     \
        asm volatile("cp.async.cg.shared.global [%0], [%1], 16;" :: "r"(bs_+16), "l"(Bp + (kt) + 4)); \
    } while (0)

#pragma unroll
    for (int s = 0; s < STAGES-1; s++) {
        if (s < niter) GEMM_ISSUE(s, s*16);
        asm volatile("cp.async.commit_group;");
    }

    for (int it = 0; it < niter; it++) {
        asm volatile("cp.async.wait_group 2;");
        __syncthreads();
        int cur = it & 3;
        const unsigned* Ac = gsm + cur*STG_WORDS;
        const unsigned* Bc = gsm + STAGES*STG_WORDS + cur*STG_WORDS;
#pragma unroll
        for (int ks = 0; ks < 2; ks++) {
            int kb = ks * 8;
            unsigned af[4][4], bf[4][2];
#pragma unroll
            for (int mi = 0; mi < 4; mi++) {
                int r = wm + mi*16 + lr;
                af[mi][0] = Ac[r*LDB + kb + lk];
                af[mi][1] = Ac[(r+8)*LDB + kb + lk];
                af[mi][2] = Ac[r*LDB + kb + lk + 4];
                af[mi][3] = Ac[(r+8)*LDB + kb + lk + 4];
            }
#pragma unroll
            for (int ni = 0; ni < 4; ni++) {
                int n = wn + ni*8 + lr;
                bf[ni][0] = Bc[n*LDB + kb + lk];
                bf[ni][1] = Bc[n*LDB + kb + lk + 4];
            }
#pragma unroll
            for (int mi = 0; mi < 4; mi++)
#pragma unroll
                for (int ni = 0; ni < 4; ni++)
                    mma_tf32(acc[mi][ni], af[mi], bf[ni]);
        }
        int nx = it + STAGES - 1;
        if (nx < niter) GEMM_ISSUE(nx & 3, nx*16);
        asm volatile("cp.async.commit_group;");
    }

#pragma unroll
    for (int mi = 0; mi < 4; mi++) {
        int r0 = bm + wm + mi*16 + lr;
#pragma unroll
        for (int ni = 0; ni < 4; ni++) {
            int c = bn + wn + ni*8 + 2*lk;
            float v[4] = {acc[mi][ni][0], acc[mi][ni][1], acc[mi][ni][2], acc[mi][ni][3]};
            if (mode == 1) {
                float b0 = bias[c], b1 = bias[c+1];
                v[0] += b0; v[1] += b1; v[2] += b0; v[3] += b1;
#pragma unroll
                for (int j = 0; j < 4; j++)
                    v[j] = 0.5f * v[j] * (1.f + erff(v[j] * 0.70710678118654752f));
            }
            float2 lo = {v[0], v[1]};
            float2 hi = {v[2], v[3]};
            *(float2*)&C[(size_t)r0*N + c]       = lo;
            *(float2*)&C[(size_t)(r0+8)*N + c]   = hi;
        }
    }
}

// ------------------- depthwise causal conv4 + SiLU (3 streams batched) ------
__global__ __launch_bounds__(256) void conv4_silu3(
    const float* __restrict__ x0, const float* __restrict__ x1, const float* __restrict__ x2,
    const float* __restrict__ w0, const float* __restrict__ w1, const float* __restrict__ w2,
    float* __restrict__ y0, float* __restrict__ y1, float* __restrict__ y2)
{
    const float* x; const float* w; float* y;
    if (blockIdx.y == 0)      { x = x0; w = w0; y = y0; }
    else if (blockIdx.y == 1) { x = x1; w = w1; y = y1; }
    else                      { x = x2; w = w2; y = y2; }
    int idx = blockIdx.x * 256 + threadIdx.x;       // over NROW*DD
    int d = idx & (DD-1);
    int l = (idx >> 10) & (LL-1);
    float4 wv = *(const float4*)(w + d*4);
    const float* xp = x + (size_t)idx;
    float acc = wv.w * xp[0];
    if (l >= 1) acc += wv.z * xp[-DD];
    if (l >= 2) acc += wv.y * xp[-2*DD];
    if (l >= 3) acc += wv.x * xp[-3*DD];
    y[idx] = acc / (1.f + expf(-acc));
}

// ------------------------- beta = sigmoid(hs @ Wb^T) ------------------------
__global__ __launch_bounds__(128) void beta_kernel(
    const float* __restrict__ hs, const float* __restrict__ Wb)
{
    __shared__ float red[4][128];
    int n = blockIdx.x, tid = threadIdx.x;
    const float* hr = hs + (size_t)n * DD;
    float s0=0,s1=0,s2=0,s3=0;
    for (int i = tid; i < DD; i += 128) {
        float x = hr[i];
        s0 += x * Wb[i];
        s1 += x * Wb[DD + i];
        s2 += x * Wb[2*DD + i];
        s3 += x * Wb[3*DD + i];
    }
    red[0][tid]=s0; red[1][tid]=s1; red[2][tid]=s2; red[3][tid]=s3;
    __syncthreads();
    for (int st = 64; st > 0; st >>= 1) {
        if (tid < st)
#pragma unroll
            for (int h = 0; h < 4; h++) red[h][tid] += red[h][tid + st];
        __syncthreads();
    }
    if (tid < 4) g_beta[(size_t)n*HH + tid] = 1.f / (1.f + expf(-red[tid][0]));
}

// ---------------- per-chunk delta-rule precompute (tensor-core mma) ---------
#define PSTR 264
#define PSMEM ((2*32*PSTR + 32*33 + 32*36 + 96) * 4)
__global__ __launch_bounds__(256) void precompute_kernel()
{
    extern __shared__ float psm[];
    float*    Kt  = psm;                     // [32][PSTR] k fp32 -> kn tf32
    float*    Qt  = Kt + 32*PSTR;            // [32][PSTR] q fp32 -> qn tf32 -> v tf32
    float*    Am  = Qt + 32*PSTR;            // [32][33]
    unsigned* Ttf = (unsigned*)(Am + 32*33); // [32][36]
    float*    bet = (float*)(Ttf + 32*36);   // [32]
    float*    rnk = bet + 32;                // [32]
    float*    rnq = rnk + 32;                // [32]

    int blk = blockIdx.x;           // (b*HH + h)*NC + c
    int c  = blk % NC;
    int bh = blk / NC;
    int h  = bh % HH;
    int b  = bh / HH;
    int tid = threadIdx.x;
    int l0 = c * 32;
    int wid = tid >> 5, lane = tid & 31;
    int lr = lane >> 2, lk = lane & 3;

    // 1. load k, q tiles (fp32)
    for (int e = tid*4; e < 32*256; e += 1024) {
        int r = e >> 8, d = e & 255;
        size_t gb = ((size_t)(b*LL + l0 + r))*DD + h*DV + d;
        *(float4*)&Kt[r*PSTR + d] = *(const float4*)&g_kc[gb];
        *(float4*)&Qt[r*PSTR + d] = *(const float4*)&g_qc[gb];
    }
    if (tid < 32) bet[tid] = g_beta[((size_t)(b*LL + l0 + tid))*HH + h];
    __syncthreads();

    // 2. row norms (8 threads per row)
    {
        int r = tid >> 3, part = tid & 7;
        float sk = 0.f, sq = 0.f;
        for (int j = part*32; j < part*32 + 32; j++) {
            float x = Kt[r*PSTR + j]; sk += x*x;
            float y = Qt[r*PSTR + j]; sq += y*y;
        }
        sk += __shfl_down_sync(0xffffffffu, sk, 4, 8);
        sk += __shfl_down_sync(0xffffffffu, sk, 2, 8);
        sk += __shfl_down_sync(0xffffffffu, sk, 1, 8);
        sq += __shfl_down_sync(0xffffffffu, sq, 4, 8);
        sq += __shfl_down_sync(0xffffffffu, sq, 2, 8);
        sq += __shfl_down_sync(0xffffffffu, sq, 1, 8);
        if (part == 0) { rnk[r] = rsqrtf(sk + 1e-6f); rnq[r] = rsqrtf(sq + 1e-6f); }
    }
    __syncthreads();

    // 3. normalize in place (fp32 -> global, tf32 -> smem)
    size_t obase = (size_t)blk * (32*256);
    for (int e = tid*4; e < 32*256; e += 1024) {
        int r = e >> 8, d = e & 255;
        float rk = rnk[r], rq = rnq[r];
        float4 kv = *(float4*)&Kt[r*PSTR + d];
        kv.x *= rk; kv.y *= rk; kv.z *= rk; kv.w *= rk;
        *(float4*)&g_kn[obase + e] = kv;
        unsigned* kd = (unsigned*)&Kt[r*PSTR + d];
        kd[0]=f2tf(kv.x); kd[1]=f2tf(kv.y); kd[2]=f2tf(kv.z); kd[3]=f2tf(kv.w);
        float4 qv = *(float4*)&Qt[r*PSTR + d];
        qv.x *= rq; qv.y *= rq; qv.z *= rq; qv.w *= rq;
        *(float4*)&g_qn[obase + e] = qv;
        unsigned* qd = (unsigned*)&Qt[r*PSTR + d];
        qd[0]=f2tf(qv.x); qd[1]=f2tf(qv.y); qd[2]=f2tf(qv.z); qd[3]=f2tf(qv.w);
    }
    __syncthreads();

    // 4. fused mma: Afull = kn@kn^T, attnF = qn@kn^T  (32x32, K=256)
    {
        int m0 = (wid >> 2) * 16, n0 = (wid & 3) * 8;
        const unsigned* Ku = (const unsigned*)Kt;
        const unsigned* Qu = (const unsigned*)Qt;
        float accA[4] = {0,0,0,0}, accQ[4] = {0,0,0,0};
#pragma unroll 4
        for (int kb = 0; kb < 256; kb += 8) {
            unsigned ak[4], aq[4], bf[2];
            ak[0] = Ku[(m0+lr)*PSTR + kb+lk];
            ak[1] = Ku[(m0+lr+8)*PSTR + kb+lk];
            ak[2] = Ku[(m0+lr)*PSTR + kb+lk+4];
            ak[3] = Ku[(m0+lr+8)*PSTR + kb+lk+4];
            aq[0] = Qu[(m0+lr)*PSTR + kb+lk];
            aq[1] = Qu[(m0+lr+8)*PSTR + kb+lk];
            aq[2] = Qu[(m0+lr)*PSTR + kb+lk+4];
            aq[3] = Qu[(m0+lr+8)*PSTR + kb+lk+4];
            bf[0] = Ku[(n0+lr)*PSTR + kb+lk];       // B = kn^T (transposed read)
            bf[1] = Ku[(n0+lr)*PSTR + kb+lk+4];
            mma_tf32(accA, ak, bf);
            mma_tf32(accQ, aq, bf);
        }
        size_t abase = (size_t)blk * 1024;
        int r0 = m0 + lr, r1 = r0 + 8, c0 = n0 + 2*lk, c1 = c0 + 1;
        g_attn[abase + r0*32 + c0] = (c0 <= r0) ? accQ[0] : 0.f;
        g_attn[abase + r0*32 + c1] = (c1 <= r0) ? accQ[1] : 0.f;
        g_attn[abase + r1*32 + c0] = (c0 <= r1) ? accQ[2] : 0.f;
        g_attn[abase + r1*32 + c1] = (c1 <= r1) ? accQ[3] : 0.f;
        Am[r0*33 + c0] = (c0 < r0) ? -bet[r0]*accA[0] : 0.f;
        Am[r0*33 + c1] = (c1 < r0) ? -bet[r0]*accA[1] : 0.f;
        Am[r1*33 + c0] = (c0 < r1) ? -bet[r1]*accA[2] : 0.f;
        Am[r1*33 + c1] = (c1 < r1) ? -bet[r1]*accA[3] : 0.f;
    }
    __syncthreads();

    // 5. iterative inversion (warp 0), then T' = (A+I)*diag(beta) as tf32
    if (tid < 32) {
        int ln = tid;
        for (int i = 1; i < 32; i++) {
            float t = 0.f;
            if (ln < i) for (int p = 0; p < i; p++) t += Am[i*33 + p] * Am[p*33 + ln];
            __syncwarp();
            if (ln < i) Am[i*33 + ln] += t;
            __syncwarp();
        }
    }
    __syncthreads();
    for (int e = tid; e < 1024; e += 256) {
        int i = e >> 5, j = e & 31;
        float t = Am[i*33 + j] + (i == j ? 1.f : 0.f);
        Ttf[i*36 + j] = f2tf(t * bet[j]);
    }
    // 6. load raw v tile as tf32 into Qt (reuse)
    __syncthreads();
    for (int e = tid*4; e < 32*256; e += 1024) {
        int r = e >> 8, d = e & 255;
        float4 vv = *(const float4*)&g_vc[((size_t)(b*LL + l0 + r))*DD + h*DV + d];
        unsigned* qd = (unsigned*)&Qt[r*PSTR + d];
        qd[0]=f2tf(vv.x); qd[1]=f2tf(vv.y); qd[2]=f2tf(vv.z); qd[3]=f2tf(vv.w);
    }
    __syncthreads();

    // 7. u = T'@v, w = T'@kn   (32x256, K=32)
    {
        int m0 = (wid & 1) * 16;
        int nb = (wid >> 1) * 64;
        const unsigned* Ku = (const unsigned*)Kt;
        const unsigned* Vu = (const unsigned*)Qt;
        unsigned a[4][4];
#pragma unroll
        for (int kk = 0; kk < 4; kk++) {
            int kb = kk*8;
            a[kk][0] = Ttf[(m0+lr)*36 + kb+lk];
            a[kk][1] = Ttf[(m0+lr+8)*36 + kb+lk];
            a[kk][2] = Ttf[(m0+lr)*36 + kb+lk+4];
            a[kk][3] = Ttf[(m0+lr+8)*36 + kb+lk+4];
        }
#pragma unroll
        for (int nt = 0; nt < 8; nt++) {
            int n0 = nb + nt*8;
            float au[4] = {0,0,0,0}, aw[4] = {0,0,0,0};
#pragma unroll
            for (int kk = 0; kk < 4; kk++) {
                int kb = kk*8;
                unsigned bu[2], bw[2];
                bu[0] = Vu[(kb+lk)*PSTR + n0+lr];
                bu[1] = Vu[(kb+lk+4)*PSTR + n0+lr];
                bw[0] = Ku[(kb+lk)*PSTR + n0+lr];
                bw[1] = Ku[(kb+lk+4)*PSTR + n0+lr];
                mma_tf32(au, a[kk], bu);
                mma_tf32(aw, a[kk], bw);
            }
            int r0 = m0 + lr, r1 = r0 + 8, cc = n0 + 2*lk;
            float2 u01 = {au[0], au[1]}, u23 = {au[2], au[3]};
            float2 w01 = {aw[0], aw[1]}, w23 = {aw[2], aw[3]};
            *(float2*)&g_u[obase + r0*256 + cc] = u01;
            *(float2*)&g_u[obase + r1*256 + cc] = u23;
            *(float2*)&g_w[obase + r0*256 + cc] = w01;
            *(float2*)&g_w[obase + r1*256 + cc] = w23;
        }
    }
}

// --------------- sequential inter-chunk scan (tensor-core mma) --------------
#define SSTR 40     // stride for [.. x 32] arrays (bank-conflict-free frags)
#define TSTR 264    // stride for [32 x 256] tiles
#define SCAN_SMEM ((256*SSTR*2 + 32*TSTR + 3*32*SSTR) * 4)
__global__ __launch_bounds__(256) void scan_kernel()
{
    extern __shared__ float sm[];
    float*    Sf  = sm;                           // [256][SSTR] fp32 master
    unsigned* Stf = (unsigned*)(sm + 256*SSTR);   // [256][SSTR] tf32 shadow
    unsigned* Ttf = Stf + 256*SSTR;               // [32][TSTR]  w/q/k tile tf32
    float*    Ui  = (float*)(Ttf + 32*TSTR);      // [32][SSTR]  u then u_i fp32
    unsigned* Utf = (unsigned*)(Ui + 32*SSTR);    // [32][SSTR]  u_i tf32
    unsigned* Atf = Utf + 32*SSTR;                // [32][SSTR]  attn tf32

    int blk = blockIdx.x;               // (b*HH+h)*NG + g
    int g  = blk & (NG-1);
    int bh = blk >> 3;
    int b  = bh >> 2;
    int h  = bh & 3;
    int tid = threadIdx.x;
    int wid = tid >> 5, lane = tid & 31;
    int lr = lane >> 2, lk = lane & 3;
    int m0 = (wid >> 2) * 16;           // (1)/(2) warp tile: 2 x 4
    int n0 = (wid & 3) * 8;

    for (int e = tid; e < 256*SSTR; e += 256) { Sf[e] = 0.f; Stf[e] = 0u; }
    __syncthreads();

    for (int c = 0; c < NC; c++) {
        size_t base = ((size_t)bh*NC + c) * (32*256);
        size_t abase = ((size_t)bh*NC + c) * 1024;

        // load u slice (32x32) + attn (32x32) ; w tile (32x256) as tf32
        for (int e = tid; e < 1024; e += 256) {
            int r = e >> 5, j = e & 31;
            Ui[r*SSTR + j]  = g_u[base + r*256 + g*32 + j];
            Atf[r*SSTR + j] = f2tf(g_attn[abase + e]);
        }
        for (int e = tid*4; e < 8192; e += 1024) {
            float4 v = *(const float4*)&g_w[base + e];
            unsigned* dst = &Ttf[(e >> 8)*TSTR + (e & 255)];
            dst[0]=f2tf(v.x); dst[1]=f2tf(v.y); dst[2]=f2tf(v.z); dst[3]=f2tf(v.w);
        }
        __syncthreads();

        // (1) u_i = u - w@S    (32x32, K=256)
        {
            float acc[4] = {0.f, 0.f, 0.f, 0.f};
#pragma unroll 4
            for (int kb = 0; kb < 256; kb += 8) {
                unsigned a[4], bf[2];
                a[0] = Ttf[(m0+lr)*TSTR + kb+lk];
                a[1] = Ttf[(m0+lr+8)*TSTR + kb+lk];
                a[2] = Ttf[(m0+lr)*TSTR + kb+lk+4];
                a[3] = Ttf[(m0+lr+8)*TSTR + kb+lk+4];
                bf[0] = Stf[(kb+lk)*SSTR + n0+lr];
                bf[1] = Stf[(kb+lk+4)*SSTR + n0+lr];
                mma_tf32(acc, a, bf);
            }
            int r0 = m0 + lr, r1 = r0 + 8, cb = n0 + 2*lk;
            float u0 = Ui[r0*SSTR+cb]   - acc[0];
            float u1 = Ui[r0*SSTR+cb+1] - acc[1];
            float u2 = Ui[r1*SSTR+cb]   - acc[2];
            float u3 = Ui[r1*SSTR+cb+1] - acc[3];
            Ui[r0*SSTR+cb] = u0; Ui[r0*SSTR+cb+1] = u1;
            Ui[r1*SSTR+cb] = u2; Ui[r1*SSTR+cb+1] = u3;
            Utf[r0*SSTR+cb] = f2tf(u0); Utf[r0*SSTR+cb+1] = f2tf(u1);
            Utf[r1*SSTR+cb] = f2tf(u2); Utf[r1*SSTR+cb+1] = f2tf(u3);
        }
        __syncthreads();

        // load q tile
        for (int e = tid*4; e < 8192; e += 1024) {
            float4 v = *(const float4*)&g_qn[base + e];
            unsigned* dst = &Ttf[(e >> 8)*TSTR + (e & 255)];
            dst[0]=f2tf(v.x); dst[1]=f2tf(v.y); dst[2]=f2tf(v.z); dst[3]=f2tf(v.w);
        }
        __syncthreads();

        // (2) o = q@S + attn@u_i  -> g_delta
        {
            float acc[4] = {0.f, 0.f, 0.f, 0.f};
#pragma unroll 4
            for (int kb = 0; kb < 256; kb += 8) {
                unsigned a[4], bf[2];
                a[0] = Ttf[(m0+lr)*TSTR + kb+lk];
                a[1] = Ttf[(m0+lr+8)*TSTR + kb+lk];
                a[2] = Ttf[(m0+lr)*TSTR + kb+lk+4];
                a[3] = Ttf[(m0+lr+8)*TSTR + kb+lk+4];
                bf[0] = Stf[(kb+lk)*SSTR + n0+lr];
                bf[1] = Stf[(kb+lk+4)*SSTR + n0+lr];
                mma_tf32(acc, a, bf);
            }
#pragma unroll
            for (int kb = 0; kb < 32; kb += 8) {
                unsigned a[4], bf[2];
                a[0] = Atf[(m0+lr)*SSTR + kb+lk];
                a[1] = Atf[(m0+lr+8)*SSTR + kb+lk];
                a[2] = Atf[(m0+lr)*SSTR + kb+lk+4];
                a[3] = Atf[(m0+lr+8)*SSTR + kb+lk+4];
                bf[0] = Utf[(kb+lk)*SSTR + n0+lr];
                bf[1] = Utf[(kb+lk+4)*SSTR + n0+lr];
                mma_tf32(acc, a, bf);
            }
            size_t ob = ((size_t)(b*LL + c*32 + m0 + lr))*DD + h*DV + g*32 + n0 + 2*lk;
            float2 lo = {acc[0], acc[1]};
            float2 hi = {acc[2], acc[3]};
            *(float2*)&g_delta[ob]        = lo;
            *(float2*)&g_delta[ob + 8*DD] = hi;
        }
        __syncthreads();

        // load k tile
        for (int e = tid*4; e < 8192; e += 1024) {
            float4 v = *(const float4*)&g_kn[base + e];
            unsigned* dst = &Ttf[(e >> 8)*TSTR + (e & 255)];
            dst[0]=f2tf(v.x); dst[1]=f2tf(v.y); dst[2]=f2tf(v.z); dst[3]=f2tf(v.w);
        }
        __syncthreads();

        // (3) S += k^T @ u_i   (M=256, N=32, K=32); k^T read transposed
#pragma unroll
        for (int t = 0; t < 2; t++) {
            int tm = (wid*2 + t) * 16;
#pragma unroll
            for (int tn = 0; tn < 4; tn++) {
                int nn = tn*8;
                int r0 = tm + lr, r1 = r0 + 8, cb = nn + 2*lk;
                float acc[4];
                acc[0] = Sf[r0*SSTR+cb]; acc[1] = Sf[r0*SSTR+cb+1];
                acc[2] = Sf[r1*SSTR+cb]; acc[3] = Sf[r1*SSTR+cb+1];
#pragma unroll
                for (int kb = 0; kb < 32; kb += 8) {
                    unsigned a[4], bf[2];
                    a[0] = Ttf[(kb+lk)*TSTR + tm+lr];
                    a[1] = Ttf[(kb+lk)*TSTR + tm+lr+8];
                    a[2] = Ttf[(kb+lk+4)*TSTR + tm+lr];
                    a[3] = Ttf[(kb+lk+4)*TSTR + tm+lr+8];
                    bf[0] = Utf[(kb+lk)*SSTR + nn+lr];
                    bf[1] = Utf[(kb+lk+4)*SSTR + nn+lr];
                    mma_tf32(acc, a, bf);
                }
                Sf[r0*SSTR+cb] = acc[0]; Sf[r0*SSTR+cb+1] = acc[1];
                Sf[r1*SSTR+cb] = acc[2]; Sf[r1*SSTR+cb+1] = acc[3];
                Stf[r0*SSTR+cb] = f2tf(acc[0]); Stf[r0*SSTR+cb+1] = f2tf(acc[1]);
                Stf[r1*SSTR+cb] = f2tf(acc[2]); Stf[r1*SSTR+cb+1] = f2tf(acc[3]);
            }
        }
        __syncthreads();
    }
}

// ------------------- per-(head,channel) FIR conv (float2) -------------------
template<int K>
__global__ __launch_bounds__(256) void fir_kernel(
    const float* __restrict__ fw, float* __restrict__ y)
{
    __shared__ float2 vbuf[(128 + K - 1) * 16];
    __shared__ float2 wbuf[16 * K];
    int bh = blockIdx.x;
    int b = bh / HH, h = bh % HH;
    int l0 = blockIdx.y * 128;
    int d0 = blockIdx.z * 32;
    int tid = threadIdx.x;

    for (int idx = tid; idx < 16*K; idx += 256) {
        int dp = idx / K, t = idx % K;
        float2 wv;
        wv.x = fw[(size_t)(h*DV + d0 + 2*dp)*K + t];
        wv.y = fw[(size_t)(h*DV + d0 + 2*dp + 1)*K + t];
        wbuf[dp*K + t] = wv;
    }
    for (int idx = tid; idx < (128 + K - 1)*16; idx += 256) {
        int lrr = idx >> 4, dp = idx & 15;
        int l = l0 - (K - 1) + lrr;
        vbuf[idx] = (l >= 0)
            ? *(const float2*)&g_vc[((size_t)(b*LL + l))*DD + h*DV + d0 + 2*dp]
            : make_float2(0.f, 0.f);
    }
    __syncthreads();

    int dp = tid & 15;
    int lr0 = (tid >> 4) * 8;
    for (int m = 0; m < 8; m++) {
        int lrr = lr0 + m;
        float2 acc = {0.f, 0.f};
#pragma unroll
        for (int t = 0; t < K; t++) {
            float2 v = vbuf[(lrr + t)*16 + dp];
            float2 wv = wbuf[dp*K + t];
            acc.x = fmaf(v.x, wv.x, acc.x);
            acc.y = fmaf(v.y, wv.y, acc.y);
        }
        *(float2*)&y[((size_t)(b*LL + l0 + lrr))*DD + h*DV + d0 + 2*dp] = acc;
    }
}

// ------------- gate input assembly (hs + stats), stored as tf32 bits --------
__global__ __launch_bounds__(256) void stats_kernel(const float* __restrict__ hs)
{
    int n = blockIdx.x, tid = threadIdx.x;
    for (int i = tid; i < DD; i += 256)
        g_gatein[(size_t)n*GIN + i] = __uint_as_float(f2tf(hs[(size_t)n*DD + i]));
    int warp = tid >> 5, lane = tid & 31;
    for (int rep = 0; rep < 2; rep++) {
        int combo = warp*2 + rep;
        int path = combo >> 2, h = combo & 3;
        const float* p;
        if      (path == 0) p = g_short;
        else if (path == 1) p = g_long;
        else if (path == 2) p = g_delta;
        else                p = g_vc;
        p += (size_t)n*DD + h*DV;
        float s1 = 0.f, s2 = 0.f;
        for (int j = lane; j < 256; j += 32) { float x = p[j]; s1 += x; s2 += x*x; }
#pragma unroll
        for (int st = 16; st > 0; st >>= 1) {
            s1 += __shfl_down_sync(0xffffffffu, s1, st);
            s2 += __shfl_down_sync(0xffffffffu, s2, st);
        }
        if (lane == 0) {
            float m  = s1 * (1.f/256.f);
            float va = s2 * (1.f/256.f) - m*m;
            g_gatein[(size_t)n*GIN + DD + path*8 + h*2]     = __uint_as_float(f2tf(m));
            g_gatein[(size_t)n*GIN + DD + path*8 + h*2 + 1] = __uint_as_float(f2tf(va));
        }
    }
}

// ------------------------- gate2 + softmax + floor --------------------------
__global__ __launch_bounds__(256) void gate2_kernel(
    const float* __restrict__ w2, const float* __restrict__ log_temp,
    const float* __restrict__ base_bias, const float* __restrict__ floor_raw)
{
    __shared__ float hrow[HID];
    __shared__ float lg[16];
    int n = blockIdx.x, tid = threadIdx.x;
    for (int i = tid; i < HID; i += 256) hrow[i] = g_hmid[(size_t)n*HID + i];
    __syncthreads();
    int warp = tid >> 5, lane = tid & 31;
    for (int rep = 0; rep < 2; rep++) {
        int o = warp*2 + rep;
        const float* wr = w2 + (size_t)o*HID;
        float s = 0.f;
        for (int i = lane; i < HID; i += 32) s = fmaf(hrow[i], wr[i], s);
#pragma unroll
        for (int st = 16; st > 0; st >>= 1) s += __shfl_down_sync(0xffffffffu, s, st);
        if (lane == 0) lg[o] = s;
    }
    __syncthreads();
    if (tid < 4) {
        int h = tid;
        float temp = log1pf(expf(log_temp[h])) + 1e-4f;
        float z[4], m = -1e30f;
#pragma unroll
        for (int i = 0; i < 4; i++) {
            z[i] = (lg[h*4+i] + base_bias[h*4+i]) / temp;
            m = fmaxf(m, z[i]);
        }
        float e[4], s = 0.f;
#pragma unroll
        for (int i = 0; i < 4; i++) { e[i] = expf(z[i] - m); s += e[i]; }
        float p[4], s2 = 0.f;
#pragma unroll
        for (int i = 0; i < 4; i++) {
            p[i] = e[i] / s;
            float f = 0.05f / (1.f + expf(-floor_raw[h*4+i]));
            p[i] = fmaxf(p[i], f);
            s2 += p[i];
        }
#pragma unroll
        for (int i = 0; i < 4; i++) g_probs[(size_t)n*16 + h*4 + i] = p[i] / s2;
    }
}

// ------------- path mix + RMS norm, output stored as tf32 bits --------------
__global__ __launch_bounds__(256) void mix_kernel(const float* __restrict__ onorm)
{
    __shared__ float pr[16];
    __shared__ float wsum[8];
    int n = blockIdx.x, tid = threadIdx.x;
    if (tid < 16) pr[tid] = g_probs[(size_t)n*16 + tid];
    __syncthreads();
    int h = tid >> 6;
    int dd = (tid & 63) * 4;
    size_t pb = (size_t)n*DD + h*DV + dd;
    float4 sh = *(const float4*)&g_short[pb];
    float4 lo = *(const float4*)&g_long[pb];
    float4 de = *(const float4*)&g_delta[pb];
    float4 vv = *(const float4*)&g_vc[pb];
    float p0 = pr[h*4+0], p1 = pr[h*4+1], p2 = pr[h*4+2], p3 = pr[h*4+3];
    float o[4];
    o[0] = p0*sh.x + p1*lo.x + p2*de.x + p3*vv.x;
    o[1] = p0*sh.y + p1*lo.y + p2*de.y + p3*vv.y;
    o[2] = p0*sh.z + p1*lo.z + p2*de.z + p3*vv.z;
    o[3] = p0*sh.w + p1*lo.w + p2*de.w + p3*vv.w;
    float ss = o[0]*o[0] + o[1]*o[1] + o[2]*o[2] + o[3]*o[3];
#pragma unroll
    for (int st = 16; st > 0; st >>= 1) ss += __shfl_down_sync(0xffffffffu, ss, st);
    int warp = tid >> 5, lane = tid & 31;
    if (lane == 0) wsum[warp] = ss;
    __syncthreads();
    float tot = wsum[h*2] + wsum[h*2+1];
    float scale = rsqrtf(tot * (1.f/256.f) + 1e-5f);
    float r[4];
#pragma unroll
    for (int j = 0; j < 4; j++)
        r[j] = __uint_as_float(f2tf(o[j] * scale * onorm[dd + j]));
    *(float4*)&g_mix[pb] = *(float4*)r;
}

// ------------------------- launch ------------------------------------------
extern "C" void kernel_launch(void* const* d_in, const int* in_sizes, int n_in,
                              void* d_out, int out_size)
{
    const float* hs        = (const float*)d_in[0];
    const float* Wq        = (const float*)d_in[1];
    const float* Wk        = (const float*)d_in[2];
    const float* Wv        = (const float*)d_in[3];
    const float* Wb        = (const float*)d_in[4];
    const float* qconv_w   = (const float*)d_in[5];
    const float* kconv_w   = (const float*)d_in[6];
    const float* vconv_w   = (const float*)d_in[7];
    const float* fir_s     = (const float*)d_in[8];
    const float* fir_l     = (const float*)d_in[9];
    const float* gate_w1   = (const float*)d_in[10];
    const float* gate_b1   = (const float*)d_in[11];
    const float* gate_w2   = (const float*)d_in[12];
    const float* log_temp  = (const float*)d_in[13];
    const float* base_bias = (const float*)d_in[14];
    const float* floor_raw = (const float*)d_in[15];
    const float* onorm_w   = (const float*)d_in[16];
    const float* Wo        = (const float*)d_in[17];
    float* out = (float*)d_out;

    void *p_qlin, *p_klin, *p_vlin, *p_qc, *p_kc, *p_vc, *p_gatein, *p_hmid,
         *p_mix, *p_short, *p_long;
    void *p_hstf, *p_wqtf, *p_wktf, *p_wvtf, *p_wotf, *p_gw1tf;
    cudaGetSymbolAddress(&p_qlin, g_qlin);
    cudaGetSymbolAddress(&p_klin, g_klin);
    cudaGetSymbolAddress(&p_vlin, g_vlin);
    cudaGetSymbolAddress(&p_qc, g_qc);
    cudaGetSymbolAddress(&p_kc, g_kc);
    cudaGetSymbolAddress(&p_vc, g_vc);
    cudaGetSymbolAddress(&p_gatein, g_gatein);
    cudaGetSymbolAddress(&p_hmid, g_hmid);
    cudaGetSymbolAddress(&p_mix, g_mix);
    cudaGetSymbolAddress(&p_short, g_short);
    cudaGetSymbolAddress(&p_long, g_long);
    cudaGetSymbolAddress(&p_hstf, g_hs_tf);
    cudaGetSymbolAddress(&p_wqtf, g_wq_tf);
    cudaGetSymbolAddress(&p_wktf, g_wk_tf);
    cudaGetSymbolAddress(&p_wvtf, g_wv_tf);
    cudaGetSymbolAddress(&p_wotf, g_wo_tf);
    cudaGetSymbolAddress(&p_gw1tf, g_gw1_tf);

    cudaFuncSetAttribute(scan_kernel,
        cudaFuncAttributeMaxDynamicSharedMemorySize, SCAN_SMEM);
    cudaFuncSetAttribute(precompute_kernel,
        cudaFuncAttributeMaxDynamicSharedMemorySize, PSMEM);
    cudaFuncSetAttribute(tf32_gemm,
        cudaFuncAttributeMaxDynamicSharedMemorySize, GEMM_SMEM);

    dim3 blk(256);

    // 0. pre-convert hs + weights to tf32 bit patterns
    cvt_tf32_6<<<dim3(NROW*DD/1024, 6), blk>>>(
        hs,      (unsigned*)p_hstf,  NROW*DD,
        Wq,      (unsigned*)p_wqtf,  DD*DD,
        Wk,      (unsigned*)p_wktf,  DD*DD,
        Wv,      (unsigned*)p_wvtf,  DD*DD,
        Wo,      (unsigned*)p_wotf,  DD*DD,
        gate_w1, (unsigned*)p_gw1tf, HID*GIN);

    // q/k/v projections — one batched tensor-core launch
    tf32_gemm<<<dim3(DD/128, NROW/128, 3), blk, GEMM_SMEM>>>(
        (const unsigned*)p_hstf,
        (const unsigned*)p_wqtf, (const unsigned*)p_wktf, (const unsigned*)p_wvtf,
        (float*)p_qlin, (float*)p_klin, (float*)p_vlin,
        nullptr, NROW, DD, DD, 0);

    // causal conv4 + SiLU (all three streams in one launch)
    conv4_silu3<<<dim3(NROW*DD/256, 3), blk>>>(
        (const float*)p_qlin, (const float*)p_klin, (const float*)p_vlin,
        qconv_w, kconv_w, vconv_w,
        (float*)p_qc, (float*)p_kc, (float*)p_vc);

    // beta
    beta_kernel<<<NROW, 128>>>(hs, Wb);

    // delta-rule
    precompute_kernel<<<BB*HH*NC, blk, PSMEM>>>();
    scan_kernel<<<BB*HH*NG, blk, SCAN_SMEM>>>();

    // FIR paths
    fir_kernel<3><<<dim3(BB*HH, LL/128, DV/32), blk>>>(fir_s, (float*)p_short);
    fir_kernel<63><<<dim3(BB*HH, LL/128, DV/32), blk>>>(fir_l, (float*)p_long);

    // gate
    stats_kernel<<<NROW, blk>>>(hs);
    tf32_gemm<<<dim3(HID/128, NROW/128, 1), blk, GEMM_SMEM>>>(
        (const unsigned*)p_gatein,
        (const unsigned*)p_gw1tf, nullptr, nullptr,
        (float*)p_hmid, nullptr, nullptr,
        gate_b1, NROW, HID, GIN, 1);
    gate2_kernel<<<NROW, blk>>>(gate_w2, log_temp, base_bias, floor_raw);

    // mix + RMS norm
    mix_kernel<<<NROW, blk>>>(onorm_w);

    // output projection
    tf32_gemm<<<dim3(DD/128, NROW/128, 1), blk, GEMM_SMEM>>>(
        (const unsigned*)p_mix,
        (const unsigned*)p_wotf, nullptr, nullptr,
        out, nullptr, nullptr,
        nullptr, NROW, DD, DD, 0);
}

// round 9
// speedup vs baseline: 2.5198x; 1.1548x over previous
#include <cuda_runtime.h>
#include <cuda_fp16.h>
#include <math.h>
#include <stdint.h>

#define BB 2
#define LL 2048
#define DD 1024
#define HH 4
#define DV 256
#define CKN 32
#define NC 64              // LL / CKN
#define NROW (BB*LL)       // 4096
#define GIN 1056
#define HID 2048
#define NG 8               // Dv groups of 32 in the scan

// ------------------------- scratch (device globals) -------------------------
__device__ float g_qlin[NROW*DD];
__device__ float g_klin[NROW*DD];
__device__ float g_vlin[NROW*DD];
__device__ float g_qc[NROW*DD];
__device__ float g_kc[NROW*DD];
__device__ float g_vc[NROW*DD];
__device__ float g_beta[NROW*HH];
__device__ float g_qn[NROW*DD];
__device__ float g_kn[NROW*DD];
__device__ float g_u[NROW*DD];
__device__ float g_w[NROW*DD];
__device__ float g_attn[BB*HH*NC*CKN*CKN];
__device__ float g_delta[NROW*DD];
__device__ float g_short[NROW*DD];
__device__ float g_long[NROW*DD];
__device__ float g_hmid[NROW*HID];
__device__ float g_probs[NROW*16];
// fp16 GEMM operands
__device__ __half g_hs_h[NROW*DD];
__device__ __half g_wq_h[DD*DD];
__device__ __half g_wk_h[DD*DD];
__device__ __half g_wv_h[DD*DD];
__device__ __half g_wo_h[DD*DD];
__device__ __half g_gw1_h[HID*GIN];
__device__ __half g_gatein_h[NROW*GIN];
__device__ __half g_mix_h[NROW*DD];

// ------------------------- helpers ------------------------------------------
__device__ __forceinline__ unsigned f2tf(float x) {
    unsigned r;
    asm("cvt.rna.tf32.f32 %0, %1;" : "=r"(r) : "f"(x));
    return r;
}

__device__ __forceinline__ void mma_tf32(float* c, const unsigned* a, const unsigned* b) {
    asm volatile(
        "mma.sync.aligned.m16n8k8.row.col.f32.tf32.tf32.f32 "
        "{%0,%1,%2,%3}, {%4,%5,%6,%7}, {%8,%9}, {%0,%1,%2,%3};"
        : "+f"(c[0]), "+f"(c[1]), "+f"(c[2]), "+f"(c[3])
        : "r"(a[0]), "r"(a[1]), "r"(a[2]), "r"(a[3]), "r"(b[0]), "r"(b[1]));
}

__device__ __forceinline__ void mma_f16(float* c, const unsigned* a, const unsigned* b) {
    asm volatile(
        "mma.sync.aligned.m16n8k16.row.col.f32.f16.f16.f32 "
        "{%0,%1,%2,%3}, {%4,%5,%6,%7}, {%8,%9}, {%0,%1,%2,%3};"
        : "+f"(c[0]), "+f"(c[1]), "+f"(c[2]), "+f"(c[3])
        : "r"(a[0]), "r"(a[1]), "r"(a[2]), "r"(a[3]), "r"(b[0]), "r"(b[1]));
}

// ------------------------- bulk fp32 -> fp16 conversion ---------------------
__global__ __launch_bounds__(256) void cvt_h6(
    const float* __restrict__ s0, __half* __restrict__ d0, int n0,
    const float* __restrict__ s1, __half* __restrict__ d1, int n1,
    const float* __restrict__ s2, __half* __restrict__ d2, int n2,
    const float* __restrict__ s3, __half* __restrict__ d3, int n3,
    const float* __restrict__ s4, __half* __restrict__ d4, int n4,
    const float* __restrict__ s5, __half* __restrict__ d5, int n5)
{
    const float* s; __half* d; int n;
    switch (blockIdx.y) {
        case 0: s=s0; d=d0; n=n0; break;
        case 1: s=s1; d=d1; n=n1; break;
        case 2: s=s2; d=d2; n=n2; break;
        case 3: s=s3; d=d3; n=n3; break;
        case 4: s=s4; d=d4; n=n4; break;
        default: s=s5; d=d5; n=n5; break;
    }
    int i = (blockIdx.x * 256 + threadIdx.x) * 4;
    if (i < n) {
        float4 v = *(const float4*)(s + i);
        __half2 lo = __floats2half2_rn(v.x, v.y);
        __half2 hi = __floats2half2_rn(v.z, v.w);
        uint2 o = {*(unsigned*)&lo, *(unsigned*)&hi};
        *(uint2*)(d + i) = o;
    }
}

// ---------------- fp16 tensor GEMM: C = A(MxK) @ B(NxK)^T -------------------
// A,B fp16, K-major. 128x128 CTA tile, 8 warps (2x4), warp tile 64x32.
// m16n8k16 mma, K=32 staged per iter, 3-stage cp.async pipeline.
// Smem rows: 32 halves @ 112B stride (16B aligned; word-stride 28 -> 32 banks).
#define HSTRB 112
#define HSTRW 28
#define HSTAGE_BYTES (128*HSTRB)        // 14336
#define HGEMM_SMEM (6*HSTAGE_BYTES)     // 86016

#define HLOAD(kt, st) do {                                                     \
    const __half* Ap_ = A + (size_t)bm*K + (kt)*32;                            \
    const __half* Bp_ = B + (size_t)bn*K + (kt)*32;                            \
    char* as_ = tsm + (st)*HSTAGE_BYTES;                                       \
    char* bs_ = tsm + 3*HSTAGE_BYTES + (st)*HSTAGE_BYTES;                      \
    _Pragma("unroll")                                                          \
    for (int i_ = 0; i_ < 2; i_++) {                                           \
        int e_ = tid + i_*256;                                                 \
        int row_ = e_ >> 2, seg_ = e_ & 3;                                     \
        unsigned doff_ = (unsigned)row_*HSTRB + (unsigned)seg_*16;             \
        asm volatile("cp.async.cg.shared.global [%0], [%1], 16;"               \
            :: "r"(smb + (unsigned)((st)*HSTAGE_BYTES) + doff_),               \
               "l"(Ap_ + (size_t)row_*K + seg_*8));                            \
        asm volatile("cp.async.cg.shared.global [%0], [%1], 16;"               \
            :: "r"(smb + (unsigned)(3*HSTAGE_BYTES + (st)*HSTAGE_BYTES) + doff_), \
               "l"(Bp_ + (size_t)row_*K + seg_*8));                            \
    }                                                                          \
} while (0)

__global__ __launch_bounds__(256, 2) void hgemm(
    const __half* __restrict__ A,
    const __half* __restrict__ Bm0, const __half* __restrict__ Bm1, const __half* __restrict__ Bm2,
    float* __restrict__ Cm0, float* __restrict__ Cm1, float* __restrict__ Cm2,
    const float* __restrict__ bias, int M, int N, int K, int mode)
{
    extern __shared__ char tsm[];

    const __half* B = (blockIdx.z == 0) ? Bm0 : (blockIdx.z == 1) ? Bm1 : Bm2;
    float*        C = (blockIdx.z == 0) ? Cm0 : (blockIdx.z == 1) ? Cm1 : Cm2;

    int tid = threadIdx.x;
    int bm = blockIdx.y * 128, bn = blockIdx.x * 128;
    unsigned smb;
    asm("{ .reg .u64 t; cvta.to.shared.u64 t, %1; cvt.u32.u64 %0, t; }"
        : "=r"(smb) : "l"(tsm));

    int wid = tid >> 5, lane = tid & 31;
    int wm = (wid >> 2) * 64, wn = (wid & 3) * 32;
    int lr = lane >> 2, lk = lane & 3;

    float acc[4][4][4];
#pragma unroll
    for (int mi = 0; mi < 4; mi++)
#pragma unroll
        for (int ni = 0; ni < 4; ni++)
#pragma unroll
            for (int j = 0; j < 4; j++) acc[mi][ni][j] = 0.f;

    int niter = K >> 5;          // K=1024 -> 32, K=1056 -> 33

    HLOAD(0, 0);
    asm volatile("cp.async.commit_group;");
    HLOAD(1, 1);
    asm volatile("cp.async.commit_group;");

    for (int t = 0; t < niter; t++) {
        asm volatile("cp.async.wait_group 1;");
        __syncthreads();
        if (t + 2 < niter) HLOAD(t + 2, (t + 2) % 3);
        asm volatile("cp.async.commit_group;");

        int cur = t % 3;
        const unsigned* Ac = (const unsigned*)(tsm + cur*HSTAGE_BYTES);
        const unsigned* Bc = (const unsigned*)(tsm + 3*HSTAGE_BYTES + cur*HSTAGE_BYTES);
#pragma unroll
        for (int ks = 0; ks < 2; ks++) {
            int kw = ks * 8 + lk;        // word offset within row
            unsigned af[4][4], bf[4][2];
#pragma unroll
            for (int mi = 0; mi < 4; mi++) {
                int r = wm + mi*16 + lr;
                af[mi][0] = Ac[r*HSTRW + kw];
                af[mi][1] = Ac[(r+8)*HSTRW + kw];
                af[mi][2] = Ac[r*HSTRW + kw + 4];
                af[mi][3] = Ac[(r+8)*HSTRW + kw + 4];
            }
#pragma unroll
            for (int ni = 0; ni < 4; ni++) {
                int n = wn + ni*8 + lr;
                bf[ni][0] = Bc[n*HSTRW + kw];
                bf[ni][1] = Bc[n*HSTRW + kw + 4];
            }
#pragma unroll
            for (int mi = 0; mi < 4; mi++)
#pragma unroll
                for (int ni = 0; ni < 4; ni++)
                    mma_f16(acc[mi][ni], af[mi], bf[ni]);
        }
    }

#pragma unroll
    for (int mi = 0; mi < 4; mi++) {
        int r0 = bm + wm + mi*16 + lr;
#pragma unroll
        for (int ni = 0; ni < 4; ni++) {
            int c = bn + wn + ni*8 + 2*lk;
            float v[4] = {acc[mi][ni][0], acc[mi][ni][1], acc[mi][ni][2], acc[mi][ni][3]};
            if (mode == 1) {
                float b0 = bias[c], b1 = bias[c+1];
                v[0] += b0; v[1] += b1; v[2] += b0; v[3] += b1;
#pragma unroll
                for (int j = 0; j < 4; j++)
                    v[j] = 0.5f * v[j] * (1.f + erff(v[j] * 0.70710678118654752f));
            }
            float2 lo = {v[0], v[1]};
            float2 hi = {v[2], v[3]};
            *(float2*)&C[(size_t)r0*N + c]       = lo;
            *(float2*)&C[(size_t)(r0+8)*N + c]   = hi;
        }
    }
}

// ------------------- depthwise causal conv4 + SiLU (3 streams batched) ------
__global__ __launch_bounds__(256) void conv4_silu3(
    const float* __restrict__ x0, const float* __restrict__ x1, const float* __restrict__ x2,
    const float* __restrict__ w0, const float* __restrict__ w1, const float* __restrict__ w2,
    float* __restrict__ y0, float* __restrict__ y1, float* __restrict__ y2)
{
    const float* x; const float* w; float* y;
    if (blockIdx.y == 0)      { x = x0; w = w0; y = y0; }
    else if (blockIdx.y == 1) { x = x1; w = w1; y = y1; }
    else                      { x = x2; w = w2; y = y2; }
    int idx = blockIdx.x * 256 + threadIdx.x;       // over NROW*DD
    int d = idx & (DD-1);
    int l = (idx >> 10) & (LL-1);
    float4 wv = *(const float4*)(w + d*4);
    const float* xp = x + (size_t)idx;
    float acc = wv.w * xp[0];
    if (l >= 1) acc += wv.z * xp[-DD];
    if (l >= 2) acc += wv.y * xp[-2*DD];
    if (l >= 3) acc += wv.x * xp[-3*DD];
    y[idx] = acc / (1.f + expf(-acc));
}

// ------------------------- beta = sigmoid(hs @ Wb^T) ------------------------
__global__ __launch_bounds__(128) void beta_kernel(
    const float* __restrict__ hs, const float* __restrict__ Wb)
{
    __shared__ float red[4][128];
    int n = blockIdx.x, tid = threadIdx.x;
    const float* hr = hs + (size_t)n * DD;
    float s0=0,s1=0,s2=0,s3=0;
    for (int i = tid; i < DD; i += 128) {
        float x = hr[i];
        s0 += x * Wb[i];
        s1 += x * Wb[DD + i];
        s2 += x * Wb[2*DD + i];
        s3 += x * Wb[3*DD + i];
    }
    red[0][tid]=s0; red[1][tid]=s1; red[2][tid]=s2; red[3][tid]=s3;
    __syncthreads();
    for (int st = 64; st > 0; st >>= 1) {
        if (tid < st)
#pragma unroll
            for (int h = 0; h < 4; h++) red[h][tid] += red[h][tid + st];
        __syncthreads();
    }
    if (tid < 4) g_beta[(size_t)n*HH + tid] = 1.f / (1.f + expf(-red[tid][0]));
}

// ---------------- per-chunk delta-rule precompute (tensor-core mma) ---------
#define PSTR 264
#define PSMEM ((2*32*PSTR + 32*33 + 32*36 + 96) * 4)
__global__ __launch_bounds__(256) void precompute_kernel()
{
    extern __shared__ float psm[];
    float*    Kt  = psm;                     // [32][PSTR] k fp32 -> kn tf32
    float*    Qt  = Kt + 32*PSTR;            // [32][PSTR] q fp32 -> qn tf32 -> v tf32
    float*    Am  = Qt + 32*PSTR;            // [32][33]
    unsigned* Ttf = (unsigned*)(Am + 32*33); // [32][36]
    float*    bet = (float*)(Ttf + 32*36);   // [32]
    float*    rnk = bet + 32;                // [32]
    float*    rnq = rnk + 32;                // [32]

    int blk = blockIdx.x;           // (b*HH + h)*NC + c
    int c  = blk % NC;
    int bh = blk / NC;
    int h  = bh % HH;
    int b  = bh / HH;
    int tid = threadIdx.x;
    int l0 = c * 32;
    int wid = tid >> 5, lane = tid & 31;
    int lr = lane >> 2, lk = lane & 3;

    // 1. load k, q tiles (fp32)
    for (int e = tid*4; e < 32*256; e += 1024) {
        int r = e >> 8, d = e & 255;
        size_t gb = ((size_t)(b*LL + l0 + r))*DD + h*DV + d;
        *(float4*)&Kt[r*PSTR + d] = *(const float4*)&g_kc[gb];
        *(float4*)&Qt[r*PSTR + d] = *(const float4*)&g_qc[gb];
    }
    if (tid < 32) bet[tid] = g_beta[((size_t)(b*LL + l0 + tid))*HH + h];
    __syncthreads();

    // 2. row norms (8 threads per row)
    {
        int r = tid >> 3, part = tid & 7;
        float sk = 0.f, sq = 0.f;
        for (int j = part*32; j < part*32 + 32; j++) {
            float x = Kt[r*PSTR + j]; sk += x*x;
            float y = Qt[r*PSTR + j]; sq += y*y;
        }
        sk += __shfl_down_sync(0xffffffffu, sk, 4, 8);
        sk += __shfl_down_sync(0xffffffffu, sk, 2, 8);
        sk += __shfl_down_sync(0xffffffffu, sk, 1, 8);
        sq += __shfl_down_sync(0xffffffffu, sq, 4, 8);
        sq += __shfl_down_sync(0xffffffffu, sq, 2, 8);
        sq += __shfl_down_sync(0xffffffffu, sq, 1, 8);
        if (part == 0) { rnk[r] = rsqrtf(sk + 1e-6f); rnq[r] = rsqrtf(sq + 1e-6f); }
    }
    __syncthreads();

    // 3. normalize in place (fp32 -> global, tf32 -> smem)
    size_t obase = (size_t)blk * (32*256);
    for (int e = tid*4; e < 32*256; e += 1024) {
        int r = e >> 8, d = e & 255;
        float rk = rnk[r], rq = rnq[r];
        float4 kv = *(float4*)&Kt[r*PSTR + d];
        kv.x *= rk; kv.y *= rk; kv.z *= rk; kv.w *= rk;
        *(float4*)&g_kn[obase + e] = kv;
        unsigned* kd = (unsigned*)&Kt[r*PSTR + d];
        kd[0]=f2tf(kv.x); kd[1]=f2tf(kv.y); kd[2]=f2tf(kv.z); kd[3]=f2tf(kv.w);
        float4 qv = *(float4*)&Qt[r*PSTR + d];
        qv.x *= rq; qv.y *= rq; qv.z *= rq; qv.w *= rq;
        *(float4*)&g_qn[obase + e] = qv;
        unsigned* qd = (unsigned*)&Qt[r*PSTR + d];
        qd[0]=f2tf(qv.x); qd[1]=f2tf(qv.y); qd[2]=f2tf(qv.z); qd[3]=f2tf(qv.w);
    }
    __syncthreads();

    // 4. fused mma: Afull = kn@kn^T, attnF = qn@kn^T  (32x32, K=256)
    {
        int m0 = (wid >> 2) * 16, n0 = (wid & 3) * 8;
        const unsigned* Ku = (const unsigned*)Kt;
        const unsigned* Qu = (const unsigned*)Qt;
        float accA[4] = {0,0,0,0}, accQ[4] = {0,0,0,0};
#pragma unroll 4
        for (int kb = 0; kb < 256; kb += 8) {
            unsigned ak[4], aq[4], bf[2];
            ak[0] = Ku[(m0+lr)*PSTR + kb+lk];
            ak[1] = Ku[(m0+lr+8)*PSTR + kb+lk];
            ak[2] = Ku[(m0+lr)*PSTR + kb+lk+4];
            ak[3] = Ku[(m0+lr+8)*PSTR + kb+lk+4];
            aq[0] = Qu[(m0+lr)*PSTR + kb+lk];
            aq[1] = Qu[(m0+lr+8)*PSTR + kb+lk];
            aq[2] = Qu[(m0+lr)*PSTR + kb+lk+4];
            aq[3] = Qu[(m0+lr+8)*PSTR + kb+lk+4];
            bf[0] = Ku[(n0+lr)*PSTR + kb+lk];       // B = kn^T (transposed read)
            bf[1] = Ku[(n0+lr)*PSTR + kb+lk+4];
            mma_tf32(accA, ak, bf);
            mma_tf32(accQ, aq, bf);
        }
        size_t abase = (size_t)blk * 1024;
        int r0 = m0 + lr, r1 = r0 + 8, c0 = n0 + 2*lk, c1 = c0 + 1;
        g_attn[abase + r0*32 + c0] = (c0 <= r0) ? accQ[0] : 0.f;
        g_attn[abase + r0*32 + c1] = (c1 <= r0) ? accQ[1] : 0.f;
        g_attn[abase + r1*32 + c0] = (c0 <= r1) ? accQ[2] : 0.f;
        g_attn[abase + r1*32 + c1] = (c1 <= r1) ? accQ[3] : 0.f;
        Am[r0*33 + c0] = (c0 < r0) ? -bet[r0]*accA[0] : 0.f;
        Am[r0*33 + c1] = (c1 < r0) ? -bet[r0]*accA[1] : 0.f;
        Am[r1*33 + c0] = (c0 < r1) ? -bet[r1]*accA[2] : 0.f;
        Am[r1*33 + c1] = (c1 < r1) ? -bet[r1]*accA[3] : 0.f;
    }
    __syncthreads();

    // 5. iterative inversion (warp 0), then T' = (A+I)*diag(beta) as tf32
    if (tid < 32) {
        int ln = tid;
        for (int i = 1; i < 32; i++) {
            float t = 0.f;
            if (ln < i) for (int p = 0; p < i; p++) t += Am[i*33 + p] * Am[p*33 + ln];
            __syncwarp();
            if (ln < i) Am[i*33 + ln] += t;
            __syncwarp();
        }
    }
    __syncthreads();
    for (int e = tid; e < 1024; e += 256) {
        int i = e >> 5, j = e & 31;
        float t = Am[i*33 + j] + (i == j ? 1.f : 0.f);
        Ttf[i*36 + j] = f2tf(t * bet[j]);
    }
    // 6. load raw v tile as tf32 into Qt (reuse)
    __syncthreads();
    for (int e = tid*4; e < 32*256; e += 1024) {
        int r = e >> 8, d = e & 255;
        float4 vv = *(const float4*)&g_vc[((size_t)(b*LL + l0 + r))*DD + h*DV + d];
        unsigned* qd = (unsigned*)&Qt[r*PSTR + d];
        qd[0]=f2tf(vv.x); qd[1]=f2tf(vv.y); qd[2]=f2tf(vv.z); qd[3]=f2tf(vv.w);
    }
    __syncthreads();

    // 7. u = T'@v, w = T'@kn   (32x256, K=32)
    {
        int m0 = (wid & 1) * 16;
        int nb = (wid >> 1) * 64;
        const unsigned* Ku = (const unsigned*)Kt;
        const unsigned* Vu = (const unsigned*)Qt;
        unsigned a[4][4];
#pragma unroll
        for (int kk = 0; kk < 4; kk++) {
            int kb = kk*8;
            a[kk][0] = Ttf[(m0+lr)*36 + kb+lk];
            a[kk][1] = Ttf[(m0+lr+8)*36 + kb+lk];
            a[kk][2] = Ttf[(m0+lr)*36 + kb+lk+4];
            a[kk][3] = Ttf[(m0+lr+8)*36 + kb+lk+4];
        }
#pragma unroll
        for (int nt = 0; nt < 8; nt++) {
            int n0 = nb + nt*8;
            float au[4] = {0,0,0,0}, aw[4] = {0,0,0,0};
#pragma unroll
            for (int kk = 0; kk < 4; kk++) {
                int kb = kk*8;
                unsigned bu[2], bw[2];
                bu[0] = Vu[(kb+lk)*PSTR + n0+lr];
                bu[1] = Vu[(kb+lk+4)*PSTR + n0+lr];
                bw[0] = Ku[(kb+lk)*PSTR + n0+lr];
                bw[1] = Ku[(kb+lk+4)*PSTR + n0+lr];
                mma_tf32(au, a[kk], bu);
                mma_tf32(aw, a[kk], bw);
            }
            int r0 = m0 + lr, r1 = r0 + 8, cc = n0 + 2*lk;
            float2 u01 = {au[0], au[1]}, u23 = {au[2], au[3]};
            float2 w01 = {aw[0], aw[1]}, w23 = {aw[2], aw[3]};
            *(float2*)&g_u[obase + r0*256 + cc] = u01;
            *(float2*)&g_u[obase + r1*256 + cc] = u23;
            *(float2*)&g_w[obase + r0*256 + cc] = w01;
            *(float2*)&g_w[obase + r1*256 + cc] = w23;
        }
    }
}

// --------------- sequential inter-chunk scan (tensor-core mma) --------------
#define SSTR 40     // stride for [.. x 32] arrays (bank-conflict-free frags)
#define TSTR 264    // stride for [32 x 256] tiles
#define SCAN_SMEM ((256*SSTR*2 + 32*TSTR + 3*32*SSTR) * 4)
__global__ __launch_bounds__(256) void scan_kernel()
{
    extern __shared__ float sm[];
    float*    Sf  = sm;                           // [256][SSTR] fp32 master
    unsigned* Stf = (unsigned*)(sm + 256*SSTR);   // [256][SSTR] tf32 shadow
    unsigned* Ttf = Stf + 256*SSTR;               // [32][TSTR]  w/q/k tile tf32
    float*    Ui  = (float*)(Ttf + 32*TSTR);      // [32][SSTR]  u then u_i fp32
    unsigned* Utf = (unsigned*)(Ui + 32*SSTR);    // [32][SSTR]  u_i tf32
    unsigned* Atf = Utf + 32*SSTR;                // [32][SSTR]  attn tf32

    int blk = blockIdx.x;               // (b*HH+h)*NG + g
    int g  = blk & (NG-1);
    int bh = blk >> 3;
    int b  = bh >> 2;
    int h  = bh & 3;
    int tid = threadIdx.x;
    int wid = tid >> 5, lane = tid & 31;
    int lr = lane >> 2, lk = lane & 3;
    int m0 = (wid >> 2) * 16;           // (1)/(2) warp tile: 2 x 4
    int n0 = (wid & 3) * 8;

    for (int e = tid; e < 256*SSTR; e += 256) { Sf[e] = 0.f; Stf[e] = 0u; }
    __syncthreads();

    for (int c = 0; c < NC; c++) {
        size_t base = ((size_t)bh*NC + c) * (32*256);
        size_t abase = ((size_t)bh*NC + c) * 1024;

        // load u slice (32x32) + attn (32x32) ; w tile (32x256) as tf32
        for (int e = tid; e < 1024; e += 256) {
            int r = e >> 5, j = e & 31;
            Ui[r*SSTR + j]  = g_u[base + r*256 + g*32 + j];
            Atf[r*SSTR + j] = f2tf(g_attn[abase + e]);
        }
        for (int e = tid*4; e < 8192; e += 1024) {
            float4 v = *(const float4*)&g_w[base + e];
            unsigned* dst = &Ttf[(e >> 8)*TSTR + (e & 255)];
            dst[0]=f2tf(v.x); dst[1]=f2tf(v.y); dst[2]=f2tf(v.z); dst[3]=f2tf(v.w);
        }
        __syncthreads();

        // (1) u_i = u - w@S    (32x32, K=256)
        {
            float acc[4] = {0.f, 0.f, 0.f, 0.f};
#pragma unroll 4
            for (int kb = 0; kb < 256; kb += 8) {
                unsigned a[4], bf[2];
                a[0] = Ttf[(m0+lr)*TSTR + kb+lk];
                a[1] = Ttf[(m0+lr+8)*TSTR + kb+lk];
                a[2] = Ttf[(m0+lr)*TSTR + kb+lk+4];
                a[3] = Ttf[(m0+lr+8)*TSTR + kb+lk+4];
                bf[0] = Stf[(kb+lk)*SSTR + n0+lr];
                bf[1] = Stf[(kb+lk+4)*SSTR + n0+lr];
                mma_tf32(acc, a, bf);
            }
            int r0 = m0 + lr, r1 = r0 + 8, cb = n0 + 2*lk;
            float u0 = Ui[r0*SSTR+cb]   - acc[0];
            float u1 = Ui[r0*SSTR+cb+1] - acc[1];
            float u2 = Ui[r1*SSTR+cb]   - acc[2];
            float u3 = Ui[r1*SSTR+cb+1] - acc[3];
            Ui[r0*SSTR+cb] = u0; Ui[r0*SSTR+cb+1] = u1;
            Ui[r1*SSTR+cb] = u2; Ui[r1*SSTR+cb+1] = u3;
            Utf[r0*SSTR+cb] = f2tf(u0); Utf[r0*SSTR+cb+1] = f2tf(u1);
            Utf[r1*SSTR+cb] = f2tf(u2); Utf[r1*SSTR+cb+1] = f2tf(u3);
        }
        __syncthreads();

        // load q tile
        for (int e = tid*4; e < 8192; e += 1024) {
            float4 v = *(const float4*)&g_qn[base + e];
            unsigned* dst = &Ttf[(e >> 8)*TSTR + (e & 255)];
            dst[0]=f2tf(v.x); dst[1]=f2tf(v.y); dst[2]=f2tf(v.z); dst[3]=f2tf(v.w);
        }
        __syncthreads();

        // (2) o = q@S + attn@u_i  -> g_delta
        {
            float acc[4] = {0.f, 0.f, 0.f, 0.f};
#pragma unroll 4
            for (int kb = 0; kb < 256; kb += 8) {
                unsigned a[4], bf[2];
                a[0] = Ttf[(m0+lr)*TSTR + kb+lk];
                a[1] = Ttf[(m0+lr+8)*TSTR + kb+lk];
                a[2] = Ttf[(m0+lr)*TSTR + kb+lk+4];
                a[3] = Ttf[(m0+lr+8)*TSTR + kb+lk+4];
                bf[0] = Stf[(kb+lk)*SSTR + n0+lr];
                bf[1] = Stf[(kb+lk+4)*SSTR + n0+lr];
                mma_tf32(acc, a, bf);
            }
#pragma unroll
            for (int kb = 0; kb < 32; kb += 8) {
                unsigned a[4], bf[2];
                a[0] = Atf[(m0+lr)*SSTR + kb+lk];
                a[1] = Atf[(m0+lr+8)*SSTR + kb+lk];
                a[2] = Atf[(m0+lr)*SSTR + kb+lk+4];
                a[3] = Atf[(m0+lr+8)*SSTR + kb+lk+4];
                bf[0] = Utf[(kb+lk)*SSTR + n0+lr];
                bf[1] = Utf[(kb+lk+4)*SSTR + n0+lr];
                mma_tf32(acc, a, bf);
            }
            size_t ob = ((size_t)(b*LL + c*32 + m0 + lr))*DD + h*DV + g*32 + n0 + 2*lk;
            float2 lo = {acc[0], acc[1]};
            float2 hi = {acc[2], acc[3]};
            *(float2*)&g_delta[ob]        = lo;
            *(float2*)&g_delta[ob + 8*DD] = hi;
        }
        __syncthreads();

        // load k tile
        for (int e = tid*4; e < 8192; e += 1024) {
            float4 v = *(const float4*)&g_kn[base + e];
            unsigned* dst = &Ttf[(e >> 8)*TSTR + (e & 255)];
            dst[0]=f2tf(v.x); dst[1]=f2tf(v.y); dst[2]=f2tf(v.z); dst[3]=f2tf(v.w);
        }
        __syncthreads();

        // (3) S += k^T @ u_i   (M=256, N=32, K=32); k^T read transposed
#pragma unroll
        for (int t = 0; t < 2; t++) {
            int tm = (wid*2 + t) * 16;
#pragma unroll
            for (int tn = 0; tn < 4; tn++) {
                int nn = tn*8;
                int r0 = tm + lr, r1 = r0 + 8, cb = nn + 2*lk;
                float acc[4];
                acc[0] = Sf[r0*SSTR+cb]; acc[1] = Sf[r0*SSTR+cb+1];
                acc[2] = Sf[r1*SSTR+cb]; acc[3] = Sf[r1*SSTR+cb+1];
#pragma unroll
                for (int kb = 0; kb < 32; kb += 8) {
                    unsigned a[4], bf[2];
                    a[0] = Ttf[(kb+lk)*TSTR + tm+lr];
                    a[1] = Ttf[(kb+lk)*TSTR + tm+lr+8];
                    a[2] = Ttf[(kb+lk+4)*TSTR + tm+lr];
                    a[3] = Ttf[(kb+lk+4)*TSTR + tm+lr+8];
                    bf[0] = Utf[(kb+lk)*SSTR + nn+lr];
                    bf[1] = Utf[(kb+lk+4)*SSTR + nn+lr];
                    mma_tf32(acc, a, bf);
                }
                Sf[r0*SSTR+cb] = acc[0]; Sf[r0*SSTR+cb+1] = acc[1];
                Sf[r1*SSTR+cb] = acc[2]; Sf[r1*SSTR+cb+1] = acc[3];
                Stf[r0*SSTR+cb] = f2tf(acc[0]); Stf[r0*SSTR+cb+1] = f2tf(acc[1]);
                Stf[r1*SSTR+cb] = f2tf(acc[2]); Stf[r1*SSTR+cb+1] = f2tf(acc[3]);
            }
        }
        __syncthreads();
    }
}

// ------------------- per-(head,channel) FIR conv (float2) -------------------
template<int K>
__global__ __launch_bounds__(256) void fir_kernel(
    const float* __restrict__ fw, float* __restrict__ y)
{
    __shared__ float2 vbuf[(128 + K - 1) * 16];
    __shared__ float2 wbuf[16 * K];
    int bh = blockIdx.x;
    int b = bh / HH, h = bh % HH;
    int l0 = blockIdx.y * 128;
    int d0 = blockIdx.z * 32;
    int tid = threadIdx.x;

    for (int idx = tid; idx < 16*K; idx += 256) {
        int dp = idx / K, t = idx % K;
        float2 wv;
        wv.x = fw[(size_t)(h*DV + d0 + 2*dp)*K + t];
        wv.y = fw[(size_t)(h*DV + d0 + 2*dp + 1)*K + t];
        wbuf[dp*K + t] = wv;
    }
    for (int idx = tid; idx < (128 + K - 1)*16; idx += 256) {
        int lrr = idx >> 4, dp = idx & 15;
        int l = l0 - (K - 1) + lrr;
        vbuf[idx] = (l >= 0)
            ? *(const float2*)&g_vc[((size_t)(b*LL + l))*DD + h*DV + d0 + 2*dp]
            : make_float2(0.f, 0.f);
    }
    __syncthreads();

    int dp = tid & 15;
    int lr0 = (tid >> 4) * 8;
    for (int m = 0; m < 8; m++) {
        int lrr = lr0 + m;
        float2 acc = {0.f, 0.f};
#pragma unroll
        for (int t = 0; t < K; t++) {
            float2 v = vbuf[(lrr + t)*16 + dp];
            float2 wv = wbuf[dp*K + t];
            acc.x = fmaf(v.x, wv.x, acc.x);
            acc.y = fmaf(v.y, wv.y, acc.y);
        }
        *(float2*)&y[((size_t)(b*LL + l0 + lrr))*DD + h*DV + d0 + 2*dp] = acc;
    }
}

// ------------- gate input assembly (hs + stats), stored as fp16 -------------
__global__ __launch_bounds__(256) void stats_kernel(const float* __restrict__ hs)
{
    int n = blockIdx.x, tid = threadIdx.x;
    {
        int i = tid * 4;
        float4 v = *(const float4*)&hs[(size_t)n*DD + i];
        __half2 lo = __floats2half2_rn(v.x, v.y);
        __half2 hi = __floats2half2_rn(v.z, v.w);
        uint2 o = {*(unsigned*)&lo, *(unsigned*)&hi};
        *(uint2*)&g_gatein_h[(size_t)n*GIN + i] = o;
    }
    int warp = tid >> 5, lane = tid & 31;
    for (int rep = 0; rep < 2; rep++) {
        int combo = warp*2 + rep;
        int path = combo >> 2, h = combo & 3;
        const float* p;
        if      (path == 0) p = g_short;
        else if (path == 1) p = g_long;
        else if (path == 2) p = g_delta;
        else                p = g_vc;
        p += (size_t)n*DD + h*DV;
        float s1 = 0.f, s2 = 0.f;
        for (int j = lane; j < 256; j += 32) { float x = p[j]; s1 += x; s2 += x*x; }
#pragma unroll
        for (int st = 16; st > 0; st >>= 1) {
            s1 += __shfl_down_sync(0xffffffffu, s1, st);
            s2 += __shfl_down_sync(0xffffffffu, s2, st);
        }
        if (lane == 0) {
            float m  = s1 * (1.f/256.f);
            float va = s2 * (1.f/256.f) - m*m;
            g_gatein_h[(size_t)n*GIN + DD + path*8 + h*2]     = __float2half_rn(m);
            g_gatein_h[(size_t)n*GIN + DD + path*8 + h*2 + 1] = __float2half_rn(va);
        }
    }
}

// ------------------------- gate2 + softmax + floor --------------------------
__global__ __launch_bounds__(256) void gate2_kernel(
    const float* __restrict__ w2, const float* __restrict__ log_temp,
    const float* __restrict__ base_bias, const float* __restrict__ floor_raw)
{
    __shared__ float hrow[HID];
    __shared__ float lg[16];
    int n = blockIdx.x, tid = threadIdx.x;
    for (int i = tid; i < HID; i += 256) hrow[i] = g_hmid[(size_t)n*HID + i];
    __syncthreads();
    int warp = tid >> 5, lane = tid & 31;
    for (int rep = 0; rep < 2; rep++) {
        int o = warp*2 + rep;
        const float* wr = w2 + (size_t)o*HID;
        float s = 0.f;
        for (int i = lane; i < HID; i += 32) s = fmaf(hrow[i], wr[i], s);
#pragma unroll
        for (int st = 16; st > 0; st >>= 1) s += __shfl_down_sync(0xffffffffu, s, st);
        if (lane == 0) lg[o] = s;
    }
    __syncthreads();
    if (tid < 4) {
        int h = tid;
        float temp = log1pf(expf(log_temp[h])) + 1e-4f;
        float z[4], m = -1e30f;
#pragma unroll
        for (int i = 0; i < 4; i++) {
            z[i] = (lg[h*4+i] + base_bias[h*4+i]) / temp;
            m = fmaxf(m, z[i]);
        }
        float e[4], s = 0.f;
#pragma unroll
        for (int i = 0; i < 4; i++) { e[i] = expf(z[i] - m); s += e[i]; }
        float p[4], s2 = 0.f;
#pragma unroll
        for (int i = 0; i < 4; i++) {
            p[i] = e[i] / s;
            float f = 0.05f / (1.f + expf(-floor_raw[h*4+i]));
            p[i] = fmaxf(p[i], f);
            s2 += p[i];
        }
#pragma unroll
        for (int i = 0; i < 4; i++) g_probs[(size_t)n*16 + h*4 + i] = p[i] / s2;
    }
}

// ------------- path mix + RMS norm, output stored as fp16 -------------------
__global__ __launch_bounds__(256) void mix_kernel(const float* __restrict__ onorm)
{
    __shared__ float pr[16];
    __shared__ float wsum[8];
    int n = blockIdx.x, tid = threadIdx.x;
    if (tid < 16) pr[tid] = g_probs[(size_t)n*16 + tid];
    __syncthreads();
    int h = tid >> 6;
    int dd = (tid & 63) * 4;
    size_t pb = (size_t)n*DD + h*DV + dd;
    float4 sh = *(const float4*)&g_short[pb];
    float4 lo = *(const float4*)&g_long[pb];
    float4 de = *(const float4*)&g_delta[pb];
    float4 vv = *(const float4*)&g_vc[pb];
    float p0 = pr[h*4+0], p1 = pr[h*4+1], p2 = pr[h*4+2], p3 = pr[h*4+3];
    float o[4];
    o[0] = p0*sh.x + p1*lo.x + p2*de.x + p3*vv.x;
    o[1] = p0*sh.y + p1*lo.y + p2*de.y + p3*vv.y;
    o[2] = p0*sh.z + p1*lo.z + p2*de.z + p3*vv.z;
    o[3] = p0*sh.w + p1*lo.w + p2*de.w + p3*vv.w;
    float ss = o[0]*o[0] + o[1]*o[1] + o[2]*o[2] + o[3]*o[3];
#pragma unroll
    for (int st = 16; st > 0; st >>= 1) ss += __shfl_down_sync(0xffffffffu, ss, st);
    int warp = tid >> 5, lane = tid & 31;
    if (lane == 0) wsum[warp] = ss;
    __syncthreads();
    float tot = wsum[h*2] + wsum[h*2+1];
    float scale = rsqrtf(tot * (1.f/256.f) + 1e-5f);
    __half2 h0 = __floats2half2_rn(o[0]*scale*onorm[dd],   o[1]*scale*onorm[dd+1]);
    __half2 h1 = __floats2half2_rn(o[2]*scale*onorm[dd+2], o[3]*scale*onorm[dd+3]);
    uint2 pk = {*(unsigned*)&h0, *(unsigned*)&h1};
    *(uint2*)&g_mix_h[pb] = pk;
}

// ------------------------- launch ------------------------------------------
extern "C" void kernel_launch(void* const* d_in, const int* in_sizes, int n_in,
                              void* d_out, int out_size)
{
    const float* hs        = (const float*)d_in[0];
    const float* Wq        = (const float*)d_in[1];
    const float* Wk        = (const float*)d_in[2];
    const float* Wv        = (const float*)d_in[3];
    const float* Wb        = (const float*)d_in[4];
    const float* qconv_w   = (const float*)d_in[5];
    const float* kconv_w   = (const float*)d_in[6];
    const float* vconv_w   = (const float*)d_in[7];
    const float* fir_s     = (const float*)d_in[8];
    const float* fir_l     = (const float*)d_in[9];
    const float* gate_w1   = (const float*)d_in[10];
    const float* gate_b1   = (const float*)d_in[11];
    const float* gate_w2   = (const float*)d_in[12];
    const float* log_temp  = (const float*)d_in[13];
    const float* base_bias = (const float*)d_in[14];
    const float* floor_raw = (const float*)d_in[15];
    const float* onorm_w   = (const float*)d_in[16];
    const float* Wo        = (const float*)d_in[17];
    float* out = (float*)d_out;

    void *p_qlin, *p_klin, *p_vlin, *p_qc, *p_kc, *p_vc, *p_hmid, *p_short, *p_long;
    void *p_hsh, *p_wqh, *p_wkh, *p_wvh, *p_woh, *p_gw1h, *p_gateinh, *p_mixh;
    cudaGetSymbolAddress(&p_qlin, g_qlin);
    cudaGetSymbolAddress(&p_klin, g_klin);
    cudaGetSymbolAddress(&p_vlin, g_vlin);
    cudaGetSymbolAddress(&p_qc, g_qc);
    cudaGetSymbolAddress(&p_kc, g_kc);
    cudaGetSymbolAddress(&p_vc, g_vc);
    cudaGetSymbolAddress(&p_hmid, g_hmid);
    cudaGetSymbolAddress(&p_short, g_short);
    cudaGetSymbolAddress(&p_long, g_long);
    cudaGetSymbolAddress(&p_hsh, g_hs_h);
    cudaGetSymbolAddress(&p_wqh, g_wq_h);
    cudaGetSymbolAddress(&p_wkh, g_wk_h);
    cudaGetSymbolAddress(&p_wvh, g_wv_h);
    cudaGetSymbolAddress(&p_woh, g_wo_h);
    cudaGetSymbolAddress(&p_gw1h, g_gw1_h);
    cudaGetSymbolAddress(&p_gateinh, g_gatein_h);
    cudaGetSymbolAddress(&p_mixh, g_mix_h);

    cudaFuncSetAttribute(scan_kernel,
        cudaFuncAttributeMaxDynamicSharedMemorySize, SCAN_SMEM);
    cudaFuncSetAttribute(precompute_kernel,
        cudaFuncAttributeMaxDynamicSharedMemorySize, PSMEM);
    cudaFuncSetAttribute(hgemm,
        cudaFuncAttributeMaxDynamicSharedMemorySize, HGEMM_SMEM);

    dim3 blk(256);

    // 0. pre-convert hs + weights to fp16
    cvt_h6<<<dim3(NROW*DD/1024, 6), blk>>>(
        hs,      (__half*)p_hsh,  NROW*DD,
        Wq,      (__half*)p_wqh,  DD*DD,
        Wk,      (__half*)p_wkh,  DD*DD,
        Wv,      (__half*)p_wvh,  DD*DD,
        Wo,      (__half*)p_woh,  DD*DD,
        gate_w1, (__half*)p_gw1h, HID*GIN);

    // q/k/v projections — one batched fp16 tensor-core launch
    hgemm<<<dim3(DD/128, NROW/128, 3), blk, HGEMM_SMEM>>>(
        (const __half*)p_hsh,
        (const __half*)p_wqh, (const __half*)p_wkh, (const __half*)p_wvh,
        (float*)p_qlin, (float*)p_klin, (float*)p_vlin,
        nullptr, NROW, DD, DD, 0);

    // causal conv4 + SiLU (all three streams in one launch)
    conv4_silu3<<<dim3(NROW*DD/256, 3), blk>>>(
        (const float*)p_qlin, (const float*)p_klin, (const float*)p_vlin,
        qconv_w, kconv_w, vconv_w,
        (float*)p_qc, (float*)p_kc, (float*)p_vc);

    // beta
    beta_kernel<<<NROW, 128>>>(hs, Wb);

    // delta-rule
    precompute_kernel<<<BB*HH*NC, blk, PSMEM>>>();
    scan_kernel<<<BB*HH*NG, blk, SCAN_SMEM>>>();

    // FIR paths
    fir_kernel<3><<<dim3(BB*HH, LL/128, DV/32), blk>>>(fir_s, (float*)p_short);
    fir_kernel<63><<<dim3(BB*HH, LL/128, DV/32), blk>>>(fir_l, (float*)p_long);

    // gate
    stats_kernel<<<NROW, blk>>>(hs);
    hgemm<<<dim3(HID/128, NROW/128, 1), blk, HGEMM_SMEM>>>(
        (const __half*)p_gateinh,
        (const __half*)p_gw1h, nullptr, nullptr,
        (float*)p_hmid, nullptr, nullptr,
        gate_b1, NROW, HID, GIN, 1);
    gate2_kernel<<<NROW, blk>>>(gate_w2, log_temp, base_bias, floor_raw);

    // mix + RMS norm
    mix_kernel<<<NROW, blk>>>(onorm_w);

    // output projection
    hgemm<<<dim3(DD/128, NROW/128, 1), blk, HGEMM_SMEM>>>(
        (const __half*)p_mixh,
        (const __half*)p_woh, nullptr, nullptr,
        out, nullptr, nullptr,
        nullptr, NROW, DD, DD, 0);
}

// round 10
// speedup vs baseline: 2.6175x; 1.0388x over previous
#include <cuda_runtime.h>
#include <cuda_fp16.h>
#include <math.h>
#include <stdint.h>

#define BB 2
#define LL 2048
#define DD 1024
#define HH 4
#define DV 256
#define CKN 32
#define NC 64              // LL / CKN
#define NROW (BB*LL)       // 4096
#define GIN 1056
#define HID 2048
#define NG 8               // Dv groups of 32 in the scan

// ------------------------- scratch (device globals) -------------------------
__device__ float g_qlin[NROW*DD];
__device__ float g_klin[NROW*DD];
__device__ float g_vlin[NROW*DD];
__device__ float g_qc[NROW*DD];
__device__ float g_kc[NROW*DD];
__device__ float g_vc[NROW*DD];
__device__ float g_beta[NROW*HH];
__device__ float g_qn[NROW*DD];
__device__ float g_kn[NROW*DD];
__device__ float g_u[NROW*DD];
__device__ float g_w[NROW*DD];
__device__ float g_attn[BB*HH*NC*CKN*CKN];
__device__ float g_delta[NROW*DD];
__device__ float g_short[NROW*DD];
__device__ float g_long[NROW*DD];
__device__ float g_hmid[NROW*HID];
__device__ float g_probs[NROW*16];
// fp16 GEMM operands
__device__ __half g_hs_h[NROW*DD];
__device__ __half g_wq_h[DD*DD];
__device__ __half g_wk_h[DD*DD];
__device__ __half g_wv_h[DD*DD];
__device__ __half g_wo_h[DD*DD];
__device__ __half g_gw1_h[HID*GIN];
__device__ __half g_gatein_h[NROW*GIN];
__device__ __half g_mix_h[NROW*DD];

// ------------------------- helpers ------------------------------------------
__device__ __forceinline__ unsigned f2tf(float x) {
    unsigned r;
    asm("cvt.rna.tf32.f32 %0, %1;" : "=r"(r) : "f"(x));
    return r;
}

__device__ __forceinline__ void mma_tf32(float* c, const unsigned* a, const unsigned* b) {
    asm volatile(
        "mma.sync.aligned.m16n8k8.row.col.f32.tf32.tf32.f32 "
        "{%0,%1,%2,%3}, {%4,%5,%6,%7}, {%8,%9}, {%0,%1,%2,%3};"
        : "+f"(c[0]), "+f"(c[1]), "+f"(c[2]), "+f"(c[3])
        : "r"(a[0]), "r"(a[1]), "r"(a[2]), "r"(a[3]), "r"(b[0]), "r"(b[1]));
}

__device__ __forceinline__ void mma_f16(float* c, const unsigned* a, const unsigned* b) {
    asm volatile(
        "mma.sync.aligned.m16n8k16.row.col.f32.f16.f16.f32 "
        "{%0,%1,%2,%3}, {%4,%5,%6,%7}, {%8,%9}, {%0,%1,%2,%3};"
        : "+f"(c[0]), "+f"(c[1]), "+f"(c[2]), "+f"(c[3])
        : "r"(a[0]), "r"(a[1]), "r"(a[2]), "r"(a[3]), "r"(b[0]), "r"(b[1]));
}

#define LDSM4(r, addr)                                                        \
    asm volatile("ldmatrix.sync.aligned.m8n8.x4.shared.b16 {%0,%1,%2,%3}, [%4];" \
        : "=r"((r)[0]), "=r"((r)[1]), "=r"((r)[2]), "=r"((r)[3]) : "r"(addr))

// ------------------------- bulk fp32 -> fp16 conversion ---------------------
__global__ __launch_bounds__(256) void cvt_h6(
    const float* __restrict__ s0, __half* __restrict__ d0, int n0,
    const float* __restrict__ s1, __half* __restrict__ d1, int n1,
    const float* __restrict__ s2, __half* __restrict__ d2, int n2,
    const float* __restrict__ s3, __half* __restrict__ d3, int n3,
    const float* __restrict__ s4, __half* __restrict__ d4, int n4,
    const float* __restrict__ s5, __half* __restrict__ d5, int n5)
{
    const float* s; __half* d; int n;
    switch (blockIdx.y) {
        case 0: s=s0; d=d0; n=n0; break;
        case 1: s=s1; d=d1; n=n1; break;
        case 2: s=s2; d=d2; n=n2; break;
        case 3: s=s3; d=d3; n=n3; break;
        case 4: s=s4; d=d4; n=n4; break;
        default: s=s5; d=d5; n=n5; break;
    }
    int i = (blockIdx.x * 256 + threadIdx.x) * 4;
    if (i < n) {
        float4 v = *(const float4*)(s + i);
        __half2 lo = __floats2half2_rn(v.x, v.y);
        __half2 hi = __floats2half2_rn(v.z, v.w);
        uint2 o = {*(unsigned*)&lo, *(unsigned*)&hi};
        *(uint2*)(d + i) = o;
    }
}

// ---------------- fp16 tensor GEMM: C = A(MxK) @ B(NxK)^T -------------------
// A,B fp16, K-major. 128x128 CTA tile, 8 warps (2x4), warp tile 64x32.
// m16n8k16 mma, K=32 staged per iter, 3-stage cp.async pipeline, ldmatrix
// fragment loads. Smem rows: 32 halves @ 112B stride (28-word stride makes
// 8 consecutive rows hit disjoint 16B bank groups -> LDSM conflict-free).
#define HSTRB 112
#define HSTRW 28
#define HSTAGE_BYTES (128*HSTRB)        // 14336
#define HGEMM_SMEM (6*HSTAGE_BYTES)     // 86016

#define HLOAD(kt, st) do {                                                     \
    const __half* Ap_ = A + (size_t)bm*K + (kt)*32;                            \
    const __half* Bp_ = B + (size_t)bn*K + (kt)*32;                            \
    _Pragma("unroll")                                                          \
    for (int i_ = 0; i_ < 2; i_++) {                                           \
        int e_ = tid + i_*256;                                                 \
        int row_ = e_ >> 2, seg_ = e_ & 3;                                     \
        unsigned doff_ = (unsigned)row_*HSTRB + (unsigned)seg_*16;             \
        asm volatile("cp.async.cg.shared.global [%0], [%1], 16;"               \
            :: "r"(smb + (unsigned)((st)*HSTAGE_BYTES) + doff_),               \
               "l"(Ap_ + (size_t)row_*K + seg_*8));                            \
        asm volatile("cp.async.cg.shared.global [%0], [%1], 16;"               \
            :: "r"(smb + (unsigned)(3*HSTAGE_BYTES + (st)*HSTAGE_BYTES) + doff_), \
               "l"(Bp_ + (size_t)row_*K + seg_*8));                            \
    }                                                                          \
} while (0)

__global__ __launch_bounds__(256, 2) void hgemm(
    const __half* __restrict__ A,
    const __half* __restrict__ Bm0, const __half* __restrict__ Bm1, const __half* __restrict__ Bm2,
    float* __restrict__ Cm0, float* __restrict__ Cm1, float* __restrict__ Cm2,
    const float* __restrict__ bias, int M, int N, int K, int mode)
{
    extern __shared__ char tsm[];

    const __half* B = (blockIdx.z == 0) ? Bm0 : (blockIdx.z == 1) ? Bm1 : Bm2;
    float*        C = (blockIdx.z == 0) ? Cm0 : (blockIdx.z == 1) ? Cm1 : Cm2;

    int tid = threadIdx.x;
    int bm = blockIdx.y * 128, bn = blockIdx.x * 128;
    unsigned smb;
    asm("{ .reg .u64 t; cvta.to.shared.u64 t, %1; cvt.u32.u64 %0, t; }"
        : "=r"(smb) : "l"(tsm));

    int wid = tid >> 5, lane = tid & 31;
    int wm = (wid >> 2) * 64, wn = (wid & 3) * 32;
    int lr = lane >> 2, lk = lane & 3;

    // ldmatrix lane-address components
    int a_row = (lane & 7) + ((lane >> 3) & 1) * 8;   // + m-offset within pair
    int a_kb  = (lane >> 4) * 16;                     // 0 or 16 bytes
    int b_row = (lane & 7) + ((lane >> 4) & 1) * 8;
    int b_kb  = ((lane >> 3) & 1) * 16;

    float acc[4][4][4];
#pragma unroll
    for (int mi = 0; mi < 4; mi++)
#pragma unroll
        for (int ni = 0; ni < 4; ni++)
#pragma unroll
            for (int j = 0; j < 4; j++) acc[mi][ni][j] = 0.f;

    int niter = K >> 5;          // K=1024 -> 32, K=1056 -> 33

    HLOAD(0, 0);
    asm volatile("cp.async.commit_group;");
    HLOAD(1, 1);
    asm volatile("cp.async.commit_group;");

    for (int t = 0; t < niter; t++) {
        asm volatile("cp.async.wait_group 1;");
        __syncthreads();
        if (t + 2 < niter) HLOAD(t + 2, (t + 2) % 3);
        asm volatile("cp.async.commit_group;");

        int cur = t % 3;
        unsigned a_base = smb + (unsigned)(cur*HSTAGE_BYTES);
        unsigned b_base = smb + (unsigned)(3*HSTAGE_BYTES + cur*HSTAGE_BYTES);
#pragma unroll
        for (int ks = 0; ks < 2; ks++) {
            unsigned af[4][4], bq[2][4];
#pragma unroll
            for (int mi = 0; mi < 4; mi++) {
                unsigned addr = a_base + (unsigned)((wm + mi*16 + a_row)*HSTRB + ks*32 + a_kb);
                LDSM4(af[mi], addr);
            }
#pragma unroll
            for (int nq = 0; nq < 2; nq++) {
                unsigned addr = b_base + (unsigned)((wn + nq*16 + b_row)*HSTRB + ks*32 + b_kb);
                LDSM4(bq[nq], addr);
            }
#pragma unroll
            for (int mi = 0; mi < 4; mi++)
#pragma unroll
                for (int ni = 0; ni < 4; ni++)
                    mma_f16(acc[mi][ni], af[mi], &bq[ni >> 1][(ni & 1) * 2]);
        }
    }

#pragma unroll
    for (int mi = 0; mi < 4; mi++) {
        int r0 = bm + wm + mi*16 + lr;
#pragma unroll
        for (int ni = 0; ni < 4; ni++) {
            int c = bn + wn + ni*8 + 2*lk;
            float v[4] = {acc[mi][ni][0], acc[mi][ni][1], acc[mi][ni][2], acc[mi][ni][3]};
            if (mode == 1) {
                float b0 = bias[c], b1 = bias[c+1];
                v[0] += b0; v[1] += b1; v[2] += b0; v[3] += b1;
#pragma unroll
                for (int j = 0; j < 4; j++)
                    v[j] = 0.5f * v[j] * (1.f + erff(v[j] * 0.70710678118654752f));
            }
            float2 lo = {v[0], v[1]};
            float2 hi = {v[2], v[3]};
            *(float2*)&C[(size_t)r0*N + c]       = lo;
            *(float2*)&C[(size_t)(r0+8)*N + c]   = hi;
        }
    }
}

// ------------------- depthwise causal conv4 + SiLU (3 streams batched) ------
__global__ __launch_bounds__(256) void conv4_silu3(
    const float* __restrict__ x0, const float* __restrict__ x1, const float* __restrict__ x2,
    const float* __restrict__ w0, const float* __restrict__ w1, const float* __restrict__ w2,
    float* __restrict__ y0, float* __restrict__ y1, float* __restrict__ y2)
{
    const float* x; const float* w; float* y;
    if (blockIdx.y == 0)      { x = x0; w = w0; y = y0; }
    else if (blockIdx.y == 1) { x = x1; w = w1; y = y1; }
    else                      { x = x2; w = w2; y = y2; }
    int idx = blockIdx.x * 256 + threadIdx.x;       // over NROW*DD
    int d = idx & (DD-1);
    int l = (idx >> 10) & (LL-1);
    float4 wv = *(const float4*)(w + d*4);
    const float* xp = x + (size_t)idx;
    float acc = wv.w * xp[0];
    if (l >= 1) acc += wv.z * xp[-DD];
    if (l >= 2) acc += wv.y * xp[-2*DD];
    if (l >= 3) acc += wv.x * xp[-3*DD];
    y[idx] = acc / (1.f + expf(-acc));
}

// ------------------------- beta = sigmoid(hs @ Wb^T) ------------------------
__global__ __launch_bounds__(128) void beta_kernel(
    const float* __restrict__ hs, const float* __restrict__ Wb)
{
    __shared__ float red[4][128];
    int n = blockIdx.x, tid = threadIdx.x;
    const float* hr = hs + (size_t)n * DD;
    float s0=0,s1=0,s2=0,s3=0;
    for (int i = tid; i < DD; i += 128) {
        float x = hr[i];
        s0 += x * Wb[i];
        s1 += x * Wb[DD + i];
        s2 += x * Wb[2*DD + i];
        s3 += x * Wb[3*DD + i];
    }
    red[0][tid]=s0; red[1][tid]=s1; red[2][tid]=s2; red[3][tid]=s3;
    __syncthreads();
    for (int st = 64; st > 0; st >>= 1) {
        if (tid < st)
#pragma unroll
            for (int h = 0; h < 4; h++) red[h][tid] += red[h][tid + st];
        __syncthreads();
    }
    if (tid < 4) g_beta[(size_t)n*HH + tid] = 1.f / (1.f + expf(-red[tid][0]));
}

// ---------------- per-chunk delta-rule precompute (tensor-core mma) ---------
#define PSTR 264
#define PSMEM ((2*32*PSTR + 32*33 + 32*36 + 96) * 4)
__global__ __launch_bounds__(256) void precompute_kernel()
{
    extern __shared__ float psm[];
    float*    Kt  = psm;                     // [32][PSTR] k fp32 -> kn tf32
    float*    Qt  = Kt + 32*PSTR;            // [32][PSTR] q fp32 -> qn tf32 -> v tf32
    float*    Am  = Qt + 32*PSTR;            // [32][33]
    unsigned* Ttf = (unsigned*)(Am + 32*33); // [32][36]
    float*    bet = (float*)(Ttf + 32*36);   // [32]
    float*    rnk = bet + 32;                // [32]
    float*    rnq = rnk + 32;                // [32]

    int blk = blockIdx.x;           // (b*HH + h)*NC + c
    int c  = blk % NC;
    int bh = blk / NC;
    int h  = bh % HH;
    int b  = bh / HH;
    int tid = threadIdx.x;
    int l0 = c * 32;
    int wid = tid >> 5, lane = tid & 31;
    int lr = lane >> 2, lk = lane & 3;

    // 1. load k, q tiles (fp32)
    for (int e = tid*4; e < 32*256; e += 1024) {
        int r = e >> 8, d = e & 255;
        size_t gb = ((size_t)(b*LL + l0 + r))*DD + h*DV + d;
        *(float4*)&Kt[r*PSTR + d] = *(const float4*)&g_kc[gb];
        *(float4*)&Qt[r*PSTR + d] = *(const float4*)&g_qc[gb];
    }
    if (tid < 32) bet[tid] = g_beta[((size_t)(b*LL + l0 + tid))*HH + h];
    __syncthreads();

    // 2. row norms (8 threads per row)
    {
        int r = tid >> 3, part = tid & 7;
        float sk = 0.f, sq = 0.f;
        for (int j = part*32; j < part*32 + 32; j++) {
            float x = Kt[r*PSTR + j]; sk += x*x;
            float y = Qt[r*PSTR + j]; sq += y*y;
        }
        sk += __shfl_down_sync(0xffffffffu, sk, 4, 8);
        sk += __shfl_down_sync(0xffffffffu, sk, 2, 8);
        sk += __shfl_down_sync(0xffffffffu, sk, 1, 8);
        sq += __shfl_down_sync(0xffffffffu, sq, 4, 8);
        sq += __shfl_down_sync(0xffffffffu, sq, 2, 8);
        sq += __shfl_down_sync(0xffffffffu, sq, 1, 8);
        if (part == 0) { rnk[r] = rsqrtf(sk + 1e-6f); rnq[r] = rsqrtf(sq + 1e-6f); }
    }
    __syncthreads();

    // 3. normalize in place (fp32 -> global, tf32 -> smem)
    size_t obase = (size_t)blk * (32*256);
    for (int e = tid*4; e < 32*256; e += 1024) {
        int r = e >> 8, d = e & 255;
        float rk = rnk[r], rq = rnq[r];
        float4 kv = *(float4*)&Kt[r*PSTR + d];
        kv.x *= rk; kv.y *= rk; kv.z *= rk; kv.w *= rk;
        *(float4*)&g_kn[obase + e] = kv;
        unsigned* kd = (unsigned*)&Kt[r*PSTR + d];
        kd[0]=f2tf(kv.x); kd[1]=f2tf(kv.y); kd[2]=f2tf(kv.z); kd[3]=f2tf(kv.w);
        float4 qv = *(float4*)&Qt[r*PSTR + d];
        qv.x *= rq; qv.y *= rq; qv.z *= rq; qv.w *= rq;
        *(float4*)&g_qn[obase + e] = qv;
        unsigned* qd = (unsigned*)&Qt[r*PSTR + d];
        qd[0]=f2tf(qv.x); qd[1]=f2tf(qv.y); qd[2]=f2tf(qv.z); qd[3]=f2tf(qv.w);
    }
    __syncthreads();

    // 4. fused mma: Afull = kn@kn^T, attnF = qn@kn^T  (32x32, K=256)
    {
        int m0 = (wid >> 2) * 16, n0 = (wid & 3) * 8;
        const unsigned* Ku = (const unsigned*)Kt;
        const unsigned* Qu = (const unsigned*)Qt;
        float accA[4] = {0,0,0,0}, accQ[4] = {0,0,0,0};
#pragma unroll 4
        for (int kb = 0; kb < 256; kb += 8) {
            unsigned ak[4], aq[4], bf[2];
            ak[0] = Ku[(m0+lr)*PSTR + kb+lk];
            ak[1] = Ku[(m0+lr+8)*PSTR + kb+lk];
            ak[2] = Ku[(m0+lr)*PSTR + kb+lk+4];
            ak[3] = Ku[(m0+lr+8)*PSTR + kb+lk+4];
            aq[0] = Qu[(m0+lr)*PSTR + kb+lk];
            aq[1] = Qu[(m0+lr+8)*PSTR + kb+lk];
            aq[2] = Qu[(m0+lr)*PSTR + kb+lk+4];
            aq[3] = Qu[(m0+lr+8)*PSTR + kb+lk+4];
            bf[0] = Ku[(n0+lr)*PSTR + kb+lk];       // B = kn^T (transposed read)
            bf[1] = Ku[(n0+lr)*PSTR + kb+lk+4];
            mma_tf32(accA, ak, bf);
            mma_tf32(accQ, aq, bf);
        }
        size_t abase = (size_t)blk * 1024;
        int r0 = m0 + lr, r1 = r0 + 8, c0 = n0 + 2*lk, c1 = c0 + 1;
        g_attn[abase + r0*32 + c0] = (c0 <= r0) ? accQ[0] : 0.f;
        g_attn[abase + r0*32 + c1] = (c1 <= r0) ? accQ[1] : 0.f;
        g_attn[abase + r1*32 + c0] = (c0 <= r1) ? accQ[2] : 0.f;
        g_attn[abase + r1*32 + c1] = (c1 <= r1) ? accQ[3] : 0.f;
        Am[r0*33 + c0] = (c0 < r0) ? -bet[r0]*accA[0] : 0.f;
        Am[r0*33 + c1] = (c1 < r0) ? -bet[r0]*accA[1] : 0.f;
        Am[r1*33 + c0] = (c0 < r1) ? -bet[r1]*accA[2] : 0.f;
        Am[r1*33 + c1] = (c1 < r1) ? -bet[r1]*accA[3] : 0.f;
    }
    __syncthreads();

    // 5. iterative inversion (warp 0), then T' = (A+I)*diag(beta) as tf32
    if (tid < 32) {
        int ln = tid;
        for (int i = 1; i < 32; i++) {
            float t = 0.f;
            if (ln < i) for (int p = 0; p < i; p++) t += Am[i*33 + p] * Am[p*33 + ln];
            __syncwarp();
            if (ln < i) Am[i*33 + ln] += t;
            __syncwarp();
        }
    }
    __syncthreads();
    for (int e = tid; e < 1024; e += 256) {
        int i = e >> 5, j = e & 31;
        float t = Am[i*33 + j] + (i == j ? 1.f : 0.f);
        Ttf[i*36 + j] = f2tf(t * bet[j]);
    }
    // 6. load raw v tile as tf32 into Qt (reuse)
    __syncthreads();
    for (int e = tid*4; e < 32*256; e += 1024) {
        int r = e >> 8, d = e & 255;
        float4 vv = *(const float4*)&g_vc[((size_t)(b*LL + l0 + r))*DD + h*DV + d];
        unsigned* qd = (unsigned*)&Qt[r*PSTR + d];
        qd[0]=f2tf(vv.x); qd[1]=f2tf(vv.y); qd[2]=f2tf(vv.z); qd[3]=f2tf(vv.w);
    }
    __syncthreads();

    // 7. u = T'@v, w = T'@kn   (32x256, K=32)
    {
        int m0 = (wid & 1) * 16;
        int nb = (wid >> 1) * 64;
        const unsigned* Ku = (const unsigned*)Kt;
        const unsigned* Vu = (const unsigned*)Qt;
        unsigned a[4][4];
#pragma unroll
        for (int kk = 0; kk < 4; kk++) {
            int kb = kk*8;
            a[kk][0] = Ttf[(m0+lr)*36 + kb+lk];
            a[kk][1] = Ttf[(m0+lr+8)*36 + kb+lk];
            a[kk][2] = Ttf[(m0+lr)*36 + kb+lk+4];
            a[kk][3] = Ttf[(m0+lr+8)*36 + kb+lk+4];
        }
#pragma unroll
        for (int nt = 0; nt < 8; nt++) {
            int n0 = nb + nt*8;
            float au[4] = {0,0,0,0}, aw[4] = {0,0,0,0};
#pragma unroll
            for (int kk = 0; kk < 4; kk++) {
                int kb = kk*8;
                unsigned bu[2], bw[2];
                bu[0] = Vu[(kb+lk)*PSTR + n0+lr];
                bu[1] = Vu[(kb+lk+4)*PSTR + n0+lr];
                bw[0] = Ku[(kb+lk)*PSTR + n0+lr];
                bw[1] = Ku[(kb+lk+4)*PSTR + n0+lr];
                mma_tf32(au, a[kk], bu);
                mma_tf32(aw, a[kk], bw);
            }
            int r0 = m0 + lr, r1 = r0 + 8, cc = n0 + 2*lk;
            float2 u01 = {au[0], au[1]}, u23 = {au[2], au[3]};
            float2 w01 = {aw[0], aw[1]}, w23 = {aw[2], aw[3]};
            *(float2*)&g_u[obase + r0*256 + cc] = u01;
            *(float2*)&g_u[obase + r1*256 + cc] = u23;
            *(float2*)&g_w[obase + r0*256 + cc] = w01;
            *(float2*)&g_w[obase + r1*256 + cc] = w23;
        }
    }
}

// --------------- sequential inter-chunk scan (tensor-core mma) --------------
#define SSTR 40     // stride for [.. x 32] arrays (bank-conflict-free frags)
#define TSTR 264    // stride for [32 x 256] tiles
#define SCAN_SMEM ((256*SSTR*2 + 32*TSTR + 3*32*SSTR) * 4)
__global__ __launch_bounds__(256) void scan_kernel()
{
    extern __shared__ float sm[];
    float*    Sf  = sm;                           // [256][SSTR] fp32 master
    unsigned* Stf = (unsigned*)(sm + 256*SSTR);   // [256][SSTR] tf32 shadow
    unsigned* Ttf = Stf + 256*SSTR;               // [32][TSTR]  w/q/k tile tf32
    float*    Ui  = (float*)(Ttf + 32*TSTR);      // [32][SSTR]  u then u_i fp32
    unsigned* Utf = (unsigned*)(Ui + 32*SSTR);    // [32][SSTR]  u_i tf32
    unsigned* Atf = Utf + 32*SSTR;                // [32][SSTR]  attn tf32

    int blk = blockIdx.x;               // (b*HH+h)*NG + g
    int g  = blk & (NG-1);
    int bh = blk >> 3;
    int b  = bh >> 2;
    int h  = bh & 3;
    int tid = threadIdx.x;
    int wid = tid >> 5, lane = tid & 31;
    int lr = lane >> 2, lk = lane & 3;
    int m0 = (wid >> 2) * 16;           // (1)/(2) warp tile: 2 x 4
    int n0 = (wid & 3) * 8;

    for (int e = tid; e < 256*SSTR; e += 256) { Sf[e] = 0.f; Stf[e] = 0u; }
    __syncthreads();

    for (int c = 0; c < NC; c++) {
        size_t base = ((size_t)bh*NC + c) * (32*256);
        size_t abase = ((size_t)bh*NC + c) * 1024;

        // load u slice (32x32) + attn (32x32) ; w tile (32x256) as tf32
        for (int e = tid; e < 1024; e += 256) {
            int r = e >> 5, j = e & 31;
            Ui[r*SSTR + j]  = g_u[base + r*256 + g*32 + j];
            Atf[r*SSTR + j] = f2tf(g_attn[abase + e]);
        }
        for (int e = tid*4; e < 8192; e += 1024) {
            float4 v = *(const float4*)&g_w[base + e];
            unsigned* dst = &Ttf[(e >> 8)*TSTR + (e & 255)];
            dst[0]=f2tf(v.x); dst[1]=f2tf(v.y); dst[2]=f2tf(v.z); dst[3]=f2tf(v.w);
        }
        __syncthreads();

        // (1) u_i = u - w@S    (32x32, K=256)
        {
            float acc[4] = {0.f, 0.f, 0.f, 0.f};
#pragma unroll 4
            for (int kb = 0; kb < 256; kb += 8) {
                unsigned a[4], bf[2];
                a[0] = Ttf[(m0+lr)*TSTR + kb+lk];
                a[1] = Ttf[(m0+lr+8)*TSTR + kb+lk];
                a[2] = Ttf[(m0+lr)*TSTR + kb+lk+4];
                a[3] = Ttf[(m0+lr+8)*TSTR + kb+lk+4];
                bf[0] = Stf[(kb+lk)*SSTR + n0+lr];
                bf[1] = Stf[(kb+lk+4)*SSTR + n0+lr];
                mma_tf32(acc, a, bf);
            }
            int r0 = m0 + lr, r1 = r0 + 8, cb = n0 + 2*lk;
            float u0 = Ui[r0*SSTR+cb]   - acc[0];
            float u1 = Ui[r0*SSTR+cb+1] - acc[1];
            float u2 = Ui[r1*SSTR+cb]   - acc[2];
            float u3 = Ui[r1*SSTR+cb+1] - acc[3];
            Ui[r0*SSTR+cb] = u0; Ui[r0*SSTR+cb+1] = u1;
            Ui[r1*SSTR+cb] = u2; Ui[r1*SSTR+cb+1] = u3;
            Utf[r0*SSTR+cb] = f2tf(u0); Utf[r0*SSTR+cb+1] = f2tf(u1);
            Utf[r1*SSTR+cb] = f2tf(u2); Utf[r1*SSTR+cb+1] = f2tf(u3);
        }
        __syncthreads();

        // load q tile
        for (int e = tid*4; e < 8192; e += 1024) {
            float4 v = *(const float4*)&g_qn[base + e];
            unsigned* dst = &Ttf[(e >> 8)*TSTR + (e & 255)];
            dst[0]=f2tf(v.x); dst[1]=f2tf(v.y); dst[2]=f2tf(v.z); dst[3]=f2tf(v.w);
        }
        __syncthreads();

        // (2) o = q@S + attn@u_i  -> g_delta
        {
            float acc[4] = {0.f, 0.f, 0.f, 0.f};
#pragma unroll 4
            for (int kb = 0; kb < 256; kb += 8) {
                unsigned a[4], bf[2];
                a[0] = Ttf[(m0+lr)*TSTR + kb+lk];
                a[1] = Ttf[(m0+lr+8)*TSTR + kb+lk];
                a[2] = Ttf[(m0+lr)*TSTR + kb+lk+4];
                a[3] = Ttf[(m0+lr+8)*TSTR + kb+lk+4];
                bf[0] = Stf[(kb+lk)*SSTR + n0+lr];
                bf[1] = Stf[(kb+lk+4)*SSTR + n0+lr];
                mma_tf32(acc, a, bf);
            }
#pragma unroll
            for (int kb = 0; kb < 32; kb += 8) {
                unsigned a[4], bf[2];
                a[0] = Atf[(m0+lr)*SSTR + kb+lk];
                a[1] = Atf[(m0+lr+8)*SSTR + kb+lk];
                a[2] = Atf[(m0+lr)*SSTR + kb+lk+4];
                a[3] = Atf[(m0+lr+8)*SSTR + kb+lk+4];
                bf[0] = Utf[(kb+lk)*SSTR + n0+lr];
                bf[1] = Utf[(kb+lk+4)*SSTR + n0+lr];
                mma_tf32(acc, a, bf);
            }
            size_t ob = ((size_t)(b*LL + c*32 + m0 + lr))*DD + h*DV + g*32 + n0 + 2*lk;
            float2 lo = {acc[0], acc[1]};
            float2 hi = {acc[2], acc[3]};
            *(float2*)&g_delta[ob]        = lo;
            *(float2*)&g_delta[ob + 8*DD] = hi;
        }
        __syncthreads();

        // load k tile
        for (int e = tid*4; e < 8192; e += 1024) {
            float4 v = *(const float4*)&g_kn[base + e];
            unsigned* dst = &Ttf[(e >> 8)*TSTR + (e & 255)];
            dst[0]=f2tf(v.x); dst[1]=f2tf(v.y); dst[2]=f2tf(v.z); dst[3]=f2tf(v.w);
        }
        __syncthreads();

        // (3) S += k^T @ u_i   (M=256, N=32, K=32); k^T read transposed
#pragma unroll
        for (int t = 0; t < 2; t++) {
            int tm = (wid*2 + t) * 16;
#pragma unroll
            for (int tn = 0; tn < 4; tn++) {
                int nn = tn*8;
                int r0 = tm + lr, r1 = r0 + 8, cb = nn + 2*lk;
                float acc[4];
                acc[0] = Sf[r0*SSTR+cb]; acc[1] = Sf[r0*SSTR+cb+1];
                acc[2] = Sf[r1*SSTR+cb]; acc[3] = Sf[r1*SSTR+cb+1];
#pragma unroll
                for (int kb = 0; kb < 32; kb += 8) {
                    unsigned a[4], bf[2];
                    a[0] = Ttf[(kb+lk)*TSTR + tm+lr];
                    a[1] = Ttf[(kb+lk)*TSTR + tm+lr+8];
                    a[2] = Ttf[(kb+lk+4)*TSTR + tm+lr];
                    a[3] = Ttf[(kb+lk+4)*TSTR + tm+lr+8];
                    bf[0] = Utf[(kb+lk)*SSTR + nn+lr];
                    bf[1] = Utf[(kb+lk+4)*SSTR + nn+lr];
                    mma_tf32(acc, a, bf);
                }
                Sf[r0*SSTR+cb] = acc[0]; Sf[r0*SSTR+cb+1] = acc[1];
                Sf[r1*SSTR+cb] = acc[2]; Sf[r1*SSTR+cb+1] = acc[3];
                Stf[r0*SSTR+cb] = f2tf(acc[0]); Stf[r0*SSTR+cb+1] = f2tf(acc[1]);
                Stf[r1*SSTR+cb] = f2tf(acc[2]); Stf[r1*SSTR+cb+1] = f2tf(acc[3]);
            }
        }
        __syncthreads();
    }
}

// ------------------- per-(head,channel) FIR conv (float2) -------------------
template<int K>
__global__ __launch_bounds__(256) void fir_kernel(
    const float* __restrict__ fw, float* __restrict__ y)
{
    __shared__ float2 vbuf[(128 + K - 1) * 16];
    __shared__ float2 wbuf[16 * K];
    int bh = blockIdx.x;
    int b = bh / HH, h = bh % HH;
    int l0 = blockIdx.y * 128;
    int d0 = blockIdx.z * 32;
    int tid = threadIdx.x;

    for (int idx = tid; idx < 16*K; idx += 256) {
        int dp = idx / K, t = idx % K;
        float2 wv;
        wv.x = fw[(size_t)(h*DV + d0 + 2*dp)*K + t];
        wv.y = fw[(size_t)(h*DV + d0 + 2*dp + 1)*K + t];
        wbuf[dp*K + t] = wv;
    }
    for (int idx = tid; idx < (128 + K - 1)*16; idx += 256) {
        int lrr = idx >> 4, dp = idx & 15;
        int l = l0 - (K - 1) + lrr;
        vbuf[idx] = (l >= 0)
            ? *(const float2*)&g_vc[((size_t)(b*LL + l))*DD + h*DV + d0 + 2*dp]
            : make_float2(0.f, 0.f);
    }
    __syncthreads();

    int dp = tid & 15;
    int lr0 = (tid >> 4) * 8;
    for (int m = 0; m < 8; m++) {
        int lrr = lr0 + m;
        float2 acc = {0.f, 0.f};
#pragma unroll
        for (int t = 0; t < K; t++) {
            float2 v = vbuf[(lrr + t)*16 + dp];
            float2 wv = wbuf[dp*K + t];
            acc.x = fmaf(v.x, wv.x, acc.x);
            acc.y = fmaf(v.y, wv.y, acc.y);
        }
        *(float2*)&y[((size_t)(b*LL + l0 + lrr))*DD + h*DV + d0 + 2*dp] = acc;
    }
}

// ------------- gate input assembly (hs + stats), stored as fp16 -------------
__global__ __launch_bounds__(256) void stats_kernel(const float* __restrict__ hs)
{
    int n = blockIdx.x, tid = threadIdx.x;
    {
        int i = tid * 4;
        float4 v = *(const float4*)&hs[(size_t)n*DD + i];
        __half2 lo = __floats2half2_rn(v.x, v.y);
        __half2 hi = __floats2half2_rn(v.z, v.w);
        uint2 o = {*(unsigned*)&lo, *(unsigned*)&hi};
        *(uint2*)&g_gatein_h[(size_t)n*GIN + i] = o;
    }
    int warp = tid >> 5, lane = tid & 31;
    for (int rep = 0; rep < 2; rep++) {
        int combo = warp*2 + rep;
        int path = combo >> 2, h = combo & 3;
        const float* p;
        if      (path == 0) p = g_short;
        else if (path == 1) p = g_long;
        else if (path == 2) p = g_delta;
        else                p = g_vc;
        p += (size_t)n*DD + h*DV;
        float s1 = 0.f, s2 = 0.f;
        for (int j = lane; j < 256; j += 32) { float x = p[j]; s1 += x; s2 += x*x; }
#pragma unroll
        for (int st = 16; st > 0; st >>= 1) {
            s1 += __shfl_down_sync(0xffffffffu, s1, st);
            s2 += __shfl_down_sync(0xffffffffu, s2, st);
        }
        if (lane == 0) {
            float m  = s1 * (1.f/256.f);
            float va = s2 * (1.f/256.f) - m*m;
            g_gatein_h[(size_t)n*GIN + DD + path*8 + h*2]     = __float2half_rn(m);
            g_gatein_h[(size_t)n*GIN + DD + path*8 + h*2 + 1] = __float2half_rn(va);
        }
    }
}

// ------------------------- gate2 + softmax + floor --------------------------
__global__ __launch_bounds__(256) void gate2_kernel(
    const float* __restrict__ w2, const float* __restrict__ log_temp,
    const float* __restrict__ base_bias, const float* __restrict__ floor_raw)
{
    __shared__ float hrow[HID];
    __shared__ float lg[16];
    int n = blockIdx.x, tid = threadIdx.x;
    for (int i = tid; i < HID; i += 256) hrow[i] = g_hmid[(size_t)n*HID + i];
    __syncthreads();
    int warp = tid >> 5, lane = tid & 31;
    for (int rep = 0; rep < 2; rep++) {
        int o = warp*2 + rep;
        const float* wr = w2 + (size_t)o*HID;
        float s = 0.f;
        for (int i = lane; i < HID; i += 32) s = fmaf(hrow[i], wr[i], s);
#pragma unroll
        for (int st = 16; st > 0; st >>= 1) s += __shfl_down_sync(0xffffffffu, s, st);
        if (lane == 0) lg[o] = s;
    }
    __syncthreads();
    if (tid < 4) {
        int h = tid;
        float temp = log1pf(expf(log_temp[h])) + 1e-4f;
        float z[4], m = -1e30f;
#pragma unroll
        for (int i = 0; i < 4; i++) {
            z[i] = (lg[h*4+i] + base_bias[h*4+i]) / temp;
            m = fmaxf(m, z[i]);
        }
        float e[4], s = 0.f;
#pragma unroll
        for (int i = 0; i < 4; i++) { e[i] = expf(z[i] - m); s += e[i]; }
        float p[4], s2 = 0.f;
#pragma unroll
        for (int i = 0; i < 4; i++) {
            p[i] = e[i] / s;
            float f = 0.05f / (1.f + expf(-floor_raw[h*4+i]));
            p[i] = fmaxf(p[i], f);
            s2 += p[i];
        }
#pragma unroll
        for (int i = 0; i < 4; i++) g_probs[(size_t)n*16 + h*4 + i] = p[i] / s2;
    }
}

// ------------- path mix + RMS norm, output stored as fp16 -------------------
__global__ __launch_bounds__(256) void mix_kernel(const float* __restrict__ onorm)
{
    __shared__ float pr[16];
    __shared__ float wsum[8];
    int n = blockIdx.x, tid = threadIdx.x;
    if (tid < 16) pr[tid] = g_probs[(size_t)n*16 + tid];
    __syncthreads();
    int h = tid >> 6;
    int dd = (tid & 63) * 4;
    size_t pb = (size_t)n*DD + h*DV + dd;
    float4 sh = *(const float4*)&g_short[pb];
    float4 lo = *(const float4*)&g_long[pb];
    float4 de = *(const float4*)&g_delta[pb];
    float4 vv = *(const float4*)&g_vc[pb];
    float p0 = pr[h*4+0], p1 = pr[h*4+1], p2 = pr[h*4+2], p3 = pr[h*4+3];
    float o[4];
    o[0] = p0*sh.x + p1*lo.x + p2*de.x + p3*vv.x;
    o[1] = p0*sh.y + p1*lo.y + p2*de.y + p3*vv.y;
    o[2] = p0*sh.z + p1*lo.z + p2*de.z + p3*vv.z;
    o[3] = p0*sh.w + p1*lo.w + p2*de.w + p3*vv.w;
    float ss = o[0]*o[0] + o[1]*o[1] + o[2]*o[2] + o[3]*o[3];
#pragma unroll
    for (int st = 16; st > 0; st >>= 1) ss += __shfl_down_sync(0xffffffffu, ss, st);
    int warp = tid >> 5, lane = tid & 31;
    if (lane == 0) wsum[warp] = ss;
    __syncthreads();
    float tot = wsum[h*2] + wsum[h*2+1];
    float scale = rsqrtf(tot * (1.f/256.f) + 1e-5f);
    __half2 h0 = __floats2half2_rn(o[0]*scale*onorm[dd],   o[1]*scale*onorm[dd+1]);
    __half2 h1 = __floats2half2_rn(o[2]*scale*onorm[dd+2], o[3]*scale*onorm[dd+3]);
    uint2 pk = {*(unsigned*)&h0, *(unsigned*)&h1};
    *(uint2*)&g_mix_h[pb] = pk;
}

// ------------------------- launch ------------------------------------------
extern "C" void kernel_launch(void* const* d_in, const int* in_sizes, int n_in,
                              void* d_out, int out_size)
{
    const float* hs        = (const float*)d_in[0];
    const float* Wq        = (const float*)d_in[1];
    const float* Wk        = (const float*)d_in[2];
    const float* Wv        = (const float*)d_in[3];
    const float* Wb        = (const float*)d_in[4];
    const float* qconv_w   = (const float*)d_in[5];
    const float* kconv_w   = (const float*)d_in[6];
    const float* vconv_w   = (const float*)d_in[7];
    const float* fir_s     = (const float*)d_in[8];
    const float* fir_l     = (const float*)d_in[9];
    const float* gate_w1   = (const float*)d_in[10];
    const float* gate_b1   = (const float*)d_in[11];
    const float* gate_w2   = (const float*)d_in[12];
    const float* log_temp  = (const float*)d_in[13];
    const float* base_bias = (const float*)d_in[14];
    const float* floor_raw = (const float*)d_in[15];
    const float* onorm_w   = (const float*)d_in[16];
    const float* Wo        = (const float*)d_in[17];
    float* out = (float*)d_out;

    void *p_qlin, *p_klin, *p_vlin, *p_qc, *p_kc, *p_vc, *p_hmid, *p_short, *p_long;
    void *p_hsh, *p_wqh, *p_wkh, *p_wvh, *p_woh, *p_gw1h, *p_gateinh, *p_mixh;
    cudaGetSymbolAddress(&p_qlin, g_qlin);
    cudaGetSymbolAddress(&p_klin, g_klin);
    cudaGetSymbolAddress(&p_vlin, g_vlin);
    cudaGetSymbolAddress(&p_qc, g_qc);
    cudaGetSymbolAddress(&p_kc, g_kc);
    cudaGetSymbolAddress(&p_vc, g_vc);
    cudaGetSymbolAddress(&p_hmid, g_hmid);
    cudaGetSymbolAddress(&p_short, g_short);
    cudaGetSymbolAddress(&p_long, g_long);
    cudaGetSymbolAddress(&p_hsh, g_hs_h);
    cudaGetSymbolAddress(&p_wqh, g_wq_h);
    cudaGetSymbolAddress(&p_wkh, g_wk_h);
    cudaGetSymbolAddress(&p_wvh, g_wv_h);
    cudaGetSymbolAddress(&p_woh, g_wo_h);
    cudaGetSymbolAddress(&p_gw1h, g_gw1_h);
    cudaGetSymbolAddress(&p_gateinh, g_gatein_h);
    cudaGetSymbolAddress(&p_mixh, g_mix_h);

    cudaFuncSetAttribute(scan_kernel,
        cudaFuncAttributeMaxDynamicSharedMemorySize, SCAN_SMEM);
    cudaFuncSetAttribute(precompute_kernel,
        cudaFuncAttributeMaxDynamicSharedMemorySize, PSMEM);
    cudaFuncSetAttribute(hgemm,
        cudaFuncAttributeMaxDynamicSharedMemorySize, HGEMM_SMEM);

    dim3 blk(256);

    // 0. pre-convert hs + weights to fp16
    cvt_h6<<<dim3(NROW*DD/1024, 6), blk>>>(
        hs,      (__half*)p_hsh,  NROW*DD,
        Wq,      (__half*)p_wqh,  DD*DD,
        Wk,      (__half*)p_wkh,  DD*DD,
        Wv,      (__half*)p_wvh,  DD*DD,
        Wo,      (__half*)p_woh,  DD*DD,
        gate_w1, (__half*)p_gw1h, HID*GIN);

    // q/k/v projections — one batched fp16 tensor-core launch
    hgemm<<<dim3(DD/128, NROW/128, 3), blk, HGEMM_SMEM>>>(
        (const __half*)p_hsh,
        (const __half*)p_wqh, (const __half*)p_wkh, (const __half*)p_wvh,
        (float*)p_qlin, (float*)p_klin, (float*)p_vlin,
        nullptr, NROW, DD, DD, 0);

    // causal conv4 + SiLU (all three streams in one launch)
    conv4_silu3<<<dim3(NROW*DD/256, 3), blk>>>(
        (const float*)p_qlin, (const float*)p_klin, (const float*)p_vlin,
        qconv_w, kconv_w, vconv_w,
        (float*)p_qc, (float*)p_kc, (float*)p_vc);

    // beta
    beta_kernel<<<NROW, 128>>>(hs, Wb);

    // delta-rule
    precompute_kernel<<<BB*HH*NC, blk, PSMEM>>>();
    scan_kernel<<<BB*HH*NG, blk, SCAN_SMEM>>>();

    // FIR paths
    fir_kernel<3><<<dim3(BB*HH, LL/128, DV/32), blk>>>(fir_s, (float*)p_short);
    fir_kernel<63><<<dim3(BB*HH, LL/128, DV/32), blk>>>(fir_l, (float*)p_long);

    // gate
    stats_kernel<<<NROW, blk>>>(hs);
    hgemm<<<dim3(HID/128, NROW/128, 1), blk, HGEMM_SMEM>>>(
        (const __half*)p_gateinh,
        (const __half*)p_gw1h, nullptr, nullptr,
        (float*)p_hmid, nullptr, nullptr,
        gate_b1, NROW, HID, GIN, 1);
    gate2_kernel<<<NROW, blk>>>(gate_w2, log_temp, base_bias, floor_raw);

    // mix + RMS norm
    mix_kernel<<<NROW, blk>>>(onorm_w);

    // output projection
    hgemm<<<dim3(DD/128, NROW/128, 1), blk, HGEMM_SMEM>>>(
        (const __half*)p_mixh,
        (const __half*)p_woh, nullptr, nullptr,
        out, nullptr, nullptr,
        nullptr, NROW, DD, DD, 0);
}

// round 11
// speedup vs baseline: 2.7534x; 1.0519x over previous
#include <cuda_runtime.h>
#include <cuda_fp16.h>
#include <math.h>
#include <stdint.h>

#define BB 2
#define LL 2048
#define DD 1024
#define HH 4
#define DV 256
#define CKN 32
#define NC 64              // LL / CKN
#define NROW (BB*LL)       // 4096
#define GIN 1056
#define HID 2048
#define NG 8               // Dv groups of 32 in the scan

// ------------------------- scratch (device globals) -------------------------
__device__ float g_beta[NROW*HH];
__device__ float g_qn[NROW*DD];
__device__ float g_kn[NROW*DD];
__device__ float g_u[NROW*DD];
__device__ float g_w[NROW*DD];
__device__ float g_attn[BB*HH*NC*CKN*CKN];
__device__ float g_delta[NROW*DD];
__device__ float g_short[NROW*DD];
__device__ float g_long[NROW*DD];
__device__ float g_hmid[NROW*HID];
__device__ float g_probs[NROW*16];
// fp16 intermediates + GEMM operands
__device__ __half g_qlin_h[NROW*DD];
__device__ __half g_klin_h[NROW*DD];
__device__ __half g_vlin_h[NROW*DD];
__device__ __half g_qc_h[NROW*DD];
__device__ __half g_kc_h[NROW*DD];
__device__ __half g_vc_h[NROW*DD];
__device__ __half g_hs_h[NROW*DD];
__device__ __half g_wq_h[DD*DD];
__device__ __half g_wk_h[DD*DD];
__device__ __half g_wv_h[DD*DD];
__device__ __half g_wo_h[DD*DD];
__device__ __half g_gw1_h[HID*GIN];
__device__ __half g_gatein_h[NROW*GIN];
__device__ __half g_mix_h[NROW*DD];

// ------------------------- helpers ------------------------------------------
__device__ __forceinline__ unsigned f2tf(float x) {
    unsigned r;
    asm("cvt.rna.tf32.f32 %0, %1;" : "=r"(r) : "f"(x));
    return r;
}

__device__ __forceinline__ void mma_tf32(float* c, const unsigned* a, const unsigned* b) {
    asm volatile(
        "mma.sync.aligned.m16n8k8.row.col.f32.tf32.tf32.f32 "
        "{%0,%1,%2,%3}, {%4,%5,%6,%7}, {%8,%9}, {%0,%1,%2,%3};"
        : "+f"(c[0]), "+f"(c[1]), "+f"(c[2]), "+f"(c[3])
        : "r"(a[0]), "r"(a[1]), "r"(a[2]), "r"(a[3]), "r"(b[0]), "r"(b[1]));
}

__device__ __forceinline__ void mma_f16(float* c, const unsigned* a, const unsigned* b) {
    asm volatile(
        "mma.sync.aligned.m16n8k16.row.col.f32.f16.f16.f32 "
        "{%0,%1,%2,%3}, {%4,%5,%6,%7}, {%8,%9}, {%0,%1,%2,%3};"
        : "+f"(c[0]), "+f"(c[1]), "+f"(c[2]), "+f"(c[3])
        : "r"(a[0]), "r"(a[1]), "r"(a[2]), "r"(a[3]), "r"(b[0]), "r"(b[1]));
}

#define LDSM4(r, addr)                                                        \
    asm volatile("ldmatrix.sync.aligned.m8n8.x4.shared.b16 {%0,%1,%2,%3}, [%4];" \
        : "=r"((r)[0]), "=r"((r)[1]), "=r"((r)[2]), "=r"((r)[3]) : "r"(addr))

// ------------------------- bulk fp32 -> fp16 conversion ---------------------
__global__ __launch_bounds__(256) void cvt_h6(
    const float* __restrict__ s0, __half* __restrict__ d0, int n0,
    const float* __restrict__ s1, __half* __restrict__ d1, int n1,
    const float* __restrict__ s2, __half* __restrict__ d2, int n2,
    const float* __restrict__ s3, __half* __restrict__ d3, int n3,
    const float* __restrict__ s4, __half* __restrict__ d4, int n4,
    const float* __restrict__ s5, __half* __restrict__ d5, int n5)
{
    const float* s; __half* d; int n;
    switch (blockIdx.y) {
        case 0: s=s0; d=d0; n=n0; break;
        case 1: s=s1; d=d1; n=n1; break;
        case 2: s=s2; d=d2; n=n2; break;
        case 3: s=s3; d=d3; n=n3; break;
        case 4: s=s4; d=d4; n=n4; break;
        default: s=s5; d=d5; n=n5; break;
    }
    int i = (blockIdx.x * 256 + threadIdx.x) * 4;
    if (i < n) {
        float4 v = *(const float4*)(s + i);
        __half2 lo = __floats2half2_rn(v.x, v.y);
        __half2 hi = __floats2half2_rn(v.z, v.w);
        uint2 o = {*(unsigned*)&lo, *(unsigned*)&hi};
        *(uint2*)(d + i) = o;
    }
}

// ---------------- fp16 tensor GEMM: C = A(MxK) @ B(NxK)^T -------------------
// mode 0: fp32 out.  mode 1: +bias, exact GELU, fp32 out.  mode 2: fp16 out.
#define HSTRB 112
#define HSTRW 28
#define HSTAGE_BYTES (128*HSTRB)        // 14336
#define HGEMM_SMEM (6*HSTAGE_BYTES)     // 86016

#define HLOAD(kt, st) do {                                                     \
    const __half* Ap_ = A + (size_t)bm*K + (kt)*32;                            \
    const __half* Bp_ = B + (size_t)bn*K + (kt)*32;                            \
    _Pragma("unroll")                                                          \
    for (int i_ = 0; i_ < 2; i_++) {                                           \
        int e_ = tid + i_*256;                                                 \
        int row_ = e_ >> 2, seg_ = e_ & 3;                                     \
        unsigned doff_ = (unsigned)row_*HSTRB + (unsigned)seg_*16;             \
        asm volatile("cp.async.cg.shared.global [%0], [%1], 16;"               \
            :: "r"(smb + (unsigned)((st)*HSTAGE_BYTES) + doff_),               \
               "l"(Ap_ + (size_t)row_*K + seg_*8));                            \
        asm volatile("cp.async.cg.shared.global [%0], [%1], 16;"               \
            :: "r"(smb + (unsigned)(3*HSTAGE_BYTES + (st)*HSTAGE_BYTES) + doff_), \
               "l"(Bp_ + (size_t)row_*K + seg_*8));                            \
    }                                                                          \
} while (0)

__global__ __launch_bounds__(256, 2) void hgemm(
    const __half* __restrict__ A,
    const __half* __restrict__ Bm0, const __half* __restrict__ Bm1, const __half* __restrict__ Bm2,
    float* __restrict__ Cm0, float* __restrict__ Cm1, float* __restrict__ Cm2,
    const float* __restrict__ bias, int M, int N, int K, int mode)
{
    extern __shared__ char tsm[];

    const __half* B = (blockIdx.z == 0) ? Bm0 : (blockIdx.z == 1) ? Bm1 : Bm2;
    float*        C = (blockIdx.z == 0) ? Cm0 : (blockIdx.z == 1) ? Cm1 : Cm2;

    int tid = threadIdx.x;
    int bm = blockIdx.y * 128, bn = blockIdx.x * 128;
    unsigned smb;
    asm("{ .reg .u64 t; cvta.to.shared.u64 t, %1; cvt.u32.u64 %0, t; }"
        : "=r"(smb) : "l"(tsm));

    int wid = tid >> 5, lane = tid & 31;
    int wm = (wid >> 2) * 64, wn = (wid & 3) * 32;
    int lr = lane >> 2, lk = lane & 3;

    int a_row = (lane & 7) + ((lane >> 3) & 1) * 8;
    int a_kb  = (lane >> 4) * 16;
    int b_row = (lane & 7) + ((lane >> 4) & 1) * 8;
    int b_kb  = ((lane >> 3) & 1) * 16;

    float acc[4][4][4];
#pragma unroll
    for (int mi = 0; mi < 4; mi++)
#pragma unroll
        for (int ni = 0; ni < 4; ni++)
#pragma unroll
            for (int j = 0; j < 4; j++) acc[mi][ni][j] = 0.f;

    int niter = K >> 5;

    HLOAD(0, 0);
    asm volatile("cp.async.commit_group;");
    HLOAD(1, 1);
    asm volatile("cp.async.commit_group;");

    for (int t = 0; t < niter; t++) {
        asm volatile("cp.async.wait_group 1;");
        __syncthreads();
        if (t + 2 < niter) HLOAD(t + 2, (t + 2) % 3);
        asm volatile("cp.async.commit_group;");

        int cur = t % 3;
        unsigned a_base = smb + (unsigned)(cur*HSTAGE_BYTES);
        unsigned b_base = smb + (unsigned)(3*HSTAGE_BYTES + cur*HSTAGE_BYTES);
#pragma unroll
        for (int ks = 0; ks < 2; ks++) {
            unsigned af[4][4], bq[2][4];
#pragma unroll
            for (int mi = 0; mi < 4; mi++) {
                unsigned addr = a_base + (unsigned)((wm + mi*16 + a_row)*HSTRB + ks*32 + a_kb);
                LDSM4(af[mi], addr);
            }
#pragma unroll
            for (int nq = 0; nq < 2; nq++) {
                unsigned addr = b_base + (unsigned)((wn + nq*16 + b_row)*HSTRB + ks*32 + b_kb);
                LDSM4(bq[nq], addr);
            }
#pragma unroll
            for (int mi = 0; mi < 4; mi++)
#pragma unroll
                for (int ni = 0; ni < 4; ni++)
                    mma_f16(acc[mi][ni], af[mi], &bq[ni >> 1][(ni & 1) * 2]);
        }
    }

#pragma unroll
    for (int mi = 0; mi < 4; mi++) {
        int r0 = bm + wm + mi*16 + lr;
#pragma unroll
        for (int ni = 0; ni < 4; ni++) {
            int c = bn + wn + ni*8 + 2*lk;
            float v[4] = {acc[mi][ni][0], acc[mi][ni][1], acc[mi][ni][2], acc[mi][ni][3]};
            if (mode == 1) {
                float b0 = bias[c], b1 = bias[c+1];
                v[0] += b0; v[1] += b1; v[2] += b0; v[3] += b1;
#pragma unroll
                for (int j = 0; j < 4; j++)
                    v[j] = 0.5f * v[j] * (1.f + erff(v[j] * 0.70710678118654752f));
            }
            if (mode == 2) {
                __half* Ch = (__half*)C;
                *(__half2*)&Ch[(size_t)r0*N + c]     = __floats2half2_rn(v[0], v[1]);
                *(__half2*)&Ch[(size_t)(r0+8)*N + c] = __floats2half2_rn(v[2], v[3]);
            } else {
                float2 lo = {v[0], v[1]};
                float2 hi = {v[2], v[3]};
                *(float2*)&C[(size_t)r0*N + c]       = lo;
                *(float2*)&C[(size_t)(r0+8)*N + c]   = hi;
            }
        }
    }
}

// ------------- depthwise causal conv4 + SiLU, fp16 io, 2 elems/thread -------
__global__ __launch_bounds__(256) void conv4_silu3(
    const __half* __restrict__ x0, const __half* __restrict__ x1, const __half* __restrict__ x2,
    const float* __restrict__ w0, const float* __restrict__ w1, const float* __restrict__ w2,
    __half* __restrict__ y0, __half* __restrict__ y1, __half* __restrict__ y2)
{
    const __half* x; const float* w; __half* y;
    if (blockIdx.y == 0)      { x = x0; w = w0; y = y0; }
    else if (blockIdx.y == 1) { x = x1; w = w1; y = y1; }
    else                      { x = x2; w = w2; y = y2; }
    int p = blockIdx.x * 256 + threadIdx.x;     // pair index over NROW*DD/2
    int dp = p & (DD/2 - 1);
    int l = (p >> 9) & (LL - 1);
    int d = dp * 2;
    float4 wa = *(const float4*)(w + d*4);
    float4 wb = *(const float4*)(w + d*4 + 4);
    const __half2* xp = (const __half2*)x + p;
    float2 xv = __half22float2(xp[0]);
    float ax = wa.w * xv.x, ay = wb.w * xv.y;
    if (l >= 1) { float2 t = __half22float2(xp[-(DD/2)]);   ax += wa.z*t.x; ay += wb.z*t.y; }
    if (l >= 2) { float2 t = __half22float2(xp[-DD]);       ax += wa.y*t.x; ay += wb.y*t.y; }
    if (l >= 3) { float2 t = __half22float2(xp[-(3*DD/2)]); ax += wa.x*t.x; ay += wb.x*t.y; }
    ax = ax / (1.f + expf(-ax));
    ay = ay / (1.f + expf(-ay));
    ((__half2*)y)[p] = __floats2half2_rn(ax, ay);
}

// ------------------------- beta = sigmoid(hs @ Wb^T) ------------------------
__global__ __launch_bounds__(128) void beta_kernel(
    const float* __restrict__ hs, const float* __restrict__ Wb)
{
    __shared__ float red[4][128];
    int n = blockIdx.x, tid = threadIdx.x;
    const float* hr = hs + (size_t)n * DD;
    float s0=0,s1=0,s2=0,s3=0;
    for (int i = tid; i < DD; i += 128) {
        float x = hr[i];
        s0 += x * Wb[i];
        s1 += x * Wb[DD + i];
        s2 += x * Wb[2*DD + i];
        s3 += x * Wb[3*DD + i];
    }
    red[0][tid]=s0; red[1][tid]=s1; red[2][tid]=s2; red[3][tid]=s3;
    __syncthreads();
    for (int st = 64; st > 0; st >>= 1) {
        if (tid < st)
#pragma unroll
            for (int h = 0; h < 4; h++) red[h][tid] += red[h][tid + st];
        __syncthreads();
    }
    if (tid < 4) g_beta[(size_t)n*HH + tid] = 1.f / (1.f + expf(-red[tid][0]));
}

// ---------------- per-chunk delta-rule precompute (tensor-core mma) ---------
#define PSTR 264
#define PSMEM ((2*32*PSTR + 32*33 + 32*36 + 96) * 4)
__global__ __launch_bounds__(256) void precompute_kernel()
{
    extern __shared__ float psm[];
    float*    Kt  = psm;                     // [32][PSTR] k fp32 -> kn tf32
    float*    Qt  = Kt + 32*PSTR;            // [32][PSTR] q fp32 -> qn tf32 -> v tf32
    float*    Am  = Qt + 32*PSTR;            // [32][33]
    unsigned* Ttf = (unsigned*)(Am + 32*33); // [32][36]
    float*    bet = (float*)(Ttf + 32*36);   // [32]
    float*    rnk = bet + 32;                // [32]
    float*    rnq = rnk + 32;                // [32]

    int blk = blockIdx.x;           // (b*HH + h)*NC + c
    int c  = blk % NC;
    int bh = blk / NC;
    int h  = bh % HH;
    int b  = bh / HH;
    int tid = threadIdx.x;
    int l0 = c * 32;
    int wid = tid >> 5, lane = tid & 31;
    int lr = lane >> 2, lk = lane & 3;

    // 1. load k, q tiles (fp16 -> fp32)
    for (int e = tid*4; e < 32*256; e += 1024) {
        int r = e >> 8, d = e & 255;
        size_t gb = ((size_t)(b*LL + l0 + r))*DD + h*DV + d;
        uint2 kh = *(const uint2*)&g_kc_h[gb];
        float2 ka = __half22float2(*(__half2*)&kh.x);
        float2 kb2 = __half22float2(*(__half2*)&kh.y);
        *(float4*)&Kt[r*PSTR + d] = make_float4(ka.x, ka.y, kb2.x, kb2.y);
        uint2 qh = *(const uint2*)&g_qc_h[gb];
        float2 qa = __half22float2(*(__half2*)&qh.x);
        float2 qb2 = __half22float2(*(__half2*)&qh.y);
        *(float4*)&Qt[r*PSTR + d] = make_float4(qa.x, qa.y, qb2.x, qb2.y);
    }
    if (tid < 32) bet[tid] = g_beta[((size_t)(b*LL + l0 + tid))*HH + h];
    __syncthreads();

    // 2. row norms (8 threads per row)
    {
        int r = tid >> 3, part = tid & 7;
        float sk = 0.f, sq = 0.f;
        for (int j = part*32; j < part*32 + 32; j++) {
            float x = Kt[r*PSTR + j]; sk += x*x;
            float y = Qt[r*PSTR + j]; sq += y*y;
        }
        sk += __shfl_down_sync(0xffffffffu, sk, 4, 8);
        sk += __shfl_down_sync(0xffffffffu, sk, 2, 8);
        sk += __shfl_down_sync(0xffffffffu, sk, 1, 8);
        sq += __shfl_down_sync(0xffffffffu, sq, 4, 8);
        sq += __shfl_down_sync(0xffffffffu, sq, 2, 8);
        sq += __shfl_down_sync(0xffffffffu, sq, 1, 8);
        if (part == 0) { rnk[r] = rsqrtf(sk + 1e-6f); rnq[r] = rsqrtf(sq + 1e-6f); }
    }
    __syncthreads();

    // 3. normalize in place (fp32 -> global, tf32 -> smem)
    size_t obase = (size_t)blk * (32*256);
    for (int e = tid*4; e < 32*256; e += 1024) {
        int r = e >> 8, d = e & 255;
        float rk = rnk[r], rq = rnq[r];
        float4 kv = *(float4*)&Kt[r*PSTR + d];
        kv.x *= rk; kv.y *= rk; kv.z *= rk; kv.w *= rk;
        *(float4*)&g_kn[obase + e] = kv;
        unsigned* kd = (unsigned*)&Kt[r*PSTR + d];
        kd[0]=f2tf(kv.x); kd[1]=f2tf(kv.y); kd[2]=f2tf(kv.z); kd[3]=f2tf(kv.w);
        float4 qv = *(float4*)&Qt[r*PSTR + d];
        qv.x *= rq; qv.y *= rq; qv.z *= rq; qv.w *= rq;
        *(float4*)&g_qn[obase + e] = qv;
        unsigned* qd = (unsigned*)&Qt[r*PSTR + d];
        qd[0]=f2tf(qv.x); qd[1]=f2tf(qv.y); qd[2]=f2tf(qv.z); qd[3]=f2tf(qv.w);
    }
    __syncthreads();

    // 4. fused mma: Afull = kn@kn^T, attnF = qn@kn^T  (32x32, K=256)
    {
        int m0 = (wid >> 2) * 16, n0 = (wid & 3) * 8;
        const unsigned* Ku = (const unsigned*)Kt;
        const unsigned* Qu = (const unsigned*)Qt;
        float accA[4] = {0,0,0,0}, accQ[4] = {0,0,0,0};
#pragma unroll 4
        for (int kb = 0; kb < 256; kb += 8) {
            unsigned ak[4], aq[4], bf[2];
            ak[0] = Ku[(m0+lr)*PSTR + kb+lk];
            ak[1] = Ku[(m0+lr+8)*PSTR + kb+lk];
            ak[2] = Ku[(m0+lr)*PSTR + kb+lk+4];
            ak[3] = Ku[(m0+lr+8)*PSTR + kb+lk+4];
            aq[0] = Qu[(m0+lr)*PSTR + kb+lk];
            aq[1] = Qu[(m0+lr+8)*PSTR + kb+lk];
            aq[2] = Qu[(m0+lr)*PSTR + kb+lk+4];
            aq[3] = Qu[(m0+lr+8)*PSTR + kb+lk+4];
            bf[0] = Ku[(n0+lr)*PSTR + kb+lk];
            bf[1] = Ku[(n0+lr)*PSTR + kb+lk+4];
            mma_tf32(accA, ak, bf);
            mma_tf32(accQ, aq, bf);
        }
        size_t abase = (size_t)blk * 1024;
        int r0 = m0 + lr, r1 = r0 + 8, c0 = n0 + 2*lk, c1 = c0 + 1;
        g_attn[abase + r0*32 + c0] = (c0 <= r0) ? accQ[0] : 0.f;
        g_attn[abase + r0*32 + c1] = (c1 <= r0) ? accQ[1] : 0.f;
        g_attn[abase + r1*32 + c0] = (c0 <= r1) ? accQ[2] : 0.f;
        g_attn[abase + r1*32 + c1] = (c1 <= r1) ? accQ[3] : 0.f;
        Am[r0*33 + c0] = (c0 < r0) ? -bet[r0]*accA[0] : 0.f;
        Am[r0*33 + c1] = (c1 < r0) ? -bet[r0]*accA[1] : 0.f;
        Am[r1*33 + c0] = (c0 < r1) ? -bet[r1]*accA[2] : 0.f;
        Am[r1*33 + c1] = (c1 < r1) ? -bet[r1]*accA[3] : 0.f;
    }
    __syncthreads();

    // 5. iterative inversion (warp 0), then T' = (A+I)*diag(beta) as tf32
    if (tid < 32) {
        int ln = tid;
        for (int i = 1; i < 32; i++) {
            float t = 0.f;
            if (ln < i) for (int p = 0; p < i; p++) t += Am[i*33 + p] * Am[p*33 + ln];
            __syncwarp();
            if (ln < i) Am[i*33 + ln] += t;
            __syncwarp();
        }
    }
    __syncthreads();
    for (int e = tid; e < 1024; e += 256) {
        int i = e >> 5, j = e & 31;
        float t = Am[i*33 + j] + (i == j ? 1.f : 0.f);
        Ttf[i*36 + j] = f2tf(t * bet[j]);
    }
    // 6. load raw v tile (fp16) as tf32 into Qt (reuse)
    __syncthreads();
    for (int e = tid*4; e < 32*256; e += 1024) {
        int r = e >> 8, d = e & 255;
        uint2 vh = *(const uint2*)&g_vc_h[((size_t)(b*LL + l0 + r))*DD + h*DV + d];
        float2 va = __half22float2(*(__half2*)&vh.x);
        float2 vb2 = __half22float2(*(__half2*)&vh.y);
        unsigned* qd = (unsigned*)&Qt[r*PSTR + d];
        qd[0]=f2tf(va.x); qd[1]=f2tf(va.y); qd[2]=f2tf(vb2.x); qd[3]=f2tf(vb2.y);
    }
    __syncthreads();

    // 7. u = T'@v, w = T'@kn   (32x256, K=32)
    {
        int m0 = (wid & 1) * 16;
        int nb = (wid >> 1) * 64;
        const unsigned* Ku = (const unsigned*)Kt;
        const unsigned* Vu = (const unsigned*)Qt;
        unsigned a[4][4];
#pragma unroll
        for (int kk = 0; kk < 4; kk++) {
            int kb = kk*8;
            a[kk][0] = Ttf[(m0+lr)*36 + kb+lk];
            a[kk][1] = Ttf[(m0+lr+8)*36 + kb+lk];
            a[kk][2] = Ttf[(m0+lr)*36 + kb+lk+4];
            a[kk][3] = Ttf[(m0+lr+8)*36 + kb+lk+4];
        }
#pragma unroll
        for (int nt = 0; nt < 8; nt++) {
            int n0 = nb + nt*8;
            float au[4] = {0,0,0,0}, aw[4] = {0,0,0,0};
#pragma unroll
            for (int kk = 0; kk < 4; kk++) {
                int kb = kk*8;
                unsigned bu[2], bw[2];
                bu[0] = Vu[(kb+lk)*PSTR + n0+lr];
                bu[1] = Vu[(kb+lk+4)*PSTR + n0+lr];
                bw[0] = Ku[(kb+lk)*PSTR + n0+lr];
                bw[1] = Ku[(kb+lk+4)*PSTR + n0+lr];
                mma_tf32(au, a[kk], bu);
                mma_tf32(aw, a[kk], bw);
            }
            int r0 = m0 + lr, r1 = r0 + 8, cc = n0 + 2*lk;
            float2 u01 = {au[0], au[1]}, u23 = {au[2], au[3]};
            float2 w01 = {aw[0], aw[1]}, w23 = {aw[2], aw[3]};
            *(float2*)&g_u[obase + r0*256 + cc] = u01;
            *(float2*)&g_u[obase + r1*256 + cc] = u23;
            *(float2*)&g_w[obase + r0*256 + cc] = w01;
            *(float2*)&g_w[obase + r1*256 + cc] = w23;
        }
    }
}

// --------------- sequential inter-chunk scan (tensor-core mma) --------------
#define SSTR 40
#define TSTR 264
#define SCAN_SMEM ((256*SSTR*2 + 32*TSTR + 3*32*SSTR) * 4)
__global__ __launch_bounds__(256) void scan_kernel()
{
    extern __shared__ float sm[];
    float*    Sf  = sm;                           // [256][SSTR] fp32 master
    unsigned* Stf = (unsigned*)(sm + 256*SSTR);   // [256][SSTR] tf32 shadow
    unsigned* Ttf = Stf + 256*SSTR;               // [32][TSTR]  w/q/k tile tf32
    float*    Ui  = (float*)(Ttf + 32*TSTR);      // [32][SSTR]  u then u_i fp32
    unsigned* Utf = (unsigned*)(Ui + 32*SSTR);    // [32][SSTR]  u_i tf32
    unsigned* Atf = Utf + 32*SSTR;                // [32][SSTR]  attn tf32

    int blk = blockIdx.x;
    int g  = blk & (NG-1);
    int bh = blk >> 3;
    int b  = bh >> 2;
    int h  = bh & 3;
    int tid = threadIdx.x;
    int wid = tid >> 5, lane = tid & 31;
    int lr = lane >> 2, lk = lane & 3;
    int m0 = (wid >> 2) * 16;
    int n0 = (wid & 3) * 8;

    for (int e = tid; e < 256*SSTR; e += 256) { Sf[e] = 0.f; Stf[e] = 0u; }
    __syncthreads();

    for (int c = 0; c < NC; c++) {
        size_t base = ((size_t)bh*NC + c) * (32*256);
        size_t abase = ((size_t)bh*NC + c) * 1024;

        for (int e = tid; e < 1024; e += 256) {
            int r = e >> 5, j = e & 31;
            Ui[r*SSTR + j]  = g_u[base + r*256 + g*32 + j];
            Atf[r*SSTR + j] = f2tf(g_attn[abase + e]);
        }
        for (int e = tid*4; e < 8192; e += 1024) {
            float4 v = *(const float4*)&g_w[base + e];
            unsigned* dst = &Ttf[(e >> 8)*TSTR + (e & 255)];
            dst[0]=f2tf(v.x); dst[1]=f2tf(v.y); dst[2]=f2tf(v.z); dst[3]=f2tf(v.w);
        }
        __syncthreads();

        // (1) u_i = u - w@S
        {
            float acc[4] = {0.f, 0.f, 0.f, 0.f};
#pragma unroll 4
            for (int kb = 0; kb < 256; kb += 8) {
                unsigned a[4], bf[2];
                a[0] = Ttf[(m0+lr)*TSTR + kb+lk];
                a[1] = Ttf[(m0+lr+8)*TSTR + kb+lk];
                a[2] = Ttf[(m0+lr)*TSTR + kb+lk+4];
                a[3] = Ttf[(m0+lr+8)*TSTR + kb+lk+4];
                bf[0] = Stf[(kb+lk)*SSTR + n0+lr];
                bf[1] = Stf[(kb+lk+4)*SSTR + n0+lr];
                mma_tf32(acc, a, bf);
            }
            int r0 = m0 + lr, r1 = r0 + 8, cb = n0 + 2*lk;
            float u0 = Ui[r0*SSTR+cb]   - acc[0];
            float u1 = Ui[r0*SSTR+cb+1] - acc[1];
            float u2 = Ui[r1*SSTR+cb]   - acc[2];
            float u3 = Ui[r1*SSTR+cb+1] - acc[3];
            Ui[r0*SSTR+cb] = u0; Ui[r0*SSTR+cb+1] = u1;
            Ui[r1*SSTR+cb] = u2; Ui[r1*SSTR+cb+1] = u3;
            Utf[r0*SSTR+cb] = f2tf(u0); Utf[r0*SSTR+cb+1] = f2tf(u1);
            Utf[r1*SSTR+cb] = f2tf(u2); Utf[r1*SSTR+cb+1] = f2tf(u3);
        }
        __syncthreads();

        for (int e = tid*4; e < 8192; e += 1024) {
            float4 v = *(const float4*)&g_qn[base + e];
            unsigned* dst = &Ttf[(e >> 8)*TSTR + (e & 255)];
            dst[0]=f2tf(v.x); dst[1]=f2tf(v.y); dst[2]=f2tf(v.z); dst[3]=f2tf(v.w);
        }
        __syncthreads();

        // (2) o = q@S + attn@u_i  -> g_delta
        {
            float acc[4] = {0.f, 0.f, 0.f, 0.f};
#pragma unroll 4
            for (int kb = 0; kb < 256; kb += 8) {
                unsigned a[4], bf[2];
                a[0] = Ttf[(m0+lr)*TSTR + kb+lk];
                a[1] = Ttf[(m0+lr+8)*TSTR + kb+lk];
                a[2] = Ttf[(m0+lr)*TSTR + kb+lk+4];
                a[3] = Ttf[(m0+lr+8)*TSTR + kb+lk+4];
                bf[0] = Stf[(kb+lk)*SSTR + n0+lr];
                bf[1] = Stf[(kb+lk+4)*SSTR + n0+lr];
                mma_tf32(acc, a, bf);
            }
#pragma unroll
            for (int kb = 0; kb < 32; kb += 8) {
                unsigned a[4], bf[2];
                a[0] = Atf[(m0+lr)*SSTR + kb+lk];
                a[1] = Atf[(m0+lr+8)*SSTR + kb+lk];
                a[2] = Atf[(m0+lr)*SSTR + kb+lk+4];
                a[3] = Atf[(m0+lr+8)*SSTR + kb+lk+4];
                bf[0] = Utf[(kb+lk)*SSTR + n0+lr];
                bf[1] = Utf[(kb+lk+4)*SSTR + n0+lr];
                mma_tf32(acc, a, bf);
            }
            size_t ob = ((size_t)(b*LL + c*32 + m0 + lr))*DD + h*DV + g*32 + n0 + 2*lk;
            float2 lo = {acc[0], acc[1]};
            float2 hi = {acc[2], acc[3]};
            *(float2*)&g_delta[ob]        = lo;
            *(float2*)&g_delta[ob + 8*DD] = hi;
        }
        __syncthreads();

        for (int e = tid*4; e < 8192; e += 1024) {
            float4 v = *(const float4*)&g_kn[base + e];
            unsigned* dst = &Ttf[(e >> 8)*TSTR + (e & 255)];
            dst[0]=f2tf(v.x); dst[1]=f2tf(v.y); dst[2]=f2tf(v.z); dst[3]=f2tf(v.w);
        }
        __syncthreads();

        // (3) S += k^T @ u_i
#pragma unroll
        for (int t = 0; t < 2; t++) {
            int tm = (wid*2 + t) * 16;
#pragma unroll
            for (int tn = 0; tn < 4; tn++) {
                int nn = tn*8;
                int r0 = tm + lr, r1 = r0 + 8, cb = nn + 2*lk;
                float acc[4];
                acc[0] = Sf[r0*SSTR+cb]; acc[1] = Sf[r0*SSTR+cb+1];
                acc[2] = Sf[r1*SSTR+cb]; acc[3] = Sf[r1*SSTR+cb+1];
#pragma unroll
                for (int kb = 0; kb < 32; kb += 8) {
                    unsigned a[4], bf[2];
                    a[0] = Ttf[(kb+lk)*TSTR + tm+lr];
                    a[1] = Ttf[(kb+lk)*TSTR + tm+lr+8];
                    a[2] = Ttf[(kb+lk+4)*TSTR + tm+lr];
                    a[3] = Ttf[(kb+lk+4)*TSTR + tm+lr+8];
                    bf[0] = Utf[(kb+lk)*SSTR + nn+lr];
                    bf[1] = Utf[(kb+lk+4)*SSTR + nn+lr];
                    mma_tf32(acc, a, bf);
                }
                Sf[r0*SSTR+cb] = acc[0]; Sf[r0*SSTR+cb+1] = acc[1];
                Sf[r1*SSTR+cb] = acc[2]; Sf[r1*SSTR+cb+1] = acc[3];
                Stf[r0*SSTR+cb] = f2tf(acc[0]); Stf[r0*SSTR+cb+1] = f2tf(acc[1]);
                Stf[r1*SSTR+cb] = f2tf(acc[2]); Stf[r1*SSTR+cb+1] = f2tf(acc[3]);
            }
        }
        __syncthreads();
    }
}

// ------------------- per-(head,channel) FIR conv (fp16 in, fp32 out) --------
template<int K>
__global__ __launch_bounds__(256) void fir_kernel(
    const float* __restrict__ fw, float* __restrict__ y)
{
    __shared__ float2 vbuf[(128 + K - 1) * 16];
    __shared__ float2 wbuf[16 * K];
    int bh = blockIdx.x;
    int b = bh / HH, h = bh % HH;
    int l0 = blockIdx.y * 128;
    int d0 = blockIdx.z * 32;
    int tid = threadIdx.x;

    for (int idx = tid; idx < 16*K; idx += 256) {
        int dp = idx / K, t = idx % K;
        float2 wv;
        wv.x = fw[(size_t)(h*DV + d0 + 2*dp)*K + t];
        wv.y = fw[(size_t)(h*DV + d0 + 2*dp + 1)*K + t];
        wbuf[dp*K + t] = wv;
    }
    for (int idx = tid; idx < (128 + K - 1)*16; idx += 256) {
        int lrr = idx >> 4, dp = idx & 15;
        int l = l0 - (K - 1) + lrr;
        vbuf[idx] = (l >= 0)
            ? __half22float2(*(const __half2*)&g_vc_h[((size_t)(b*LL + l))*DD + h*DV + d0 + 2*dp])
            : make_float2(0.f, 0.f);
    }
    __syncthreads();

    int dp = tid & 15;
    int lr0 = (tid >> 4) * 8;
    for (int m = 0; m < 8; m++) {
        int lrr = lr0 + m;
        float2 acc = {0.f, 0.f};
#pragma unroll
        for (int t = 0; t < K; t++) {
            float2 v = vbuf[(lrr + t)*16 + dp];
            float2 wv = wbuf[dp*K + t];
            acc.x = fmaf(v.x, wv.x, acc.x);
            acc.y = fmaf(v.y, wv.y, acc.y);
        }
        *(float2*)&y[((size_t)(b*LL + l0 + lrr))*DD + h*DV + d0 + 2*dp] = acc;
    }
}

// ------------- gate input assembly (hs + stats), stored as fp16 -------------
__global__ __launch_bounds__(256) void stats_kernel(const float* __restrict__ hs)
{
    int n = blockIdx.x, tid = threadIdx.x;
    {
        int i = tid * 4;
        float4 v = *(const float4*)&hs[(size_t)n*DD + i];
        __half2 lo = __floats2half2_rn(v.x, v.y);
        __half2 hi = __floats2half2_rn(v.z, v.w);
        uint2 o = {*(unsigned*)&lo, *(unsigned*)&hi};
        *(uint2*)&g_gatein_h[(size_t)n*GIN + i] = o;
    }
    int warp = tid >> 5, lane = tid & 31;
    for (int rep = 0; rep < 2; rep++) {
        int combo = warp*2 + rep;
        int path = combo >> 2, h = combo & 3;
        float s1 = 0.f, s2 = 0.f;
        if (path == 3) {
            const __half* ph = g_vc_h + (size_t)n*DD + h*DV;
            for (int j = lane; j < 256; j += 32) {
                float x = __half2float(ph[j]); s1 += x; s2 += x*x;
            }
        } else {
            const float* p = (path == 0) ? g_short : (path == 1) ? g_long : g_delta;
            p += (size_t)n*DD + h*DV;
            for (int j = lane; j < 256; j += 32) { float x = p[j]; s1 += x; s2 += x*x; }
        }
#pragma unroll
        for (int st = 16; st > 0; st >>= 1) {
            s1 += __shfl_down_sync(0xffffffffu, s1, st);
            s2 += __shfl_down_sync(0xffffffffu, s2, st);
        }
        if (lane == 0) {
            float m  = s1 * (1.f/256.f);
            float va = s2 * (1.f/256.f) - m*m;
            g_gatein_h[(size_t)n*GIN + DD + path*8 + h*2]     = __float2half_rn(m);
            g_gatein_h[(size_t)n*GIN + DD + path*8 + h*2 + 1] = __float2half_rn(va);
        }
    }
}

// ------------------------- gate2 + softmax + floor --------------------------
__global__ __launch_bounds__(256) void gate2_kernel(
    const float* __restrict__ w2, const float* __restrict__ log_temp,
    const float* __restrict__ base_bias, const float* __restrict__ floor_raw)
{
    __shared__ float hrow[HID];
    __shared__ float lg[16];
    int n = blockIdx.x, tid = threadIdx.x;
    for (int i = tid; i < HID; i += 256) hrow[i] = g_hmid[(size_t)n*HID + i];
    __syncthreads();
    int warp = tid >> 5, lane = tid & 31;
    for (int rep = 0; rep < 2; rep++) {
        int o = warp*2 + rep;
        const float* wr = w2 + (size_t)o*HID;
        float s = 0.f;
        for (int i = lane; i < HID; i += 32) s = fmaf(hrow[i], wr[i], s);
#pragma unroll
        for (int st = 16; st > 0; st >>= 1) s += __shfl_down_sync(0xffffffffu, s, st);
        if (lane == 0) lg[o] = s;
    }
    __syncthreads();
    if (tid < 4) {
        int h = tid;
        float temp = log1pf(expf(log_temp[h])) + 1e-4f;
        float z[4], m = -1e30f;
#pragma unroll
        for (int i = 0; i < 4; i++) {
            z[i] = (lg[h*4+i] + base_bias[h*4+i]) / temp;
            m = fmaxf(m, z[i]);
        }
        float e[4], s = 0.f;
#pragma unroll
        for (int i = 0; i < 4; i++) { e[i] = expf(z[i] - m); s += e[i]; }
        float p[4], s2 = 0.f;
#pragma unroll
        for (int i = 0; i < 4; i++) {
            p[i] = e[i] / s;
            float f = 0.05f / (1.f + expf(-floor_raw[h*4+i]));
            p[i] = fmaxf(p[i], f);
            s2 += p[i];
        }
#pragma unroll
        for (int i = 0; i < 4; i++) g_probs[(size_t)n*16 + h*4 + i] = p[i] / s2;
    }
}

// ------------- path mix + RMS norm, output stored as fp16 -------------------
__global__ __launch_bounds__(256) void mix_kernel(const float* __restrict__ onorm)
{
    __shared__ float pr[16];
    __shared__ float wsum[8];
    int n = blockIdx.x, tid = threadIdx.x;
    if (tid < 16) pr[tid] = g_probs[(size_t)n*16 + tid];
    __syncthreads();
    int h = tid >> 6;
    int dd = (tid & 63) * 4;
    size_t pb = (size_t)n*DD + h*DV + dd;
    float4 sh = *(const float4*)&g_short[pb];
    float4 lo = *(const float4*)&g_long[pb];
    float4 de = *(const float4*)&g_delta[pb];
    uint2 vraw = *(const uint2*)&g_vc_h[pb];
    float2 va = __half22float2(*(__half2*)&vraw.x);
    float2 vb = __half22float2(*(__half2*)&vraw.y);
    float p0 = pr[h*4+0], p1 = pr[h*4+1], p2 = pr[h*4+2], p3 = pr[h*4+3];
    float o[4];
    o[0] = p0*sh.x + p1*lo.x + p2*de.x + p3*va.x;
    o[1] = p0*sh.y + p1*lo.y + p2*de.y + p3*va.y;
    o[2] = p0*sh.z + p1*lo.z + p2*de.z + p3*vb.x;
    o[3] = p0*sh.w + p1*lo.w + p2*de.w + p3*vb.y;
    float ss = o[0]*o[0] + o[1]*o[1] + o[2]*o[2] + o[3]*o[3];
#pragma unroll
    for (int st = 16; st > 0; st >>= 1) ss += __shfl_down_sync(0xffffffffu, ss, st);
    int warp = tid >> 5, lane = tid & 31;
    if (lane == 0) wsum[warp] = ss;
    __syncthreads();
    float tot = wsum[h*2] + wsum[h*2+1];
    float scale = rsqrtf(tot * (1.f/256.f) + 1e-5f);
    __half2 h0 = __floats2half2_rn(o[0]*scale*onorm[dd],   o[1]*scale*onorm[dd+1]);
    __half2 h1 = __floats2half2_rn(o[2]*scale*onorm[dd+2], o[3]*scale*onorm[dd+3]);
    uint2 pk = {*(unsigned*)&h0, *(unsigned*)&h1};
    *(uint2*)&g_mix_h[pb] = pk;
}

// ------------------------- launch ------------------------------------------
extern "C" void kernel_launch(void* const* d_in, const int* in_sizes, int n_in,
                              void* d_out, int out_size)
{
    const float* hs        = (const float*)d_in[0];
    const float* Wq        = (const float*)d_in[1];
    const float* Wk        = (const float*)d_in[2];
    const float* Wv        = (const float*)d_in[3];
    const float* Wb        = (const float*)d_in[4];
    const float* qconv_w   = (const float*)d_in[5];
    const float* kconv_w   = (const float*)d_in[6];
    const float* vconv_w   = (const float*)d_in[7];
    const float* fir_s     = (const float*)d_in[8];
    const float* fir_l     = (const float*)d_in[9];
    const float* gate_w1   = (const float*)d_in[10];
    const float* gate_b1   = (const float*)d_in[11];
    const float* gate_w2   = (const float*)d_in[12];
    const float* log_temp  = (const float*)d_in[13];
    const float* base_bias = (const float*)d_in[14];
    const float* floor_raw = (const float*)d_in[15];
    const float* onorm_w   = (const float*)d_in[16];
    const float* Wo        = (const float*)d_in[17];
    float* out = (float*)d_out;

    void *p_qlin, *p_klin, *p_vlin, *p_qc, *p_kc, *p_vc, *p_hmid, *p_short, *p_long;
    void *p_hsh, *p_wqh, *p_wkh, *p_wvh, *p_woh, *p_gw1h, *p_gateinh, *p_mixh;
    cudaGetSymbolAddress(&p_qlin, g_qlin_h);
    cudaGetSymbolAddress(&p_klin, g_klin_h);
    cudaGetSymbolAddress(&p_vlin, g_vlin_h);
    cudaGetSymbolAddress(&p_qc, g_qc_h);
    cudaGetSymbolAddress(&p_kc, g_kc_h);
    cudaGetSymbolAddress(&p_vc, g_vc_h);
    cudaGetSymbolAddress(&p_hmid, g_hmid);
    cudaGetSymbolAddress(&p_short, g_short);
    cudaGetSymbolAddress(&p_long, g_long);
    cudaGetSymbolAddress(&p_hsh, g_hs_h);
    cudaGetSymbolAddress(&p_wqh, g_wq_h);
    cudaGetSymbolAddress(&p_wkh, g_wk_h);
    cudaGetSymbolAddress(&p_wvh, g_wv_h);
    cudaGetSymbolAddress(&p_woh, g_wo_h);
    cudaGetSymbolAddress(&p_gw1h, g_gw1_h);
    cudaGetSymbolAddress(&p_gateinh, g_gatein_h);
    cudaGetSymbolAddress(&p_mixh, g_mix_h);

    cudaFuncSetAttribute(scan_kernel,
        cudaFuncAttributeMaxDynamicSharedMemorySize, SCAN_SMEM);
    cudaFuncSetAttribute(precompute_kernel,
        cudaFuncAttributeMaxDynamicSharedMemorySize, PSMEM);
    cudaFuncSetAttribute(hgemm,
        cudaFuncAttributeMaxDynamicSharedMemorySize, HGEMM_SMEM);

    dim3 blk(256);

    // 0. pre-convert hs + weights to fp16
    cvt_h6<<<dim3(NROW*DD/1024, 6), blk>>>(
        hs,      (__half*)p_hsh,  NROW*DD,
        Wq,      (__half*)p_wqh,  DD*DD,
        Wk,      (__half*)p_wkh,  DD*DD,
        Wv,      (__half*)p_wvh,  DD*DD,
        Wo,      (__half*)p_woh,  DD*DD,
        gate_w1, (__half*)p_gw1h, HID*GIN);

    // q/k/v projections — fp16 outputs (mode 2)
    hgemm<<<dim3(DD/128, NROW/128, 3), blk, HGEMM_SMEM>>>(
        (const __half*)p_hsh,
        (const __half*)p_wqh, (const __half*)p_wkh, (const __half*)p_wvh,
        (float*)p_qlin, (float*)p_klin, (float*)p_vlin,
        nullptr, NROW, DD, DD, 2);

    // causal conv4 + SiLU (fp16 io, 2 elems/thread)
    conv4_silu3<<<dim3(NROW*DD/512, 3), blk>>>(
        (const __half*)p_qlin, (const __half*)p_klin, (const __half*)p_vlin,
        qconv_w, kconv_w, vconv_w,
        (__half*)p_qc, (__half*)p_kc, (__half*)p_vc);

    // beta
    beta_kernel<<<NROW, 128>>>(hs, Wb);

    // delta-rule
    precompute_kernel<<<BB*HH*NC, blk, PSMEM>>>();
    scan_kernel<<<BB*HH*NG, blk, SCAN_SMEM>>>();

    // FIR paths
    fir_kernel<3><<<dim3(BB*HH, LL/128, DV/32), blk>>>(fir_s, (float*)p_short);
    fir_kernel<63><<<dim3(BB*HH, LL/128, DV/32), blk>>>(fir_l, (float*)p_long);

    // gate
    stats_kernel<<<NROW, blk>>>(hs);
    hgemm<<<dim3(HID/128, NROW/128, 1), blk, HGEMM_SMEM>>>(
        (const __half*)p_gateinh,
        (const __half*)p_gw1h, nullptr, nullptr,
        (float*)p_hmid, nullptr, nullptr,
        gate_b1, NROW, HID, GIN, 1);
    gate2_kernel<<<NROW, blk>>>(gate_w2, log_temp, base_bias, floor_raw);

    // mix + RMS norm
    mix_kernel<<<NROW, blk>>>(onorm_w);

    // output projection (fp32 out)
    hgemm<<<dim3(DD/128, NROW/128, 1), blk, HGEMM_SMEM>>>(
        (const __half*)p_mixh,
        (const __half*)p_woh, nullptr, nullptr,
        out, nullptr, nullptr,
        nullptr, NROW, DD, DD, 0);
}

// round 12
// speedup vs baseline: 3.7255x; 1.3530x over previous
#include <cuda_runtime.h>
#include <cuda_fp16.h>
#include <math.h>
#include <stdint.h>

#define BB 2
#define LL 2048
#define DD 1024
#define HH 4
#define DV 256
#define CKN 32
#define NC 64              // LL / CKN
#define NROW (BB*LL)       // 4096
#define GIN 1056
#define HID 2048
#define NG 8               // Dv groups of 32 in the scan

// ------------------------- scratch (device globals) -------------------------
__device__ float g_beta[NROW*HH];
__device__ float g_delta[NROW*DD];
__device__ float g_short[NROW*DD];
__device__ float g_long[NROW*DD];
__device__ float g_hmid[NROW*HID];
__device__ float g_probs[NROW*16];
// fp16 intermediates + GEMM operands
__device__ __half g_qn_h[NROW*DD];       // [bh][c][time32][dv256]
__device__ __half g_knT_h[NROW*DD];      // [bh][c][dv256][time32]
__device__ __half g_u_h[NROW*DD];        // [bh][c][time32][dv256]
__device__ __half g_w_h[NROW*DD];        // [bh][c][time32][dv256]
__device__ __half g_attn_h[BB*HH*NC*CKN*CKN];
__device__ __half g_qlin_h[NROW*DD];
__device__ __half g_klin_h[NROW*DD];
__device__ __half g_vlin_h[NROW*DD];
__device__ __half g_qc_h[NROW*DD];
__device__ __half g_kc_h[NROW*DD];
__device__ __half g_vc_h[NROW*DD];
__device__ __half g_hs_h[NROW*DD];
__device__ __half g_wq_h[DD*DD];
__device__ __half g_wk_h[DD*DD];
__device__ __half g_wv_h[DD*DD];
__device__ __half g_wo_h[DD*DD];
__device__ __half g_gw1_h[HID*GIN];
__device__ __half g_gatein_h[NROW*GIN];
__device__ __half g_mix_h[NROW*DD];

// ------------------------- helpers ------------------------------------------
__device__ __forceinline__ unsigned f2tf(float x) {
    unsigned r;
    asm("cvt.rna.tf32.f32 %0, %1;" : "=r"(r) : "f"(x));
    return r;
}

__device__ __forceinline__ void mma_tf32(float* c, const unsigned* a, const unsigned* b) {
    asm volatile(
        "mma.sync.aligned.m16n8k8.row.col.f32.tf32.tf32.f32 "
        "{%0,%1,%2,%3}, {%4,%5,%6,%7}, {%8,%9}, {%0,%1,%2,%3};"
        : "+f"(c[0]), "+f"(c[1]), "+f"(c[2]), "+f"(c[3])
        : "r"(a[0]), "r"(a[1]), "r"(a[2]), "r"(a[3]), "r"(b[0]), "r"(b[1]));
}

__device__ __forceinline__ void mma_f16(float* c, const unsigned* a, const unsigned* b) {
    asm volatile(
        "mma.sync.aligned.m16n8k16.row.col.f32.f16.f16.f32 "
        "{%0,%1,%2,%3}, {%4,%5,%6,%7}, {%8,%9}, {%0,%1,%2,%3};"
        : "+f"(c[0]), "+f"(c[1]), "+f"(c[2]), "+f"(c[3])
        : "r"(a[0]), "r"(a[1]), "r"(a[2]), "r"(a[3]), "r"(b[0]), "r"(b[1]));
}

#define LDSM4(r, addr)                                                        \
    asm volatile("ldmatrix.sync.aligned.m8n8.x4.shared.b16 {%0,%1,%2,%3}, [%4];" \
        : "=r"((r)[0]), "=r"((r)[1]), "=r"((r)[2]), "=r"((r)[3]) : "r"(addr))

// ------------------------- bulk fp32 -> fp16 conversion ---------------------
__global__ __launch_bounds__(256) void cvt_h6(
    const float* __restrict__ s0, __half* __restrict__ d0, int n0,
    const float* __restrict__ s1, __half* __restrict__ d1, int n1,
    const float* __restrict__ s2, __half* __restrict__ d2, int n2,
    const float* __restrict__ s3, __half* __restrict__ d3, int n3,
    const float* __restrict__ s4, __half* __restrict__ d4, int n4,
    const float* __restrict__ s5, __half* __restrict__ d5, int n5)
{
    const float* s; __half* d; int n;
    switch (blockIdx.y) {
        case 0: s=s0; d=d0; n=n0; break;
        case 1: s=s1; d=d1; n=n1; break;
        case 2: s=s2; d=d2; n=n2; break;
        case 3: s=s3; d=d3; n=n3; break;
        case 4: s=s4; d=d4; n=n4; break;
        default: s=s5; d=d5; n=n5; break;
    }
    int i = (blockIdx.x * 256 + threadIdx.x) * 4;
    if (i < n) {
        float4 v = *(const float4*)(s + i);
        __half2 lo = __floats2half2_rn(v.x, v.y);
        __half2 hi = __floats2half2_rn(v.z, v.w);
        uint2 o = {*(unsigned*)&lo, *(unsigned*)&hi};
        *(uint2*)(d + i) = o;
    }
}

// ---------------- fp16 tensor GEMM: C = A(MxK) @ B(NxK)^T -------------------
// mode 0: fp32 out.  mode 1: +bias, exact GELU, fp32 out.  mode 2: fp16 out.
#define HSTRB 112
#define HSTRW 28
#define HSTAGE_BYTES (128*HSTRB)        // 14336
#define HGEMM_SMEM (6*HSTAGE_BYTES)     // 86016

#define HLOAD(kt, st) do {                                                     \
    const __half* Ap_ = A + (size_t)bm*K + (kt)*32;                            \
    const __half* Bp_ = B + (size_t)bn*K + (kt)*32;                            \
    _Pragma("unroll")                                                          \
    for (int i_ = 0; i_ < 2; i_++) {                                           \
        int e_ = tid + i_*256;                                                 \
        int row_ = e_ >> 2, seg_ = e_ & 3;                                     \
        unsigned doff_ = (unsigned)row_*HSTRB + (unsigned)seg_*16;             \
        asm volatile("cp.async.cg.shared.global [%0], [%1], 16;"               \
            :: "r"(smb + (unsigned)((st)*HSTAGE_BYTES) + doff_),               \
               "l"(Ap_ + (size_t)row_*K + seg_*8));                            \
        asm volatile("cp.async.cg.shared.global [%0], [%1], 16;"               \
            :: "r"(smb + (unsigned)(3*HSTAGE_BYTES + (st)*HSTAGE_BYTES) + doff_), \
               "l"(Bp_ + (size_t)row_*K + seg_*8));                            \
    }                                                                          \
} while (0)

__global__ __launch_bounds__(256, 2) void hgemm(
    const __half* __restrict__ A,
    const __half* __restrict__ Bm0, const __half* __restrict__ Bm1, const __half* __restrict__ Bm2,
    float* __restrict__ Cm0, float* __restrict__ Cm1, float* __restrict__ Cm2,
    const float* __restrict__ bias, int M, int N, int K, int mode)
{
    extern __shared__ char tsm[];

    const __half* B = (blockIdx.z == 0) ? Bm0 : (blockIdx.z == 1) ? Bm1 : Bm2;
    float*        C = (blockIdx.z == 0) ? Cm0 : (blockIdx.z == 1) ? Cm1 : Cm2;

    int tid = threadIdx.x;
    int bm = blockIdx.y * 128, bn = blockIdx.x * 128;
    unsigned smb;
    asm("{ .reg .u64 t; cvta.to.shared.u64 t, %1; cvt.u32.u64 %0, t; }"
        : "=r"(smb) : "l"(tsm));

    int wid = tid >> 5, lane = tid & 31;
    int wm = (wid >> 2) * 64, wn = (wid & 3) * 32;
    int lr = lane >> 2, lk = lane & 3;

    int a_row = (lane & 7) + ((lane >> 3) & 1) * 8;
    int a_kb  = (lane >> 4) * 16;
    int b_row = (lane & 7) + ((lane >> 4) & 1) * 8;
    int b_kb  = ((lane >> 3) & 1) * 16;

    float acc[4][4][4];
#pragma unroll
    for (int mi = 0; mi < 4; mi++)
#pragma unroll
        for (int ni = 0; ni < 4; ni++)
#pragma unroll
            for (int j = 0; j < 4; j++) acc[mi][ni][j] = 0.f;

    int niter = K >> 5;

    HLOAD(0, 0);
    asm volatile("cp.async.commit_group;");
    HLOAD(1, 1);
    asm volatile("cp.async.commit_group;");

    for (int t = 0; t < niter; t++) {
        asm volatile("cp.async.wait_group 1;");
        __syncthreads();
        if (t + 2 < niter) HLOAD(t + 2, (t + 2) % 3);
        asm volatile("cp.async.commit_group;");

        int cur = t % 3;
        unsigned a_base = smb + (unsigned)(cur*HSTAGE_BYTES);
        unsigned b_base = smb + (unsigned)(3*HSTAGE_BYTES + cur*HSTAGE_BYTES);
#pragma unroll
        for (int ks = 0; ks < 2; ks++) {
            unsigned af[4][4], bq[2][4];
#pragma unroll
            for (int mi = 0; mi < 4; mi++) {
                unsigned addr = a_base + (unsigned)((wm + mi*16 + a_row)*HSTRB + ks*32 + a_kb);
                LDSM4(af[mi], addr);
            }
#pragma unroll
            for (int nq = 0; nq < 2; nq++) {
                unsigned addr = b_base + (unsigned)((wn + nq*16 + b_row)*HSTRB + ks*32 + b_kb);
                LDSM4(bq[nq], addr);
            }
#pragma unroll
            for (int mi = 0; mi < 4; mi++)
#pragma unroll
                for (int ni = 0; ni < 4; ni++)
                    mma_f16(acc[mi][ni], af[mi], &bq[ni >> 1][(ni & 1) * 2]);
        }
    }

#pragma unroll
    for (int mi = 0; mi < 4; mi++) {
        int r0 = bm + wm + mi*16 + lr;
#pragma unroll
        for (int ni = 0; ni < 4; ni++) {
            int c = bn + wn + ni*8 + 2*lk;
            float v[4] = {acc[mi][ni][0], acc[mi][ni][1], acc[mi][ni][2], acc[mi][ni][3]};
            if (mode == 1) {
                float b0 = bias[c], b1 = bias[c+1];
                v[0] += b0; v[1] += b1; v[2] += b0; v[3] += b1;
#pragma unroll
                for (int j = 0; j < 4; j++)
                    v[j] = 0.5f * v[j] * (1.f + erff(v[j] * 0.70710678118654752f));
            }
            if (mode == 2) {
                __half* Ch = (__half*)C;
                *(__half2*)&Ch[(size_t)r0*N + c]     = __floats2half2_rn(v[0], v[1]);
                *(__half2*)&Ch[(size_t)(r0+8)*N + c] = __floats2half2_rn(v[2], v[3]);
            } else {
                float2 lo = {v[0], v[1]};
                float2 hi = {v[2], v[3]};
                *(float2*)&C[(size_t)r0*N + c]       = lo;
                *(float2*)&C[(size_t)(r0+8)*N + c]   = hi;
            }
        }
    }
}

// ------------- depthwise causal conv4 + SiLU, fp16 io, 2 elems/thread -------
__global__ __launch_bounds__(256) void conv4_silu3(
    const __half* __restrict__ x0, const __half* __restrict__ x1, const __half* __restrict__ x2,
    const float* __restrict__ w0, const float* __restrict__ w1, const float* __restrict__ w2,
    __half* __restrict__ y0, __half* __restrict__ y1, __half* __restrict__ y2)
{
    const __half* x; const float* w; __half* y;
    if (blockIdx.y == 0)      { x = x0; w = w0; y = y0; }
    else if (blockIdx.y == 1) { x = x1; w = w1; y = y1; }
    else                      { x = x2; w = w2; y = y2; }
    int p = blockIdx.x * 256 + threadIdx.x;     // pair index over NROW*DD/2
    int dp = p & (DD/2 - 1);
    int l = (p >> 9) & (LL - 1);
    int d = dp * 2;
    float4 wa = *(const float4*)(w + d*4);
    float4 wb = *(const float4*)(w + d*4 + 4);
    const __half2* xp = (const __half2*)x + p;
    float2 xv = __half22float2(xp[0]);
    float ax = wa.w * xv.x, ay = wb.w * xv.y;
    if (l >= 1) { float2 t = __half22float2(xp[-(DD/2)]);   ax += wa.z*t.x; ay += wb.z*t.y; }
    if (l >= 2) { float2 t = __half22float2(xp[-DD]);       ax += wa.y*t.x; ay += wb.y*t.y; }
    if (l >= 3) { float2 t = __half22float2(xp[-(3*DD/2)]); ax += wa.x*t.x; ay += wb.x*t.y; }
    ax = ax / (1.f + expf(-ax));
    ay = ay / (1.f + expf(-ay));
    ((__half2*)y)[p] = __floats2half2_rn(ax, ay);
}

// ------------------------- beta = sigmoid(hs @ Wb^T) ------------------------
__global__ __launch_bounds__(128) void beta_kernel(
    const float* __restrict__ hs, const float* __restrict__ Wb)
{
    __shared__ float red[4][128];
    int n = blockIdx.x, tid = threadIdx.x;
    const float* hr = hs + (size_t)n * DD;
    float s0=0,s1=0,s2=0,s3=0;
    for (int i = tid; i < DD; i += 128) {
        float x = hr[i];
        s0 += x * Wb[i];
        s1 += x * Wb[DD + i];
        s2 += x * Wb[2*DD + i];
        s3 += x * Wb[3*DD + i];
    }
    red[0][tid]=s0; red[1][tid]=s1; red[2][tid]=s2; red[3][tid]=s3;
    __syncthreads();
    for (int st = 64; st > 0; st >>= 1) {
        if (tid < st)
#pragma unroll
            for (int h = 0; h < 4; h++) red[h][tid] += red[h][tid + st];
        __syncthreads();
    }
    if (tid < 4) g_beta[(size_t)n*HH + tid] = 1.f / (1.f + expf(-red[tid][0]));
}

// ---------------- per-chunk delta-rule precompute (tensor-core mma) ---------
// Outputs fp16: qn [t][d], w/u [t][d], knT [d][t], attn [t][t].
#define PSTR 264
#define PSMEM ((2*32*PSTR + 32*33 + 32*36 + 96) * 4)
__global__ __launch_bounds__(256) void precompute_kernel()
{
    extern __shared__ float psm[];
    float*    Kt  = psm;                     // [32][PSTR] k fp32 -> kn tf32
    float*    Qt  = Kt + 32*PSTR;            // [32][PSTR] q fp32 -> qn tf32 -> v tf32
    float*    Am  = Qt + 32*PSTR;            // [32][33]
    unsigned* Ttf = (unsigned*)(Am + 32*33); // [32][36]
    float*    bet = (float*)(Ttf + 32*36);   // [32]
    float*    rnk = bet + 32;                // [32]
    float*    rnq = rnk + 32;                // [32]

    int blk = blockIdx.x;           // (b*HH + h)*NC + c
    int c  = blk % NC;
    int bh = blk / NC;
    int h  = bh % HH;
    int b  = bh / HH;
    int tid = threadIdx.x;
    int l0 = c * 32;
    int wid = tid >> 5, lane = tid & 31;
    int lr = lane >> 2, lk = lane & 3;

    // 1. load k, q tiles (fp16 -> fp32)
    for (int e = tid*4; e < 32*256; e += 1024) {
        int r = e >> 8, d = e & 255;
        size_t gb = ((size_t)(b*LL + l0 + r))*DD + h*DV + d;
        uint2 kh = *(const uint2*)&g_kc_h[gb];
        float2 ka = __half22float2(*(__half2*)&kh.x);
        float2 kb2 = __half22float2(*(__half2*)&kh.y);
        *(float4*)&Kt[r*PSTR + d] = make_float4(ka.x, ka.y, kb2.x, kb2.y);
        uint2 qh = *(const uint2*)&g_qc_h[gb];
        float2 qa = __half22float2(*(__half2*)&qh.x);
        float2 qb2 = __half22float2(*(__half2*)&qh.y);
        *(float4*)&Qt[r*PSTR + d] = make_float4(qa.x, qa.y, qb2.x, qb2.y);
    }
    if (tid < 32) bet[tid] = g_beta[((size_t)(b*LL + l0 + tid))*HH + h];
    __syncthreads();

    // 2. row norms (8 threads per row)
    {
        int r = tid >> 3, part = tid & 7;
        float sk = 0.f, sq = 0.f;
        for (int j = part*32; j < part*32 + 32; j++) {
            float x = Kt[r*PSTR + j]; sk += x*x;
            float y = Qt[r*PSTR + j]; sq += y*y;
        }
        sk += __shfl_down_sync(0xffffffffu, sk, 4, 8);
        sk += __shfl_down_sync(0xffffffffu, sk, 2, 8);
        sk += __shfl_down_sync(0xffffffffu, sk, 1, 8);
        sq += __shfl_down_sync(0xffffffffu, sq, 4, 8);
        sq += __shfl_down_sync(0xffffffffu, sq, 2, 8);
        sq += __shfl_down_sync(0xffffffffu, sq, 1, 8);
        if (part == 0) { rnk[r] = rsqrtf(sk + 1e-6f); rnq[r] = rsqrtf(sq + 1e-6f); }
    }
    __syncthreads();

    // 3. normalize in place (qn fp16 -> global, tf32 -> smem)
    size_t obase = (size_t)blk * (32*256);
    for (int e = tid*4; e < 32*256; e += 1024) {
        int r = e >> 8, d = e & 255;
        float rk = rnk[r], rq = rnq[r];
        float4 kv = *(float4*)&Kt[r*PSTR + d];
        kv.x *= rk; kv.y *= rk; kv.z *= rk; kv.w *= rk;
        unsigned* kd = (unsigned*)&Kt[r*PSTR + d];
        kd[0]=f2tf(kv.x); kd[1]=f2tf(kv.y); kd[2]=f2tf(kv.z); kd[3]=f2tf(kv.w);
        float4 qv = *(float4*)&Qt[r*PSTR + d];
        qv.x *= rq; qv.y *= rq; qv.z *= rq; qv.w *= rq;
        __half2 qh0 = __floats2half2_rn(qv.x, qv.y);
        __half2 qh1 = __floats2half2_rn(qv.z, qv.w);
        uint2 qo = {*(unsigned*)&qh0, *(unsigned*)&qh1};
        *(uint2*)&g_qn_h[obase + e] = qo;
        unsigned* qd = (unsigned*)&Qt[r*PSTR + d];
        qd[0]=f2tf(qv.x); qd[1]=f2tf(qv.y); qd[2]=f2tf(qv.z); qd[3]=f2tf(qv.w);
    }
    __syncthreads();

    // 3b. write kn transposed [dv][time] as fp16 (Kt holds tf32-bit floats)
    for (int e = tid*2; e < 32*256; e += 512) {
        int r = e & 31, d = e >> 5;          // r even
        float v0 = Kt[r*PSTR + d];
        float v1 = Kt[(r+1)*PSTR + d];
        *(__half2*)&g_knT_h[obase + e] = __floats2half2_rn(v0, v1);
    }

    // 4. fused mma: Afull = kn@kn^T, attnF = qn@kn^T  (32x32, K=256)
    {
        int m0 = (wid >> 2) * 16, n0 = (wid & 3) * 8;
        const unsigned* Ku = (const unsigned*)Kt;
        const unsigned* Qu = (const unsigned*)Qt;
        float accA[4] = {0,0,0,0}, accQ[4] = {0,0,0,0};
#pragma unroll 4
        for (int kb = 0; kb < 256; kb += 8) {
            unsigned ak[4], aq[4], bf[2];
            ak[0] = Ku[(m0+lr)*PSTR + kb+lk];
            ak[1] = Ku[(m0+lr+8)*PSTR + kb+lk];
            ak[2] = Ku[(m0+lr)*PSTR + kb+lk+4];
            ak[3] = Ku[(m0+lr+8)*PSTR + kb+lk+4];
            aq[0] = Qu[(m0+lr)*PSTR + kb+lk];
            aq[1] = Qu[(m0+lr+8)*PSTR + kb+lk];
            aq[2] = Qu[(m0+lr)*PSTR + kb+lk+4];
            aq[3] = Qu[(m0+lr+8)*PSTR + kb+lk+4];
            bf[0] = Ku[(n0+lr)*PSTR + kb+lk];
            bf[1] = Ku[(n0+lr)*PSTR + kb+lk+4];
            mma_tf32(accA, ak, bf);
            mma_tf32(accQ, aq, bf);
        }
        size_t abase = (size_t)blk * 1024;
        int r0 = m0 + lr, r1 = r0 + 8, c0 = n0 + 2*lk, c1 = c0 + 1;
        float q00 = (c0 <= r0) ? accQ[0] : 0.f;
        float q01 = (c1 <= r0) ? accQ[1] : 0.f;
        float q10 = (c0 <= r1) ? accQ[2] : 0.f;
        float q11 = (c1 <= r1) ? accQ[3] : 0.f;
        *(__half2*)&g_attn_h[abase + r0*32 + c0] = __floats2half2_rn(q00, q01);
        *(__half2*)&g_attn_h[abase + r1*32 + c0] = __floats2half2_rn(q10, q11);
        Am[r0*33 + c0] = (c0 < r0) ? -bet[r0]*accA[0] : 0.f;
        Am[r0*33 + c1] = (c1 < r0) ? -bet[r0]*accA[1] : 0.f;
        Am[r1*33 + c0] = (c0 < r1) ? -bet[r1]*accA[2] : 0.f;
        Am[r1*33 + c1] = (c1 < r1) ? -bet[r1]*accA[3] : 0.f;
    }
    __syncthreads();

    // 5. iterative inversion (warp 0), then T' = (A+I)*diag(beta) as tf32
    if (tid < 32) {
        int ln = tid;
        for (int i = 1; i < 32; i++) {
            float t = 0.f;
            if (ln < i) for (int p = 0; p < i; p++) t += Am[i*33 + p] * Am[p*33 + ln];
            __syncwarp();
            if (ln < i) Am[i*33 + ln] += t;
            __syncwarp();
        }
    }
    __syncthreads();
    for (int e = tid; e < 1024; e += 256) {
        int i = e >> 5, j = e & 31;
        float t = Am[i*33 + j] + (i == j ? 1.f : 0.f);
        Ttf[i*36 + j] = f2tf(t * bet[j]);
    }
    // 6. load raw v tile (fp16) as tf32 into Qt (reuse)
    __syncthreads();
    for (int e = tid*4; e < 32*256; e += 1024) {
        int r = e >> 8, d = e & 255;
        uint2 vh = *(const uint2*)&g_vc_h[((size_t)(b*LL + l0 + r))*DD + h*DV + d];
        float2 va = __half22float2(*(__half2*)&vh.x);
        float2 vb2 = __half22float2(*(__half2*)&vh.y);
        unsigned* qd = (unsigned*)&Qt[r*PSTR + d];
        qd[0]=f2tf(va.x); qd[1]=f2tf(va.y); qd[2]=f2tf(vb2.x); qd[3]=f2tf(vb2.y);
    }
    __syncthreads();

    // 7. u = T'@v, w = T'@kn   (32x256, K=32) — fp16 outputs
    {
        int m0 = (wid & 1) * 16;
        int nb = (wid >> 1) * 64;
        const unsigned* Ku = (const unsigned*)Kt;
        const unsigned* Vu = (const unsigned*)Qt;
        unsigned a[4][4];
#pragma unroll
        for (int kk = 0; kk < 4; kk++) {
            int kb = kk*8;
            a[kk][0] = Ttf[(m0+lr)*36 + kb+lk];
            a[kk][1] = Ttf[(m0+lr+8)*36 + kb+lk];
            a[kk][2] = Ttf[(m0+lr)*36 + kb+lk+4];
            a[kk][3] = Ttf[(m0+lr+8)*36 + kb+lk+4];
        }
#pragma unroll
        for (int nt = 0; nt < 8; nt++) {
            int n0 = nb + nt*8;
            float au[4] = {0,0,0,0}, aw[4] = {0,0,0,0};
#pragma unroll
            for (int kk = 0; kk < 4; kk++) {
                int kb = kk*8;
                unsigned bu[2], bw[2];
                bu[0] = Vu[(kb+lk)*PSTR + n0+lr];
                bu[1] = Vu[(kb+lk+4)*PSTR + n0+lr];
                bw[0] = Ku[(kb+lk)*PSTR + n0+lr];
                bw[1] = Ku[(kb+lk+4)*PSTR + n0+lr];
                mma_tf32(au, a[kk], bu);
                mma_tf32(aw, a[kk], bw);
            }
            int r0 = m0 + lr, r1 = r0 + 8, cc = n0 + 2*lk;
            *(__half2*)&g_u_h[obase + r0*256 + cc] = __floats2half2_rn(au[0], au[1]);
            *(__half2*)&g_u_h[obase + r1*256 + cc] = __floats2half2_rn(au[2], au[3]);
            *(__half2*)&g_w_h[obase + r0*256 + cc] = __floats2half2_rn(aw[0], aw[1]);
            *(__half2*)&g_w_h[obase + r1*256 + cc] = __floats2half2_rn(aw[2], aw[3]);
        }
    }
}

// --------------- sequential inter-chunk scan (fp16 tensor-core mma) ---------
// Sf fp32 master [256][40]; Sh fp16 shadow TRANSPOSED [dv32][dk256+pad];
// tiles fp16: w/q [t32][264], kT [dv256][40]; Uh/Ah fp16 [32][40].
#define SFW 40
#define SCAN_SMEM 88576
__global__ __launch_bounds__(256) void scan_kernel()
{
    extern __shared__ char ssm[];
    float*    Sf  = (float*)ssm;                      // [256][40] f32
    unsigned* Sh  = (unsigned*)(ssm + 40960);         // [32][132] words
    unsigned* Tw  = (unsigned*)(ssm + 57856);         // tile (max 20480B)
    float*    Ui  = (float*)(ssm + 78336);            // [32][40] f32
    unsigned* Uh  = (unsigned*)(ssm + 83456);         // [32][20] words
    unsigned* Ah  = (unsigned*)(ssm + 86016);         // [32][20] words
    __half*   ShH = (__half*)Sh;
    __half*   UhH = (__half*)Uh;
    __half*   TwH = (__half*)Tw;

    int blk = blockIdx.x;
    int g  = blk & (NG-1);
    int bh = blk >> 3;
    int b  = bh >> 2;
    int h  = bh & 3;
    int tid = threadIdx.x;
    int wid = tid >> 5, lane = tid & 31;
    int lr = lane >> 2, lk = lane & 3;
    int m0 = (wid >> 2) * 16;
    int n0 = (wid & 3) * 8;

    for (int e = tid; e < 256*SFW; e += 256) Sf[e] = 0.f;
    for (int e = tid; e < 32*132; e += 256) Sh[e] = 0u;
    __syncthreads();

    for (int c = 0; c < NC; c++) {
        size_t base = ((size_t)bh*NC + c) * (32*256);
        size_t abase = ((size_t)bh*NC + c) * 1024;

        // u slice (fp16 -> Ui fp32) + attn (raw fp16) + w tile (raw fp16)
        for (int e = tid*2; e < 1024; e += 512) {
            int r = e >> 5, j = e & 31;
            unsigned uw = *(const unsigned*)&g_u_h[base + r*256 + g*32 + j];
            float2 uf = __half22float2(*(__half2*)&uw);
            Ui[r*SFW + j] = uf.x; Ui[r*SFW + j + 1] = uf.y;
        }
        {
            int e = tid*4;
            int r = e >> 5, j = e & 31;
            *(uint2*)&Ah[r*20 + (j >> 1)] = *(const uint2*)&g_attn_h[abase + e];
        }
        for (int e = tid*8; e < 8192; e += 2048) {
            int r = e >> 8, jj = e & 255;
            *(uint4*)&TwH[r*264 + jj] = *(const uint4*)&g_w_h[base + e];
        }
        __syncthreads();

        // (1) u_i = u - w@S    (32x32, K=256, fp16)
        {
            float acc[4] = {0.f, 0.f, 0.f, 0.f};
#pragma unroll 4
            for (int kb = 0; kb < 256; kb += 16) {
                int kw = (kb >> 1) + lk;
                unsigned a[4], bf[2];
                a[0] = Tw[(m0+lr)*132 + kw];
                a[1] = Tw[(m0+lr+8)*132 + kw];
                a[2] = Tw[(m0+lr)*132 + kw + 4];
                a[3] = Tw[(m0+lr+8)*132 + kw + 4];
                bf[0] = Sh[(n0+lr)*132 + kw];
                bf[1] = Sh[(n0+lr)*132 + kw + 4];
                mma_f16(acc, a, bf);
            }
            int r0 = m0 + lr, r1 = r0 + 8, cb = n0 + 2*lk;
            float u0 = Ui[r0*SFW+cb]   - acc[0];
            float u1 = Ui[r0*SFW+cb+1] - acc[1];
            float u2 = Ui[r1*SFW+cb]   - acc[2];
            float u3 = Ui[r1*SFW+cb+1] - acc[3];
            UhH[cb*40 + r0]     = __float2half_rn(u0);
            UhH[(cb+1)*40 + r0] = __float2half_rn(u1);
            UhH[cb*40 + r1]     = __float2half_rn(u2);
            UhH[(cb+1)*40 + r1] = __float2half_rn(u3);
        }
        __syncthreads();

        // q tile
        for (int e = tid*8; e < 8192; e += 2048) {
            int r = e >> 8, jj = e & 255;
            *(uint4*)&TwH[r*264 + jj] = *(const uint4*)&g_qn_h[base + e];
        }
        __syncthreads();

        // (2) o = q@S + attn@u_i  -> g_delta
        {
            float acc[4] = {0.f, 0.f, 0.f, 0.f};
#pragma unroll 4
            for (int kb = 0; kb < 256; kb += 16) {
                int kw = (kb >> 1) + lk;
                unsigned a[4], bf[2];
                a[0] = Tw[(m0+lr)*132 + kw];
                a[1] = Tw[(m0+lr+8)*132 + kw];
                a[2] = Tw[(m0+lr)*132 + kw + 4];
                a[3] = Tw[(m0+lr+8)*132 + kw + 4];
                bf[0] = Sh[(n0+lr)*132 + kw];
                bf[1] = Sh[(n0+lr)*132 + kw + 4];
                mma_f16(acc, a, bf);
            }
#pragma unroll
            for (int kb = 0; kb < 32; kb += 16) {
                int kw = (kb >> 1) + lk;
                unsigned a[4], bf[2];
                a[0] = Ah[(m0+lr)*20 + kw];
                a[1] = Ah[(m0+lr+8)*20 + kw];
                a[2] = Ah[(m0+lr)*20 + kw + 4];
                a[3] = Ah[(m0+lr+8)*20 + kw + 4];
                bf[0] = Uh[(n0+lr)*20 + kw];
                bf[1] = Uh[(n0+lr)*20 + kw + 4];
                mma_f16(acc, a, bf);
            }
            size_t ob = ((size_t)(b*LL + c*32 + m0 + lr))*DD + h*DV + g*32 + n0 + 2*lk;
            float2 lo = {acc[0], acc[1]};
            float2 hi = {acc[2], acc[3]};
            *(float2*)&g_delta[ob]        = lo;
            *(float2*)&g_delta[ob + 8*DD] = hi;
        }
        __syncthreads();

        // kT tile [dv256][40]
        for (int e = tid*8; e < 8192; e += 2048) {
            int r = e >> 5, jj = e & 31;
            *(uint4*)&TwH[r*40 + jj] = *(const uint4*)&g_knT_h[base + e];
        }
        __syncthreads();

        // (3) S += k^T @ u_i   (M=256 dv rows of S... M=dk, N=dv, K=time=32)
#pragma unroll
        for (int t = 0; t < 2; t++) {
            int tm = (wid*2 + t) * 16;
#pragma unroll
            for (int tn = 0; tn < 4; tn++) {
                int nn = tn*8;
                int r0 = tm + lr, r1 = r0 + 8, cb = nn + 2*lk;
                float acc[4];
                acc[0] = Sf[r0*SFW+cb]; acc[1] = Sf[r0*SFW+cb+1];
                acc[2] = Sf[r1*SFW+cb]; acc[3] = Sf[r1*SFW+cb+1];
#pragma unroll
                for (int kb = 0; kb < 32; kb += 16) {
                    int kw = (kb >> 1) + lk;
                    unsigned a[4], bf[2];
                    a[0] = Tw[(tm+lr)*20 + kw];
                    a[1] = Tw[(tm+lr+8)*20 + kw];
                    a[2] = Tw[(tm+lr)*20 + kw + 4];
                    a[3] = Tw[(tm+lr+8)*20 + kw + 4];
                    bf[0] = Uh[(nn+lr)*20 + kw];
                    bf[1] = Uh[(nn+lr)*20 + kw + 4];
                    mma_f16(acc, a, bf);
                }
                Sf[r0*SFW+cb] = acc[0]; Sf[r0*SFW+cb+1] = acc[1];
                Sf[r1*SFW+cb] = acc[2]; Sf[r1*SFW+cb+1] = acc[3];
                ShH[cb*264 + r0]     = __float2half_rn(acc[0]);
                ShH[(cb+1)*264 + r0] = __float2half_rn(acc[1]);
                ShH[cb*264 + r1]     = __float2half_rn(acc[2]);
                ShH[(cb+1)*264 + r1] = __float2half_rn(acc[3]);
            }
        }
        __syncthreads();
    }
}

// ------------------- per-(head,channel) FIR conv (fp16 in, fp32 out) --------
template<int K>
__global__ __launch_bounds__(256) void fir_kernel(
    const float* __restrict__ fw, float* __restrict__ y)
{
    __shared__ float2 vbuf[(128 + K - 1) * 16];
    __shared__ float2 wbuf[16 * K];
    int bh = blockIdx.x;
    int b = bh / HH, h = bh % HH;
    int l0 = blockIdx.y * 128;
    int d0 = blockIdx.z * 32;
    int tid = threadIdx.x;

    for (int idx = tid; idx < 16*K; idx += 256) {
        int dp = idx / K, t = idx % K;
        float2 wv;
        wv.x = fw[(size_t)(h*DV + d0 + 2*dp)*K + t];
        wv.y = fw[(size_t)(h*DV + d0 + 2*dp + 1)*K + t];
        wbuf[dp*K + t] = wv;
    }
    for (int idx = tid; idx < (128 + K - 1)*16; idx += 256) {
        int lrr = idx >> 4, dp = idx & 15;
        int l = l0 - (K - 1) + lrr;
        vbuf[idx] = (l >= 0)
            ? __half22float2(*(const __half2*)&g_vc_h[((size_t)(b*LL + l))*DD + h*DV + d0 + 2*dp])
            : make_float2(0.f, 0.f);
    }
    __syncthreads();

    int dp = tid & 15;
    int lr0 = (tid >> 4) * 8;
    for (int m = 0; m < 8; m++) {
        int lrr = lr0 + m;
        float2 acc = {0.f, 0.f};
#pragma unroll
        for (int t = 0; t < K; t++) {
            float2 v = vbuf[(lrr + t)*16 + dp];
            float2 wv = wbuf[dp*K + t];
            acc.x = fmaf(v.x, wv.x, acc.x);
            acc.y = fmaf(v.y, wv.y, acc.y);
        }
        *(float2*)&y[((size_t)(b*LL + l0 + lrr))*DD + h*DV + d0 + 2*dp] = acc;
    }
}

// ------------- gate input assembly (hs + stats), stored as fp16 -------------
__global__ __launch_bounds__(256) void stats_kernel(const float* __restrict__ hs)
{
    int n = blockIdx.x, tid = threadIdx.x;
    {
        int i = tid * 4;
        float4 v = *(const float4*)&hs[(size_t)n*DD + i];
        __half2 lo = __floats2half2_rn(v.x, v.y);
        __half2 hi = __floats2half2_rn(v.z, v.w);
        uint2 o = {*(unsigned*)&lo, *(unsigned*)&hi};
        *(uint2*)&g_gatein_h[(size_t)n*GIN + i] = o;
    }
    int warp = tid >> 5, lane = tid & 31;
    for (int rep = 0; rep < 2; rep++) {
        int combo = warp*2 + rep;
        int path = combo >> 2, h = combo & 3;
        float s1 = 0.f, s2 = 0.f;
        if (path == 3) {
            const __half* ph = g_vc_h + (size_t)n*DD + h*DV;
            for (int j = lane; j < 256; j += 32) {
                float x = __half2float(ph[j]); s1 += x; s2 += x*x;
            }
        } else {
            const float* p = (path == 0) ? g_short : (path == 1) ? g_long : g_delta;
            p += (size_t)n*DD + h*DV;
            for (int j = lane; j < 256; j += 32) { float x = p[j]; s1 += x; s2 += x*x; }
        }
#pragma unroll
        for (int st = 16; st > 0; st >>= 1) {
            s1 += __shfl_down_sync(0xffffffffu, s1, st);
            s2 += __shfl_down_sync(0xffffffffu, s2, st);
        }
        if (lane == 0) {
            float m  = s1 * (1.f/256.f);
            float va = s2 * (1.f/256.f) - m*m;
            g_gatein_h[(size_t)n*GIN + DD + path*8 + h*2]     = __float2half_rn(m);
            g_gatein_h[(size_t)n*GIN + DD + path*8 + h*2 + 1] = __float2half_rn(va);
        }
    }
}

// ------------------------- gate2 + softmax + floor --------------------------
__global__ __launch_bounds__(256) void gate2_kernel(
    const float* __restrict__ w2, const float* __restrict__ log_temp,
    const float* __restrict__ base_bias, const float* __restrict__ floor_raw)
{
    __shared__ float hrow[HID];
    __shared__ float lg[16];
    int n = blockIdx.x, tid = threadIdx.x;
    for (int i = tid; i < HID; i += 256) hrow[i] = g_hmid[(size_t)n*HID + i];
    __syncthreads();
    int warp = tid >> 5, lane = tid & 31;
    for (int rep = 0; rep < 2; rep++) {
        int o = warp*2 + rep;
        const float* wr = w2 + (size_t)o*HID;
        float s = 0.f;
        for (int i = lane; i < HID; i += 32) s = fmaf(hrow[i], wr[i], s);
#pragma unroll
        for (int st = 16; st > 0; st >>= 1) s += __shfl_down_sync(0xffffffffu, s, st);
        if (lane == 0) lg[o] = s;
    }
    __syncthreads();
    if (tid < 4) {
        int h = tid;
        float temp = log1pf(expf(log_temp[h])) + 1e-4f;
        float z[4], m = -1e30f;
#pragma unroll
        for (int i = 0; i < 4; i++) {
            z[i] = (lg[h*4+i] + base_bias[h*4+i]) / temp;
            m = fmaxf(m, z[i]);
        }
        float e[4], s = 0.f;
#pragma unroll
        for (int i = 0; i < 4; i++) { e[i] = expf(z[i] - m); s += e[i]; }
        float p[4], s2 = 0.f;
#pragma unroll
        for (int i = 0; i < 4; i++) {
            p[i] = e[i] / s;
            float f = 0.05f / (1.f + expf(-floor_raw[h*4+i]));
            p[i] = fmaxf(p[i], f);
            s2 += p[i];
        }
#pragma unroll
        for (int i = 0; i < 4; i++) g_probs[(size_t)n*16 + h*4 + i] = p[i] / s2;
    }
}

// ------------- path mix + RMS norm, output stored as fp16 -------------------
__global__ __launch_bounds__(256) void mix_kernel(const float* __restrict__ onorm)
{
    __shared__ float pr[16];
    __shared__ float wsum[8];
    int n = blockIdx.x, tid = threadIdx.x;
    if (tid < 16) pr[tid] = g_probs[(size_t)n*16 + tid];
    __syncthreads();
    int h = tid >> 6;
    int dd = (tid & 63) * 4;
    size_t pb = (size_t)n*DD + h*DV + dd;
    float4 sh = *(const float4*)&g_short[pb];
    float4 lo = *(const float4*)&g_long[pb];
    float4 de = *(const float4*)&g_delta[pb];
    uint2 vraw = *(const uint2*)&g_vc_h[pb];
    float2 va = __half22float2(*(__half2*)&vraw.x);
    float2 vb = __half22float2(*(__half2*)&vraw.y);
    float p0 = pr[h*4+0], p1 = pr[h*4+1], p2 = pr[h*4+2], p3 = pr[h*4+3];
    float o[4];
    o[0] = p0*sh.x + p1*lo.x + p2*de.x + p3*va.x;
    o[1] = p0*sh.y + p1*lo.y + p2*de.y + p3*va.y;
    o[2] = p0*sh.z + p1*lo.z + p2*de.z + p3*vb.x;
    o[3] = p0*sh.w + p1*lo.w + p2*de.w + p3*vb.y;
    float ss = o[0]*o[0] + o[1]*o[1] + o[2]*o[2] + o[3]*o[3];
#pragma unroll
    for (int st = 16; st > 0; st >>= 1) ss += __shfl_down_sync(0xffffffffu, ss, st);
    int warp = tid >> 5, lane = tid & 31;
    if (lane == 0) wsum[warp] = ss;
    __syncthreads();
    float tot = wsum[h*2] + wsum[h*2+1];
    float scale = rsqrtf(tot * (1.f/256.f) + 1e-5f);
    __half2 h0 = __floats2half2_rn(o[0]*scale*onorm[dd],   o[1]*scale*onorm[dd+1]);
    __half2 h1 = __floats2half2_rn(o[2]*scale*onorm[dd+2], o[3]*scale*onorm[dd+3]);
    uint2 pk = {*(unsigned*)&h0, *(unsigned*)&h1};
    *(uint2*)&g_mix_h[pb] = pk;
}

// ------------------------- launch ------------------------------------------
extern "C" void kernel_launch(void* const* d_in, const int* in_sizes, int n_in,
                              void* d_out, int out_size)
{
    const float* hs        = (const float*)d_in[0];
    const float* Wq        = (const float*)d_in[1];
    const float* Wk        = (const float*)d_in[2];
    const float* Wv        = (const float*)d_in[3];
    const float* Wb        = (const float*)d_in[4];
    const float* qconv_w   = (const float*)d_in[5];
    const float* kconv_w   = (const float*)d_in[6];
    const float* vconv_w   = (const float*)d_in[7];
    const float* fir_s     = (const float*)d_in[8];
    const float* fir_l     = (const float*)d_in[9];
    const float* gate_w1   = (const float*)d_in[10];
    const float* gate_b1   = (const float*)d_in[11];
    const float* gate_w2   = (const float*)d_in[12];
    const float* log_temp  = (const float*)d_in[13];
    const float* base_bias = (const float*)d_in[14];
    const float* floor_raw = (const float*)d_in[15];
    const float* onorm_w   = (const float*)d_in[16];
    const float* Wo        = (const float*)d_in[17];
    float* out = (float*)d_out;

    void *p_qlin, *p_klin, *p_vlin, *p_qc, *p_kc, *p_vc, *p_hmid, *p_short, *p_long;
    void *p_hsh, *p_wqh, *p_wkh, *p_wvh, *p_woh, *p_gw1h, *p_gateinh, *p_mixh;
    cudaGetSymbolAddress(&p_qlin, g_qlin_h);
    cudaGetSymbolAddress(&p_klin, g_klin_h);
    cudaGetSymbolAddress(&p_vlin, g_vlin_h);
    cudaGetSymbolAddress(&p_qc, g_qc_h);
    cudaGetSymbolAddress(&p_kc, g_kc_h);
    cudaGetSymbolAddress(&p_vc, g_vc_h);
    cudaGetSymbolAddress(&p_hmid, g_hmid);
    cudaGetSymbolAddress(&p_short, g_short);
    cudaGetSymbolAddress(&p_long, g_long);
    cudaGetSymbolAddress(&p_hsh, g_hs_h);
    cudaGetSymbolAddress(&p_wqh, g_wq_h);
    cudaGetSymbolAddress(&p_wkh, g_wk_h);
    cudaGetSymbolAddress(&p_wvh, g_wv_h);
    cudaGetSymbolAddress(&p_woh, g_wo_h);
    cudaGetSymbolAddress(&p_gw1h, g_gw1_h);
    cudaGetSymbolAddress(&p_gateinh, g_gatein_h);
    cudaGetSymbolAddress(&p_mixh, g_mix_h);

    cudaFuncSetAttribute(scan_kernel,
        cudaFuncAttributeMaxDynamicSharedMemorySize, SCAN_SMEM);
    cudaFuncSetAttribute(precompute_kernel,
        cudaFuncAttributeMaxDynamicSharedMemorySize, PSMEM);
    cudaFuncSetAttribute(hgemm,
        cudaFuncAttributeMaxDynamicSharedMemorySize, HGEMM_SMEM);

    dim3 blk(256);

    // 0. pre-convert hs + weights to fp16
    cvt_h6<<<dim3(NROW*DD/1024, 6), blk>>>(
        hs,      (__half*)p_hsh,  NROW*DD,
        Wq,      (__half*)p_wqh,  DD*DD,
        Wk,      (__half*)p_wkh,  DD*DD,
        Wv,      (__half*)p_wvh,  DD*DD,
        Wo,      (__half*)p_woh,  DD*DD,
        gate_w1, (__half*)p_gw1h, HID*GIN);

    // q/k/v projections — fp16 outputs (mode 2)
    hgemm<<<dim3(DD/128, NROW/128, 3), blk, HGEMM_SMEM>>>(
        (const __half*)p_hsh,
        (const __half*)p_wqh, (const __half*)p_wkh, (const __half*)p_wvh,
        (float*)p_qlin, (float*)p_klin, (float*)p_vlin,
        nullptr, NROW, DD, DD, 2);

    // causal conv4 + SiLU (fp16 io, 2 elems/thread)
    conv4_silu3<<<dim3(NROW*DD/512, 3), blk>>>(
        (const __half*)p_qlin, (const __half*)p_klin, (const __half*)p_vlin,
        qconv_w, kconv_w, vconv_w,
        (__half*)p_qc, (__half*)p_kc, (__half*)p_vc);

    // beta
    beta_kernel<<<NROW, 128>>>(hs, Wb);

    // delta-rule
    precompute_kernel<<<BB*HH*NC, blk, PSMEM>>>();
    scan_kernel<<<BB*HH*NG, blk, SCAN_SMEM>>>();

    // FIR paths
    fir_kernel<3><<<dim3(BB*HH, LL/128, DV/32), blk>>>(fir_s, (float*)p_short);
    fir_kernel<63><<<dim3(BB*HH, LL/128, DV/32), blk>>>(fir_l, (float*)p_long);

    // gate
    stats_kernel<<<NROW, blk>>>(hs);
    hgemm<<<dim3(HID/128, NROW/128, 1), blk, HGEMM_SMEM>>>(
        (const __half*)p_gateinh,
        (const __half*)p_gw1h, nullptr, nullptr,
        (float*)p_hmid, nullptr, nullptr,
        gate_b1, NROW, HID, GIN, 1);
    gate2_kernel<<<NROW, blk>>>(gate_w2, log_temp, base_bias, floor_raw);

    // mix + RMS norm
    mix_kernel<<<NROW, blk>>>(onorm_w);

    // output projection (fp32 out)
    hgemm<<<dim3(DD/128, NROW/128, 1), blk, HGEMM_SMEM>>>(
        (const __half*)p_mixh,
        (const __half*)p_woh, nullptr, nullptr,
        out, nullptr, nullptr,
        nullptr, NROW, DD, DD, 0);
}

// round 13
// speedup vs baseline: 3.8969x; 1.0460x over previous
#include <cuda_runtime.h>
#include <cuda_fp16.h>
#include <math.h>
#include <stdint.h>

#define BB 2
#define LL 2048
#define DD 1024
#define HH 4
#define DV 256
#define CKN 32
#define NC 64              // LL / CKN
#define NROW (BB*LL)       // 4096
#define GIN 1056
#define GINP 1088          // padded to multiple of 64
#define HID 2048
#define NG 8               // Dv groups of 32 in the scan

// ------------------------- scratch (device globals) -------------------------
__device__ float g_beta[NROW*HH];
__device__ float g_hmid[NROW*HID];
__device__ float g_probs[NROW*16];
// fp16 intermediates + GEMM operands
__device__ __half g_qn_h[NROW*DD];       // [bh][c][time32][dv256]
__device__ __half g_knT_h[NROW*DD];      // [bh][c][dv256][time32]
__device__ __half g_u_h[NROW*DD];        // [bh][c][time32][dv256]
__device__ __half g_w_h[NROW*DD];        // [bh][c][time32][dv256]
__device__ __half g_attn_h[BB*HH*NC*CKN*CKN];
__device__ __half g_delta_h[NROW*DD];
__device__ __half g_short_h[NROW*DD];
__device__ __half g_long_h[NROW*DD];
__device__ __half g_qlin_h[NROW*DD];
__device__ __half g_klin_h[NROW*DD];
__device__ __half g_vlin_h[NROW*DD];
__device__ __half g_qc_h[NROW*DD];
__device__ __half g_kc_h[NROW*DD];
__device__ __half g_vc_h[NROW*DD];
__device__ __half g_hs_h[NROW*DD];
__device__ __half g_wq_h[DD*DD];
__device__ __half g_wk_h[DD*DD];
__device__ __half g_wv_h[DD*DD];
__device__ __half g_wo_h[DD*DD];
__device__ __half g_gw1_h[HID*GINP];
__device__ __half g_gatein_h[NROW*GINP];
__device__ __half g_mix_h[NROW*DD];

// ------------------------- helpers ------------------------------------------
__device__ __forceinline__ unsigned f2tf(float x) {
    unsigned r;
    asm("cvt.rna.tf32.f32 %0, %1;" : "=r"(r) : "f"(x));
    return r;
}

__device__ __forceinline__ void mma_tf32(float* c, const unsigned* a, const unsigned* b) {
    asm volatile(
        "mma.sync.aligned.m16n8k8.row.col.f32.tf32.tf32.f32 "
        "{%0,%1,%2,%3}, {%4,%5,%6,%7}, {%8,%9}, {%0,%1,%2,%3};"
        : "+f"(c[0]), "+f"(c[1]), "+f"(c[2]), "+f"(c[3])
        : "r"(a[0]), "r"(a[1]), "r"(a[2]), "r"(a[3]), "r"(b[0]), "r"(b[1]));
}

__device__ __forceinline__ void mma_f16(float* c, const unsigned* a, const unsigned* b) {
    asm volatile(
        "mma.sync.aligned.m16n8k16.row.col.f32.f16.f16.f32 "
        "{%0,%1,%2,%3}, {%4,%5,%6,%7}, {%8,%9}, {%0,%1,%2,%3};"
        : "+f"(c[0]), "+f"(c[1]), "+f"(c[2]), "+f"(c[3])
        : "r"(a[0]), "r"(a[1]), "r"(a[2]), "r"(a[3]), "r"(b[0]), "r"(b[1]));
}

#define LDSM4(r, addr)                                                        \
    asm volatile("ldmatrix.sync.aligned.m8n8.x4.shared.b16 {%0,%1,%2,%3}, [%4];" \
        : "=r"((r)[0]), "=r"((r)[1]), "=r"((r)[2]), "=r"((r)[3]) : "r"(addr))

// ------------------------- bulk fp32 -> fp16 conversion ---------------------
__global__ __launch_bounds__(256) void cvt_h6(
    const float* __restrict__ s0, __half* __restrict__ d0, int n0,
    const float* __restrict__ s1, __half* __restrict__ d1, int n1,
    const float* __restrict__ s2, __half* __restrict__ d2, int n2,
    const float* __restrict__ s3, __half* __restrict__ d3, int n3,
    const float* __restrict__ s4, __half* __restrict__ d4, int n4,
    const float* __restrict__ s5, __half* __restrict__ d5, int n5)
{
    const float* s; __half* d; int n;
    switch (blockIdx.y) {
        case 0: s=s0; d=d0; n=n0; break;
        case 1: s=s1; d=d1; n=n1; break;
        case 2: s=s2; d=d2; n=n2; break;
        case 3: s=s3; d=d3; n=n3; break;
        case 4: s=s4; d=d4; n=n4; break;
        default: s=s5; d=d5; n=n5; break;
    }
    int i = (blockIdx.x * 256 + threadIdx.x) * 4;
    if (i < n) {
        float4 v = *(const float4*)(s + i);
        __half2 lo = __floats2half2_rn(v.x, v.y);
        __half2 hi = __floats2half2_rn(v.z, v.w);
        uint2 o = {*(unsigned*)&lo, *(unsigned*)&hi};
        *(uint2*)(d + i) = o;
    }
}

// --------- gate_w1 fp32[HID][GIN] -> fp16[HID][GINP] with zero pad ----------
__global__ __launch_bounds__(256) void cvt_gw1pad(const float* __restrict__ src)
{
    int i = (blockIdx.x * 256 + threadIdx.x) * 4;
    if (i >= HID*GINP) return;
    int row = i / GINP, col = i % GINP;
    float4 v;
    if (col < GIN) v = *(const float4*)&src[(size_t)row*GIN + col];
    else v = make_float4(0.f, 0.f, 0.f, 0.f);
    __half2 lo = __floats2half2_rn(v.x, v.y);
    __half2 hi = __floats2half2_rn(v.z, v.w);
    uint2 o = {*(unsigned*)&lo, *(unsigned*)&hi};
    *(uint2*)&g_gw1_h[i] = o;
}

// ---------------- fp16 tensor GEMM: C = A(MxK) @ B(NxK)^T -------------------
// K=64 per stage, 2-stage cp.async pipeline, 128x128 tile, ldmatrix frags.
// Smem rows: 64 halves @ 144B stride (144/16 = 9 ≡ 1 mod 8 -> LDSM conflict-free).
// mode 0: fp32 out.  mode 1: +bias, exact GELU, fp32 out.  mode 2: fp16 out.
#define HSTRB 144
#define HSTAGE_BYTES (128*HSTRB)        // 18432
#define HGEMM_SMEM (4*HSTAGE_BYTES)     // 73728

#define HLOAD64(kt, st) do {                                                   \
    const __half* Ap_ = A + (size_t)bm*K + (kt)*64;                            \
    const __half* Bp_ = B + (size_t)bn*K + (kt)*64;                            \
    _Pragma("unroll")                                                          \
    for (int i_ = 0; i_ < 4; i_++) {                                           \
        int e_ = tid + i_*256;                                                 \
        int row_ = e_ >> 3, seg_ = e_ & 7;                                     \
        unsigned doff_ = (unsigned)row_*HSTRB + (unsigned)seg_*16;             \
        asm volatile("cp.async.cg.shared.global [%0], [%1], 16;"               \
            :: "r"(smb + (unsigned)((st)*HSTAGE_BYTES) + doff_),               \
               "l"(Ap_ + (size_t)row_*K + seg_*8));                            \
        asm volatile("cp.async.cg.shared.global [%0], [%1], 16;"               \
            :: "r"(smb + (unsigned)(2*HSTAGE_BYTES + (st)*HSTAGE_BYTES) + doff_), \
               "l"(Bp_ + (size_t)row_*K + seg_*8));                            \
    }                                                                          \
} while (0)

__global__ __launch_bounds__(256, 2) void hgemm(
    const __half* __restrict__ A,
    const __half* __restrict__ Bm0, const __half* __restrict__ Bm1, const __half* __restrict__ Bm2,
    float* __restrict__ Cm0, float* __restrict__ Cm1, float* __restrict__ Cm2,
    const float* __restrict__ bias, int M, int N, int K, int mode)
{
    extern __shared__ char tsm[];

    const __half* B = (blockIdx.z == 0) ? Bm0 : (blockIdx.z == 1) ? Bm1 : Bm2;
    float*        C = (blockIdx.z == 0) ? Cm0 : (blockIdx.z == 1) ? Cm1 : Cm2;

    int tid = threadIdx.x;
    int bm = blockIdx.y * 128, bn = blockIdx.x * 128;
    unsigned smb;
    asm("{ .reg .u64 t; cvta.to.shared.u64 t, %1; cvt.u32.u64 %0, t; }"
        : "=r"(smb) : "l"(tsm));

    int wid = tid >> 5, lane = tid & 31;
    int wm = (wid >> 2) * 64, wn = (wid & 3) * 32;
    int lr = lane >> 2, lk = lane & 3;

    int a_row = (lane & 7) + ((lane >> 3) & 1) * 8;
    int a_kb  = (lane >> 4) * 16;
    int b_row = (lane & 7) + ((lane >> 4) & 1) * 8;
    int b_kb  = ((lane >> 3) & 1) * 16;

    float acc[4][4][4];
#pragma unroll
    for (int mi = 0; mi < 4; mi++)
#pragma unroll
        for (int ni = 0; ni < 4; ni++)
#pragma unroll
            for (int j = 0; j < 4; j++) acc[mi][ni][j] = 0.f;

    int niter = K >> 6;

    HLOAD64(0, 0);
    asm volatile("cp.async.commit_group;");

    for (int t = 0; t < niter; t++) {
        asm volatile("cp.async.wait_group 0;");
        __syncthreads();
        if (t + 1 < niter) {
            HLOAD64(t + 1, (t + 1) & 1);
            asm volatile("cp.async.commit_group;");
        }
        int cur = t & 1;
        unsigned a_base = smb + (unsigned)(cur*HSTAGE_BYTES);
        unsigned b_base = smb + (unsigned)(2*HSTAGE_BYTES + cur*HSTAGE_BYTES);
#pragma unroll
        for (int ks = 0; ks < 4; ks++) {
            unsigned af[4][4], bq[2][4];
#pragma unroll
            for (int mi = 0; mi < 4; mi++) {
                unsigned addr = a_base + (unsigned)((wm + mi*16 + a_row)*HSTRB + ks*32 + a_kb);
                LDSM4(af[mi], addr);
            }
#pragma unroll
            for (int nq = 0; nq < 2; nq++) {
                unsigned addr = b_base + (unsigned)((wn + nq*16 + b_row)*HSTRB + ks*32 + b_kb);
                LDSM4(bq[nq], addr);
            }
#pragma unroll
            for (int mi = 0; mi < 4; mi++)
#pragma unroll
                for (int ni = 0; ni < 4; ni++)
                    mma_f16(acc[mi][ni], af[mi], &bq[ni >> 1][(ni & 1) * 2]);
        }
        __syncthreads();
    }

#pragma unroll
    for (int mi = 0; mi < 4; mi++) {
        int r0 = bm + wm + mi*16 + lr;
#pragma unroll
        for (int ni = 0; ni < 4; ni++) {
            int c = bn + wn + ni*8 + 2*lk;
            float v[4] = {acc[mi][ni][0], acc[mi][ni][1], acc[mi][ni][2], acc[mi][ni][3]};
            if (mode == 1) {
                float b0 = bias[c], b1 = bias[c+1];
                v[0] += b0; v[1] += b1; v[2] += b0; v[3] += b1;
#pragma unroll
                for (int j = 0; j < 4; j++)
                    v[j] = 0.5f * v[j] * (1.f + erff(v[j] * 0.70710678118654752f));
            }
            if (mode == 2) {
                __half* Ch = (__half*)C;
                *(__half2*)&Ch[(size_t)r0*N + c]     = __floats2half2_rn(v[0], v[1]);
                *(__half2*)&Ch[(size_t)(r0+8)*N + c] = __floats2half2_rn(v[2], v[3]);
            } else {
                float2 lo = {v[0], v[1]};
                float2 hi = {v[2], v[3]};
                *(float2*)&C[(size_t)r0*N + c]       = lo;
                *(float2*)&C[(size_t)(r0+8)*N + c]   = hi;
            }
        }
    }
}

// ------------- depthwise causal conv4 + SiLU, fp16 io, 2 elems/thread -------
__global__ __launch_bounds__(256) void conv4_silu3(
    const __half* __restrict__ x0, const __half* __restrict__ x1, const __half* __restrict__ x2,
    const float* __restrict__ w0, const float* __restrict__ w1, const float* __restrict__ w2,
    __half* __restrict__ y0, __half* __restrict__ y1, __half* __restrict__ y2)
{
    const __half* x; const float* w; __half* y;
    if (blockIdx.y == 0)      { x = x0; w = w0; y = y0; }
    else if (blockIdx.y == 1) { x = x1; w = w1; y = y1; }
    else                      { x = x2; w = w2; y = y2; }
    int p = blockIdx.x * 256 + threadIdx.x;     // pair index over NROW*DD/2
    int dp = p & (DD/2 - 1);
    int l = (p >> 9) & (LL - 1);
    int d = dp * 2;
    float4 wa = *(const float4*)(w + d*4);
    float4 wb = *(const float4*)(w + d*4 + 4);
    const __half2* xp = (const __half2*)x + p;
    float2 xv = __half22float2(xp[0]);
    float ax = wa.w * xv.x, ay = wb.w * xv.y;
    if (l >= 1) { float2 t = __half22float2(xp[-(DD/2)]);   ax += wa.z*t.x; ay += wb.z*t.y; }
    if (l >= 2) { float2 t = __half22float2(xp[-DD]);       ax += wa.y*t.x; ay += wb.y*t.y; }
    if (l >= 3) { float2 t = __half22float2(xp[-(3*DD/2)]); ax += wa.x*t.x; ay += wb.x*t.y; }
    ax = ax / (1.f + expf(-ax));
    ay = ay / (1.f + expf(-ay));
    ((__half2*)y)[p] = __floats2half2_rn(ax, ay);
}

// ------------------------- beta = sigmoid(hs @ Wb^T) ------------------------
__global__ __launch_bounds__(128) void beta_kernel(
    const float* __restrict__ hs, const float* __restrict__ Wb)
{
    __shared__ float red[4][128];
    int n = blockIdx.x, tid = threadIdx.x;
    const float* hr = hs + (size_t)n * DD;
    float s0=0,s1=0,s2=0,s3=0;
    for (int i = tid; i < DD; i += 128) {
        float x = hr[i];
        s0 += x * Wb[i];
        s1 += x * Wb[DD + i];
        s2 += x * Wb[2*DD + i];
        s3 += x * Wb[3*DD + i];
    }
    red[0][tid]=s0; red[1][tid]=s1; red[2][tid]=s2; red[3][tid]=s3;
    __syncthreads();
    for (int st = 64; st > 0; st >>= 1) {
        if (tid < st)
#pragma unroll
            for (int h = 0; h < 4; h++) red[h][tid] += red[h][tid + st];
        __syncthreads();
    }
    if (tid < 4) g_beta[(size_t)n*HH + tid] = 1.f / (1.f + expf(-red[tid][0]));
}

// ---------------- per-chunk delta-rule precompute (tensor-core mma) ---------
// Outputs fp16: qn [t][d], w/u [t][d], knT [d][t], attn [t][t].
#define PSTR 264
#define PSMEM ((2*32*PSTR + 32*33 + 32*36 + 96) * 4)
__global__ __launch_bounds__(256) void precompute_kernel()
{
    extern __shared__ float psm[];
    float*    Kt  = psm;                     // [32][PSTR] k fp32 -> kn tf32
    float*    Qt  = Kt + 32*PSTR;            // [32][PSTR] q fp32 -> qn tf32 -> v tf32
    float*    Am  = Qt + 32*PSTR;            // [32][33]
    unsigned* Ttf = (unsigned*)(Am + 32*33); // [32][36]
    float*    bet = (float*)(Ttf + 32*36);   // [32]
    float*    rnk = bet + 32;                // [32]
    float*    rnq = rnk + 32;                // [32]

    int blk = blockIdx.x;           // (b*HH + h)*NC + c
    int c  = blk % NC;
    int bh = blk / NC;
    int h  = bh % HH;
    int b  = bh / HH;
    int tid = threadIdx.x;
    int l0 = c * 32;
    int wid = tid >> 5, lane = tid & 31;
    int lr = lane >> 2, lk = lane & 3;

    // 1. load k, q tiles (fp16 -> fp32)
    for (int e = tid*4; e < 32*256; e += 1024) {
        int r = e >> 8, d = e & 255;
        size_t gb = ((size_t)(b*LL + l0 + r))*DD + h*DV + d;
        uint2 kh = *(const uint2*)&g_kc_h[gb];
        float2 ka = __half22float2(*(__half2*)&kh.x);
        float2 kb2 = __half22float2(*(__half2*)&kh.y);
        *(float4*)&Kt[r*PSTR + d] = make_float4(ka.x, ka.y, kb2.x, kb2.y);
        uint2 qh = *(const uint2*)&g_qc_h[gb];
        float2 qa = __half22float2(*(__half2*)&qh.x);
        float2 qb2 = __half22float2(*(__half2*)&qh.y);
        *(float4*)&Qt[r*PSTR + d] = make_float4(qa.x, qa.y, qb2.x, qb2.y);
    }
    if (tid < 32) bet[tid] = g_beta[((size_t)(b*LL + l0 + tid))*HH + h];
    __syncthreads();

    // 2. row norms (8 threads per row)
    {
        int r = tid >> 3, part = tid & 7;
        float sk = 0.f, sq = 0.f;
        for (int j = part*32; j < part*32 + 32; j++) {
            float x = Kt[r*PSTR + j]; sk += x*x;
            float y = Qt[r*PSTR + j]; sq += y*y;
        }
        sk += __shfl_down_sync(0xffffffffu, sk, 4, 8);
        sk += __shfl_down_sync(0xffffffffu, sk, 2, 8);
        sk += __shfl_down_sync(0xffffffffu, sk, 1, 8);
        sq += __shfl_down_sync(0xffffffffu, sq, 4, 8);
        sq += __shfl_down_sync(0xffffffffu, sq, 2, 8);
        sq += __shfl_down_sync(0xffffffffu, sq, 1, 8);
        if (part == 0) { rnk[r] = rsqrtf(sk + 1e-6f); rnq[r] = rsqrtf(sq + 1e-6f); }
    }
    __syncthreads();

    // 3. normalize in place (qn fp16 -> global, tf32 -> smem)
    size_t obase = (size_t)blk * (32*256);
    for (int e = tid*4; e < 32*256; e += 1024) {
        int r = e >> 8, d = e & 255;
        float rk = rnk[r], rq = rnq[r];
        float4 kv = *(float4*)&Kt[r*PSTR + d];
        kv.x *= rk; kv.y *= rk; kv.z *= rk; kv.w *= rk;
        unsigned* kd = (unsigned*)&Kt[r*PSTR + d];
        kd[0]=f2tf(kv.x); kd[1]=f2tf(kv.y); kd[2]=f2tf(kv.z); kd[3]=f2tf(kv.w);
        float4 qv = *(float4*)&Qt[r*PSTR + d];
        qv.x *= rq; qv.y *= rq; qv.z *= rq; qv.w *= rq;
        __half2 qh0 = __floats2half2_rn(qv.x, qv.y);
        __half2 qh1 = __floats2half2_rn(qv.z, qv.w);
        uint2 qo = {*(unsigned*)&qh0, *(unsigned*)&qh1};
        *(uint2*)&g_qn_h[obase + e] = qo;
        unsigned* qd = (unsigned*)&Qt[r*PSTR + d];
        qd[0]=f2tf(qv.x); qd[1]=f2tf(qv.y); qd[2]=f2tf(qv.z); qd[3]=f2tf(qv.w);
    }
    __syncthreads();

    // 3b. write kn transposed [dv][time] as fp16 (Kt holds tf32-bit floats)
    for (int e = tid*2; e < 32*256; e += 512) {
        int r = e & 31, d = e >> 5;          // r even
        float v0 = Kt[r*PSTR + d];
        float v1 = Kt[(r+1)*PSTR + d];
        *(__half2*)&g_knT_h[obase + e] = __floats2half2_rn(v0, v1);
    }

    // 4. fused mma: Afull = kn@kn^T, attnF = qn@kn^T  (32x32, K=256)
    {
        int m0 = (wid >> 2) * 16, n0 = (wid & 3) * 8;
        const unsigned* Ku = (const unsigned*)Kt;
        const unsigned* Qu = (const unsigned*)Qt;
        float accA[4] = {0,0,0,0}, accQ[4] = {0,0,0,0};
#pragma unroll 4
        for (int kb = 0; kb < 256; kb += 8) {
            unsigned ak[4], aq[4], bf[2];
            ak[0] = Ku[(m0+lr)*PSTR + kb+lk];
            ak[1] = Ku[(m0+lr+8)*PSTR + kb+lk];
            ak[2] = Ku[(m0+lr)*PSTR + kb+lk+4];
            ak[3] = Ku[(m0+lr+8)*PSTR + kb+lk+4];
            aq[0] = Qu[(m0+lr)*PSTR + kb+lk];
            aq[1] = Qu[(m0+lr+8)*PSTR + kb+lk];
            aq[2] = Qu[(m0+lr)*PSTR + kb+lk+4];
            aq[3] = Qu[(m0+lr+8)*PSTR + kb+lk+4];
            bf[0] = Ku[(n0+lr)*PSTR + kb+lk];
            bf[1] = Ku[(n0+lr)*PSTR + kb+lk+4];
            mma_tf32(accA, ak, bf);
            mma_tf32(accQ, aq, bf);
        }
        size_t abase = (size_t)blk * 1024;
        int r0 = m0 + lr, r1 = r0 + 8, c0 = n0 + 2*lk, c1 = c0 + 1;
        float q00 = (c0 <= r0) ? accQ[0] : 0.f;
        float q01 = (c1 <= r0) ? accQ[1] : 0.f;
        float q10 = (c0 <= r1) ? accQ[2] : 0.f;
        float q11 = (c1 <= r1) ? accQ[3] : 0.f;
        *(__half2*)&g_attn_h[abase + r0*32 + c0] = __floats2half2_rn(q00, q01);
        *(__half2*)&g_attn_h[abase + r1*32 + c0] = __floats2half2_rn(q10, q11);
        Am[r0*33 + c0] = (c0 < r0) ? -bet[r0]*accA[0] : 0.f;
        Am[r0*33 + c1] = (c1 < r0) ? -bet[r0]*accA[1] : 0.f;
        Am[r1*33 + c0] = (c0 < r1) ? -bet[r1]*accA[2] : 0.f;
        Am[r1*33 + c1] = (c1 < r1) ? -bet[r1]*accA[3] : 0.f;
    }
    __syncthreads();

    // 5. iterative inversion (warp 0), then T' = (A+I)*diag(beta) as tf32
    if (tid < 32) {
        int ln = tid;
        for (int i = 1; i < 32; i++) {
            float t = 0.f;
            if (ln < i) for (int p = 0; p < i; p++) t += Am[i*33 + p] * Am[p*33 + ln];
            __syncwarp();
            if (ln < i) Am[i*33 + ln] += t;
            __syncwarp();
        }
    }
    __syncthreads();
    for (int e = tid; e < 1024; e += 256) {
        int i = e >> 5, j = e & 31;
        float t = Am[i*33 + j] + (i == j ? 1.f : 0.f);
        Ttf[i*36 + j] = f2tf(t * bet[j]);
    }
    // 6. load raw v tile (fp16) as tf32 into Qt (reuse)
    __syncthreads();
    for (int e = tid*4; e < 32*256; e += 1024) {
        int r = e >> 8, d = e & 255;
        uint2 vh = *(const uint2*)&g_vc_h[((size_t)(b*LL + l0 + r))*DD + h*DV + d];
        float2 va = __half22float2(*(__half2*)&vh.x);
        float2 vb2 = __half22float2(*(__half2*)&vh.y);
        unsigned* qd = (unsigned*)&Qt[r*PSTR + d];
        qd[0]=f2tf(va.x); qd[1]=f2tf(va.y); qd[2]=f2tf(vb2.x); qd[3]=f2tf(vb2.y);
    }
    __syncthreads();

    // 7. u = T'@v, w = T'@kn   (32x256, K=32) — fp16 outputs
    {
        int m0 = (wid & 1) * 16;
        int nb = (wid >> 1) * 64;
        const unsigned* Ku = (const unsigned*)Kt;
        const unsigned* Vu = (const unsigned*)Qt;
        unsigned a[4][4];
#pragma unroll
        for (int kk = 0; kk < 4; kk++) {
            int kb = kk*8;
            a[kk][0] = Ttf[(m0+lr)*36 + kb+lk];
            a[kk][1] = Ttf[(m0+lr+8)*36 + kb+lk];
            a[kk][2] = Ttf[(m0+lr)*36 + kb+lk+4];
            a[kk][3] = Ttf[(m0+lr+8)*36 + kb+lk+4];
        }
#pragma unroll
        for (int nt = 0; nt < 8; nt++) {
            int n0 = nb + nt*8;
            float au[4] = {0,0,0,0}, aw[4] = {0,0,0,0};
#pragma unroll
            for (int kk = 0; kk < 4; kk++) {
                int kb = kk*8;
                unsigned bu[2], bw[2];
                bu[0] = Vu[(kb+lk)*PSTR + n0+lr];
                bu[1] = Vu[(kb+lk+4)*PSTR + n0+lr];
                bw[0] = Ku[(kb+lk)*PSTR + n0+lr];
                bw[1] = Ku[(kb+lk+4)*PSTR + n0+lr];
                mma_tf32(au, a[kk], bu);
                mma_tf32(aw, a[kk], bw);
            }
            int r0 = m0 + lr, r1 = r0 + 8, cc = n0 + 2*lk;
            *(__half2*)&g_u_h[obase + r0*256 + cc] = __floats2half2_rn(au[0], au[1]);
            *(__half2*)&g_u_h[obase + r1*256 + cc] = __floats2half2_rn(au[2], au[3]);
            *(__half2*)&g_w_h[obase + r0*256 + cc] = __floats2half2_rn(aw[0], aw[1]);
            *(__half2*)&g_w_h[obase + r1*256 + cc] = __floats2half2_rn(aw[2], aw[3]);
        }
    }
}

// --------------- sequential inter-chunk scan (fp16 tensor-core mma) ---------
#define SFW 40
#define SCAN_SMEM 88576
__global__ __launch_bounds__(256) void scan_kernel()
{
    extern __shared__ char ssm[];
    float*    Sf  = (float*)ssm;                      // [256][40] f32
    unsigned* Sh  = (unsigned*)(ssm + 40960);         // [32][132] words
    unsigned* Tw  = (unsigned*)(ssm + 57856);         // tile (max 20480B)
    float*    Ui  = (float*)(ssm + 78336);            // [32][40] f32
    unsigned* Uh  = (unsigned*)(ssm + 83456);         // [32][20] words
    unsigned* Ah  = (unsigned*)(ssm + 86016);         // [32][20] words
    __half*   ShH = (__half*)Sh;
    __half*   UhH = (__half*)Uh;
    __half*   TwH = (__half*)Tw;

    int blk = blockIdx.x;
    int g  = blk & (NG-1);
    int bh = blk >> 3;
    int b  = bh >> 2;
    int h  = bh & 3;
    int tid = threadIdx.x;
    int wid = tid >> 5, lane = tid & 31;
    int lr = lane >> 2, lk = lane & 3;
    int m0 = (wid >> 2) * 16;
    int n0 = (wid & 3) * 8;

    for (int e = tid; e < 256*SFW; e += 256) Sf[e] = 0.f;
    for (int e = tid; e < 32*132; e += 256) Sh[e] = 0u;
    __syncthreads();

    for (int c = 0; c < NC; c++) {
        size_t base = ((size_t)bh*NC + c) * (32*256);
        size_t abase = ((size_t)bh*NC + c) * 1024;

        for (int e = tid*2; e < 1024; e += 512) {
            int r = e >> 5, j = e & 31;
            unsigned uw = *(const unsigned*)&g_u_h[base + r*256 + g*32 + j];
            float2 uf = __half22float2(*(__half2*)&uw);
            Ui[r*SFW + j] = uf.x; Ui[r*SFW + j + 1] = uf.y;
        }
        {
            int e = tid*4;
            int r = e >> 5, j = e & 31;
            *(uint2*)&Ah[r*20 + (j >> 1)] = *(const uint2*)&g_attn_h[abase + e];
        }
        for (int e = tid*8; e < 8192; e += 2048) {
            int r = e >> 8, jj = e & 255;
            *(uint4*)&TwH[r*264 + jj] = *(const uint4*)&g_w_h[base + e];
        }
        __syncthreads();

        // (1) u_i = u - w@S    (32x32, K=256, fp16)
        {
            float acc[4] = {0.f, 0.f, 0.f, 0.f};
#pragma unroll 4
            for (int kb = 0; kb < 256; kb += 16) {
                int kw = (kb >> 1) + lk;
                unsigned a[4], bf[2];
                a[0] = Tw[(m0+lr)*132 + kw];
                a[1] = Tw[(m0+lr+8)*132 + kw];
                a[2] = Tw[(m0+lr)*132 + kw + 4];
                a[3] = Tw[(m0+lr+8)*132 + kw + 4];
                bf[0] = Sh[(n0+lr)*132 + kw];
                bf[1] = Sh[(n0+lr)*132 + kw + 4];
                mma_f16(acc, a, bf);
            }
            int r0 = m0 + lr, r1 = r0 + 8, cb = n0 + 2*lk;
            float u0 = Ui[r0*SFW+cb]   - acc[0];
            float u1 = Ui[r0*SFW+cb+1] - acc[1];
            float u2 = Ui[r1*SFW+cb]   - acc[2];
            float u3 = Ui[r1*SFW+cb+1] - acc[3];
            UhH[cb*40 + r0]     = __float2half_rn(u0);
            UhH[(cb+1)*40 + r0] = __float2half_rn(u1);
            UhH[cb*40 + r1]     = __float2half_rn(u2);
            UhH[(cb+1)*40 + r1] = __float2half_rn(u3);
        }
        __syncthreads();

        for (int e = tid*8; e < 8192; e += 2048) {
            int r = e >> 8, jj = e & 255;
            *(uint4*)&TwH[r*264 + jj] = *(const uint4*)&g_qn_h[base + e];
        }
        __syncthreads();

        // (2) o = q@S + attn@u_i  -> g_delta (fp16)
        {
            float acc[4] = {0.f, 0.f, 0.f, 0.f};
#pragma unroll 4
            for (int kb = 0; kb < 256; kb += 16) {
                int kw = (kb >> 1) + lk;
                unsigned a[4], bf[2];
                a[0] = Tw[(m0+lr)*132 + kw];
                a[1] = Tw[(m0+lr+8)*132 + kw];
                a[2] = Tw[(m0+lr)*132 + kw + 4];
                a[3] = Tw[(m0+lr+8)*132 + kw + 4];
                bf[0] = Sh[(n0+lr)*132 + kw];
                bf[1] = Sh[(n0+lr)*132 + kw + 4];
                mma_f16(acc, a, bf);
            }
#pragma unroll
            for (int kb = 0; kb < 32; kb += 16) {
                int kw = (kb >> 1) + lk;
                unsigned a[4], bf[2];
                a[0] = Ah[(m0+lr)*20 + kw];
                a[1] = Ah[(m0+lr+8)*20 + kw];
                a[2] = Ah[(m0+lr)*20 + kw + 4];
                a[3] = Ah[(m0+lr+8)*20 + kw + 4];
                bf[0] = Uh[(n0+lr)*20 + kw];
                bf[1] = Uh[(n0+lr)*20 + kw + 4];
                mma_f16(acc, a, bf);
            }
            size_t ob = ((size_t)(b*LL + c*32 + m0 + lr))*DD + h*DV + g*32 + n0 + 2*lk;
            *(__half2*)&g_delta_h[ob]        = __floats2half2_rn(acc[0], acc[1]);
            *(__half2*)&g_delta_h[ob + 8*DD] = __floats2half2_rn(acc[2], acc[3]);
        }
        __syncthreads();

        for (int e = tid*8; e < 8192; e += 2048) {
            int r = e >> 5, jj = e & 31;
            *(uint4*)&TwH[r*40 + jj] = *(const uint4*)&g_knT_h[base + e];
        }
        __syncthreads();

        // (3) S += k^T @ u_i
#pragma unroll
        for (int t = 0; t < 2; t++) {
            int tm = (wid*2 + t) * 16;
#pragma unroll
            for (int tn = 0; tn < 4; tn++) {
                int nn = tn*8;
                int r0 = tm + lr, r1 = r0 + 8, cb = nn + 2*lk;
                float acc[4];
                acc[0] = Sf[r0*SFW+cb]; acc[1] = Sf[r0*SFW+cb+1];
                acc[2] = Sf[r1*SFW+cb]; acc[3] = Sf[r1*SFW+cb+1];
#pragma unroll
                for (int kb = 0; kb < 32; kb += 16) {
                    int kw = (kb >> 1) + lk;
                    unsigned a[4], bf[2];
                    a[0] = Tw[(tm+lr)*20 + kw];
                    a[1] = Tw[(tm+lr+8)*20 + kw];
                    a[2] = Tw[(tm+lr)*20 + kw + 4];
                    a[3] = Tw[(tm+lr+8)*20 + kw + 4];
                    bf[0] = Uh[(nn+lr)*20 + kw];
                    bf[1] = Uh[(nn+lr)*20 + kw + 4];
                    mma_f16(acc, a, bf);
                }
                Sf[r0*SFW+cb] = acc[0]; Sf[r0*SFW+cb+1] = acc[1];
                Sf[r1*SFW+cb] = acc[2]; Sf[r1*SFW+cb+1] = acc[3];
                ShH[cb*264 + r0]     = __float2half_rn(acc[0]);
                ShH[(cb+1)*264 + r0] = __float2half_rn(acc[1]);
                ShH[cb*264 + r1]     = __float2half_rn(acc[2]);
                ShH[(cb+1)*264 + r1] = __float2half_rn(acc[3]);
            }
        }
        __syncthreads();
    }
}

// ------------------- per-(head,channel) FIR conv (fp16 io) ------------------
template<int K>
__global__ __launch_bounds__(256) void fir_kernel(
    const float* __restrict__ fw, __half* __restrict__ y)
{
    __shared__ float2 vbuf[(128 + K - 1) * 16];
    __shared__ float2 wbuf[16 * K];
    int bh = blockIdx.x;
    int b = bh / HH, h = bh % HH;
    int l0 = blockIdx.y * 128;
    int d0 = blockIdx.z * 32;
    int tid = threadIdx.x;

    for (int idx = tid; idx < 16*K; idx += 256) {
        int dp = idx / K, t = idx % K;
        float2 wv;
        wv.x = fw[(size_t)(h*DV + d0 + 2*dp)*K + t];
        wv.y = fw[(size_t)(h*DV + d0 + 2*dp + 1)*K + t];
        wbuf[dp*K + t] = wv;
    }
    for (int idx = tid; idx < (128 + K - 1)*16; idx += 256) {
        int lrr = idx >> 4, dp = idx & 15;
        int l = l0 - (K - 1) + lrr;
        vbuf[idx] = (l >= 0)
            ? __half22float2(*(const __half2*)&g_vc_h[((size_t)(b*LL + l))*DD + h*DV + d0 + 2*dp])
            : make_float2(0.f, 0.f);
    }
    __syncthreads();

    int dp = tid & 15;
    int lr0 = (tid >> 4) * 8;
    for (int m = 0; m < 8; m++) {
        int lrr = lr0 + m;
        float2 acc = {0.f, 0.f};
#pragma unroll
        for (int t = 0; t < K; t++) {
            float2 v = vbuf[(lrr + t)*16 + dp];
            float2 wv = wbuf[dp*K + t];
            acc.x = fmaf(v.x, wv.x, acc.x);
            acc.y = fmaf(v.y, wv.y, acc.y);
        }
        *(__half2*)&y[((size_t)(b*LL + l0 + lrr))*DD + h*DV + d0 + 2*dp]
            = __floats2half2_rn(acc.x, acc.y);
    }
}

// ------------- gate input assembly (hs + stats), stored as fp16 -------------
__global__ __launch_bounds__(256) void stats_kernel(const float* __restrict__ hs)
{
    int n = blockIdx.x, tid = threadIdx.x;
    {
        int i = tid * 4;
        float4 v = *(const float4*)&hs[(size_t)n*DD + i];
        __half2 lo = __floats2half2_rn(v.x, v.y);
        __half2 hi = __floats2half2_rn(v.z, v.w);
        uint2 o = {*(unsigned*)&lo, *(unsigned*)&hi};
        *(uint2*)&g_gatein_h[(size_t)n*GINP + i] = o;
    }
    if (tid < 32) g_gatein_h[(size_t)n*GINP + GIN + tid] = __float2half_rn(0.f);
    int warp = tid >> 5, lane = tid & 31;
    for (int rep = 0; rep < 2; rep++) {
        int combo = warp*2 + rep;
        int path = combo >> 2, h = combo & 3;
        const __half* p;
        if      (path == 0) p = g_short_h;
        else if (path == 1) p = g_long_h;
        else if (path == 2) p = g_delta_h;
        else                p = g_vc_h;
        p += (size_t)n*DD + h*DV;
        float s1 = 0.f, s2 = 0.f;
        for (int j = lane; j < 256; j += 32) {
            float x = __half2float(p[j]); s1 += x; s2 += x*x;
        }
#pragma unroll
        for (int st = 16; st > 0; st >>= 1) {
            s1 += __shfl_down_sync(0xffffffffu, s1, st);
            s2 += __shfl_down_sync(0xffffffffu, s2, st);
        }
        if (lane == 0) {
            float m  = s1 * (1.f/256.f);
            float va = s2 * (1.f/256.f) - m*m;
            g_gatein_h[(size_t)n*GINP + DD + path*8 + h*2]     = __float2half_rn(m);
            g_gatein_h[(size_t)n*GINP + DD + path*8 + h*2 + 1] = __float2half_rn(va);
        }
    }
}

// ------------------------- gate2 + softmax + floor --------------------------
__global__ __launch_bounds__(256) void gate2_kernel(
    const float* __restrict__ w2, const float* __restrict__ log_temp,
    const float* __restrict__ base_bias, const float* __restrict__ floor_raw)
{
    __shared__ float hrow[HID];
    __shared__ float lg[16];
    int n = blockIdx.x, tid = threadIdx.x;
    for (int i = tid; i < HID; i += 256) hrow[i] = g_hmid[(size_t)n*HID + i];
    __syncthreads();
    int warp = tid >> 5, lane = tid & 31;
    for (int rep = 0; rep < 2; rep++) {
        int o = warp*2 + rep;
        const float* wr = w2 + (size_t)o*HID;
        float s = 0.f;
        for (int i = lane; i < HID; i += 32) s = fmaf(hrow[i], wr[i], s);
#pragma unroll
        for (int st = 16; st > 0; st >>= 1) s += __shfl_down_sync(0xffffffffu, s, st);
        if (lane == 0) lg[o] = s;
    }
    __syncthreads();
    if (tid < 4) {
        int h = tid;
        float temp = log1pf(expf(log_temp[h])) + 1e-4f;
        float z[4], m = -1e30f;
#pragma unroll
        for (int i = 0; i < 4; i++) {
            z[i] = (lg[h*4+i] + base_bias[h*4+i]) / temp;
            m = fmaxf(m, z[i]);
        }
        float e[4], s = 0.f;
#pragma unroll
        for (int i = 0; i < 4; i++) { e[i] = expf(z[i] - m); s += e[i]; }
        float p[4], s2 = 0.f;
#pragma unroll
        for (int i = 0; i < 4; i++) {
            p[i] = e[i] / s;
            float f = 0.05f / (1.f + expf(-floor_raw[h*4+i]));
            p[i] = fmaxf(p[i], f);
            s2 += p[i];
        }
#pragma unroll
        for (int i = 0; i < 4; i++) g_probs[(size_t)n*16 + h*4 + i] = p[i] / s2;
    }
}

// ------------- path mix + RMS norm, output stored as fp16 -------------------
__global__ __launch_bounds__(256) void mix_kernel(const float* __restrict__ onorm)
{
    __shared__ float pr[16];
    __shared__ float wsum[8];
    int n = blockIdx.x, tid = threadIdx.x;
    if (tid < 16) pr[tid] = g_probs[(size_t)n*16 + tid];
    __syncthreads();
    int h = tid >> 6;
    int dd = (tid & 63) * 4;
    size_t pb = (size_t)n*DD + h*DV + dd;
    uint2 sraw = *(const uint2*)&g_short_h[pb];
    uint2 lraw = *(const uint2*)&g_long_h[pb];
    uint2 draw = *(const uint2*)&g_delta_h[pb];
    uint2 vraw = *(const uint2*)&g_vc_h[pb];
    float2 sa = __half22float2(*(__half2*)&sraw.x), sb = __half22float2(*(__half2*)&sraw.y);
    float2 la = __half22float2(*(__half2*)&lraw.x), lb = __half22float2(*(__half2*)&lraw.y);
    float2 da = __half22float2(*(__half2*)&draw.x), db = __half22float2(*(__half2*)&draw.y);
    float2 va = __half22float2(*(__half2*)&vraw.x), vb = __half22float2(*(__half2*)&vraw.y);
    float p0 = pr[h*4+0], p1 = pr[h*4+1], p2 = pr[h*4+2], p3 = pr[h*4+3];
    float o[4];
    o[0] = p0*sa.x + p1*la.x + p2*da.x + p3*va.x;
    o[1] = p0*sa.y + p1*la.y + p2*da.y + p3*va.y;
    o[2] = p0*sb.x + p1*lb.x + p2*db.x + p3*vb.x;
    o[3] = p0*sb.y + p1*lb.y + p2*db.y + p3*vb.y;
    float ss = o[0]*o[0] + o[1]*o[1] + o[2]*o[2] + o[3]*o[3];
#pragma unroll
    for (int st = 16; st > 0; st >>= 1) ss += __shfl_down_sync(0xffffffffu, ss, st);
    int warp = tid >> 5, lane = tid & 31;
    if (lane == 0) wsum[warp] = ss;
    __syncthreads();
    float tot = wsum[h*2] + wsum[h*2+1];
    float scale = rsqrtf(tot * (1.f/256.f) + 1e-5f);
    __half2 h0 = __floats2half2_rn(o[0]*scale*onorm[dd],   o[1]*scale*onorm[dd+1]);
    __half2 h1 = __floats2half2_rn(o[2]*scale*onorm[dd+2], o[3]*scale*onorm[dd+3]);
    uint2 pk = {*(unsigned*)&h0, *(unsigned*)&h1};
    *(uint2*)&g_mix_h[pb] = pk;
}

// ------------------------- launch ------------------------------------------
extern "C" void kernel_launch(void* const* d_in, const int* in_sizes, int n_in,
                              void* d_out, int out_size)
{
    const float* hs        = (const float*)d_in[0];
    const float* Wq        = (const float*)d_in[1];
    const float* Wk        = (const float*)d_in[2];
    const float* Wv        = (const float*)d_in[3];
    const float* Wb        = (const float*)d_in[4];
    const float* qconv_w   = (const float*)d_in[5];
    const float* kconv_w   = (const float*)d_in[6];
    const float* vconv_w   = (const float*)d_in[7];
    const float* fir_s     = (const float*)d_in[8];
    const float* fir_l     = (const float*)d_in[9];
    const float* gate_w1   = (const float*)d_in[10];
    const float* gate_b1   = (const float*)d_in[11];
    const float* gate_w2   = (const float*)d_in[12];
    const float* log_temp  = (const float*)d_in[13];
    const float* base_bias = (const float*)d_in[14];
    const float* floor_raw = (const float*)d_in[15];
    const float* onorm_w   = (const float*)d_in[16];
    const float* Wo        = (const float*)d_in[17];
    float* out = (float*)d_out;

    void *p_qlin, *p_klin, *p_vlin, *p_qc, *p_kc, *p_vc, *p_hmid, *p_short, *p_long;
    void *p_hsh, *p_wqh, *p_wkh, *p_wvh, *p_woh, *p_gateinh, *p_mixh;
    cudaGetSymbolAddress(&p_qlin, g_qlin_h);
    cudaGetSymbolAddress(&p_klin, g_klin_h);
    cudaGetSymbolAddress(&p_vlin, g_vlin_h);
    cudaGetSymbolAddress(&p_qc, g_qc_h);
    cudaGetSymbolAddress(&p_kc, g_kc_h);
    cudaGetSymbolAddress(&p_vc, g_vc_h);
    cudaGetSymbolAddress(&p_hmid, g_hmid);
    cudaGetSymbolAddress(&p_short, g_short_h);
    cudaGetSymbolAddress(&p_long, g_long_h);
    cudaGetSymbolAddress(&p_hsh, g_hs_h);
    cudaGetSymbolAddress(&p_wqh, g_wq_h);
    cudaGetSymbolAddress(&p_wkh, g_wk_h);
    cudaGetSymbolAddress(&p_wvh, g_wv_h);
    cudaGetSymbolAddress(&p_woh, g_wo_h);
    void *p_gw1h;
    cudaGetSymbolAddress(&p_gw1h, g_gw1_h);
    cudaGetSymbolAddress(&p_gateinh, g_gatein_h);
    cudaGetSymbolAddress(&p_mixh, g_mix_h);

    cudaFuncSetAttribute(scan_kernel,
        cudaFuncAttributeMaxDynamicSharedMemorySize, SCAN_SMEM);
    cudaFuncSetAttribute(precompute_kernel,
        cudaFuncAttributeMaxDynamicSharedMemorySize, PSMEM);
    cudaFuncSetAttribute(hgemm,
        cudaFuncAttributeMaxDynamicSharedMemorySize, HGEMM_SMEM);

    dim3 blk(256);

    // 0. pre-convert hs + weights to fp16 (gate_w1 padded separately)
    cvt_h6<<<dim3(NROW*DD/1024, 6), blk>>>(
        hs, (__half*)p_hsh, NROW*DD,
        Wq, (__half*)p_wqh, DD*DD,
        Wk, (__half*)p_wkh, DD*DD,
        Wv, (__half*)p_wvh, DD*DD,
        Wo, (__half*)p_woh, DD*DD,
        nullptr, nullptr, 0);
    cvt_gw1pad<<<(HID*GINP/4 + 255)/256, blk>>>(gate_w1);

    // q/k/v projections — fp16 outputs (mode 2)
    hgemm<<<dim3(DD/128, NROW/128, 3), blk, HGEMM_SMEM>>>(
        (const __half*)p_hsh,
        (const __half*)p_wqh, (const __half*)p_wkh, (const __half*)p_wvh,
        (float*)p_qlin, (float*)p_klin, (float*)p_vlin,
        nullptr, NROW, DD, DD, 2);

    // causal conv4 + SiLU (fp16 io, 2 elems/thread)
    conv4_silu3<<<dim3(NROW*DD/512, 3), blk>>>(
        (const __half*)p_qlin, (const __half*)p_klin, (const __half*)p_vlin,
        qconv_w, kconv_w, vconv_w,
        (__half*)p_qc, (__half*)p_kc, (__half*)p_vc);

    // beta
    beta_kernel<<<NROW, 128>>>(hs, Wb);

    // delta-rule
    precompute_kernel<<<BB*HH*NC, blk, PSMEM>>>();
    scan_kernel<<<BB*HH*NG, blk, SCAN_SMEM>>>();

    // FIR paths
    fir_kernel<3><<<dim3(BB*HH, LL/128, DV/32), blk>>>(fir_s, (__half*)p_short);
    fir_kernel<63><<<dim3(BB*HH, LL/128, DV/32), blk>>>(fir_l, (__half*)p_long);

    // gate
    stats_kernel<<<NROW, blk>>>(hs);
    hgemm<<<dim3(HID/128, NROW/128, 1), blk, HGEMM_SMEM>>>(
        (const __half*)p_gateinh,
        (const __half*)p_gw1h, nullptr, nullptr,
        (float*)p_hmid, nullptr, nullptr,
        gate_b1, NROW, HID, GINP, 1);
    gate2_kernel<<<NROW, blk>>>(gate_w2, log_temp, base_bias, floor_raw);

    // mix + RMS norm
    mix_kernel<<<NROW, blk>>>(onorm_w);

    // output projection (fp32 out)
    hgemm<<<dim3(DD/128, NROW/128, 1), blk, HGEMM_SMEM>>>(
        (const __half*)p_mixh,
        (const __half*)p_woh, nullptr, nullptr,
        out, nullptr, nullptr,
        nullptr, NROW, DD, DD, 0);
}